// round 1
// baseline (speedup 1.0000x reference)
#include <cuda_runtime.h>
#include <math.h>

#define H_DIM 128
#define TE 64          // edges (rows) per block tile
#define BS1 129        // padded row stride for activation buffers

#define MAX_B 2
#define MAX_N 20000

// Scratch (allocation-free rule: __device__ globals)
__device__ float g_msg_acc[(size_t)MAX_B * MAX_N * H_DIM];   // ~20.5 MB
__device__ float g_pos_upd[(size_t)MAX_B * MAX_N * 3];

__device__ __forceinline__ float silu_f(float v) {
    return v / (1.0f + expf(-v));
}

// ---------------------------------------------------------------------------
// Edge kernel: for a tile of 64 edges (one batch), compute
//   messages = silu([h_src|h_dst|dist] @ W1 + b1) @ W2 + b2
//   atomicAdd msg_acc[dst] += messages * invdeg[dst]
//   hidden   = silu(messages @ Wp1 + bp1)
//   w        = tanh(hidden . wp2 + bp2)
//   atomicAdd pos_upd[dst] += w * rel_pos
// Three SGEMMs (M=64, N=128, K=257/128/128) with SMEM-staged weights.
// ---------------------------------------------------------------------------
__global__ void __launch_bounds__(256, 2)
edge_kernel(const float* __restrict__ feat, const float* __restrict__ pos,
            const int*   __restrict__ ei,   const float* __restrict__ deg,
            const float* __restrict__ w1,  const float* __restrict__ b1,
            const float* __restrict__ w2,  const float* __restrict__ b2,
            const float* __restrict__ wp1, const float* __restrict__ bp1,
            const float* __restrict__ wp2, const float* __restrict__ bp2,
            float* __restrict__ msg_acc, float* __restrict__ pos_upd,
            int nE, int N)
{
    extern __shared__ float sm[];
    float* sB      = sm;                    // [64][128] weight chunk
    float* sb1     = sB  + TE * H_DIM;      // [64][129] activations
    float* sb2     = sb1 + TE * BS1;        // [64][129] A-stage / messages
    float* s_rel   = sb2 + TE * BS1;        // [64*3]
    float* s_dist  = s_rel + 3 * TE;        // [64]
    float* s_invdeg= s_dist + TE;           // [64]
    float* s_wp2   = s_invdeg + TE;         // [128]
    int*   s_src   = (int*)(s_wp2 + H_DIM); // [64]
    int*   s_dst   = s_src + TE;            // [64]

    const int tid = threadIdx.x;
    const int tx  = tid & 15;
    const int ty  = tid >> 4;
    const int b   = blockIdx.y;
    const int e0  = blockIdx.x * TE;
    const int c0  = tx * 8;
    const int r0  = ty * 4;

    // per-edge preamble
    if (tid < TE) {
        int e = e0 + tid;
        int s = 0, d = 0;
        float x0 = 0.f, x1 = 0.f, x2 = 0.f, dist = 0.f, inv = 0.f;
        if (e < nE) {
            s = ei[e];
            d = ei[nE + e];
            const float* ps = pos + ((size_t)b * N + s) * 3;
            const float* pd = pos + ((size_t)b * N + d) * 3;
            x0 = ps[0] - pd[0];
            x1 = ps[1] - pd[1];
            x2 = ps[2] - pd[2];
            dist = sqrtf(x0 * x0 + x1 * x1 + x2 * x2);
            inv  = 1.0f / fmaxf(deg[d], 1.0f);
        }
        s_src[tid] = s;
        s_dst[tid] = d;
        s_rel[tid * 3 + 0] = x0;
        s_rel[tid * 3 + 1] = x1;
        s_rel[tid * 3 + 2] = x2;
        s_dist[tid]   = dist;
        s_invdeg[tid] = inv;
    }
    if (tid < H_DIM) s_wp2[tid] = wp2[tid];
    __syncthreads();

    float acc[4][8];
    #pragma unroll
    for (int i = 0; i < 4; i++)
        #pragma unroll
        for (int j = 0; j < 8; j++) acc[i][j] = 0.f;

    // ---------------- GEMM1: msg_in[64][257] @ w1[257][128] ----------------
    for (int seg = 0; seg < 4; ++seg) {
        // stage A chunk (64x64) from gathered features
        #pragma unroll
        for (int p = 0; p < 16; ++p) {
            int idx = p * 256 + tid;
            int r = idx >> 6, c = idx & 63;
            int node = (seg < 2) ? s_src[r] : s_dst[r];
            int col  = ((seg & 1) << 6) | c;
            sb2[r * BS1 + c] = feat[((size_t)b * N + node) * H_DIM + col];
        }
        // stage B chunk (64x128) from w1
        {
            const float4* wv = (const float4*)(w1 + (size_t)seg * 64 * H_DIM);
            float4* sBv = (float4*)sB;
            #pragma unroll
            for (int p = 0; p < 8; ++p) sBv[p * 256 + tid] = wv[p * 256 + tid];
        }
        __syncthreads();
        #pragma unroll 8
        for (int k = 0; k < 64; ++k) {
            float av[4];
            #pragma unroll
            for (int i = 0; i < 4; i++) av[i] = sb2[(r0 + i) * BS1 + k];
            float4 bl = *(const float4*)&sB[k * H_DIM + c0];
            float4 bh = *(const float4*)&sB[k * H_DIM + c0 + 4];
            #pragma unroll
            for (int i = 0; i < 4; i++) {
                acc[i][0] += av[i] * bl.x; acc[i][1] += av[i] * bl.y;
                acc[i][2] += av[i] * bl.z; acc[i][3] += av[i] * bl.w;
                acc[i][4] += av[i] * bh.x; acc[i][5] += av[i] * bh.y;
                acc[i][6] += av[i] * bh.z; acc[i][7] += av[i] * bh.w;
            }
        }
        __syncthreads();
    }
    // k=256 (dist) term + bias + silu -> sb1
    {
        float wl[8], bs[8];
        #pragma unroll
        for (int j = 0; j < 8; j++) {
            wl[j] = w1[256 * H_DIM + c0 + j];
            bs[j] = b1[c0 + j];
        }
        #pragma unroll
        for (int i = 0; i < 4; i++) {
            int r = r0 + i;
            float dd = s_dist[r];
            #pragma unroll
            for (int j = 0; j < 8; j++) {
                float v = acc[i][j] + dd * wl[j] + bs[j];
                sb1[r * BS1 + c0 + j] = silu_f(v);
            }
        }
    }
    __syncthreads();

    // ---------------- GEMM2: hidden[64][128] @ w2[128][128] ----------------
    #pragma unroll
    for (int i = 0; i < 4; i++)
        #pragma unroll
        for (int j = 0; j < 8; j++) acc[i][j] = 0.f;

    for (int hseg = 0; hseg < 2; ++hseg) {
        const float4* wv = (const float4*)(w2 + (size_t)hseg * 64 * H_DIM);
        float4* sBv = (float4*)sB;
        #pragma unroll
        for (int p = 0; p < 8; ++p) sBv[p * 256 + tid] = wv[p * 256 + tid];
        __syncthreads();
        #pragma unroll 8
        for (int k = 0; k < 64; ++k) {
            float av[4];
            #pragma unroll
            for (int i = 0; i < 4; i++) av[i] = sb1[(r0 + i) * BS1 + hseg * 64 + k];
            float4 bl = *(const float4*)&sB[k * H_DIM + c0];
            float4 bh = *(const float4*)&sB[k * H_DIM + c0 + 4];
            #pragma unroll
            for (int i = 0; i < 4; i++) {
                acc[i][0] += av[i] * bl.x; acc[i][1] += av[i] * bl.y;
                acc[i][2] += av[i] * bl.z; acc[i][3] += av[i] * bl.w;
                acc[i][4] += av[i] * bh.x; acc[i][5] += av[i] * bh.y;
                acc[i][6] += av[i] * bh.z; acc[i][7] += av[i] * bh.w;
            }
        }
        __syncthreads();
    }
    // messages: +bias, store to sb2, scatter into msg_acc
    {
        float bs[8];
        #pragma unroll
        for (int j = 0; j < 8; j++) bs[j] = b2[c0 + j];
        #pragma unroll
        for (int i = 0; i < 4; i++) {
            int r = r0 + i;
            int d = s_dst[r];
            float inv = s_invdeg[r];
            float* mp = msg_acc + ((size_t)b * N + d) * H_DIM + c0;
            #pragma unroll
            for (int j = 0; j < 8; j++) {
                float m = acc[i][j] + bs[j];
                sb2[r * BS1 + c0 + j] = m;
                atomicAdd(&mp[j], m * inv);
            }
        }
    }
    __syncthreads();

    // ---------------- GEMM3: messages @ wp1[128][128], silu -> sb1 ---------
    #pragma unroll
    for (int i = 0; i < 4; i++)
        #pragma unroll
        for (int j = 0; j < 8; j++) acc[i][j] = 0.f;

    for (int hseg = 0; hseg < 2; ++hseg) {
        const float4* wv = (const float4*)(wp1 + (size_t)hseg * 64 * H_DIM);
        float4* sBv = (float4*)sB;
        #pragma unroll
        for (int p = 0; p < 8; ++p) sBv[p * 256 + tid] = wv[p * 256 + tid];
        __syncthreads();
        #pragma unroll 8
        for (int k = 0; k < 64; ++k) {
            float av[4];
            #pragma unroll
            for (int i = 0; i < 4; i++) av[i] = sb2[(r0 + i) * BS1 + hseg * 64 + k];
            float4 bl = *(const float4*)&sB[k * H_DIM + c0];
            float4 bh = *(const float4*)&sB[k * H_DIM + c0 + 4];
            #pragma unroll
            for (int i = 0; i < 4; i++) {
                acc[i][0] += av[i] * bl.x; acc[i][1] += av[i] * bl.y;
                acc[i][2] += av[i] * bl.z; acc[i][3] += av[i] * bl.w;
                acc[i][4] += av[i] * bh.x; acc[i][5] += av[i] * bh.y;
                acc[i][6] += av[i] * bh.z; acc[i][7] += av[i] * bh.w;
            }
        }
        __syncthreads();
    }
    {
        float bs[8];
        #pragma unroll
        for (int j = 0; j < 8; j++) bs[j] = bp1[c0 + j];
        #pragma unroll
        for (int i = 0; i < 4; i++) {
            int r = r0 + i;
            #pragma unroll
            for (int j = 0; j < 8; j++) {
                float v = acc[i][j] + bs[j];
                sb1[r * BS1 + c0 + j] = silu_f(v);
            }
        }
    }
    __syncthreads();

    // ---------------- dot(hidden, wp2) -> tanh -> pos scatter --------------
    {
        int r = tid >> 2;
        int part = tid & 3;
        float s = 0.f;
        #pragma unroll 8
        for (int j = part; j < H_DIM; j += 4)
            s += sb1[r * BS1 + j] * s_wp2[j];
        s += __shfl_xor_sync(0xFFFFFFFFu, s, 1);
        s += __shfl_xor_sync(0xFFFFFFFFu, s, 2);
        if (part == 0 && (e0 + r) < nE) {
            float w = tanhf(s + bp2[0]);
            int d = s_dst[r];
            float* pp = pos_upd + ((size_t)b * N + d) * 3;
            atomicAdd(&pp[0], w * s_rel[r * 3 + 0]);
            atomicAdd(&pp[1], w * s_rel[r * 3 + 1]);
            atomicAdd(&pp[2], w * s_rel[r * 3 + 2]);
        }
    }
}

// ---------------------------------------------------------------------------
// Node kernel: feat_update = silu([feat|msg_acc] @ w_upd1 + b1) @ w_upd2 + b2
//              out_feat = feat + feat_update
// ---------------------------------------------------------------------------
__global__ void __launch_bounds__(256, 2)
node_kernel(const float* __restrict__ feat, const float* __restrict__ msg_acc,
            const float* __restrict__ w1, const float* __restrict__ b1,
            const float* __restrict__ w2, const float* __restrict__ b2,
            float* __restrict__ outf, int nRows)
{
    extern __shared__ float sm[];
    float* sB  = sm;
    float* sb1 = sB  + TE * H_DIM;
    float* sb2 = sb1 + TE * BS1;

    const int tid = threadIdx.x;
    const int tx  = tid & 15;
    const int ty  = tid >> 4;
    const int c0  = tx * 8;
    const int r0  = ty * 4;
    const int g0  = blockIdx.x * TE;

    float acc[4][8];
    #pragma unroll
    for (int i = 0; i < 4; i++)
        #pragma unroll
        for (int j = 0; j < 8; j++) acc[i][j] = 0.f;

    for (int seg = 0; seg < 4; ++seg) {
        const float* src = (seg < 2) ? feat : msg_acc;
        int colbase = (seg & 1) << 6;
        #pragma unroll
        for (int p = 0; p < 16; ++p) {
            int idx = p * 256 + tid;
            int r = idx >> 6, c = idx & 63;
            int g = g0 + r;
            sb2[r * BS1 + c] = (g < nRows)
                ? src[(size_t)g * H_DIM + colbase + c] : 0.f;
        }
        {
            const float4* wv = (const float4*)(w1 + (size_t)seg * 64 * H_DIM);
            float4* sBv = (float4*)sB;
            #pragma unroll
            for (int p = 0; p < 8; ++p) sBv[p * 256 + tid] = wv[p * 256 + tid];
        }
        __syncthreads();
        #pragma unroll 8
        for (int k = 0; k < 64; ++k) {
            float av[4];
            #pragma unroll
            for (int i = 0; i < 4; i++) av[i] = sb2[(r0 + i) * BS1 + k];
            float4 bl = *(const float4*)&sB[k * H_DIM + c0];
            float4 bh = *(const float4*)&sB[k * H_DIM + c0 + 4];
            #pragma unroll
            for (int i = 0; i < 4; i++) {
                acc[i][0] += av[i] * bl.x; acc[i][1] += av[i] * bl.y;
                acc[i][2] += av[i] * bl.z; acc[i][3] += av[i] * bl.w;
                acc[i][4] += av[i] * bh.x; acc[i][5] += av[i] * bh.y;
                acc[i][6] += av[i] * bh.z; acc[i][7] += av[i] * bh.w;
            }
        }
        __syncthreads();
    }
    {
        float bs[8];
        #pragma unroll
        for (int j = 0; j < 8; j++) bs[j] = b1[c0 + j];
        #pragma unroll
        for (int i = 0; i < 4; i++) {
            int r = r0 + i;
            #pragma unroll
            for (int j = 0; j < 8; j++) {
                float v = acc[i][j] + bs[j];
                sb1[r * BS1 + c0 + j] = silu_f(v);
            }
        }
    }
    __syncthreads();

    #pragma unroll
    for (int i = 0; i < 4; i++)
        #pragma unroll
        for (int j = 0; j < 8; j++) acc[i][j] = 0.f;

    for (int hseg = 0; hseg < 2; ++hseg) {
        const float4* wv = (const float4*)(w2 + (size_t)hseg * 64 * H_DIM);
        float4* sBv = (float4*)sB;
        #pragma unroll
        for (int p = 0; p < 8; ++p) sBv[p * 256 + tid] = wv[p * 256 + tid];
        __syncthreads();
        #pragma unroll 8
        for (int k = 0; k < 64; ++k) {
            float av[4];
            #pragma unroll
            for (int i = 0; i < 4; i++) av[i] = sb1[(r0 + i) * BS1 + hseg * 64 + k];
            float4 bl = *(const float4*)&sB[k * H_DIM + c0];
            float4 bh = *(const float4*)&sB[k * H_DIM + c0 + 4];
            #pragma unroll
            for (int i = 0; i < 4; i++) {
                acc[i][0] += av[i] * bl.x; acc[i][1] += av[i] * bl.y;
                acc[i][2] += av[i] * bl.z; acc[i][3] += av[i] * bl.w;
                acc[i][4] += av[i] * bh.x; acc[i][5] += av[i] * bh.y;
                acc[i][6] += av[i] * bh.z; acc[i][7] += av[i] * bh.w;
            }
        }
        __syncthreads();
    }
    {
        float bs[8];
        #pragma unroll
        for (int j = 0; j < 8; j++) bs[j] = b2[c0 + j];
        #pragma unroll
        for (int i = 0; i < 4; i++) {
            int g = g0 + r0 + i;
            if (g < nRows) {
                #pragma unroll
                for (int j = 0; j < 8; j++) {
                    size_t o = (size_t)g * H_DIM + c0 + j;
                    outf[o] = feat[o] + acc[i][j] + bs[j];
                }
            }
        }
    }
}

__global__ void pos_kernel(const float* __restrict__ pos,
                           const float* __restrict__ pos_upd,
                           float* __restrict__ out, int n)
{
    int i = blockIdx.x * blockDim.x + threadIdx.x;
    if (i < n) out[i] = pos[i] + 0.5f * pos_upd[i];
}

extern "C" void kernel_launch(void* const* d_in, const int* in_sizes, int n_in,
                              void* d_out, int out_size)
{
    const float* feat   = (const float*)d_in[0];
    const float* pos    = (const float*)d_in[1];
    const int*   ei_up  = (const int*)d_in[2];
    const int*   ei_dn  = (const int*)d_in[3];
    const float* deg_up = (const float*)d_in[4];
    const float* deg_dn = (const float*)d_in[5];

    const float* w1u  = (const float*)d_in[6];
    const float* b1u  = (const float*)d_in[7];
    const float* w2u  = (const float*)d_in[8];
    const float* b2u  = (const float*)d_in[9];
    const float* wp1u = (const float*)d_in[10];
    const float* bp1u = (const float*)d_in[11];
    const float* wp2u = (const float*)d_in[12];
    const float* bp2u = (const float*)d_in[13];

    const float* w1d  = (const float*)d_in[14];
    const float* b1d  = (const float*)d_in[15];
    const float* w2d  = (const float*)d_in[16];
    const float* b2d  = (const float*)d_in[17];
    const float* wp1d = (const float*)d_in[18];
    const float* bp1d = (const float*)d_in[19];
    const float* wp2d = (const float*)d_in[20];
    const float* bp2d = (const float*)d_in[21];

    const float* wu1 = (const float*)d_in[22];
    const float* bu1 = (const float*)d_in[23];
    const float* wu2 = (const float*)d_in[24];
    const float* bu2 = (const float*)d_in[25];

    int E = in_sizes[2] / 2;
    int N = in_sizes[4];
    int B = in_sizes[0] / (N * H_DIM);

    float* msg_acc = nullptr;
    float* pos_upd = nullptr;
    cudaGetSymbolAddress((void**)&msg_acc, g_msg_acc);
    cudaGetSymbolAddress((void**)&pos_upd, g_pos_upd);

    size_t featN = (size_t)B * N * H_DIM;
    size_t posN  = (size_t)B * N * 3;
    cudaMemsetAsync(msg_acc, 0, featN * sizeof(float));
    cudaMemsetAsync(pos_upd, 0, posN * sizeof(float));

    int smemE = (TE * H_DIM + 2 * TE * BS1 + 3 * TE + TE + TE + H_DIM) * 4
              + 2 * TE * 4;
    int smemN = (TE * H_DIM + 2 * TE * BS1) * 4;
    cudaFuncSetAttribute(edge_kernel,
                         cudaFuncAttributeMaxDynamicSharedMemorySize, smemE);
    cudaFuncSetAttribute(node_kernel,
                         cudaFuncAttributeMaxDynamicSharedMemorySize, smemN);

    dim3 egrid((E + TE - 1) / TE, B);
    edge_kernel<<<egrid, 256, smemE>>>(feat, pos, ei_up, deg_up,
        w1u, b1u, w2u, b2u, wp1u, bp1u, wp2u, bp2u, msg_acc, pos_upd, E, N);
    edge_kernel<<<egrid, 256, smemE>>>(feat, pos, ei_dn, deg_dn,
        w1d, b1d, w2d, b2d, wp1d, bp1d, wp2d, bp2d, msg_acc, pos_upd, E, N);

    int nRows = B * N;
    node_kernel<<<(nRows + TE - 1) / TE, 256, smemN>>>(
        feat, msg_acc, wu1, bu1, wu2, bu2, (float*)d_out, nRows);

    int pn = B * N * 3;
    pos_kernel<<<(pn + 255) / 256, 256>>>(
        pos, pos_upd, (float*)d_out + featN, pn);
}

// round 2
// speedup vs baseline: 2.7494x; 2.7494x over previous
#include <cuda_runtime.h>
#include <math.h>

#define H_DIM 128
#define TE 64          // rows per block tile
#define BS1 129        // padded row stride for activation buffers

#define MAX_B 2
#define MAX_N 20000
#define MAX_BN (MAX_B * MAX_N)

// ---------------------------------------------------------------------------
// Scratch (allocation-free rule: __device__ globals)
// ---------------------------------------------------------------------------
__device__ __align__(128) float g_pre[4][(size_t)MAX_BN * H_DIM];   // a_up,b_up,a_dn,b_dn
__device__ __align__(128) float g_hacc[2][(size_t)MAX_BN * H_DIM];  // hidden*inv per dst
__device__ __align__(128) float g_einv[2][MAX_N];                    // inv*cnt per dst
__device__ __align__(128) float g_pos_upd[(size_t)MAX_BN * 3];
__device__ __align__(128) float g_Cp[2][H_DIM * H_DIM];   // W2@Wp1
__device__ __align__(128) float g_Cu[2][H_DIM * H_DIM];   // W2@Wu1_bot
__device__ __align__(128) float g_bpc[2][H_DIM];          // b2@Wp1 + bp1
__device__ __align__(128) float g_bcu[2][H_DIM];          // b2@Wu1_bot

__device__ __forceinline__ float silu_f(float v) {
    return __fdividef(v, 1.0f + __expf(-v));
}

// ---------------------------------------------------------------------------
// combine_kernel: tiny 128x128x128 GEMMs for folded weights + biases
//   y=0: Cp_up = w2u@wp1u, bpc_up = b2u@wp1u + bp1u
//   y=1: Cp_dn,  bpc_dn
//   y=2: Cu_up = w2u@wu1_bot, bcu_up = b2u@wu1_bot
//   y=3: Cu_dn,  bcu_dn
// grid (129, 4), block 128. Row 128 = bias row.
// ---------------------------------------------------------------------------
__global__ void combine_kernel(
    const float* __restrict__ w2u, const float* __restrict__ wp1u,
    const float* __restrict__ b2u, const float* __restrict__ bp1u,
    const float* __restrict__ w2d, const float* __restrict__ wp1d,
    const float* __restrict__ b2d, const float* __restrict__ bp1d,
    const float* __restrict__ wu1,
    float* __restrict__ Cp0, float* __restrict__ Cp1,
    float* __restrict__ Cu0, float* __restrict__ Cu1,
    float* __restrict__ bpc0, float* __restrict__ bpc1,
    float* __restrict__ bcu0, float* __restrict__ bcu1)
{
    const float* wu1b = wu1 + 128 * H_DIM;
    const float* A; const float* Bm; const float* bvec; const float* badd;
    float* C; float* bout;
    switch (blockIdx.y) {
        case 0:  A = w2u; Bm = wp1u; bvec = b2u; badd = bp1u; C = Cp0; bout = bpc0; break;
        case 1:  A = w2d; Bm = wp1d; bvec = b2d; badd = bp1d; C = Cp1; bout = bpc1; break;
        case 2:  A = w2u; Bm = wu1b; bvec = b2u; badd = 0;    C = Cu0; bout = bcu0; break;
        default: A = w2d; Bm = wu1b; bvec = b2d; badd = 0;    C = Cu1; bout = bcu1; break;
    }
    int i = blockIdx.x;
    int j = threadIdx.x;
    const float* arow = (i < H_DIM) ? (A + (size_t)i * H_DIM) : bvec;
    float s = 0.f;
    #pragma unroll 8
    for (int k = 0; k < H_DIM; ++k) s += arow[k] * Bm[k * H_DIM + j];
    if (i < H_DIM) C[i * H_DIM + j] = s;
    else           bout[j] = s + (badd ? badd[j] : 0.f);
}

// ---------------------------------------------------------------------------
// pre_kernel: pre[y] = feat @ W[y], W in {W1a_up, W1b_up, W1a_dn, W1b_dn}
// ---------------------------------------------------------------------------
__global__ void __launch_bounds__(256, 2)
pre_kernel(const float* __restrict__ feat,
           const float* __restrict__ w1u, const float* __restrict__ w1d,
           float* __restrict__ p0, float* __restrict__ p1,
           float* __restrict__ p2, float* __restrict__ p3, int nRows)
{
    extern __shared__ float sm[];
    float* sA = sm;              // [64][129]
    float* sB = sA + TE * BS1;   // [64][128]

    const int tid = threadIdx.x;
    const int tx = tid & 15, ty = tid >> 4;
    const int c0 = tx * 8, r0 = ty * 4;
    const int g0 = blockIdx.x * TE;

    const float* W; float* out;
    switch (blockIdx.y) {
        case 0:  W = w1u;                 out = p0; break;
        case 1:  W = w1u + 128 * H_DIM;   out = p1; break;
        case 2:  W = w1d;                 out = p2; break;
        default: W = w1d + 128 * H_DIM;   out = p3; break;
    }

    // stage A (64 x 128)
    #pragma unroll
    for (int p = 0; p < 8; ++p) {
        int idx = p * 256 + tid;
        int r = idx >> 5, c4 = idx & 31;
        float4 v = make_float4(0.f, 0.f, 0.f, 0.f);
        if (g0 + r < nRows)
            v = __ldg((const float4*)feat + (size_t)(g0 + r) * 32 + c4);
        float* ap = sA + r * BS1 + c4 * 4;
        ap[0] = v.x; ap[1] = v.y; ap[2] = v.z; ap[3] = v.w;
    }

    float acc[4][8];
    #pragma unroll
    for (int i = 0; i < 4; i++)
        #pragma unroll
        for (int j = 0; j < 8; j++) acc[i][j] = 0.f;

    for (int seg = 0; seg < 2; ++seg) {
        const float4* wv = (const float4*)(W + (size_t)seg * 64 * H_DIM);
        float4* sBv = (float4*)sB;
        #pragma unroll
        for (int p = 0; p < 8; ++p) sBv[p * 256 + tid] = wv[p * 256 + tid];
        __syncthreads();
        #pragma unroll 8
        for (int k = 0; k < 64; ++k) {
            float av[4];
            #pragma unroll
            for (int i = 0; i < 4; i++) av[i] = sA[(r0 + i) * BS1 + seg * 64 + k];
            float4 bl = *(const float4*)&sB[k * H_DIM + c0];
            float4 bh = *(const float4*)&sB[k * H_DIM + c0 + 4];
            #pragma unroll
            for (int i = 0; i < 4; i++) {
                acc[i][0] += av[i] * bl.x; acc[i][1] += av[i] * bl.y;
                acc[i][2] += av[i] * bl.z; acc[i][3] += av[i] * bl.w;
                acc[i][4] += av[i] * bh.x; acc[i][5] += av[i] * bh.y;
                acc[i][6] += av[i] * bh.z; acc[i][7] += av[i] * bh.w;
            }
        }
        __syncthreads();
    }
    #pragma unroll
    for (int i = 0; i < 4; i++) {
        int g = g0 + r0 + i;
        if (g < nRows) {
            #pragma unroll
            for (int j = 0; j < 8; j++)
                out[(size_t)g * H_DIM + c0 + j] = acc[i][j];
        }
    }
}

// ---------------------------------------------------------------------------
// edge_kernel: per 64-edge tile:
//   hidden = silu(pre_a[src] + pre_b[dst] + dist*w1c + b1)   (no GEMM)
//   red.v4  hacc[dst] += hidden * inv ;  einv[dst] += inv (batch 0)
//   h2 = silu(hidden @ Cp + bpc); w = tanh(h2.wp2 + bp2); pos scatter
// ---------------------------------------------------------------------------
__global__ void __launch_bounds__(256, 2)
edge_kernel(const float* __restrict__ pre_a, const float* __restrict__ pre_b,
            const float* __restrict__ pos,
            const int* __restrict__ ei, const float* __restrict__ deg,
            const float* __restrict__ w1, const float* __restrict__ b1,
            const float* __restrict__ Cp, const float* __restrict__ bpc,
            const float* __restrict__ wp2, const float* __restrict__ bp2,
            float* __restrict__ hacc, float* __restrict__ einv,
            float* __restrict__ pos_upd, int nE, int N)
{
    extern __shared__ float sm[];
    float* sHid  = sm;                   // [64][129]
    float* sB    = sHid + TE * BS1;      // [64][128]
    float* s_w1c = sB + TE * H_DIM;      // [128] (16B aligned)
    float* s_b1  = s_w1c + H_DIM;
    float* s_bpc = s_b1 + H_DIM;
    float* s_wp2 = s_bpc + H_DIM;
    float* s_rel = s_wp2 + H_DIM;        // [64*3]
    float* s_dist= s_rel + 3 * TE;
    float* s_inv = s_dist + TE;
    int*   s_src = (int*)(s_inv + TE);
    int*   s_dst = s_src + TE;

    const int tid = threadIdx.x;
    const int tx = tid & 15, ty = tid >> 4;
    const int c0 = tx * 8, r0 = ty * 4;
    const int b  = blockIdx.y;
    const int e0 = blockIdx.x * TE;
    const size_t bN = (size_t)b * N;

    if (tid < TE) {
        int e = e0 + tid;
        int s = 0, d = 0;
        float x0 = 0.f, x1 = 0.f, x2 = 0.f, dist = 0.f, inv = 0.f;
        if (e < nE) {
            s = ei[e];
            d = ei[nE + e];
            const float* ps = pos + (bN + s) * 3;
            const float* pd = pos + (bN + d) * 3;
            x0 = ps[0] - pd[0];
            x1 = ps[1] - pd[1];
            x2 = ps[2] - pd[2];
            dist = sqrtf(x0 * x0 + x1 * x1 + x2 * x2);
            inv  = 1.0f / fmaxf(deg[d], 1.0f);
        }
        s_src[tid] = s; s_dst[tid] = d;
        s_rel[tid * 3 + 0] = x0; s_rel[tid * 3 + 1] = x1; s_rel[tid * 3 + 2] = x2;
        s_dist[tid] = dist; s_inv[tid] = inv;
    }
    if (tid < H_DIM) {
        s_w1c[tid] = w1[256 * H_DIM + tid];
        s_b1[tid]  = b1[tid];
        s_bpc[tid] = bpc[tid];
        s_wp2[tid] = wp2[tid];
    }
    __syncthreads();

    // hidden + scatter (whole warp works one row -> coalesced gathers & reds)
    #pragma unroll
    for (int p = 0; p < 8; ++p) {
        int idx = p * 256 + tid;
        int r = idx >> 5, c4 = idx & 31;
        int s = s_src[r], d = s_dst[r];
        float4 va = __ldg((const float4*)pre_a + (bN + s) * 32 + c4);
        float4 vb = __ldg((const float4*)pre_b + (bN + d) * 32 + c4);
        float dd = s_dist[r], inv = s_inv[r];
        float4 wc = *(const float4*)(s_w1c + c4 * 4);
        float4 bb = *(const float4*)(s_b1 + c4 * 4);
        float h0 = silu_f(va.x + vb.x + dd * wc.x + bb.x);
        float h1 = silu_f(va.y + vb.y + dd * wc.y + bb.y);
        float h2 = silu_f(va.z + vb.z + dd * wc.z + bb.z);
        float h3 = silu_f(va.w + vb.w + dd * wc.w + bb.w);
        float* hp = sHid + r * BS1 + c4 * 4;
        hp[0] = h0; hp[1] = h1; hp[2] = h2; hp[3] = h3;
        float* gp = hacc + (bN + d) * H_DIM + c4 * 4;
        asm volatile("red.global.add.v4.f32 [%0], {%1, %2, %3, %4};"
                     :: "l"(gp), "f"(h0 * inv), "f"(h1 * inv),
                        "f"(h2 * inv), "f"(h3 * inv) : "memory");
    }
    if (tid < TE && b == 0 && (e0 + tid) < nE)
        atomicAdd(&einv[s_dst[tid]], s_inv[tid]);
    __syncthreads();

    // GEMM: hidden[64][128] @ Cp[128][128]
    float acc[4][8];
    #pragma unroll
    for (int i = 0; i < 4; i++)
        #pragma unroll
        for (int j = 0; j < 8; j++) acc[i][j] = 0.f;

    for (int hseg = 0; hseg < 2; ++hseg) {
        const float4* wv = (const float4*)(Cp + (size_t)hseg * 64 * H_DIM);
        float4* sBv = (float4*)sB;
        #pragma unroll
        for (int p = 0; p < 8; ++p) sBv[p * 256 + tid] = wv[p * 256 + tid];
        __syncthreads();
        #pragma unroll 8
        for (int k = 0; k < 64; ++k) {
            float av[4];
            #pragma unroll
            for (int i = 0; i < 4; i++) av[i] = sHid[(r0 + i) * BS1 + hseg * 64 + k];
            float4 bl = *(const float4*)&sB[k * H_DIM + c0];
            float4 bh = *(const float4*)&sB[k * H_DIM + c0 + 4];
            #pragma unroll
            for (int i = 0; i < 4; i++) {
                acc[i][0] += av[i] * bl.x; acc[i][1] += av[i] * bl.y;
                acc[i][2] += av[i] * bl.z; acc[i][3] += av[i] * bl.w;
                acc[i][4] += av[i] * bh.x; acc[i][5] += av[i] * bh.y;
                acc[i][6] += av[i] * bh.z; acc[i][7] += av[i] * bh.w;
            }
        }
        __syncthreads();
    }
    // h2 = silu(acc + bpc) -> overwrite sHid
    #pragma unroll
    for (int i = 0; i < 4; i++) {
        int r = r0 + i;
        #pragma unroll
        for (int j = 0; j < 8; j++)
            sHid[r * BS1 + c0 + j] = silu_f(acc[i][j] + s_bpc[c0 + j]);
    }
    __syncthreads();

    // dot(h2, wp2) -> tanh -> pos scatter
    {
        int r = tid >> 2;
        int part = tid & 3;
        float s = 0.f;
        #pragma unroll 8
        for (int j = part; j < H_DIM; j += 4)
            s += sHid[r * BS1 + j] * s_wp2[j];
        s += __shfl_xor_sync(0xFFFFFFFFu, s, 1);
        s += __shfl_xor_sync(0xFFFFFFFFu, s, 2);
        if (part == 0 && (e0 + r) < nE) {
            float w = tanhf(s + bp2[0]);
            int d = s_dst[r];
            float* pp = pos_upd + (bN + d) * 3;
            atomicAdd(&pp[0], w * s_rel[r * 3 + 0]);
            atomicAdd(&pp[1], w * s_rel[r * 3 + 1]);
            atomicAdd(&pp[2], w * s_rel[r * 3 + 2]);
        }
    }
}

// ---------------------------------------------------------------------------
// node2_kernel: h1 = silu(feat@Wu1_top + hacc_up@Cu_up + hacc_dn@Cu_dn
//                         + einv_up*bcu_up + einv_dn*bcu_dn + bu1)
//               out = feat + h1@Wu2 + bu2
// ---------------------------------------------------------------------------
__global__ void __launch_bounds__(256, 2)
node2_kernel(const float* __restrict__ feat,
             const float* __restrict__ hacc0, const float* __restrict__ hacc1,
             const float* __restrict__ wu1,
             const float* __restrict__ Cu0, const float* __restrict__ Cu1,
             const float* __restrict__ einv0, const float* __restrict__ einv1,
             const float* __restrict__ bcu0, const float* __restrict__ bcu1,
             const float* __restrict__ bu1,
             const float* __restrict__ wu2, const float* __restrict__ bu2,
             float* __restrict__ outf, int N, int nRows)
{
    extern __shared__ float sm[];
    float* sB  = sm;                 // [64][128]
    float* sA  = sB + TE * H_DIM;    // [64][129]
    float* sb1 = sA + TE * BS1;      // [64][129]
    float* s_eU = sb1 + TE * BS1;    // [64]
    float* s_eD = s_eU + TE;         // [64]

    const int tid = threadIdx.x;
    const int tx = tid & 15, ty = tid >> 4;
    const int c0 = tx * 8, r0 = ty * 4;
    const int g0 = blockIdx.x * TE;

    if (tid < TE) {
        int g = g0 + tid;
        float eu = 0.f, ed = 0.f;
        if (g < nRows) {
            int node = g % N;
            eu = einv0[node];
            ed = einv1[node];
        }
        s_eU[tid] = eu; s_eD[tid] = ed;
    }

    float acc[4][8];
    #pragma unroll
    for (int i = 0; i < 4; i++)
        #pragma unroll
        for (int j = 0; j < 8; j++) acc[i][j] = 0.f;

    for (int m = 0; m < 3; ++m) {
        const float* src = (m == 0) ? feat : (m == 1) ? hacc0 : hacc1;
        const float* Wm  = (m == 0) ? wu1  : (m == 1) ? Cu0   : Cu1;
        for (int seg = 0; seg < 2; ++seg) {
            // stage A chunk (64 x 64)
            #pragma unroll
            for (int p = 0; p < 4; ++p) {
                int idx = p * 256 + tid;
                int r = idx >> 4, c4 = idx & 15;
                float4 v = make_float4(0.f, 0.f, 0.f, 0.f);
                if (g0 + r < nRows)
                    v = __ldg((const float4*)src + (size_t)(g0 + r) * 32 + seg * 16 + c4);
                float* ap = sA + r * BS1 + c4 * 4;
                ap[0] = v.x; ap[1] = v.y; ap[2] = v.z; ap[3] = v.w;
            }
            // stage B chunk (64 x 128)
            {
                const float4* wv = (const float4*)(Wm + (size_t)seg * 64 * H_DIM);
                float4* sBv = (float4*)sB;
                #pragma unroll
                for (int p = 0; p < 8; ++p) sBv[p * 256 + tid] = wv[p * 256 + tid];
            }
            __syncthreads();
            #pragma unroll 8
            for (int k = 0; k < 64; ++k) {
                float av[4];
                #pragma unroll
                for (int i = 0; i < 4; i++) av[i] = sA[(r0 + i) * BS1 + k];
                float4 bl = *(const float4*)&sB[k * H_DIM + c0];
                float4 bh = *(const float4*)&sB[k * H_DIM + c0 + 4];
                #pragma unroll
                for (int i = 0; i < 4; i++) {
                    acc[i][0] += av[i] * bl.x; acc[i][1] += av[i] * bl.y;
                    acc[i][2] += av[i] * bl.z; acc[i][3] += av[i] * bl.w;
                    acc[i][4] += av[i] * bh.x; acc[i][5] += av[i] * bh.y;
                    acc[i][6] += av[i] * bh.z; acc[i][7] += av[i] * bh.w;
                }
            }
            __syncthreads();
        }
    }
    // bias + silu -> sb1
    {
        float b_u[8], b_c0[8], b_c1[8];
        #pragma unroll
        for (int j = 0; j < 8; j++) {
            b_u[j]  = bu1[c0 + j];
            b_c0[j] = bcu0[c0 + j];
            b_c1[j] = bcu1[c0 + j];
        }
        #pragma unroll
        for (int i = 0; i < 4; i++) {
            int r = r0 + i;
            float eu = s_eU[r], ed = s_eD[r];
            #pragma unroll
            for (int j = 0; j < 8; j++) {
                float v = acc[i][j] + b_u[j] + eu * b_c0[j] + ed * b_c1[j];
                sb1[r * BS1 + c0 + j] = silu_f(v);
            }
        }
    }
    __syncthreads();

    #pragma unroll
    for (int i = 0; i < 4; i++)
        #pragma unroll
        for (int j = 0; j < 8; j++) acc[i][j] = 0.f;

    for (int seg = 0; seg < 2; ++seg) {
        const float4* wv = (const float4*)(wu2 + (size_t)seg * 64 * H_DIM);
        float4* sBv = (float4*)sB;
        #pragma unroll
        for (int p = 0; p < 8; ++p) sBv[p * 256 + tid] = wv[p * 256 + tid];
        __syncthreads();
        #pragma unroll 8
        for (int k = 0; k < 64; ++k) {
            float av[4];
            #pragma unroll
            for (int i = 0; i < 4; i++) av[i] = sb1[(r0 + i) * BS1 + seg * 64 + k];
            float4 bl = *(const float4*)&sB[k * H_DIM + c0];
            float4 bh = *(const float4*)&sB[k * H_DIM + c0 + 4];
            #pragma unroll
            for (int i = 0; i < 4; i++) {
                acc[i][0] += av[i] * bl.x; acc[i][1] += av[i] * bl.y;
                acc[i][2] += av[i] * bl.z; acc[i][3] += av[i] * bl.w;
                acc[i][4] += av[i] * bh.x; acc[i][5] += av[i] * bh.y;
                acc[i][6] += av[i] * bh.z; acc[i][7] += av[i] * bh.w;
            }
        }
        __syncthreads();
    }
    {
        float bs[8];
        #pragma unroll
        for (int j = 0; j < 8; j++) bs[j] = bu2[c0 + j];
        #pragma unroll
        for (int i = 0; i < 4; i++) {
            int g = g0 + r0 + i;
            if (g < nRows) {
                #pragma unroll
                for (int j = 0; j < 8; j++) {
                    size_t o = (size_t)g * H_DIM + c0 + j;
                    outf[o] = feat[o] + acc[i][j] + bs[j];
                }
            }
        }
    }
}

__global__ void pos_kernel(const float* __restrict__ pos,
                           const float* __restrict__ pos_upd,
                           float* __restrict__ out, int n)
{
    int i = blockIdx.x * blockDim.x + threadIdx.x;
    if (i < n) out[i] = pos[i] + 0.5f * pos_upd[i];
}

extern "C" void kernel_launch(void* const* d_in, const int* in_sizes, int n_in,
                              void* d_out, int out_size)
{
    const float* feat   = (const float*)d_in[0];
    const float* pos    = (const float*)d_in[1];
    const int*   ei_up  = (const int*)d_in[2];
    const int*   ei_dn  = (const int*)d_in[3];
    const float* deg_up = (const float*)d_in[4];
    const float* deg_dn = (const float*)d_in[5];

    const float* w1u  = (const float*)d_in[6];
    const float* b1u  = (const float*)d_in[7];
    const float* w2u  = (const float*)d_in[8];
    const float* b2u  = (const float*)d_in[9];
    const float* wp1u = (const float*)d_in[10];
    const float* bp1u = (const float*)d_in[11];
    const float* wp2u = (const float*)d_in[12];
    const float* bp2u = (const float*)d_in[13];

    const float* w1d  = (const float*)d_in[14];
    const float* b1d  = (const float*)d_in[15];
    const float* w2d  = (const float*)d_in[16];
    const float* b2d  = (const float*)d_in[17];
    const float* wp1d = (const float*)d_in[18];
    const float* bp1d = (const float*)d_in[19];
    const float* wp2d = (const float*)d_in[20];
    const float* bp2d = (const float*)d_in[21];

    const float* wu1 = (const float*)d_in[22];
    const float* bu1 = (const float*)d_in[23];
    const float* wu2 = (const float*)d_in[24];
    const float* bu2 = (const float*)d_in[25];

    int E = in_sizes[2] / 2;
    int N = in_sizes[4];
    int B = in_sizes[0] / (N * H_DIM);
    int nRows = B * N;

    float *pre, *hacc, *einv, *pos_upd, *Cp, *Cu, *bpc, *bcu;
    cudaGetSymbolAddress((void**)&pre,     g_pre);
    cudaGetSymbolAddress((void**)&hacc,    g_hacc);
    cudaGetSymbolAddress((void**)&einv,    g_einv);
    cudaGetSymbolAddress((void**)&pos_upd, g_pos_upd);
    cudaGetSymbolAddress((void**)&Cp,      g_Cp);
    cudaGetSymbolAddress((void**)&Cu,      g_Cu);
    cudaGetSymbolAddress((void**)&bpc,     g_bpc);
    cudaGetSymbolAddress((void**)&bcu,     g_bcu);

    const size_t PS = (size_t)MAX_BN * H_DIM;   // per-array stride in g_pre/g_hacc
    float* pre_au = pre;
    float* pre_bu = pre + PS;
    float* pre_ad = pre + 2 * PS;
    float* pre_bd = pre + 3 * PS;
    float* hacc_u = hacc;
    float* hacc_d = hacc + PS;
    float* einv_u = einv;
    float* einv_d = einv + MAX_N;

    cudaMemsetAsync(hacc, 0, 2 * PS * sizeof(float));
    cudaMemsetAsync(einv, 0, 2 * MAX_N * sizeof(float));
    cudaMemsetAsync(pos_upd, 0, (size_t)nRows * 3 * sizeof(float));

    int smemPre  = (TE * BS1 + TE * H_DIM) * 4;
    int smemEdge = (TE * BS1 + TE * H_DIM + 4 * H_DIM + 3 * TE + 2 * TE) * 4
                 + 2 * TE * 4;
    int smemNode = (TE * H_DIM + 2 * TE * BS1 + 2 * TE) * 4;
    cudaFuncSetAttribute(pre_kernel,
                         cudaFuncAttributeMaxDynamicSharedMemorySize, smemPre);
    cudaFuncSetAttribute(edge_kernel,
                         cudaFuncAttributeMaxDynamicSharedMemorySize, smemEdge);
    cudaFuncSetAttribute(node2_kernel,
                         cudaFuncAttributeMaxDynamicSharedMemorySize, smemNode);

    combine_kernel<<<dim3(H_DIM + 1, 4), H_DIM>>>(
        w2u, wp1u, b2u, bp1u, w2d, wp1d, b2d, bp1d, wu1,
        Cp, Cp + H_DIM * H_DIM, Cu, Cu + H_DIM * H_DIM,
        bpc, bpc + H_DIM, bcu, bcu + H_DIM);

    pre_kernel<<<dim3((nRows + TE - 1) / TE, 4), 256, smemPre>>>(
        feat, w1u, w1d, pre_au, pre_bu, pre_ad, pre_bd, nRows);

    dim3 egrid((E + TE - 1) / TE, B);
    edge_kernel<<<egrid, 256, smemEdge>>>(
        pre_au, pre_bu, pos, ei_up, deg_up, w1u, b1u,
        Cp, bpc, wp2u, bp2u, hacc_u, einv_u, pos_upd, E, N);
    edge_kernel<<<egrid, 256, smemEdge>>>(
        pre_ad, pre_bd, pos, ei_dn, deg_dn, w1d, b1d,
        Cp + H_DIM * H_DIM, bpc + H_DIM, wp2d, bp2d,
        hacc_d, einv_d, pos_upd, E, N);

    node2_kernel<<<(nRows + TE - 1) / TE, 256, smemNode>>>(
        feat, hacc_u, hacc_d, wu1, Cu, Cu + H_DIM * H_DIM,
        einv_u, einv_d, bcu, bcu + H_DIM, bu1, wu2, bu2,
        (float*)d_out, N, nRows);

    size_t featN = (size_t)nRows * H_DIM;
    int pn = nRows * 3;
    pos_kernel<<<(pn + 255) / 256, 256>>>(
        pos, pos_upd, (float*)d_out + featN, pn);
}

// round 3
// speedup vs baseline: 3.4878x; 1.2686x over previous
#include <cuda_runtime.h>
#include <math.h>

#define H_DIM 128
#define TE 64          // rows per block tile
#define BS1 132        // padded row stride (float4-aligned, 16B multiple)

#define MAX_B 2
#define MAX_N 20000
#define MAX_BN (MAX_B * MAX_N)

// ---------------------------------------------------------------------------
// Scratch (allocation-free rule: __device__ globals)
// ---------------------------------------------------------------------------
__device__ __align__(128) float g_pre[4][(size_t)MAX_BN * H_DIM];   // a_up,b_up,a_dn,b_dn
__device__ __align__(128) float g_hacc[2][(size_t)MAX_BN * H_DIM];  // hidden*inv per dst
__device__ __align__(128) float g_einv[2][MAX_N];                   // sum inv per dst
__device__ __align__(128) float g_pos_upd[(size_t)MAX_BN * 3];
__device__ __align__(128) float g_Cp[2][H_DIM * H_DIM];   // W2@Wp1
__device__ __align__(128) float g_Cu[2][H_DIM * H_DIM];   // W2@Wu1_bot
__device__ __align__(128) float g_bpc[2][H_DIM];          // b2@Wp1 + bp1
__device__ __align__(128) float g_bcu[2][H_DIM];          // b2@Wu1_bot

__device__ __forceinline__ float silu_f(float v) {
    return __fdividef(v, 1.0f + __expf(-v));
}

// ---- packed fp32 helpers (FFMA2) ------------------------------------------
__device__ __forceinline__ void ffma2(unsigned long long& d,
                                      unsigned long long a,
                                      unsigned long long b) {
    asm("fma.rn.f32x2 %0, %1, %2, %0;" : "+l"(d) : "l"(a), "l"(b));
}
__device__ __forceinline__ unsigned long long pack2(float lo, float hi) {
    unsigned long long r;
    asm("mov.b64 %0, {%1, %2};" : "=l"(r) : "f"(lo), "f"(hi));
    return r;
}
__device__ __forceinline__ float2 unpack2(unsigned long long v) {
    float2 r;
    asm("mov.b64 {%0, %1}, %2;" : "=f"(r.x), "=f"(r.y) : "l"(v));
    return r;
}

// ---------------------------------------------------------------------------
// combine_kernel: folded-weight GEMMs (tiny)
// ---------------------------------------------------------------------------
__global__ void combine_kernel(
    const float* __restrict__ w2u, const float* __restrict__ wp1u,
    const float* __restrict__ b2u, const float* __restrict__ bp1u,
    const float* __restrict__ w2d, const float* __restrict__ wp1d,
    const float* __restrict__ b2d, const float* __restrict__ bp1d,
    const float* __restrict__ wu1,
    float* __restrict__ Cp0, float* __restrict__ Cp1,
    float* __restrict__ Cu0, float* __restrict__ Cu1,
    float* __restrict__ bpc0, float* __restrict__ bpc1,
    float* __restrict__ bcu0, float* __restrict__ bcu1)
{
    const float* wu1b = wu1 + 128 * H_DIM;
    const float* A; const float* Bm; const float* bvec; const float* badd;
    float* C; float* bout;
    switch (blockIdx.y) {
        case 0:  A = w2u; Bm = wp1u; bvec = b2u; badd = bp1u; C = Cp0; bout = bpc0; break;
        case 1:  A = w2d; Bm = wp1d; bvec = b2d; badd = bp1d; C = Cp1; bout = bpc1; break;
        case 2:  A = w2u; Bm = wu1b; bvec = b2u; badd = 0;    C = Cu0; bout = bcu0; break;
        default: A = w2d; Bm = wu1b; bvec = b2d; badd = 0;    C = Cu1; bout = bcu1; break;
    }
    int i = blockIdx.x;
    int j = threadIdx.x;
    const float* arow = (i < H_DIM) ? (A + (size_t)i * H_DIM) : bvec;
    float s = 0.f;
    #pragma unroll 8
    for (int k = 0; k < H_DIM; ++k) s += arow[k] * Bm[k * H_DIM + j];
    if (i < H_DIM) C[i * H_DIM + j] = s;
    else           bout[j] = s + (badd ? badd[j] : 0.f);
}

// ---------------------------------------------------------------------------
// pre_kernel: pre[y] = feat @ W[y]   (256 thr, 4x8 tile, FFMA2)
// ---------------------------------------------------------------------------
__global__ void __launch_bounds__(256, 2)
pre_kernel(const float* __restrict__ feat,
           const float* __restrict__ w1u, const float* __restrict__ w1d,
           float* __restrict__ p0, float* __restrict__ p1,
           float* __restrict__ p2, float* __restrict__ p3, int nRows)
{
    extern __shared__ float sm[];
    float* sA = sm;              // [64][132]
    float* sB = sA + TE * BS1;   // [64][128]

    const int tid = threadIdx.x;
    const int tx = tid & 15, ty = tid >> 4;
    const int c0 = tx * 8, r0 = ty * 4;
    const int g0 = blockIdx.x * TE;

    const float* W; float* out;
    switch (blockIdx.y) {
        case 0:  W = w1u;                 out = p0; break;
        case 1:  W = w1u + 128 * H_DIM;   out = p1; break;
        case 2:  W = w1d;                 out = p2; break;
        default: W = w1d + 128 * H_DIM;   out = p3; break;
    }

    // stage A (64 x 128)
    #pragma unroll
    for (int p = 0; p < 8; ++p) {
        int idx = p * 256 + tid;
        int r = idx >> 5, c4 = idx & 31;
        float4 v = make_float4(0.f, 0.f, 0.f, 0.f);
        if (g0 + r < nRows)
            v = __ldg((const float4*)feat + (size_t)(g0 + r) * 32 + c4);
        *(float4*)(sA + r * BS1 + c4 * 4) = v;
    }

    unsigned long long acc[4][4];
    #pragma unroll
    for (int i = 0; i < 4; i++)
        #pragma unroll
        for (int j = 0; j < 4; j++) acc[i][j] = 0ull;

    for (int seg = 0; seg < 2; ++seg) {
        const float4* wv = (const float4*)(W + (size_t)seg * 64 * H_DIM);
        float4* sBv = (float4*)sB;
        #pragma unroll
        for (int p = 0; p < 8; ++p) sBv[p * 256 + tid] = wv[p * 256 + tid];
        __syncthreads();
        #pragma unroll 2
        for (int kc = 0; kc < 64; kc += 4) {
            float4 a4[4];
            #pragma unroll
            for (int i = 0; i < 4; i++)
                a4[i] = *(const float4*)&sA[(r0 + i) * BS1 + seg * 64 + kc];
            #pragma unroll
            for (int kk = 0; kk < 4; ++kk) {
                const ulonglong2* bp =
                    (const ulonglong2*)&sB[(kc + kk) * H_DIM + c0];
                ulonglong2 b01 = bp[0], b23 = bp[1];
                #pragma unroll
                for (int i = 0; i < 4; i++) {
                    float a = (kk == 0) ? a4[i].x : (kk == 1) ? a4[i].y
                            : (kk == 2) ? a4[i].z : a4[i].w;
                    unsigned long long ap = pack2(a, a);
                    ffma2(acc[i][0], ap, b01.x);
                    ffma2(acc[i][1], ap, b01.y);
                    ffma2(acc[i][2], ap, b23.x);
                    ffma2(acc[i][3], ap, b23.y);
                }
            }
        }
        __syncthreads();
    }
    #pragma unroll
    for (int i = 0; i < 4; i++) {
        int g = g0 + r0 + i;
        if (g < nRows) {
            #pragma unroll
            for (int j = 0; j < 4; j++) {
                float2 v = unpack2(acc[i][j]);
                out[(size_t)g * H_DIM + c0 + 2 * j]     = v.x;
                out[(size_t)g * H_DIM + c0 + 2 * j + 1] = v.y;
            }
        }
    }
}

// ---------------------------------------------------------------------------
// edge_kernel: 128 threads, 8x8 tile, FFMA2
//   hidden = silu(pre_a[src] + pre_b[dst] + dist*w1c + b1)
//   red.v4  hacc[dst] += hidden * inv ;  einv[dst] += inv (batch 0)
//   h2 = silu(hidden @ Cp + bpc); w = tanh(h2.wp2 + bp2); pos scatter
// ---------------------------------------------------------------------------
__global__ void __launch_bounds__(128)
edge_kernel(const float* __restrict__ pre_a, const float* __restrict__ pre_b,
            const float* __restrict__ pos,
            const int* __restrict__ ei, const float* __restrict__ deg,
            const float* __restrict__ w1, const float* __restrict__ b1,
            const float* __restrict__ Cp, const float* __restrict__ bpc,
            const float* __restrict__ wp2, const float* __restrict__ bp2,
            float* __restrict__ hacc, float* __restrict__ einv,
            float* __restrict__ pos_upd, int nE, int N)
{
    extern __shared__ float sm[];
    float* sHid  = sm;                   // [64][132]
    float* sB    = sHid + TE * BS1;      // [64][128]
    float* s_w1c = sB + TE * H_DIM;      // [128]
    float* s_b1  = s_w1c + H_DIM;
    float* s_bpc = s_b1 + H_DIM;
    float* s_wp2 = s_bpc + H_DIM;
    float* s_rel = s_wp2 + H_DIM;        // [64*3]
    float* s_dist= s_rel + 3 * TE;
    float* s_inv = s_dist + TE;
    int*   s_src = (int*)(s_inv + TE);
    int*   s_dst = s_src + TE;

    const int tid = threadIdx.x;
    const int tx = tid & 15, ty = tid >> 4;      // 16 col groups x 8 row groups
    const int c0 = tx * 8, r0 = ty * 8;
    const int b  = blockIdx.y;
    const int e0 = blockIdx.x * TE;
    const size_t bN = (size_t)b * N;

    if (tid < TE) {
        int e = e0 + tid;
        int s = 0, d = 0;
        float x0 = 0.f, x1 = 0.f, x2 = 0.f, dist = 0.f, inv = 0.f;
        if (e < nE) {
            s = ei[e];
            d = ei[nE + e];
            const float* ps = pos + (bN + s) * 3;
            const float* pd = pos + (bN + d) * 3;
            x0 = ps[0] - pd[0];
            x1 = ps[1] - pd[1];
            x2 = ps[2] - pd[2];
            dist = sqrtf(x0 * x0 + x1 * x1 + x2 * x2);
            inv  = 1.0f / fmaxf(deg[d], 1.0f);
        }
        s_src[tid] = s; s_dst[tid] = d;
        s_rel[tid * 3 + 0] = x0; s_rel[tid * 3 + 1] = x1; s_rel[tid * 3 + 2] = x2;
        s_dist[tid] = dist; s_inv[tid] = inv;
    }
    {
        s_w1c[tid] = w1[256 * H_DIM + tid];
        s_b1[tid]  = b1[tid];
        s_bpc[tid] = bpc[tid];
        s_wp2[tid] = wp2[tid];
    }
    __syncthreads();

    // hidden + scatter (each warp covers one row per step -> coalesced)
    #pragma unroll
    for (int p = 0; p < 16; ++p) {
        int idx = p * 128 + tid;
        int r = idx >> 5, c4 = idx & 31;
        int s = s_src[r], d = s_dst[r];
        float4 va = __ldg((const float4*)pre_a + (bN + s) * 32 + c4);
        float4 vb = __ldg((const float4*)pre_b + (bN + d) * 32 + c4);
        float dd = s_dist[r], inv = s_inv[r];
        float4 wc = *(const float4*)(s_w1c + c4 * 4);
        float4 bb = *(const float4*)(s_b1 + c4 * 4);
        float h0 = silu_f(va.x + vb.x + dd * wc.x + bb.x);
        float h1 = silu_f(va.y + vb.y + dd * wc.y + bb.y);
        float h2 = silu_f(va.z + vb.z + dd * wc.z + bb.z);
        float h3 = silu_f(va.w + vb.w + dd * wc.w + bb.w);
        *(float4*)(sHid + r * BS1 + c4 * 4) = make_float4(h0, h1, h2, h3);
        float* gp = hacc + (bN + d) * H_DIM + c4 * 4;
        asm volatile("red.global.add.v4.f32 [%0], {%1, %2, %3, %4};"
                     :: "l"(gp), "f"(h0 * inv), "f"(h1 * inv),
                        "f"(h2 * inv), "f"(h3 * inv) : "memory");
    }
    if (tid < TE && b == 0 && (e0 + tid) < nE)
        atomicAdd(&einv[s_dst[tid]], s_inv[tid]);
    __syncthreads();

    // GEMM: hidden[64][128] @ Cp[128][128], 8x8 per thread, FFMA2
    unsigned long long acc[8][4];
    #pragma unroll
    for (int i = 0; i < 8; i++)
        #pragma unroll
        for (int j = 0; j < 4; j++) acc[i][j] = 0ull;

    for (int hseg = 0; hseg < 2; ++hseg) {
        const float4* wv = (const float4*)(Cp + (size_t)hseg * 64 * H_DIM);
        float4* sBv = (float4*)sB;
        #pragma unroll
        for (int p = 0; p < 16; ++p) sBv[p * 128 + tid] = wv[p * 128 + tid];
        __syncthreads();
        #pragma unroll 1
        for (int kc = 0; kc < 64; kc += 4) {
            float4 a4[8];
            #pragma unroll
            for (int i = 0; i < 8; i++)
                a4[i] = *(const float4*)&sHid[(r0 + i) * BS1 + hseg * 64 + kc];
            #pragma unroll
            for (int kk = 0; kk < 4; ++kk) {
                const ulonglong2* bp =
                    (const ulonglong2*)&sB[(kc + kk) * H_DIM + c0];
                ulonglong2 b01 = bp[0], b23 = bp[1];
                #pragma unroll
                for (int i = 0; i < 8; i++) {
                    float a = (kk == 0) ? a4[i].x : (kk == 1) ? a4[i].y
                            : (kk == 2) ? a4[i].z : a4[i].w;
                    unsigned long long ap = pack2(a, a);
                    ffma2(acc[i][0], ap, b01.x);
                    ffma2(acc[i][1], ap, b01.y);
                    ffma2(acc[i][2], ap, b23.x);
                    ffma2(acc[i][3], ap, b23.y);
                }
            }
        }
        __syncthreads();
    }
    // h2 = silu(acc + bpc) -> overwrite sHid
    #pragma unroll
    for (int i = 0; i < 8; i++) {
        int r = r0 + i;
        #pragma unroll
        for (int j = 0; j < 4; j++) {
            float2 v = unpack2(acc[i][j]);
            sHid[r * BS1 + c0 + 2 * j]     = silu_f(v.x + s_bpc[c0 + 2 * j]);
            sHid[r * BS1 + c0 + 2 * j + 1] = silu_f(v.y + s_bpc[c0 + 2 * j + 1]);
        }
    }
    __syncthreads();

    // dot(h2, wp2) -> tanh -> pos scatter  (2 threads per row)
    {
        int r = tid >> 1;
        int part = tid & 1;
        float s = 0.f;
        #pragma unroll 16
        for (int j = part; j < H_DIM; j += 2)
            s += sHid[r * BS1 + j] * s_wp2[j];
        s += __shfl_xor_sync(0xFFFFFFFFu, s, 1);
        if (part == 0 && (e0 + r) < nE) {
            float w = tanhf(s + bp2[0]);
            int d = s_dst[r];
            float* pp = pos_upd + (bN + d) * 3;
            atomicAdd(&pp[0], w * s_rel[r * 3 + 0]);
            atomicAdd(&pp[1], w * s_rel[r * 3 + 1]);
            atomicAdd(&pp[2], w * s_rel[r * 3 + 2]);
        }
    }
}

// ---------------------------------------------------------------------------
// node2_kernel: h1 = silu(feat@Wu1_top + hacc_up@Cu_up + hacc_dn@Cu_dn
//                         + einv_up*bcu_up + einv_dn*bcu_dn + bu1)
//               out = feat + h1@Wu2 + bu2        (256 thr, 4x8 tile, FFMA2)
// ---------------------------------------------------------------------------
__global__ void __launch_bounds__(256, 2)
node2_kernel(const float* __restrict__ feat,
             const float* __restrict__ hacc0, const float* __restrict__ hacc1,
             const float* __restrict__ wu1,
             const float* __restrict__ Cu0, const float* __restrict__ Cu1,
             const float* __restrict__ einv0, const float* __restrict__ einv1,
             const float* __restrict__ bcu0, const float* __restrict__ bcu1,
             const float* __restrict__ bu1,
             const float* __restrict__ wu2, const float* __restrict__ bu2,
             float* __restrict__ outf, int N, int nRows)
{
    extern __shared__ float sm[];
    float* sB  = sm;                 // [64][128]
    float* sA  = sB + TE * H_DIM;    // [64][132]
    float* sb1 = sA + TE * BS1;      // [64][132]
    float* s_eU = sb1 + TE * BS1;    // [64]
    float* s_eD = s_eU + TE;         // [64]

    const int tid = threadIdx.x;
    const int tx = tid & 15, ty = tid >> 4;
    const int c0 = tx * 8, r0 = ty * 4;
    const int g0 = blockIdx.x * TE;

    if (tid < TE) {
        int g = g0 + tid;
        float eu = 0.f, ed = 0.f;
        if (g < nRows) {
            int node = g % N;
            eu = einv0[node];
            ed = einv1[node];
        }
        s_eU[tid] = eu; s_eD[tid] = ed;
    }

    unsigned long long acc[4][4];
    #pragma unroll
    for (int i = 0; i < 4; i++)
        #pragma unroll
        for (int j = 0; j < 4; j++) acc[i][j] = 0ull;

    for (int m = 0; m < 3; ++m) {
        const float* src = (m == 0) ? feat : (m == 1) ? hacc0 : hacc1;
        const float* Wm  = (m == 0) ? wu1  : (m == 1) ? Cu0   : Cu1;
        for (int seg = 0; seg < 2; ++seg) {
            // stage A chunk (64 x 64)
            #pragma unroll
            for (int p = 0; p < 4; ++p) {
                int idx = p * 256 + tid;
                int r = idx >> 4, c4 = idx & 15;
                float4 v = make_float4(0.f, 0.f, 0.f, 0.f);
                if (g0 + r < nRows)
                    v = __ldg((const float4*)src + (size_t)(g0 + r) * 32 + seg * 16 + c4);
                *(float4*)(sA + r * BS1 + c4 * 4) = v;
            }
            // stage B chunk (64 x 128)
            {
                const float4* wv = (const float4*)(Wm + (size_t)seg * 64 * H_DIM);
                float4* sBv = (float4*)sB;
                #pragma unroll
                for (int p = 0; p < 8; ++p) sBv[p * 256 + tid] = wv[p * 256 + tid];
            }
            __syncthreads();
            #pragma unroll 2
            for (int kc = 0; kc < 64; kc += 4) {
                float4 a4[4];
                #pragma unroll
                for (int i = 0; i < 4; i++)
                    a4[i] = *(const float4*)&sA[(r0 + i) * BS1 + kc];
                #pragma unroll
                for (int kk = 0; kk < 4; ++kk) {
                    const ulonglong2* bp =
                        (const ulonglong2*)&sB[(kc + kk) * H_DIM + c0];
                    ulonglong2 b01 = bp[0], b23 = bp[1];
                    #pragma unroll
                    for (int i = 0; i < 4; i++) {
                        float a = (kk == 0) ? a4[i].x : (kk == 1) ? a4[i].y
                                : (kk == 2) ? a4[i].z : a4[i].w;
                        unsigned long long ap = pack2(a, a);
                        ffma2(acc[i][0], ap, b01.x);
                        ffma2(acc[i][1], ap, b01.y);
                        ffma2(acc[i][2], ap, b23.x);
                        ffma2(acc[i][3], ap, b23.y);
                    }
                }
            }
            __syncthreads();
        }
    }
    // bias + silu -> sb1
    {
        #pragma unroll
        for (int i = 0; i < 4; i++) {
            int r = r0 + i;
            float eu = s_eU[r], ed = s_eD[r];
            #pragma unroll
            for (int j = 0; j < 4; j++) {
                float2 v = unpack2(acc[i][j]);
                int cA = c0 + 2 * j, cB = c0 + 2 * j + 1;
                float vA = v.x + bu1[cA] + eu * bcu0[cA] + ed * bcu1[cA];
                float vB = v.y + bu1[cB] + eu * bcu0[cB] + ed * bcu1[cB];
                sb1[r * BS1 + cA] = silu_f(vA);
                sb1[r * BS1 + cB] = silu_f(vB);
            }
        }
    }
    __syncthreads();

    #pragma unroll
    for (int i = 0; i < 4; i++)
        #pragma unroll
        for (int j = 0; j < 4; j++) acc[i][j] = 0ull;

    for (int seg = 0; seg < 2; ++seg) {
        const float4* wv = (const float4*)(wu2 + (size_t)seg * 64 * H_DIM);
        float4* sBv = (float4*)sB;
        #pragma unroll
        for (int p = 0; p < 8; ++p) sBv[p * 256 + tid] = wv[p * 256 + tid];
        __syncthreads();
        #pragma unroll 2
        for (int kc = 0; kc < 64; kc += 4) {
            float4 a4[4];
            #pragma unroll
            for (int i = 0; i < 4; i++)
                a4[i] = *(const float4*)&sb1[(r0 + i) * BS1 + seg * 64 + kc];
            #pragma unroll
            for (int kk = 0; kk < 4; ++kk) {
                const ulonglong2* bp =
                    (const ulonglong2*)&sB[(kc + kk) * H_DIM + c0];
                ulonglong2 b01 = bp[0], b23 = bp[1];
                #pragma unroll
                for (int i = 0; i < 4; i++) {
                    float a = (kk == 0) ? a4[i].x : (kk == 1) ? a4[i].y
                            : (kk == 2) ? a4[i].z : a4[i].w;
                    unsigned long long ap = pack2(a, a);
                    ffma2(acc[i][0], ap, b01.x);
                    ffma2(acc[i][1], ap, b01.y);
                    ffma2(acc[i][2], ap, b23.x);
                    ffma2(acc[i][3], ap, b23.y);
                }
            }
        }
        __syncthreads();
    }
    {
        #pragma unroll
        for (int i = 0; i < 4; i++) {
            int g = g0 + r0 + i;
            if (g < nRows) {
                #pragma unroll
                for (int j = 0; j < 4; j++) {
                    float2 v = unpack2(acc[i][j]);
                    size_t oA = (size_t)g * H_DIM + c0 + 2 * j;
                    outf[oA]     = feat[oA]     + v.x + bu2[c0 + 2 * j];
                    outf[oA + 1] = feat[oA + 1] + v.y + bu2[c0 + 2 * j + 1];
                }
            }
        }
    }
}

__global__ void pos_kernel(const float* __restrict__ pos,
                           const float* __restrict__ pos_upd,
                           float* __restrict__ out, int n)
{
    int i = blockIdx.x * blockDim.x + threadIdx.x;
    if (i < n) out[i] = pos[i] + 0.5f * pos_upd[i];
}

extern "C" void kernel_launch(void* const* d_in, const int* in_sizes, int n_in,
                              void* d_out, int out_size)
{
    const float* feat   = (const float*)d_in[0];
    const float* pos    = (const float*)d_in[1];
    const int*   ei_up  = (const int*)d_in[2];
    const int*   ei_dn  = (const int*)d_in[3];
    const float* deg_up = (const float*)d_in[4];
    const float* deg_dn = (const float*)d_in[5];

    const float* w1u  = (const float*)d_in[6];
    const float* b1u  = (const float*)d_in[7];
    const float* w2u  = (const float*)d_in[8];
    const float* b2u  = (const float*)d_in[9];
    const float* wp1u = (const float*)d_in[10];
    const float* bp1u = (const float*)d_in[11];
    const float* wp2u = (const float*)d_in[12];
    const float* bp2u = (const float*)d_in[13];

    const float* w1d  = (const float*)d_in[14];
    const float* b1d  = (const float*)d_in[15];
    const float* w2d  = (const float*)d_in[16];
    const float* b2d  = (const float*)d_in[17];
    const float* wp1d = (const float*)d_in[18];
    const float* bp1d = (const float*)d_in[19];
    const float* wp2d = (const float*)d_in[20];
    const float* bp2d = (const float*)d_in[21];

    const float* wu1 = (const float*)d_in[22];
    const float* bu1 = (const float*)d_in[23];
    const float* wu2 = (const float*)d_in[24];
    const float* bu2 = (const float*)d_in[25];

    int E = in_sizes[2] / 2;
    int N = in_sizes[4];
    int B = in_sizes[0] / (N * H_DIM);
    int nRows = B * N;

    float *pre, *hacc, *einv, *pos_upd, *Cp, *Cu, *bpc, *bcu;
    cudaGetSymbolAddress((void**)&pre,     g_pre);
    cudaGetSymbolAddress((void**)&hacc,    g_hacc);
    cudaGetSymbolAddress((void**)&einv,    g_einv);
    cudaGetSymbolAddress((void**)&pos_upd, g_pos_upd);
    cudaGetSymbolAddress((void**)&Cp,      g_Cp);
    cudaGetSymbolAddress((void**)&Cu,      g_Cu);
    cudaGetSymbolAddress((void**)&bpc,     g_bpc);
    cudaGetSymbolAddress((void**)&bcu,     g_bcu);

    const size_t PS = (size_t)MAX_BN * H_DIM;
    float* pre_au = pre;
    float* pre_bu = pre + PS;
    float* pre_ad = pre + 2 * PS;
    float* pre_bd = pre + 3 * PS;
    float* hacc_u = hacc;
    float* hacc_d = hacc + PS;
    float* einv_u = einv;
    float* einv_d = einv + MAX_N;

    cudaMemsetAsync(hacc, 0, 2 * PS * sizeof(float));
    cudaMemsetAsync(einv, 0, 2 * MAX_N * sizeof(float));
    cudaMemsetAsync(pos_upd, 0, (size_t)nRows * 3 * sizeof(float));

    int smemPre  = (TE * BS1 + TE * H_DIM) * 4;
    int smemEdge = (TE * BS1 + TE * H_DIM + 4 * H_DIM + 3 * TE + 2 * TE) * 4
                 + 2 * TE * 4;
    int smemNode = (TE * H_DIM + 2 * TE * BS1 + 2 * TE) * 4;
    cudaFuncSetAttribute(pre_kernel,
                         cudaFuncAttributeMaxDynamicSharedMemorySize, smemPre);
    cudaFuncSetAttribute(edge_kernel,
                         cudaFuncAttributeMaxDynamicSharedMemorySize, smemEdge);
    cudaFuncSetAttribute(node2_kernel,
                         cudaFuncAttributeMaxDynamicSharedMemorySize, smemNode);

    combine_kernel<<<dim3(H_DIM + 1, 4), H_DIM>>>(
        w2u, wp1u, b2u, bp1u, w2d, wp1d, b2d, bp1d, wu1,
        Cp, Cp + H_DIM * H_DIM, Cu, Cu + H_DIM * H_DIM,
        bpc, bpc + H_DIM, bcu, bcu + H_DIM);

    pre_kernel<<<dim3((nRows + TE - 1) / TE, 4), 256, smemPre>>>(
        feat, w1u, w1d, pre_au, pre_bu, pre_ad, pre_bd, nRows);

    dim3 egrid((E + TE - 1) / TE, B);
    edge_kernel<<<egrid, 128, smemEdge>>>(
        pre_au, pre_bu, pos, ei_up, deg_up, w1u, b1u,
        Cp, bpc, wp2u, bp2u, hacc_u, einv_u, pos_upd, E, N);
    edge_kernel<<<egrid, 128, smemEdge>>>(
        pre_ad, pre_bd, pos, ei_dn, deg_dn, w1d, b1d,
        Cp + H_DIM * H_DIM, bpc + H_DIM, wp2d, bp2d,
        hacc_d, einv_d, pos_upd, E, N);

    node2_kernel<<<(nRows + TE - 1) / TE, 256, smemNode>>>(
        feat, hacc_u, hacc_d, wu1, Cu, Cu + H_DIM * H_DIM,
        einv_u, einv_d, bcu, bcu + H_DIM, bu1, wu2, bu2,
        (float*)d_out, N, nRows);

    size_t featN = (size_t)nRows * H_DIM;
    int pn = nRows * 3;
    pos_kernel<<<(pn + 255) / 256, 256>>>(
        pos, pos_upd, (float*)d_out + featN, pn);
}

// round 5
// speedup vs baseline: 4.3603x; 1.2501x over previous
#include <cuda_runtime.h>
#include <math.h>
#include <cstdint>

#define H_DIM 128
#define TE 64          // rows per block tile (pre/node kernels)
#define TEC 128        // edges per block (mma edge kernel)
#define BS1 132        // padded row stride (float4-aligned)
#define HS 132         // hidden tile stride in edge kernel

#define MAX_B 2
#define MAX_N 20000
#define MAX_BN (MAX_B * MAX_N)

// ---------------------------------------------------------------------------
// Scratch (allocation-free rule: __device__ globals)
// ---------------------------------------------------------------------------
__device__ __align__(128) float g_pre[4][(size_t)MAX_BN * H_DIM];
__device__ __align__(128) float g_hacc[2][(size_t)MAX_BN * H_DIM];
__device__ __align__(128) float g_einv[2][MAX_N];
__device__ __align__(128) float g_pos_upd[(size_t)MAX_BN * 3];
__device__ __align__(128) float g_CpFrag[2][H_DIM * H_DIM];  // fragment-major tf32 image of Cp
__device__ __align__(128) float g_Cu[2][H_DIM * H_DIM];      // W2@Wu1_bot (row-major)
__device__ __align__(128) float g_bpc[2][H_DIM];             // b2@Wp1 + bp1
__device__ __align__(128) float g_bcu[2][H_DIM];             // b2@Wu1_bot

__device__ __forceinline__ float silu_f(float v) {
    return __fdividef(v, 1.0f + __expf(-v));
}

// ---- packed fp32 helpers (FFMA2) ------------------------------------------
__device__ __forceinline__ void ffma2(unsigned long long& d,
                                      unsigned long long a,
                                      unsigned long long b) {
    asm("fma.rn.f32x2 %0, %1, %2, %0;" : "+l"(d) : "l"(a), "l"(b));
}
__device__ __forceinline__ unsigned long long pack2(float lo, float hi) {
    unsigned long long r;
    asm("mov.b64 %0, {%1, %2};" : "=l"(r) : "f"(lo), "f"(hi));
    return r;
}
__device__ __forceinline__ float2 unpack2(unsigned long long v) {
    float2 r;
    asm("mov.b64 {%0, %1}, %2;" : "=f"(r.x), "=f"(r.y) : "l"(v));
    return r;
}

// ---- tf32 mma.sync helpers (sm_80 PTX — compiles for bare sm_103) ----------
__device__ __forceinline__ uint32_t cvt_tf32(float x) {
    uint32_t r;
    asm("cvt.rna.tf32.f32 %0, %1;" : "=r"(r) : "f"(x));
    return r;
}
__device__ __forceinline__ void mma_tf32(float c[4], const uint32_t a[4],
                                         uint32_t b0, uint32_t b1) {
    asm volatile(
        "mma.sync.aligned.m16n8k8.row.col.f32.tf32.tf32.f32 "
        "{%0,%1,%2,%3}, {%4,%5,%6,%7}, {%8,%9}, {%0,%1,%2,%3};"
        : "+f"(c[0]), "+f"(c[1]), "+f"(c[2]), "+f"(c[3])
        : "r"(a[0]), "r"(a[1]), "r"(a[2]), "r"(a[3]), "r"(b0), "r"(b1));
}

// ---------------------------------------------------------------------------
// combine_kernel: folded-weight GEMMs
//  y=0/1: CpFrag (fragment-major, tf32-rounded) for up/down + bpc
//  y=2/3: Cu (row-major) + bcu
// ---------------------------------------------------------------------------
__global__ void combine_kernel(
    const float* __restrict__ w2u, const float* __restrict__ wp1u,
    const float* __restrict__ b2u, const float* __restrict__ bp1u,
    const float* __restrict__ w2d, const float* __restrict__ wp1d,
    const float* __restrict__ b2d, const float* __restrict__ bp1d,
    const float* __restrict__ wu1,
    float* __restrict__ Cf0, float* __restrict__ Cf1,
    float* __restrict__ Cu0, float* __restrict__ Cu1,
    float* __restrict__ bpc0, float* __restrict__ bpc1,
    float* __restrict__ bcu0, float* __restrict__ bcu1)
{
    const float* wu1b = wu1 + 128 * H_DIM;
    const float* A; const float* Bm; const float* bvec; const float* badd;
    float* C; float* bout; bool frag;
    switch (blockIdx.y) {
        case 0:  A = w2u; Bm = wp1u; bvec = b2u; badd = bp1u; C = Cf0; bout = bpc0; frag = true;  break;
        case 1:  A = w2d; Bm = wp1d; bvec = b2d; badd = bp1d; C = Cf1; bout = bpc1; frag = true;  break;
        case 2:  A = w2u; Bm = wu1b; bvec = b2u; badd = 0;    C = Cu0; bout = bcu0; frag = false; break;
        default: A = w2d; Bm = wu1b; bvec = b2d; badd = 0;    C = Cu1; bout = bcu1; frag = false; break;
    }
    int i = blockIdx.x;   // k index (row of Cp)
    int j = threadIdx.x;  // n index (col of Cp)
    const float* arow = (i < H_DIM) ? (A + (size_t)i * H_DIM) : bvec;
    float s = 0.f;
    #pragma unroll 8
    for (int k = 0; k < H_DIM; ++k) s += arow[k] * Bm[k * H_DIM + j];
    if (i < H_DIM) {
        if (frag) {
            // mma B-fragment placement: b0 (k=lane&3), b1 (k=lane&3+4), n = lane>>2
            int kstep = i >> 3, kk = i & 7;
            int ntile = j >> 3, nn = j & 7;
            int lane = nn * 4 + (kk & 3);
            int reg  = kk >> 2;
            C[((size_t)(ntile * 16 + kstep) * 32 + lane) * 2 + reg] =
                __uint_as_float(cvt_tf32(s));
        } else {
            C[i * H_DIM + j] = s;
        }
    } else {
        bout[j] = s + (badd ? badd[j] : 0.f);
    }
}

// ---------------------------------------------------------------------------
// pre_kernel: pre[y] = feat @ W[y]   (256 thr, 4x8 tile, FFMA2)
// ---------------------------------------------------------------------------
__global__ void __launch_bounds__(256, 2)
pre_kernel(const float* __restrict__ feat,
           const float* __restrict__ w1u, const float* __restrict__ w1d,
           float* __restrict__ p0, float* __restrict__ p1,
           float* __restrict__ p2, float* __restrict__ p3, int nRows)
{
    extern __shared__ float sm[];
    float* sA = sm;              // [64][132]
    float* sB = sA + TE * BS1;   // [64][128]

    const int tid = threadIdx.x;
    const int tx = tid & 15, ty = tid >> 4;
    const int c0 = tx * 8, r0 = ty * 4;
    const int g0 = blockIdx.x * TE;

    const float* W; float* out;
    switch (blockIdx.y) {
        case 0:  W = w1u;                 out = p0; break;
        case 1:  W = w1u + 128 * H_DIM;   out = p1; break;
        case 2:  W = w1d;                 out = p2; break;
        default: W = w1d + 128 * H_DIM;   out = p3; break;
    }

    #pragma unroll
    for (int p = 0; p < 8; ++p) {
        int idx = p * 256 + tid;
        int r = idx >> 5, c4 = idx & 31;
        float4 v = make_float4(0.f, 0.f, 0.f, 0.f);
        if (g0 + r < nRows)
            v = __ldg((const float4*)feat + (size_t)(g0 + r) * 32 + c4);
        *(float4*)(sA + r * BS1 + c4 * 4) = v;
    }

    unsigned long long acc[4][4];
    #pragma unroll
    for (int i = 0; i < 4; i++)
        #pragma unroll
        for (int j = 0; j < 4; j++) acc[i][j] = 0ull;

    for (int seg = 0; seg < 2; ++seg) {
        const float4* wv = (const float4*)(W + (size_t)seg * 64 * H_DIM);
        float4* sBv = (float4*)sB;
        #pragma unroll
        for (int p = 0; p < 8; ++p) sBv[p * 256 + tid] = wv[p * 256 + tid];
        __syncthreads();
        #pragma unroll 2
        for (int kc = 0; kc < 64; kc += 4) {
            float4 a4[4];
            #pragma unroll
            for (int i = 0; i < 4; i++)
                a4[i] = *(const float4*)&sA[(r0 + i) * BS1 + seg * 64 + kc];
            #pragma unroll
            for (int kk = 0; kk < 4; ++kk) {
                const ulonglong2* bp =
                    (const ulonglong2*)&sB[(kc + kk) * H_DIM + c0];
                ulonglong2 b01 = bp[0], b23 = bp[1];
                #pragma unroll
                for (int i = 0; i < 4; i++) {
                    float a = (kk == 0) ? a4[i].x : (kk == 1) ? a4[i].y
                            : (kk == 2) ? a4[i].z : a4[i].w;
                    unsigned long long ap = pack2(a, a);
                    ffma2(acc[i][0], ap, b01.x);
                    ffma2(acc[i][1], ap, b01.y);
                    ffma2(acc[i][2], ap, b23.x);
                    ffma2(acc[i][3], ap, b23.y);
                }
            }
        }
        __syncthreads();
    }
    #pragma unroll
    for (int i = 0; i < 4; i++) {
        int g = g0 + r0 + i;
        if (g < nRows) {
            #pragma unroll
            for (int j = 0; j < 4; j++) {
                float2 v = unpack2(acc[i][j]);
                out[(size_t)g * H_DIM + c0 + 2 * j]     = v.x;
                out[(size_t)g * H_DIM + c0 + 2 * j + 1] = v.y;
            }
        }
    }
}

// ---------------------------------------------------------------------------
// edge_mma_kernel: 256 thr, 128 edges/block.
//   gather -> hidden (fp32, exact) -> red.v4 hacc ; hidden -> padded SMEM
//   -> warp-level tf32 mma.sync vs CpFrag -> silu/dot/tanh in registers
//   -> pos scatter.
// ---------------------------------------------------------------------------
__global__ void __launch_bounds__(256)
edge_mma_kernel(const float* __restrict__ pre_a, const float* __restrict__ pre_b,
                const float* __restrict__ pos,
                const int* __restrict__ ei, const float* __restrict__ deg,
                const float* __restrict__ w1, const float* __restrict__ b1,
                const float* __restrict__ CpFrag, const float* __restrict__ bpc,
                const float* __restrict__ wp2, const float* __restrict__ bp2,
                float* __restrict__ hacc, float* __restrict__ einv,
                float* __restrict__ pos_upd, int nE, int N)
{
    extern __shared__ float sm[];
    float* sHid  = sm;                      // [128][132]
    float* sBf   = sHid + 128 * HS;         // [16384] fragment-major Cp
    float* s_w1c = sBf + 16384;             // [128]
    float* s_b1  = s_w1c + 128;
    float* s_bpc = s_b1 + 128;
    float* s_wp2 = s_bpc + 128;
    float* s_rel = s_wp2 + 128;             // [128*3]
    float* s_dist= s_rel + 384;
    float* s_inv = s_dist + 128;
    float* s_p   = s_inv + 128;             // [128] row dot results
    int*   s_src = (int*)(s_p + 128);
    int*   s_dst = s_src + 128;

    const int tid  = threadIdx.x;
    const int wid  = tid >> 5;
    const int lane = tid & 31;
    const int b    = blockIdx.y;
    const int e0   = blockIdx.x * TEC;
    const size_t bN = (size_t)b * N;

    // preamble (one edge per thread for tid<128)
    if (tid < TEC) {
        int e = e0 + tid;
        int s = 0, d = 0;
        float x0 = 0.f, x1 = 0.f, x2 = 0.f, dist = 0.f, inv = 0.f;
        if (e < nE) {
            s = ei[e];
            d = ei[nE + e];
            const float* ps = pos + (bN + s) * 3;
            const float* pd = pos + (bN + d) * 3;
            x0 = ps[0] - pd[0];
            x1 = ps[1] - pd[1];
            x2 = ps[2] - pd[2];
            dist = sqrtf(x0 * x0 + x1 * x1 + x2 * x2);
            inv  = 1.0f / fmaxf(deg[d], 1.0f);
        }
        s_src[tid] = s; s_dst[tid] = d;
        s_rel[tid * 3 + 0] = x0; s_rel[tid * 3 + 1] = x1; s_rel[tid * 3 + 2] = x2;
        s_dist[tid] = dist; s_inv[tid] = inv;
        s_w1c[tid] = w1[256 * H_DIM + tid];
        s_b1[tid]  = b1[tid];
        s_bpc[tid] = bpc[tid];
        s_wp2[tid] = wp2[tid];
    }
    // stage B fragments (already fragment-major + tf32 in global)
    {
        const float4* src4 = (const float4*)CpFrag;
        float4* dst4 = (float4*)sBf;
        #pragma unroll
        for (int p = 0; p < 16; ++p) dst4[p * 256 + tid] = src4[p * 256 + tid];
    }
    __syncthreads();

    // gather -> hidden (exact fp32) -> sHid + hacc scatter
    #pragma unroll
    for (int p = 0; p < 16; ++p) {
        int idx = p * 256 + tid;
        int r = idx >> 5, c4 = idx & 31;
        int s = s_src[r], d = s_dst[r];
        float4 va = __ldg((const float4*)pre_a + (bN + s) * 32 + c4);
        float4 vb = __ldg((const float4*)pre_b + (bN + d) * 32 + c4);
        float dd = s_dist[r], inv = s_inv[r];
        float4 wc = *(const float4*)(s_w1c + c4 * 4);
        float4 bb = *(const float4*)(s_b1 + c4 * 4);
        float h0 = silu_f(va.x + vb.x + dd * wc.x + bb.x);
        float h1 = silu_f(va.y + vb.y + dd * wc.y + bb.y);
        float h2 = silu_f(va.z + vb.z + dd * wc.z + bb.z);
        float h3 = silu_f(va.w + vb.w + dd * wc.w + bb.w);
        *(float4*)(sHid + r * HS + c4 * 4) = make_float4(h0, h1, h2, h3);
        float* gp = hacc + (bN + d) * H_DIM + c4 * 4;
        asm volatile("red.global.add.v4.f32 [%0], {%1, %2, %3, %4};"
                     :: "l"(gp), "f"(h0 * inv), "f"(h1 * inv),
                        "f"(h2 * inv), "f"(h3 * inv) : "memory");
    }
    if (tid < TEC && b == 0 && (e0 + tid) < nE)
        atomicAdd(&einv[s_dst[tid]], s_inv[tid]);
    __syncthreads();

    // warp-level tf32 mma: warp wid owns rows [16*wid, 16*wid+16)
    float c[16][4];
    #pragma unroll
    for (int nt = 0; nt < 16; ++nt)
        #pragma unroll
        for (int q = 0; q < 4; ++q) c[nt][q] = 0.f;

    const int ar = wid * 16 + (lane >> 2);
    const int ak = lane & 3;
    #pragma unroll 4
    for (int ks = 0; ks < 16; ++ks) {
        uint32_t a[4];
        int k0 = ks * 8 + ak;
        a[0] = cvt_tf32(sHid[ar * HS + k0]);
        a[1] = cvt_tf32(sHid[(ar + 8) * HS + k0]);
        a[2] = cvt_tf32(sHid[ar * HS + k0 + 4]);
        a[3] = cvt_tf32(sHid[(ar + 8) * HS + k0 + 4]);
        #pragma unroll
        for (int nt = 0; nt < 16; ++nt) {
            uint2 bv = *(const uint2*)(sBf + ((size_t)(nt * 16 + ks) * 32 + lane) * 2);
            mma_tf32(c[nt], a, bv.x, bv.y);
        }
    }

    // epilogue: h2 = silu(d + bpc); row-dot with wp2; 4-lane reduce
    {
        float sum0 = 0.f, sum1 = 0.f;   // rows ar, ar+8
        #pragma unroll
        for (int nt = 0; nt < 16; ++nt) {
            int cb = nt * 8 + 2 * (lane & 3);
            float w0 = s_wp2[cb], w1v = s_wp2[cb + 1];
            float p0 = s_bpc[cb], p1 = s_bpc[cb + 1];
            sum0 += silu_f(c[nt][0] + p0) * w0 + silu_f(c[nt][1] + p1) * w1v;
            sum1 += silu_f(c[nt][2] + p0) * w0 + silu_f(c[nt][3] + p1) * w1v;
        }
        sum0 += __shfl_xor_sync(0xFFFFFFFFu, sum0, 1);
        sum0 += __shfl_xor_sync(0xFFFFFFFFu, sum0, 2);
        sum1 += __shfl_xor_sync(0xFFFFFFFFu, sum1, 1);
        sum1 += __shfl_xor_sync(0xFFFFFFFFu, sum1, 2);
        if ((lane & 3) == 0) {
            s_p[ar]     = sum0;
            s_p[ar + 8] = sum1;
        }
    }
    __syncthreads();

    if (tid < TEC && (e0 + tid) < nE) {
        float w = tanhf(s_p[tid] + bp2[0]);
        int d = s_dst[tid];
        float* pp = pos_upd + (bN + d) * 3;
        atomicAdd(&pp[0], w * s_rel[tid * 3 + 0]);
        atomicAdd(&pp[1], w * s_rel[tid * 3 + 1]);
        atomicAdd(&pp[2], w * s_rel[tid * 3 + 2]);
    }
}

// ---------------------------------------------------------------------------
// node2_kernel (FFMA2 path, unchanged)
// ---------------------------------------------------------------------------
__global__ void __launch_bounds__(256, 2)
node2_kernel(const float* __restrict__ feat,
             const float* __restrict__ hacc0, const float* __restrict__ hacc1,
             const float* __restrict__ wu1,
             const float* __restrict__ Cu0, const float* __restrict__ Cu1,
             const float* __restrict__ einv0, const float* __restrict__ einv1,
             const float* __restrict__ bcu0, const float* __restrict__ bcu1,
             const float* __restrict__ bu1,
             const float* __restrict__ wu2, const float* __restrict__ bu2,
             float* __restrict__ outf, int N, int nRows)
{
    extern __shared__ float sm[];
    float* sB  = sm;
    float* sA  = sB + TE * H_DIM;
    float* sb1 = sA + TE * BS1;
    float* s_eU = sb1 + TE * BS1;
    float* s_eD = s_eU + TE;

    const int tid = threadIdx.x;
    const int tx = tid & 15, ty = tid >> 4;
    const int c0 = tx * 8, r0 = ty * 4;
    const int g0 = blockIdx.x * TE;

    if (tid < TE) {
        int g = g0 + tid;
        float eu = 0.f, ed = 0.f;
        if (g < nRows) {
            int node = g % N;
            eu = einv0[node];
            ed = einv1[node];
        }
        s_eU[tid] = eu; s_eD[tid] = ed;
    }

    unsigned long long acc[4][4];
    #pragma unroll
    for (int i = 0; i < 4; i++)
        #pragma unroll
        for (int j = 0; j < 4; j++) acc[i][j] = 0ull;

    for (int m = 0; m < 3; ++m) {
        const float* src = (m == 0) ? feat : (m == 1) ? hacc0 : hacc1;
        const float* Wm  = (m == 0) ? wu1  : (m == 1) ? Cu0   : Cu1;
        for (int seg = 0; seg < 2; ++seg) {
            #pragma unroll
            for (int p = 0; p < 4; ++p) {
                int idx = p * 256 + tid;
                int r = idx >> 4, c4 = idx & 15;
                float4 v = make_float4(0.f, 0.f, 0.f, 0.f);
                if (g0 + r < nRows)
                    v = __ldg((const float4*)src + (size_t)(g0 + r) * 32 + seg * 16 + c4);
                *(float4*)(sA + r * BS1 + c4 * 4) = v;
            }
            {
                const float4* wv = (const float4*)(Wm + (size_t)seg * 64 * H_DIM);
                float4* sBv = (float4*)sB;
                #pragma unroll
                for (int p = 0; p < 8; ++p) sBv[p * 256 + tid] = wv[p * 256 + tid];
            }
            __syncthreads();
            #pragma unroll 2
            for (int kc = 0; kc < 64; kc += 4) {
                float4 a4[4];
                #pragma unroll
                for (int i = 0; i < 4; i++)
                    a4[i] = *(const float4*)&sA[(r0 + i) * BS1 + kc];
                #pragma unroll
                for (int kk = 0; kk < 4; ++kk) {
                    const ulonglong2* bp =
                        (const ulonglong2*)&sB[(kc + kk) * H_DIM + c0];
                    ulonglong2 b01 = bp[0], b23 = bp[1];
                    #pragma unroll
                    for (int i = 0; i < 4; i++) {
                        float a = (kk == 0) ? a4[i].x : (kk == 1) ? a4[i].y
                                : (kk == 2) ? a4[i].z : a4[i].w;
                        unsigned long long ap = pack2(a, a);
                        ffma2(acc[i][0], ap, b01.x);
                        ffma2(acc[i][1], ap, b01.y);
                        ffma2(acc[i][2], ap, b23.x);
                        ffma2(acc[i][3], ap, b23.y);
                    }
                }
            }
            __syncthreads();
        }
    }
    {
        #pragma unroll
        for (int i = 0; i < 4; i++) {
            int r = r0 + i;
            float eu = s_eU[r], ed = s_eD[r];
            #pragma unroll
            for (int j = 0; j < 4; j++) {
                float2 v = unpack2(acc[i][j]);
                int cA = c0 + 2 * j, cB = c0 + 2 * j + 1;
                float vA = v.x + bu1[cA] + eu * bcu0[cA] + ed * bcu1[cA];
                float vB = v.y + bu1[cB] + eu * bcu0[cB] + ed * bcu1[cB];
                sb1[r * BS1 + cA] = silu_f(vA);
                sb1[r * BS1 + cB] = silu_f(vB);
            }
        }
    }
    __syncthreads();

    #pragma unroll
    for (int i = 0; i < 4; i++)
        #pragma unroll
        for (int j = 0; j < 4; j++) acc[i][j] = 0ull;

    for (int seg = 0; seg < 2; ++seg) {
        const float4* wv = (const float4*)(wu2 + (size_t)seg * 64 * H_DIM);
        float4* sBv = (float4*)sB;
        #pragma unroll
        for (int p = 0; p < 8; ++p) sBv[p * 256 + tid] = wv[p * 256 + tid];
        __syncthreads();
        #pragma unroll 2
        for (int kc = 0; kc < 64; kc += 4) {
            float4 a4[4];
            #pragma unroll
            for (int i = 0; i < 4; i++)
                a4[i] = *(const float4*)&sb1[(r0 + i) * BS1 + seg * 64 + kc];
            #pragma unroll
            for (int kk = 0; kk < 4; ++kk) {
                const ulonglong2* bp =
                    (const ulonglong2*)&sB[(kc + kk) * H_DIM + c0];
                ulonglong2 b01 = bp[0], b23 = bp[1];
                #pragma unroll
                for (int i = 0; i < 4; i++) {
                    float a = (kk == 0) ? a4[i].x : (kk == 1) ? a4[i].y
                            : (kk == 2) ? a4[i].z : a4[i].w;
                    unsigned long long ap = pack2(a, a);
                    ffma2(acc[i][0], ap, b01.x);
                    ffma2(acc[i][1], ap, b01.y);
                    ffma2(acc[i][2], ap, b23.x);
                    ffma2(acc[i][3], ap, b23.y);
                }
            }
        }
        __syncthreads();
    }
    {
        #pragma unroll
        for (int i = 0; i < 4; i++) {
            int g = g0 + r0 + i;
            if (g < nRows) {
                #pragma unroll
                for (int j = 0; j < 4; j++) {
                    float2 v = unpack2(acc[i][j]);
                    size_t oA = (size_t)g * H_DIM + c0 + 2 * j;
                    outf[oA]     = feat[oA]     + v.x + bu2[c0 + 2 * j];
                    outf[oA + 1] = feat[oA + 1] + v.y + bu2[c0 + 2 * j + 1];
                }
            }
        }
    }
}

__global__ void pos_kernel(const float* __restrict__ pos,
                           const float* __restrict__ pos_upd,
                           float* __restrict__ out, int n)
{
    int i = blockIdx.x * blockDim.x + threadIdx.x;
    if (i < n) out[i] = pos[i] + 0.5f * pos_upd[i];
}

extern "C" void kernel_launch(void* const* d_in, const int* in_sizes, int n_in,
                              void* d_out, int out_size)
{
    const float* feat   = (const float*)d_in[0];
    const float* pos    = (const float*)d_in[1];
    const int*   ei_up  = (const int*)d_in[2];
    const int*   ei_dn  = (const int*)d_in[3];
    const float* deg_up = (const float*)d_in[4];
    const float* deg_dn = (const float*)d_in[5];

    const float* w1u  = (const float*)d_in[6];
    const float* b1u  = (const float*)d_in[7];
    const float* w2u  = (const float*)d_in[8];
    const float* b2u  = (const float*)d_in[9];
    const float* wp1u = (const float*)d_in[10];
    const float* bp1u = (const float*)d_in[11];
    const float* wp2u = (const float*)d_in[12];
    const float* bp2u = (const float*)d_in[13];

    const float* w1d  = (const float*)d_in[14];
    const float* b1d  = (const float*)d_in[15];
    const float* w2d  = (const float*)d_in[16];
    const float* b2d  = (const float*)d_in[17];
    const float* wp1d = (const float*)d_in[18];
    const float* bp1d = (const float*)d_in[19];
    const float* wp2d = (const float*)d_in[20];
    const float* bp2d = (const float*)d_in[21];

    const float* wu1 = (const float*)d_in[22];
    const float* bu1 = (const float*)d_in[23];
    const float* wu2 = (const float*)d_in[24];
    const float* bu2 = (const float*)d_in[25];

    int E = in_sizes[2] / 2;
    int N = in_sizes[4];
    int B = in_sizes[0] / (N * H_DIM);
    int nRows = B * N;

    float *pre, *hacc, *einv, *pos_upd, *CpFrag, *Cu, *bpc, *bcu;
    cudaGetSymbolAddress((void**)&pre,     g_pre);
    cudaGetSymbolAddress((void**)&hacc,    g_hacc);
    cudaGetSymbolAddress((void**)&einv,    g_einv);
    cudaGetSymbolAddress((void**)&pos_upd, g_pos_upd);
    cudaGetSymbolAddress((void**)&CpFrag,  g_CpFrag);
    cudaGetSymbolAddress((void**)&Cu,      g_Cu);
    cudaGetSymbolAddress((void**)&bpc,     g_bpc);
    cudaGetSymbolAddress((void**)&bcu,     g_bcu);

    const size_t PS = (size_t)MAX_BN * H_DIM;
    float* pre_au = pre;
    float* pre_bu = pre + PS;
    float* pre_ad = pre + 2 * PS;
    float* pre_bd = pre + 3 * PS;
    float* hacc_u = hacc;
    float* hacc_d = hacc + PS;
    float* einv_u = einv;
    float* einv_d = einv + MAX_N;

    cudaMemsetAsync(hacc, 0, 2 * PS * sizeof(float));
    cudaMemsetAsync(einv, 0, 2 * MAX_N * sizeof(float));
    cudaMemsetAsync(pos_upd, 0, (size_t)nRows * 3 * sizeof(float));

    int smemPre  = (TE * BS1 + TE * H_DIM) * 4;
    int smemEdge = (128 * HS + 16384 + 4 * 128 + 384 + 128 + 128 + 128
                    + 2 * 128) * 4;   // = 139264 B
    int smemNode = (TE * H_DIM + 2 * TE * BS1 + 2 * TE) * 4;
    cudaFuncSetAttribute(pre_kernel,
                         cudaFuncAttributeMaxDynamicSharedMemorySize, smemPre);
    cudaFuncSetAttribute(edge_mma_kernel,
                         cudaFuncAttributeMaxDynamicSharedMemorySize, smemEdge);
    cudaFuncSetAttribute(node2_kernel,
                         cudaFuncAttributeMaxDynamicSharedMemorySize, smemNode);

    combine_kernel<<<dim3(H_DIM + 1, 4), H_DIM>>>(
        w2u, wp1u, b2u, bp1u, w2d, wp1d, b2d, bp1d, wu1,
        CpFrag, CpFrag + H_DIM * H_DIM, Cu, Cu + H_DIM * H_DIM,
        bpc, bpc + H_DIM, bcu, bcu + H_DIM);

    pre_kernel<<<dim3((nRows + TE - 1) / TE, 4), 256, smemPre>>>(
        feat, w1u, w1d, pre_au, pre_bu, pre_ad, pre_bd, nRows);

    dim3 egrid((E + TEC - 1) / TEC, B);
    edge_mma_kernel<<<egrid, 256, smemEdge>>>(
        pre_au, pre_bu, pos, ei_up, deg_up, w1u, b1u,
        CpFrag, bpc, wp2u, bp2u, hacc_u, einv_u, pos_upd, E, N);
    edge_mma_kernel<<<egrid, 256, smemEdge>>>(
        pre_ad, pre_bd, pos, ei_dn, deg_dn, w1d, b1d,
        CpFrag + H_DIM * H_DIM, bpc + H_DIM, wp2d, bp2d,
        hacc_d, einv_d, pos_upd, E, N);

    node2_kernel<<<(nRows + TE - 1) / TE, 256, smemNode>>>(
        feat, hacc_u, hacc_d, wu1, Cu, Cu + H_DIM * H_DIM,
        einv_u, einv_d, bcu, bcu + H_DIM, bu1, wu2, bu2,
        (float*)d_out, N, nRows);

    size_t featN = (size_t)nRows * H_DIM;
    int pn = nRows * 3;
    pos_kernel<<<(pn + 255) / 256, 256>>>(
        pos, pos_upd, (float*)d_out + featN, pn);
}

// round 6
// speedup vs baseline: 5.7417x; 1.3168x over previous
#include <cuda_runtime.h>
#include <math.h>
#include <cstdint>

#define H_DIM 128
#define TE 64          // rows per block tile (node kernel)
#define TEC 128        // edges per block (mma edge kernel)
#define BS1 132        // padded row stride (float4-aligned)
#define HS 132         // hidden tile stride in edge kernel

#define MAX_B 2
#define MAX_N 20000
#define MAX_BN (MAX_B * MAX_N)

// ---------------------------------------------------------------------------
// Scratch (allocation-free rule: __device__ globals)
// ---------------------------------------------------------------------------
__device__ __align__(128) float g_pre[4][(size_t)MAX_BN * H_DIM];
__device__ __align__(128) float g_hacc[2][(size_t)MAX_BN * H_DIM];
__device__ __align__(128) float g_einv[2][MAX_N];
__device__ __align__(128) float g_pos_upd[(size_t)MAX_BN * 3];
__device__ __align__(128) float g_CpFrag[2][H_DIM * H_DIM];  // frag-major tf32 Cp
__device__ __align__(128) float g_Cu[2][H_DIM * H_DIM];      // W2@Wu1_bot (row-major)
__device__ __align__(128) float g_bpc[2][H_DIM];             // b2@Wp1 + bp1
__device__ __align__(128) float g_bcu[2][H_DIM];             // b2@Wu1_bot
__device__ __align__(128) float g_preFrag[4][2][H_DIM * H_DIM]; // [mat][hi/lo] frag images

__device__ __forceinline__ float silu_f(float v) {
    return __fdividef(v, 1.0f + __expf(-v));
}

// ---- packed fp32 helpers (FFMA2) ------------------------------------------
__device__ __forceinline__ void ffma2(unsigned long long& d,
                                      unsigned long long a,
                                      unsigned long long b) {
    asm("fma.rn.f32x2 %0, %1, %2, %0;" : "+l"(d) : "l"(a), "l"(b));
}
__device__ __forceinline__ unsigned long long pack2(float lo, float hi) {
    unsigned long long r;
    asm("mov.b64 %0, {%1, %2};" : "=l"(r) : "f"(lo), "f"(hi));
    return r;
}
__device__ __forceinline__ float2 unpack2(unsigned long long v) {
    float2 r;
    asm("mov.b64 {%0, %1}, %2;" : "=f"(r.x), "=f"(r.y) : "l"(v));
    return r;
}

// ---- tf32 mma.sync helpers --------------------------------------------------
__device__ __forceinline__ uint32_t cvt_tf32(float x) {
    uint32_t r;
    asm("cvt.rna.tf32.f32 %0, %1;" : "=r"(r) : "f"(x));
    return r;
}
__device__ __forceinline__ void mma_tf32(float c[4], const uint32_t a[4],
                                         uint32_t b0, uint32_t b1) {
    asm volatile(
        "mma.sync.aligned.m16n8k8.row.col.f32.tf32.tf32.f32 "
        "{%0,%1,%2,%3}, {%4,%5,%6,%7}, {%8,%9}, {%0,%1,%2,%3};"
        : "+f"(c[0]), "+f"(c[1]), "+f"(c[2]), "+f"(c[3])
        : "r"(a[0]), "r"(a[1]), "r"(a[2]), "r"(a[3]), "r"(b0), "r"(b1));
}

// ---------------------------------------------------------------------------
// combine_kernel: folded-weight GEMMs (Cp frag image, Cu row-major, biases)
// ---------------------------------------------------------------------------
__global__ void combine_kernel(
    const float* __restrict__ w2u, const float* __restrict__ wp1u,
    const float* __restrict__ b2u, const float* __restrict__ bp1u,
    const float* __restrict__ w2d, const float* __restrict__ wp1d,
    const float* __restrict__ b2d, const float* __restrict__ bp1d,
    const float* __restrict__ wu1,
    float* __restrict__ Cf0, float* __restrict__ Cf1,
    float* __restrict__ Cu0, float* __restrict__ Cu1,
    float* __restrict__ bpc0, float* __restrict__ bpc1,
    float* __restrict__ bcu0, float* __restrict__ bcu1)
{
    const float* wu1b = wu1 + 128 * H_DIM;
    const float* A; const float* Bm; const float* bvec; const float* badd;
    float* C; float* bout; bool frag;
    switch (blockIdx.y) {
        case 0:  A = w2u; Bm = wp1u; bvec = b2u; badd = bp1u; C = Cf0; bout = bpc0; frag = true;  break;
        case 1:  A = w2d; Bm = wp1d; bvec = b2d; badd = bp1d; C = Cf1; bout = bpc1; frag = true;  break;
        case 2:  A = w2u; Bm = wu1b; bvec = b2u; badd = 0;    C = Cu0; bout = bcu0; frag = false; break;
        default: A = w2d; Bm = wu1b; bvec = b2d; badd = 0;    C = Cu1; bout = bcu1; frag = false; break;
    }
    int i = blockIdx.x;   // k index
    int j = threadIdx.x;  // n index
    const float* arow = (i < H_DIM) ? (A + (size_t)i * H_DIM) : bvec;
    float s = 0.f;
    #pragma unroll 8
    for (int k = 0; k < H_DIM; ++k) s += arow[k] * Bm[k * H_DIM + j];
    if (i < H_DIM) {
        if (frag) {
            int kstep = i >> 3, kk = i & 7;
            int ntile = j >> 3, nn = j & 7;
            int lane = nn * 4 + (kk & 3);
            int reg  = kk >> 2;
            C[((size_t)(ntile * 16 + kstep) * 32 + lane) * 2 + reg] =
                __uint_as_float(cvt_tf32(s));
        } else {
            C[i * H_DIM + j] = s;
        }
    } else {
        bout[j] = s + (badd ? badd[j] : 0.f);
    }
}

// ---------------------------------------------------------------------------
// fragw_kernel: hi/lo tf32 fragment images of the 4 pre-weight matrices
//   y=0: w1u[0:128], y=1: w1u[128:256], y=2: w1d[0:128], y=3: w1d[128:256]
// ---------------------------------------------------------------------------
__global__ void fragw_kernel(const float* __restrict__ w1u,
                             const float* __restrict__ w1d,
                             float* __restrict__ out)
{
    int y = blockIdx.y;
    const float* W = (y == 0) ? w1u : (y == 1) ? w1u + 128 * H_DIM
                   : (y == 2) ? w1d : w1d + 128 * H_DIM;
    int i = blockIdx.x;   // k
    int j = threadIdx.x;  // n
    float w = W[i * H_DIM + j];
    uint32_t hi = cvt_tf32(w);
    uint32_t lo = cvt_tf32(w - __uint_as_float(hi));
    int kstep = i >> 3, kk = i & 7;
    int ntile = j >> 3, nn = j & 7;
    int lane = nn * 4 + (kk & 3);
    int reg  = kk >> 2;
    size_t idx = ((size_t)(ntile * 16 + kstep) * 32 + lane) * 2 + reg;
    out[(size_t)y * 2 * 16384 + idx]         = __uint_as_float(hi);
    out[(size_t)y * 2 * 16384 + 16384 + idx] = __uint_as_float(lo);
}

// ---------------------------------------------------------------------------
// pre_mma_kernel: pre[y] = feat @ W[y] via split-tf32 mma (fp32-accurate)
//   M=64 rows/block, N=128 in two 8-ntile passes, 256 thr / 8 warps.
// ---------------------------------------------------------------------------
__global__ void __launch_bounds__(256)
pre_mma_kernel(const float* __restrict__ feat, const float* __restrict__ frag,
               float* __restrict__ p0, float* __restrict__ p1,
               float* __restrict__ p2, float* __restrict__ p3, int nRows)
{
    extern __shared__ float sm[];
    float* sA  = sm;               // [64][132]
    float* sBf = sA + 64 * BS1;    // 16384 floats: hi[8192] lo[8192]

    const int tid = threadIdx.x;
    const int wid = tid >> 5, lane = tid & 31;
    const int g0 = blockIdx.x * 64;
    const int y  = blockIdx.y;
    float* out = (y == 0) ? p0 : (y == 1) ? p1 : (y == 2) ? p2 : p3;
    const float* fhi = frag + (size_t)y * 2 * 16384;
    const float* flo = fhi + 16384;

    // stage A (64 x 128)
    #pragma unroll
    for (int p = 0; p < 8; ++p) {
        int idx = p * 256 + tid;
        int r = idx >> 5, c4 = idx & 31;
        float4 v = make_float4(0.f, 0.f, 0.f, 0.f);
        if (g0 + r < nRows)
            v = __ldg((const float4*)feat + (size_t)(g0 + r) * 32 + c4);
        *(float4*)(sA + r * BS1 + c4 * 4) = v;
    }

    const int rg = wid & 3, cg = wid >> 2;
    const int ar = rg * 16 + (lane >> 2);
    const int ak = lane & 3;

    for (int pass = 0; pass < 2; ++pass) {
        __syncthreads();
        {
            const float4* shi = (const float4*)(fhi + pass * 8192);
            const float4* slo = (const float4*)(flo + pass * 8192);
            float4* d = (float4*)sBf;
            #pragma unroll
            for (int p = 0; p < 8; ++p) {
                d[p * 256 + tid]        = shi[p * 256 + tid];
                d[2048 + p * 256 + tid] = slo[p * 256 + tid];
            }
        }
        __syncthreads();

        float c[4][4];
        #pragma unroll
        for (int nt = 0; nt < 4; ++nt)
            #pragma unroll
            for (int q = 0; q < 4; ++q) c[nt][q] = 0.f;

        #pragma unroll 4
        for (int ks = 0; ks < 16; ++ks) {
            int k0 = ks * 8 + ak;
            float x0 = sA[ar * BS1 + k0];
            float x1 = sA[(ar + 8) * BS1 + k0];
            float x2 = sA[ar * BS1 + k0 + 4];
            float x3 = sA[(ar + 8) * BS1 + k0 + 4];
            uint32_t ah[4], al[4];
            ah[0] = cvt_tf32(x0); al[0] = cvt_tf32(x0 - __uint_as_float(ah[0]));
            ah[1] = cvt_tf32(x1); al[1] = cvt_tf32(x1 - __uint_as_float(ah[1]));
            ah[2] = cvt_tf32(x2); al[2] = cvt_tf32(x2 - __uint_as_float(ah[2]));
            ah[3] = cvt_tf32(x3); al[3] = cvt_tf32(x3 - __uint_as_float(ah[3]));
            #pragma unroll
            for (int nt = 0; nt < 4; ++nt) {
                int ntl = cg * 4 + nt;
                const float* bp = sBf + ((size_t)(ntl * 16 + ks) * 32 + lane) * 2;
                uint2 bh = *(const uint2*)bp;
                uint2 bl = *(const uint2*)(bp + 8192);
                mma_tf32(c[nt], ah, bh.x, bh.y);   // hi*hi
                mma_tf32(c[nt], al, bh.x, bh.y);   // lo*hi
                mma_tf32(c[nt], ah, bl.x, bl.y);   // hi*lo
            }
        }
        // write
        int row0 = g0 + rg * 16 + (lane >> 2);
        #pragma unroll
        for (int nt = 0; nt < 4; ++nt) {
            int col = (pass * 8 + cg * 4 + nt) * 8 + 2 * (lane & 3);
            if (row0 < nRows)
                *(float2*)&out[(size_t)row0 * H_DIM + col] =
                    make_float2(c[nt][0], c[nt][1]);
            if (row0 + 8 < nRows)
                *(float2*)&out[(size_t)(row0 + 8) * H_DIM + col] =
                    make_float2(c[nt][2], c[nt][3]);
        }
    }
}

// ---------------------------------------------------------------------------
// edge_mma_kernel: 256 thr, 128 edges/block, two-pass B staging (2 CTA/SM)
// ---------------------------------------------------------------------------
__global__ void __launch_bounds__(256)
edge_mma_kernel(const float* __restrict__ pre_a, const float* __restrict__ pre_b,
                const float* __restrict__ pos,
                const int* __restrict__ ei, const float* __restrict__ deg,
                const float* __restrict__ w1, const float* __restrict__ b1,
                const float* __restrict__ CpFrag, const float* __restrict__ bpc,
                const float* __restrict__ wp2, const float* __restrict__ bp2,
                float* __restrict__ hacc, float* __restrict__ einv,
                float* __restrict__ pos_upd, int nE, int N)
{
    extern __shared__ float sm[];
    float* sHid  = sm;                      // [128][132]
    float* sBf   = sHid + 128 * HS;         // [8192] half of Cp frags
    float* s_w1c = sBf + 8192;              // [128]
    float* s_b1  = s_w1c + 128;
    float* s_bpc = s_b1 + 128;
    float* s_wp2 = s_bpc + 128;
    float* s_rel = s_wp2 + 128;             // [128*3]
    float* s_dist= s_rel + 384;
    float* s_inv = s_dist + 128;
    float* s_p   = s_inv + 128;             // [128]
    int*   s_src = (int*)(s_p + 128);
    int*   s_dst = s_src + 128;

    const int tid  = threadIdx.x;
    const int wid  = tid >> 5;
    const int lane = tid & 31;
    const int b    = blockIdx.y;
    const int e0   = blockIdx.x * TEC;
    const size_t bN = (size_t)b * N;

    // preamble
    if (tid < TEC) {
        int e = e0 + tid;
        int s = 0, d = 0;
        float x0 = 0.f, x1 = 0.f, x2 = 0.f, dist = 0.f, inv = 0.f;
        if (e < nE) {
            s = ei[e];
            d = ei[nE + e];
            const float* ps = pos + (bN + s) * 3;
            const float* pd = pos + (bN + d) * 3;
            x0 = ps[0] - pd[0];
            x1 = ps[1] - pd[1];
            x2 = ps[2] - pd[2];
            dist = sqrtf(x0 * x0 + x1 * x1 + x2 * x2);
            inv  = 1.0f / fmaxf(deg[d], 1.0f);
        }
        s_src[tid] = s; s_dst[tid] = d;
        s_rel[tid * 3 + 0] = x0; s_rel[tid * 3 + 1] = x1; s_rel[tid * 3 + 2] = x2;
        s_dist[tid] = dist; s_inv[tid] = inv;
        s_w1c[tid] = w1[256 * H_DIM + tid];
        s_b1[tid]  = b1[tid];
        s_bpc[tid] = bpc[tid];
        s_wp2[tid] = wp2[tid];
    }
    __syncthreads();

    // gather -> hidden (exact fp32) -> sHid + hacc scatter
    #pragma unroll
    for (int p = 0; p < 16; ++p) {
        int idx = p * 256 + tid;
        int r = idx >> 5, c4 = idx & 31;
        int s = s_src[r], d = s_dst[r];
        float4 va = __ldg((const float4*)pre_a + (bN + s) * 32 + c4);
        float4 vb = __ldg((const float4*)pre_b + (bN + d) * 32 + c4);
        float dd = s_dist[r], inv = s_inv[r];
        float4 wc = *(const float4*)(s_w1c + c4 * 4);
        float4 bb = *(const float4*)(s_b1 + c4 * 4);
        float h0 = silu_f(va.x + vb.x + dd * wc.x + bb.x);
        float h1 = silu_f(va.y + vb.y + dd * wc.y + bb.y);
        float h2 = silu_f(va.z + vb.z + dd * wc.z + bb.z);
        float h3 = silu_f(va.w + vb.w + dd * wc.w + bb.w);
        *(float4*)(sHid + r * HS + c4 * 4) = make_float4(h0, h1, h2, h3);
        float* gp = hacc + (bN + d) * H_DIM + c4 * 4;
        asm volatile("red.global.add.v4.f32 [%0], {%1, %2, %3, %4};"
                     :: "l"(gp), "f"(h0 * inv), "f"(h1 * inv),
                        "f"(h2 * inv), "f"(h3 * inv) : "memory");
    }
    if (tid < TEC && b == 0 && (e0 + tid) < nE)
        atomicAdd(&einv[s_dst[tid]], s_inv[tid]);

    // two-pass mma + epilogue
    const int ar = wid * 16 + (lane >> 2);
    const int ak = lane & 3;
    float sum0 = 0.f, sum1 = 0.f;

    for (int pass = 0; pass < 2; ++pass) {
        __syncthreads();    // sHid ready (pass0) / sBf readers done (pass1)
        {
            const float4* src4 = (const float4*)(CpFrag + pass * 8192);
            float4* dst4 = (float4*)sBf;
            #pragma unroll
            for (int p = 0; p < 8; ++p) dst4[p * 256 + tid] = src4[p * 256 + tid];
        }
        __syncthreads();

        float c[8][4];
        #pragma unroll
        for (int nt = 0; nt < 8; ++nt)
            #pragma unroll
            for (int q = 0; q < 4; ++q) c[nt][q] = 0.f;

        #pragma unroll 4
        for (int ks = 0; ks < 16; ++ks) {
            uint32_t a[4];
            int k0 = ks * 8 + ak;
            a[0] = cvt_tf32(sHid[ar * HS + k0]);
            a[1] = cvt_tf32(sHid[(ar + 8) * HS + k0]);
            a[2] = cvt_tf32(sHid[ar * HS + k0 + 4]);
            a[3] = cvt_tf32(sHid[(ar + 8) * HS + k0 + 4]);
            #pragma unroll
            for (int nt = 0; nt < 8; ++nt) {
                uint2 bv = *(const uint2*)(sBf + ((size_t)(nt * 16 + ks) * 32 + lane) * 2);
                mma_tf32(c[nt], a, bv.x, bv.y);
            }
        }
        #pragma unroll
        for (int nt = 0; nt < 8; ++nt) {
            int cb = pass * 64 + nt * 8 + 2 * (lane & 3);
            float w0 = s_wp2[cb], w1v = s_wp2[cb + 1];
            float q0 = s_bpc[cb], q1 = s_bpc[cb + 1];
            sum0 += silu_f(c[nt][0] + q0) * w0 + silu_f(c[nt][1] + q1) * w1v;
            sum1 += silu_f(c[nt][2] + q0) * w0 + silu_f(c[nt][3] + q1) * w1v;
        }
    }

    sum0 += __shfl_xor_sync(0xFFFFFFFFu, sum0, 1);
    sum0 += __shfl_xor_sync(0xFFFFFFFFu, sum0, 2);
    sum1 += __shfl_xor_sync(0xFFFFFFFFu, sum1, 1);
    sum1 += __shfl_xor_sync(0xFFFFFFFFu, sum1, 2);
    if ((lane & 3) == 0) {
        s_p[ar]     = sum0;
        s_p[ar + 8] = sum1;
    }
    __syncthreads();

    if (tid < TEC && (e0 + tid) < nE) {
        float w = tanhf(s_p[tid] + bp2[0]);
        int d = s_dst[tid];
        float* pp = pos_upd + (bN + d) * 3;
        atomicAdd(&pp[0], w * s_rel[tid * 3 + 0]);
        atomicAdd(&pp[1], w * s_rel[tid * 3 + 1]);
        atomicAdd(&pp[2], w * s_rel[tid * 3 + 2]);
    }
}

// ---------------------------------------------------------------------------
// node2_kernel (FFMA2 path, unchanged)
// ---------------------------------------------------------------------------
__global__ void __launch_bounds__(256, 2)
node2_kernel(const float* __restrict__ feat,
             const float* __restrict__ hacc0, const float* __restrict__ hacc1,
             const float* __restrict__ wu1,
             const float* __restrict__ Cu0, const float* __restrict__ Cu1,
             const float* __restrict__ einv0, const float* __restrict__ einv1,
             const float* __restrict__ bcu0, const float* __restrict__ bcu1,
             const float* __restrict__ bu1,
             const float* __restrict__ wu2, const float* __restrict__ bu2,
             float* __restrict__ outf, int N, int nRows)
{
    extern __shared__ float sm[];
    float* sB  = sm;
    float* sA  = sB + TE * H_DIM;
    float* sb1 = sA + TE * BS1;
    float* s_eU = sb1 + TE * BS1;
    float* s_eD = s_eU + TE;

    const int tid = threadIdx.x;
    const int tx = tid & 15, ty = tid >> 4;
    const int c0 = tx * 8, r0 = ty * 4;
    const int g0 = blockIdx.x * TE;

    if (tid < TE) {
        int g = g0 + tid;
        float eu = 0.f, ed = 0.f;
        if (g < nRows) {
            int node = g % N;
            eu = einv0[node];
            ed = einv1[node];
        }
        s_eU[tid] = eu; s_eD[tid] = ed;
    }

    unsigned long long acc[4][4];
    #pragma unroll
    for (int i = 0; i < 4; i++)
        #pragma unroll
        for (int j = 0; j < 4; j++) acc[i][j] = 0ull;

    for (int m = 0; m < 3; ++m) {
        const float* src = (m == 0) ? feat : (m == 1) ? hacc0 : hacc1;
        const float* Wm  = (m == 0) ? wu1  : (m == 1) ? Cu0   : Cu1;
        for (int seg = 0; seg < 2; ++seg) {
            #pragma unroll
            for (int p = 0; p < 4; ++p) {
                int idx = p * 256 + tid;
                int r = idx >> 4, c4 = idx & 15;
                float4 v = make_float4(0.f, 0.f, 0.f, 0.f);
                if (g0 + r < nRows)
                    v = __ldg((const float4*)src + (size_t)(g0 + r) * 32 + seg * 16 + c4);
                *(float4*)(sA + r * BS1 + c4 * 4) = v;
            }
            {
                const float4* wv = (const float4*)(Wm + (size_t)seg * 64 * H_DIM);
                float4* sBv = (float4*)sB;
                #pragma unroll
                for (int p = 0; p < 8; ++p) sBv[p * 256 + tid] = wv[p * 256 + tid];
            }
            __syncthreads();
            #pragma unroll 2
            for (int kc = 0; kc < 64; kc += 4) {
                float4 a4[4];
                #pragma unroll
                for (int i = 0; i < 4; i++)
                    a4[i] = *(const float4*)&sA[(r0 + i) * BS1 + kc];
                #pragma unroll
                for (int kk = 0; kk < 4; ++kk) {
                    const ulonglong2* bp =
                        (const ulonglong2*)&sB[(kc + kk) * H_DIM + c0];
                    ulonglong2 b01 = bp[0], b23 = bp[1];
                    #pragma unroll
                    for (int i = 0; i < 4; i++) {
                        float a = (kk == 0) ? a4[i].x : (kk == 1) ? a4[i].y
                                : (kk == 2) ? a4[i].z : a4[i].w;
                        unsigned long long ap = pack2(a, a);
                        ffma2(acc[i][0], ap, b01.x);
                        ffma2(acc[i][1], ap, b01.y);
                        ffma2(acc[i][2], ap, b23.x);
                        ffma2(acc[i][3], ap, b23.y);
                    }
                }
            }
            __syncthreads();
        }
    }
    {
        #pragma unroll
        for (int i = 0; i < 4; i++) {
            int r = r0 + i;
            float eu = s_eU[r], ed = s_eD[r];
            #pragma unroll
            for (int j = 0; j < 4; j++) {
                float2 v = unpack2(acc[i][j]);
                int cA = c0 + 2 * j, cB = c0 + 2 * j + 1;
                float vA = v.x + bu1[cA] + eu * bcu0[cA] + ed * bcu1[cA];
                float vB = v.y + bu1[cB] + eu * bcu0[cB] + ed * bcu1[cB];
                sb1[r * BS1 + cA] = silu_f(vA);
                sb1[r * BS1 + cB] = silu_f(vB);
            }
        }
    }
    __syncthreads();

    #pragma unroll
    for (int i = 0; i < 4; i++)
        #pragma unroll
        for (int j = 0; j < 4; j++) acc[i][j] = 0ull;

    for (int seg = 0; seg < 2; ++seg) {
        const float4* wv = (const float4*)(wu2 + (size_t)seg * 64 * H_DIM);
        float4* sBv = (float4*)sB;
        #pragma unroll
        for (int p = 0; p < 8; ++p) sBv[p * 256 + tid] = wv[p * 256 + tid];
        __syncthreads();
        #pragma unroll 2
        for (int kc = 0; kc < 64; kc += 4) {
            float4 a4[4];
            #pragma unroll
            for (int i = 0; i < 4; i++)
                a4[i] = *(const float4*)&sb1[(r0 + i) * BS1 + seg * 64 + kc];
            #pragma unroll
            for (int kk = 0; kk < 4; ++kk) {
                const ulonglong2* bp =
                    (const ulonglong2*)&sB[(kc + kk) * H_DIM + c0];
                ulonglong2 b01 = bp[0], b23 = bp[1];
                #pragma unroll
                for (int i = 0; i < 4; i++) {
                    float a = (kk == 0) ? a4[i].x : (kk == 1) ? a4[i].y
                            : (kk == 2) ? a4[i].z : a4[i].w;
                    unsigned long long ap = pack2(a, a);
                    ffma2(acc[i][0], ap, b01.x);
                    ffma2(acc[i][1], ap, b01.y);
                    ffma2(acc[i][2], ap, b23.x);
                    ffma2(acc[i][3], ap, b23.y);
                }
            }
        }
        __syncthreads();
    }
    {
        #pragma unroll
        for (int i = 0; i < 4; i++) {
            int g = g0 + r0 + i;
            if (g < nRows) {
                #pragma unroll
                for (int j = 0; j < 4; j++) {
                    float2 v = unpack2(acc[i][j]);
                    size_t oA = (size_t)g * H_DIM + c0 + 2 * j;
                    outf[oA]     = feat[oA]     + v.x + bu2[c0 + 2 * j];
                    outf[oA + 1] = feat[oA + 1] + v.y + bu2[c0 + 2 * j + 1];
                }
            }
        }
    }
}

__global__ void pos_kernel(const float* __restrict__ pos,
                           const float* __restrict__ pos_upd,
                           float* __restrict__ out, int n)
{
    int i = blockIdx.x * blockDim.x + threadIdx.x;
    if (i < n) out[i] = pos[i] + 0.5f * pos_upd[i];
}

extern "C" void kernel_launch(void* const* d_in, const int* in_sizes, int n_in,
                              void* d_out, int out_size)
{
    const float* feat   = (const float*)d_in[0];
    const float* pos    = (const float*)d_in[1];
    const int*   ei_up  = (const int*)d_in[2];
    const int*   ei_dn  = (const int*)d_in[3];
    const float* deg_up = (const float*)d_in[4];
    const float* deg_dn = (const float*)d_in[5];

    const float* w1u  = (const float*)d_in[6];
    const float* b1u  = (const float*)d_in[7];
    const float* w2u  = (const float*)d_in[8];
    const float* b2u  = (const float*)d_in[9];
    const float* wp1u = (const float*)d_in[10];
    const float* bp1u = (const float*)d_in[11];
    const float* wp2u = (const float*)d_in[12];
    const float* bp2u = (const float*)d_in[13];

    const float* w1d  = (const float*)d_in[14];
    const float* b1d  = (const float*)d_in[15];
    const float* w2d  = (const float*)d_in[16];
    const float* b2d  = (const float*)d_in[17];
    const float* wp1d = (const float*)d_in[18];
    const float* bp1d = (const float*)d_in[19];
    const float* wp2d = (const float*)d_in[20];
    const float* bp2d = (const float*)d_in[21];

    const float* wu1 = (const float*)d_in[22];
    const float* bu1 = (const float*)d_in[23];
    const float* wu2 = (const float*)d_in[24];
    const float* bu2 = (const float*)d_in[25];

    int E = in_sizes[2] / 2;
    int N = in_sizes[4];
    int B = in_sizes[0] / (N * H_DIM);
    int nRows = B * N;

    float *pre, *hacc, *einv, *pos_upd, *CpFrag, *Cu, *bpc, *bcu, *preFrag;
    cudaGetSymbolAddress((void**)&pre,     g_pre);
    cudaGetSymbolAddress((void**)&hacc,    g_hacc);
    cudaGetSymbolAddress((void**)&einv,    g_einv);
    cudaGetSymbolAddress((void**)&pos_upd, g_pos_upd);
    cudaGetSymbolAddress((void**)&CpFrag,  g_CpFrag);
    cudaGetSymbolAddress((void**)&Cu,      g_Cu);
    cudaGetSymbolAddress((void**)&bpc,     g_bpc);
    cudaGetSymbolAddress((void**)&bcu,     g_bcu);
    cudaGetSymbolAddress((void**)&preFrag, g_preFrag);

    const size_t PS = (size_t)MAX_BN * H_DIM;
    float* pre_au = pre;
    float* pre_bu = pre + PS;
    float* pre_ad = pre + 2 * PS;
    float* pre_bd = pre + 3 * PS;
    float* hacc_u = hacc;
    float* hacc_d = hacc + PS;
    float* einv_u = einv;
    float* einv_d = einv + MAX_N;

    cudaMemsetAsync(hacc, 0, 2 * PS * sizeof(float));
    cudaMemsetAsync(einv, 0, 2 * MAX_N * sizeof(float));
    cudaMemsetAsync(pos_upd, 0, (size_t)nRows * 3 * sizeof(float));

    int smemPre  = (64 * BS1 + 16384) * 4;                     //  99328 B
    int smemEdge = (128 * HS + 8192 + 4 * 128 + 384 + 128 + 128 + 128
                    + 2 * 128) * 4;                            // 106496 B
    int smemNode = (TE * H_DIM + 2 * TE * BS1 + 2 * TE) * 4;
    cudaFuncSetAttribute(pre_mma_kernel,
                         cudaFuncAttributeMaxDynamicSharedMemorySize, smemPre);
    cudaFuncSetAttribute(edge_mma_kernel,
                         cudaFuncAttributeMaxDynamicSharedMemorySize, smemEdge);
    cudaFuncSetAttribute(node2_kernel,
                         cudaFuncAttributeMaxDynamicSharedMemorySize, smemNode);

    combine_kernel<<<dim3(H_DIM + 1, 4), H_DIM>>>(
        w2u, wp1u, b2u, bp1u, w2d, wp1d, b2d, bp1d, wu1,
        CpFrag, CpFrag + H_DIM * H_DIM, Cu, Cu + H_DIM * H_DIM,
        bpc, bpc + H_DIM, bcu, bcu + H_DIM);

    fragw_kernel<<<dim3(H_DIM, 4), H_DIM>>>(w1u, w1d, preFrag);

    pre_mma_kernel<<<dim3((nRows + 63) / 64, 4), 256, smemPre>>>(
        feat, preFrag, pre_au, pre_bu, pre_ad, pre_bd, nRows);

    dim3 egrid((E + TEC - 1) / TEC, B);
    edge_mma_kernel<<<egrid, 256, smemEdge>>>(
        pre_au, pre_bu, pos, ei_up, deg_up, w1u, b1u,
        CpFrag, bpc, wp2u, bp2u, hacc_u, einv_u, pos_upd, E, N);
    edge_mma_kernel<<<egrid, 256, smemEdge>>>(
        pre_ad, pre_bd, pos, ei_dn, deg_dn, w1d, b1d,
        CpFrag + H_DIM * H_DIM, bpc + H_DIM, wp2d, bp2d,
        hacc_d, einv_d, pos_upd, E, N);

    node2_kernel<<<(nRows + TE - 1) / TE, 256, smemNode>>>(
        feat, hacc_u, hacc_d, wu1, Cu, Cu + H_DIM * H_DIM,
        einv_u, einv_d, bcu, bcu + H_DIM, bu1, wu2, bu2,
        (float*)d_out, N, nRows);

    size_t featN = (size_t)nRows * H_DIM;
    int pn = nRows * 3;
    pos_kernel<<<(pn + 255) / 256, 256>>>(
        pos, pos_upd, (float*)d_out + featN, pn);
}

// round 7
// speedup vs baseline: 6.1039x; 1.0631x over previous
#include <cuda_runtime.h>
#include <math.h>
#include <cstdint>

#define H_DIM 128
#define TEC 128        // edges per block (mma edge kernel)
#define BS1 132        // padded row stride (float4-aligned)
#define HS 132         // hidden tile stride in edge kernel

#define MAX_B 2
#define MAX_N 20000
#define MAX_BN (MAX_B * MAX_N)

// ---------------------------------------------------------------------------
// Scratch (allocation-free rule: __device__ globals)
// ---------------------------------------------------------------------------
__device__ __align__(128) float g_pre[4][(size_t)MAX_BN * H_DIM];
__device__ __align__(128) float g_hacc[2][(size_t)MAX_BN * H_DIM];
__device__ __align__(128) float g_einv[2][MAX_N];
__device__ __align__(128) float g_pos_upd[(size_t)MAX_BN * 3];
__device__ __align__(128) float g_CpFrag[2][H_DIM * H_DIM];      // frag tf32 Cp (hi only)
__device__ __align__(128) float g_bpc[2][H_DIM];                 // b2@Wp1 + bp1
__device__ __align__(128) float g_bcu[2][H_DIM];                 // b2@Wu1_bot
__device__ __align__(128) float g_preFrag[4][2][H_DIM * H_DIM];  // [mat][hi/lo]
__device__ __align__(128) float g_nodeFrag[4][2][H_DIM * H_DIM]; // wu1top,Cu0,Cu1,wu2

__device__ __forceinline__ float silu_f(float v) {
    return __fdividef(v, 1.0f + __expf(-v));
}

// ---- tf32 mma.sync helpers --------------------------------------------------
__device__ __forceinline__ uint32_t cvt_tf32(float x) {
    uint32_t r;
    asm("cvt.rna.tf32.f32 %0, %1;" : "=r"(r) : "f"(x));
    return r;
}
__device__ __forceinline__ void mma_tf32(float c[4], const uint32_t a[4],
                                         uint32_t b0, uint32_t b1) {
    asm volatile(
        "mma.sync.aligned.m16n8k8.row.col.f32.tf32.tf32.f32 "
        "{%0,%1,%2,%3}, {%4,%5,%6,%7}, {%8,%9}, {%0,%1,%2,%3};"
        : "+f"(c[0]), "+f"(c[1]), "+f"(c[2]), "+f"(c[3])
        : "r"(a[0]), "r"(a[1]), "r"(a[2]), "r"(a[3]), "r"(b0), "r"(b1));
}
// fragment index for element (k=i, n=j) of a 128x128 B operand
__device__ __forceinline__ size_t frag_idx(int i, int j) {
    int kstep = i >> 3, kk = i & 7;
    int ntile = j >> 3, nn = j & 7;
    int lane = nn * 4 + (kk & 3);
    int reg  = kk >> 2;
    return ((size_t)(ntile * 16 + kstep) * 32 + lane) * 2 + reg;
}

// ---------------------------------------------------------------------------
// combine_kernel: folded-weight GEMMs
//  y=0/1: Cp frag image (hi only, tf32) for up/down + bpc
//  y=2/3: Cu = W2@Wu1_bot frag hi/lo images into nodeFrag[1]/[2] + bcu
// ---------------------------------------------------------------------------
__global__ void combine_kernel(
    const float* __restrict__ w2u, const float* __restrict__ wp1u,
    const float* __restrict__ b2u, const float* __restrict__ bp1u,
    const float* __restrict__ w2d, const float* __restrict__ wp1d,
    const float* __restrict__ b2d, const float* __restrict__ bp1d,
    const float* __restrict__ wu1,
    float* __restrict__ CpFrag, float* __restrict__ nodeFrag,
    float* __restrict__ bpc, float* __restrict__ bcu)
{
    const float* wu1b = wu1 + 128 * H_DIM;
    const float* A; const float* Bm; const float* bvec; const float* badd;
    float* C; float* bout; bool split;
    switch (blockIdx.y) {
        case 0:  A = w2u; Bm = wp1u; bvec = b2u; badd = bp1u;
                 C = CpFrag;                bout = bpc;         split = false; break;
        case 1:  A = w2d; Bm = wp1d; bvec = b2d; badd = bp1d;
                 C = CpFrag + 16384;        bout = bpc + H_DIM; split = false; break;
        case 2:  A = w2u; Bm = wu1b; bvec = b2u; badd = 0;
                 C = nodeFrag + 1 * 32768;  bout = bcu;         split = true;  break;
        default: A = w2d; Bm = wu1b; bvec = b2d; badd = 0;
                 C = nodeFrag + 2 * 32768;  bout = bcu + H_DIM; split = true;  break;
    }
    int i = blockIdx.x;   // k index
    int j = threadIdx.x;  // n index
    const float* arow = (i < H_DIM) ? (A + (size_t)i * H_DIM) : bvec;
    float s = 0.f;
    #pragma unroll 8
    for (int k = 0; k < H_DIM; ++k) s += arow[k] * Bm[k * H_DIM + j];
    if (i < H_DIM) {
        size_t idx = frag_idx(i, j);
        uint32_t hi = cvt_tf32(s);
        C[idx] = __uint_as_float(hi);
        if (split)
            C[16384 + idx] = __uint_as_float(cvt_tf32(s - __uint_as_float(hi)));
    } else {
        bout[j] = s + (badd ? badd[j] : 0.f);
    }
}

// ---------------------------------------------------------------------------
// fragw_kernel: hi/lo tf32 fragment images of raw weight matrices
//  y=0..3 -> preFrag (w1u lo/hi halves, w1d halves); y=4 -> wu1_top; y=5 -> wu2
// ---------------------------------------------------------------------------
__global__ void fragw_kernel(const float* __restrict__ w1u,
                             const float* __restrict__ w1d,
                             const float* __restrict__ wu1,
                             const float* __restrict__ wu2,
                             float* __restrict__ preFrag,
                             float* __restrict__ nodeFrag)
{
    int y = blockIdx.y;
    const float* W; float* out;
    switch (y) {
        case 0: W = w1u;                 out = preFrag;               break;
        case 1: W = w1u + 128 * H_DIM;   out = preFrag + 32768;       break;
        case 2: W = w1d;                 out = preFrag + 2 * 32768;   break;
        case 3: W = w1d + 128 * H_DIM;   out = preFrag + 3 * 32768;   break;
        case 4: W = wu1;                 out = nodeFrag;              break;  // top rows
        default: W = wu2;                out = nodeFrag + 3 * 32768;  break;
    }
    int i = blockIdx.x;   // k
    int j = threadIdx.x;  // n
    float w = W[i * H_DIM + j];
    uint32_t hi = cvt_tf32(w);
    uint32_t lo = cvt_tf32(w - __uint_as_float(hi));
    size_t idx = frag_idx(i, j);
    out[idx]         = __uint_as_float(hi);
    out[16384 + idx] = __uint_as_float(lo);
}

// ---------------------------------------------------------------------------
// pre_mma_kernel: pre[y] = feat @ W[y] via split-tf32 mma (fp32-accurate)
//   M=64 rows/block, N=128 in two 8-ntile passes, 256 thr / 8 warps.
// ---------------------------------------------------------------------------
__global__ void __launch_bounds__(256)
pre_mma_kernel(const float* __restrict__ feat, const float* __restrict__ frag,
               float* __restrict__ p0, float* __restrict__ p1,
               float* __restrict__ p2, float* __restrict__ p3, int nRows)
{
    extern __shared__ float sm[];
    float* sA  = sm;               // [64][132]
    float* sBf = sA + 64 * BS1;    // 16384 floats: hi[8192] lo[8192]

    const int tid = threadIdx.x;
    const int wid = tid >> 5, lane = tid & 31;
    const int g0 = blockIdx.x * 64;
    const int y  = blockIdx.y;
    float* out = (y == 0) ? p0 : (y == 1) ? p1 : (y == 2) ? p2 : p3;
    const float* fhi = frag + (size_t)y * 2 * 16384;
    const float* flo = fhi + 16384;

    #pragma unroll
    for (int p = 0; p < 8; ++p) {
        int idx = p * 256 + tid;
        int r = idx >> 5, c4 = idx & 31;
        float4 v = make_float4(0.f, 0.f, 0.f, 0.f);
        if (g0 + r < nRows)
            v = __ldg((const float4*)feat + (size_t)(g0 + r) * 32 + c4);
        *(float4*)(sA + r * BS1 + c4 * 4) = v;
    }

    const int rg = wid & 3, cg = wid >> 2;
    const int ar = rg * 16 + (lane >> 2);
    const int ak = lane & 3;

    for (int pass = 0; pass < 2; ++pass) {
        __syncthreads();
        {
            const float4* shi = (const float4*)(fhi + pass * 8192);
            const float4* slo = (const float4*)(flo + pass * 8192);
            float4* d = (float4*)sBf;
            #pragma unroll
            for (int p = 0; p < 8; ++p) {
                d[p * 256 + tid]        = shi[p * 256 + tid];
                d[2048 + p * 256 + tid] = slo[p * 256 + tid];
            }
        }
        __syncthreads();

        float c[4][4];
        #pragma unroll
        for (int nt = 0; nt < 4; ++nt)
            #pragma unroll
            for (int q = 0; q < 4; ++q) c[nt][q] = 0.f;

        #pragma unroll 4
        for (int ks = 0; ks < 16; ++ks) {
            int k0 = ks * 8 + ak;
            float x0 = sA[ar * BS1 + k0];
            float x1 = sA[(ar + 8) * BS1 + k0];
            float x2 = sA[ar * BS1 + k0 + 4];
            float x3 = sA[(ar + 8) * BS1 + k0 + 4];
            uint32_t ah[4], al[4];
            ah[0] = cvt_tf32(x0); al[0] = cvt_tf32(x0 - __uint_as_float(ah[0]));
            ah[1] = cvt_tf32(x1); al[1] = cvt_tf32(x1 - __uint_as_float(ah[1]));
            ah[2] = cvt_tf32(x2); al[2] = cvt_tf32(x2 - __uint_as_float(ah[2]));
            ah[3] = cvt_tf32(x3); al[3] = cvt_tf32(x3 - __uint_as_float(ah[3]));
            #pragma unroll
            for (int nt = 0; nt < 4; ++nt) {
                int ntl = cg * 4 + nt;
                const float* bp = sBf + ((size_t)(ntl * 16 + ks) * 32 + lane) * 2;
                uint2 bh = *(const uint2*)bp;
                uint2 bl = *(const uint2*)(bp + 8192);
                mma_tf32(c[nt], ah, bh.x, bh.y);
                mma_tf32(c[nt], al, bh.x, bh.y);
                mma_tf32(c[nt], ah, bl.x, bl.y);
            }
        }
        int row0 = g0 + rg * 16 + (lane >> 2);
        #pragma unroll
        for (int nt = 0; nt < 4; ++nt) {
            int col = (pass * 8 + cg * 4 + nt) * 8 + 2 * (lane & 3);
            if (row0 < nRows)
                *(float2*)&out[(size_t)row0 * H_DIM + col] =
                    make_float2(c[nt][0], c[nt][1]);
            if (row0 + 8 < nRows)
                *(float2*)&out[(size_t)(row0 + 8) * H_DIM + col] =
                    make_float2(c[nt][2], c[nt][3]);
        }
    }
}

// ---------------------------------------------------------------------------
// edge_mma_kernel: merged both directions (blockIdx.z), 256 thr, 128 edges/blk
// ---------------------------------------------------------------------------
struct EdgeDir {
    const float* pre_a; const float* pre_b;
    const int* ei; const float* deg;
    const float* w1; const float* b1;
    const float* CpFrag; const float* bpc;
    const float* wp2; const float* bp2;
    float* hacc; float* einv;
};
struct EdgeParams { EdgeDir d[2]; };

__global__ void __launch_bounds__(256)
edge_mma_kernel(EdgeParams P, const float* __restrict__ pos,
                float* __restrict__ pos_upd, int nE, int N)
{
    extern __shared__ float sm[];
    float* sHid  = sm;                      // [128][132]
    float* sBf   = sHid + 128 * HS;         // [8192] half of Cp frags
    float* s_w1c = sBf + 8192;              // [128]
    float* s_b1  = s_w1c + 128;
    float* s_bpc = s_b1 + 128;
    float* s_wp2 = s_bpc + 128;
    float* s_rel = s_wp2 + 128;             // [128*3]
    float* s_dist= s_rel + 384;
    float* s_inv = s_dist + 128;
    float* s_p   = s_inv + 128;             // [128]
    int*   s_src = (int*)(s_p + 128);
    int*   s_dst = s_src + 128;

    const EdgeDir& D = P.d[blockIdx.z];
    const int tid  = threadIdx.x;
    const int wid  = tid >> 5;
    const int lane = tid & 31;
    const int b    = blockIdx.y;
    const int e0   = blockIdx.x * TEC;
    const size_t bN = (size_t)b * N;

    if (tid < TEC) {
        int e = e0 + tid;
        int s = 0, d = 0;
        float x0 = 0.f, x1 = 0.f, x2 = 0.f, dist = 0.f, inv = 0.f;
        if (e < nE) {
            s = D.ei[e];
            d = D.ei[nE + e];
            const float* ps = pos + (bN + s) * 3;
            const float* pd = pos + (bN + d) * 3;
            x0 = ps[0] - pd[0];
            x1 = ps[1] - pd[1];
            x2 = ps[2] - pd[2];
            dist = sqrtf(x0 * x0 + x1 * x1 + x2 * x2);
            inv  = 1.0f / fmaxf(D.deg[d], 1.0f);
        }
        s_src[tid] = s; s_dst[tid] = d;
        s_rel[tid * 3 + 0] = x0; s_rel[tid * 3 + 1] = x1; s_rel[tid * 3 + 2] = x2;
        s_dist[tid] = dist; s_inv[tid] = inv;
        s_w1c[tid] = D.w1[256 * H_DIM + tid];
        s_b1[tid]  = D.b1[tid];
        s_bpc[tid] = D.bpc[tid];
        s_wp2[tid] = D.wp2[tid];
    }
    __syncthreads();

    // gather -> hidden (exact fp32) -> sHid + hacc scatter
    #pragma unroll
    for (int p = 0; p < 16; ++p) {
        int idx = p * 256 + tid;
        int r = idx >> 5, c4 = idx & 31;
        int s = s_src[r], d = s_dst[r];
        float4 va = __ldg((const float4*)D.pre_a + (bN + s) * 32 + c4);
        float4 vb = __ldg((const float4*)D.pre_b + (bN + d) * 32 + c4);
        float dd = s_dist[r], inv = s_inv[r];
        float4 wc = *(const float4*)(s_w1c + c4 * 4);
        float4 bb = *(const float4*)(s_b1 + c4 * 4);
        float h0 = silu_f(va.x + vb.x + dd * wc.x + bb.x);
        float h1 = silu_f(va.y + vb.y + dd * wc.y + bb.y);
        float h2 = silu_f(va.z + vb.z + dd * wc.z + bb.z);
        float h3 = silu_f(va.w + vb.w + dd * wc.w + bb.w);
        *(float4*)(sHid + r * HS + c4 * 4) = make_float4(h0, h1, h2, h3);
        float* gp = D.hacc + (bN + d) * H_DIM + c4 * 4;
        asm volatile("red.global.add.v4.f32 [%0], {%1, %2, %3, %4};"
                     :: "l"(gp), "f"(h0 * inv), "f"(h1 * inv),
                        "f"(h2 * inv), "f"(h3 * inv) : "memory");
    }
    if (tid < TEC && b == 0 && (e0 + tid) < nE)
        atomicAdd(&D.einv[s_dst[tid]], s_inv[tid]);

    const int ar = wid * 16 + (lane >> 2);
    const int ak = lane & 3;
    float sum0 = 0.f, sum1 = 0.f;

    for (int pass = 0; pass < 2; ++pass) {
        __syncthreads();
        {
            const float4* src4 = (const float4*)(D.CpFrag + pass * 8192);
            float4* dst4 = (float4*)sBf;
            #pragma unroll
            for (int p = 0; p < 8; ++p) dst4[p * 256 + tid] = src4[p * 256 + tid];
        }
        __syncthreads();

        float c[8][4];
        #pragma unroll
        for (int nt = 0; nt < 8; ++nt)
            #pragma unroll
            for (int q = 0; q < 4; ++q) c[nt][q] = 0.f;

        #pragma unroll 4
        for (int ks = 0; ks < 16; ++ks) {
            uint32_t a[4];
            int k0 = ks * 8 + ak;
            a[0] = cvt_tf32(sHid[ar * HS + k0]);
            a[1] = cvt_tf32(sHid[(ar + 8) * HS + k0]);
            a[2] = cvt_tf32(sHid[ar * HS + k0 + 4]);
            a[3] = cvt_tf32(sHid[(ar + 8) * HS + k0 + 4]);
            #pragma unroll
            for (int nt = 0; nt < 8; ++nt) {
                uint2 bv = *(const uint2*)(sBf + ((size_t)(nt * 16 + ks) * 32 + lane) * 2);
                mma_tf32(c[nt], a, bv.x, bv.y);
            }
        }
        #pragma unroll
        for (int nt = 0; nt < 8; ++nt) {
            int cb = pass * 64 + nt * 8 + 2 * (lane & 3);
            float w0 = s_wp2[cb], w1v = s_wp2[cb + 1];
            float q0 = s_bpc[cb], q1 = s_bpc[cb + 1];
            sum0 += silu_f(c[nt][0] + q0) * w0 + silu_f(c[nt][1] + q1) * w1v;
            sum1 += silu_f(c[nt][2] + q0) * w0 + silu_f(c[nt][3] + q1) * w1v;
        }
    }

    sum0 += __shfl_xor_sync(0xFFFFFFFFu, sum0, 1);
    sum0 += __shfl_xor_sync(0xFFFFFFFFu, sum0, 2);
    sum1 += __shfl_xor_sync(0xFFFFFFFFu, sum1, 1);
    sum1 += __shfl_xor_sync(0xFFFFFFFFu, sum1, 2);
    if ((lane & 3) == 0) {
        s_p[ar]     = sum0;
        s_p[ar + 8] = sum1;
    }
    __syncthreads();

    if (tid < TEC && (e0 + tid) < nE) {
        float w = tanhf(s_p[tid] + D.bp2[0]);
        int d = s_dst[tid];
        float* pp = pos_upd + (bN + d) * 3;
        atomicAdd(&pp[0], w * s_rel[tid * 3 + 0]);
        atomicAdd(&pp[1], w * s_rel[tid * 3 + 1]);
        atomicAdd(&pp[2], w * s_rel[tid * 3 + 2]);
    }
}

// ---------------------------------------------------------------------------
// node2_mma_kernel: split-tf32 mma node update (fp32-accurate)
//   h1 = silu(feat@Wu1t + hacc0@Cu0 + hacc1@Cu1 + eu*bcu0 + ed*bcu1 + bu1)
//   out = feat + h1@Wu2 + bu2
// M=64 rows/block, 256 thr; B fragments read directly from global (L2/L1).
// ---------------------------------------------------------------------------
__global__ void __launch_bounds__(256)
node2_mma_kernel(const float* __restrict__ feat,
                 const float* __restrict__ hacc0, const float* __restrict__ hacc1,
                 const float* __restrict__ nodeFrag,
                 const float* __restrict__ einv0, const float* __restrict__ einv1,
                 const float* __restrict__ bcu0, const float* __restrict__ bcu1,
                 const float* __restrict__ bu1,  const float* __restrict__ bu2,
                 float* __restrict__ outf, int N, int nRows)
{
    extern __shared__ float sm[];
    float* sA   = sm;               // [64][132]
    float* sb1  = sA + 64 * BS1;    // [64][132]
    float* s_eU = sb1 + 64 * BS1;   // [64]
    float* s_eD = s_eU + 64;        // [64]
    float* s_bias = s_eD + 64;      // bu1,bcu0,bcu1,bu2 : 4*128

    const int tid = threadIdx.x;
    const int wid = tid >> 5, lane = tid & 31;
    const int rg = wid & 3, cg = wid >> 2;
    const int ar = rg * 16 + (lane >> 2);
    const int ak = lane & 3;
    const int g0 = blockIdx.x * 64;

    if (tid < 64) {
        int g = g0 + tid;
        float eu = 0.f, ed = 0.f;
        if (g < nRows) {
            int node = g % N;
            eu = einv0[node];
            ed = einv1[node];
        }
        s_eU[tid] = eu; s_eD[tid] = ed;
    }
    if (tid < 128) {
        s_bias[tid]       = bu1[tid];
        s_bias[128 + tid] = bcu0[tid];
        s_bias[256 + tid] = bcu1[tid];
        s_bias[384 + tid] = bu2[tid];
    }

    // ---- layer 1: accumulate over 3 input matrices ----
    float c[2][4][4];
    #pragma unroll
    for (int p = 0; p < 2; ++p)
        #pragma unroll
        for (int nt = 0; nt < 4; ++nt)
            #pragma unroll
            for (int q = 0; q < 4; ++q) c[p][nt][q] = 0.f;

    for (int m = 0; m < 3; ++m) {
        const float* src = (m == 0) ? feat : (m == 1) ? hacc0 : hacc1;
        __syncthreads();
        #pragma unroll
        for (int p = 0; p < 8; ++p) {
            int idx = p * 256 + tid;
            int r = idx >> 5, c4 = idx & 31;
            float4 v = make_float4(0.f, 0.f, 0.f, 0.f);
            if (g0 + r < nRows)
                v = __ldg((const float4*)src + (size_t)(g0 + r) * 32 + c4);
            *(float4*)(sA + r * BS1 + c4 * 4) = v;
        }
        __syncthreads();

        const float* Bm = nodeFrag + (size_t)m * 32768;
        #pragma unroll 2
        for (int ks = 0; ks < 16; ++ks) {
            int k0 = ks * 8 + ak;
            float x0 = sA[ar * BS1 + k0];
            float x1 = sA[(ar + 8) * BS1 + k0];
            float x2 = sA[ar * BS1 + k0 + 4];
            float x3 = sA[(ar + 8) * BS1 + k0 + 4];
            uint32_t ah[4], al[4];
            ah[0] = cvt_tf32(x0); al[0] = cvt_tf32(x0 - __uint_as_float(ah[0]));
            ah[1] = cvt_tf32(x1); al[1] = cvt_tf32(x1 - __uint_as_float(ah[1]));
            ah[2] = cvt_tf32(x2); al[2] = cvt_tf32(x2 - __uint_as_float(ah[2]));
            ah[3] = cvt_tf32(x3); al[3] = cvt_tf32(x3 - __uint_as_float(ah[3]));
            #pragma unroll
            for (int pass = 0; pass < 2; ++pass) {
                #pragma unroll
                for (int nt = 0; nt < 4; ++nt) {
                    int ntl = pass * 8 + cg * 4 + nt;
                    const float* bp = Bm + ((size_t)(ntl * 16 + ks) * 32 + lane) * 2;
                    uint2 bh = __ldg((const uint2*)bp);
                    uint2 bl = __ldg((const uint2*)(bp + 16384));
                    mma_tf32(c[pass][nt], ah, bh.x, bh.y);
                    mma_tf32(c[pass][nt], al, bh.x, bh.y);
                    mma_tf32(c[pass][nt], ah, bl.x, bl.y);
                }
            }
        }
    }
    // bias + silu -> sb1
    {
        float eu0 = s_eU[ar],     ed0 = s_eD[ar];
        float eu1 = s_eU[ar + 8], ed1 = s_eD[ar + 8];
        #pragma unroll
        for (int pass = 0; pass < 2; ++pass) {
            #pragma unroll
            for (int nt = 0; nt < 4; ++nt) {
                int col = (pass * 8 + cg * 4 + nt) * 8 + 2 * ak;
                float bA = s_bias[col],       bB = s_bias[col + 1];
                float cA0 = s_bias[128 + col], cA1 = s_bias[128 + col + 1];
                float cB0 = s_bias[256 + col], cB1 = s_bias[256 + col + 1];
                sb1[ar * BS1 + col] =
                    silu_f(c[pass][nt][0] + bA + eu0 * cA0 + ed0 * cB0);
                sb1[ar * BS1 + col + 1] =
                    silu_f(c[pass][nt][1] + bB + eu0 * cA1 + ed0 * cB1);
                sb1[(ar + 8) * BS1 + col] =
                    silu_f(c[pass][nt][2] + bA + eu1 * cA0 + ed1 * cB0);
                sb1[(ar + 8) * BS1 + col + 1] =
                    silu_f(c[pass][nt][3] + bB + eu1 * cA1 + ed1 * cB1);
            }
        }
    }
    __syncthreads();

    // ---- layer 2 ----
    #pragma unroll
    for (int p = 0; p < 2; ++p)
        #pragma unroll
        for (int nt = 0; nt < 4; ++nt)
            #pragma unroll
            for (int q = 0; q < 4; ++q) c[p][nt][q] = 0.f;

    {
        const float* Bm = nodeFrag + (size_t)3 * 32768;
        #pragma unroll 2
        for (int ks = 0; ks < 16; ++ks) {
            int k0 = ks * 8 + ak;
            float x0 = sb1[ar * BS1 + k0];
            float x1 = sb1[(ar + 8) * BS1 + k0];
            float x2 = sb1[ar * BS1 + k0 + 4];
            float x3 = sb1[(ar + 8) * BS1 + k0 + 4];
            uint32_t ah[4], al[4];
            ah[0] = cvt_tf32(x0); al[0] = cvt_tf32(x0 - __uint_as_float(ah[0]));
            ah[1] = cvt_tf32(x1); al[1] = cvt_tf32(x1 - __uint_as_float(ah[1]));
            ah[2] = cvt_tf32(x2); al[2] = cvt_tf32(x2 - __uint_as_float(ah[2]));
            ah[3] = cvt_tf32(x3); al[3] = cvt_tf32(x3 - __uint_as_float(ah[3]));
            #pragma unroll
            for (int pass = 0; pass < 2; ++pass) {
                #pragma unroll
                for (int nt = 0; nt < 4; ++nt) {
                    int ntl = pass * 8 + cg * 4 + nt;
                    const float* bp = Bm + ((size_t)(ntl * 16 + ks) * 32 + lane) * 2;
                    uint2 bh = __ldg((const uint2*)bp);
                    uint2 bl = __ldg((const uint2*)(bp + 16384));
                    mma_tf32(c[pass][nt], ah, bh.x, bh.y);
                    mma_tf32(c[pass][nt], al, bh.x, bh.y);
                    mma_tf32(c[pass][nt], ah, bl.x, bl.y);
                }
            }
        }
    }
    // out = feat + c + bu2
    {
        int gA = g0 + ar, gB = g0 + ar + 8;
        #pragma unroll
        for (int pass = 0; pass < 2; ++pass) {
            #pragma unroll
            for (int nt = 0; nt < 4; ++nt) {
                int col = (pass * 8 + cg * 4 + nt) * 8 + 2 * ak;
                float bA = s_bias[384 + col], bB = s_bias[384 + col + 1];
                if (gA < nRows) {
                    size_t o = (size_t)gA * H_DIM + col;
                    float2 f = *(const float2*)&feat[o];
                    *(float2*)&outf[o] = make_float2(
                        f.x + c[pass][nt][0] + bA, f.y + c[pass][nt][1] + bB);
                }
                if (gB < nRows) {
                    size_t o = (size_t)gB * H_DIM + col;
                    float2 f = *(const float2*)&feat[o];
                    *(float2*)&outf[o] = make_float2(
                        f.x + c[pass][nt][2] + bA, f.y + c[pass][nt][3] + bB);
                }
            }
        }
    }
}

__global__ void pos_kernel(const float* __restrict__ pos,
                           const float* __restrict__ pos_upd,
                           float* __restrict__ out, int n)
{
    int i = blockIdx.x * blockDim.x + threadIdx.x;
    if (i < n) out[i] = pos[i] + 0.5f * pos_upd[i];
}

extern "C" void kernel_launch(void* const* d_in, const int* in_sizes, int n_in,
                              void* d_out, int out_size)
{
    const float* feat   = (const float*)d_in[0];
    const float* pos    = (const float*)d_in[1];
    const int*   ei_up  = (const int*)d_in[2];
    const int*   ei_dn  = (const int*)d_in[3];
    const float* deg_up = (const float*)d_in[4];
    const float* deg_dn = (const float*)d_in[5];

    const float* w1u  = (const float*)d_in[6];
    const float* b1u  = (const float*)d_in[7];
    const float* w2u  = (const float*)d_in[8];
    const float* b2u  = (const float*)d_in[9];
    const float* wp1u = (const float*)d_in[10];
    const float* bp1u = (const float*)d_in[11];
    const float* wp2u = (const float*)d_in[12];
    const float* bp2u = (const float*)d_in[13];

    const float* w1d  = (const float*)d_in[14];
    const float* b1d  = (const float*)d_in[15];
    const float* w2d  = (const float*)d_in[16];
    const float* b2d  = (const float*)d_in[17];
    const float* wp1d = (const float*)d_in[18];
    const float* bp1d = (const float*)d_in[19];
    const float* wp2d = (const float*)d_in[20];
    const float* bp2d = (const float*)d_in[21];

    const float* wu1 = (const float*)d_in[22];
    const float* bu1 = (const float*)d_in[23];
    const float* wu2 = (const float*)d_in[24];
    const float* bu2 = (const float*)d_in[25];

    int E = in_sizes[2] / 2;
    int N = in_sizes[4];
    int B = in_sizes[0] / (N * H_DIM);
    int nRows = B * N;

    float *pre, *hacc, *einv, *pos_upd, *CpFrag, *bpc, *bcu, *preFrag, *nodeFrag;
    cudaGetSymbolAddress((void**)&pre,      g_pre);
    cudaGetSymbolAddress((void**)&hacc,     g_hacc);
    cudaGetSymbolAddress((void**)&einv,     g_einv);
    cudaGetSymbolAddress((void**)&pos_upd,  g_pos_upd);
    cudaGetSymbolAddress((void**)&CpFrag,   g_CpFrag);
    cudaGetSymbolAddress((void**)&bpc,      g_bpc);
    cudaGetSymbolAddress((void**)&bcu,      g_bcu);
    cudaGetSymbolAddress((void**)&preFrag,  g_preFrag);
    cudaGetSymbolAddress((void**)&nodeFrag, g_nodeFrag);

    const size_t PS = (size_t)MAX_BN * H_DIM;
    float* pre_au = pre;
    float* pre_bu = pre + PS;
    float* pre_ad = pre + 2 * PS;
    float* pre_bd = pre + 3 * PS;
    float* hacc_u = hacc;
    float* hacc_d = hacc + PS;
    float* einv_u = einv;
    float* einv_d = einv + MAX_N;

    cudaMemsetAsync(hacc, 0, 2 * PS * sizeof(float));
    cudaMemsetAsync(einv, 0, 2 * MAX_N * sizeof(float));
    cudaMemsetAsync(pos_upd, 0, (size_t)nRows * 3 * sizeof(float));

    int smemPre  = (64 * BS1 + 16384) * 4;                     //  99328 B
    int smemEdge = (128 * HS + 8192 + 4 * 128 + 384 + 128 + 128 + 128
                    + 2 * 128) * 4;                            // 106496 B
    int smemNode = (2 * 64 * BS1 + 128 + 512) * 4;             //  70144 B
    cudaFuncSetAttribute(pre_mma_kernel,
                         cudaFuncAttributeMaxDynamicSharedMemorySize, smemPre);
    cudaFuncSetAttribute(edge_mma_kernel,
                         cudaFuncAttributeMaxDynamicSharedMemorySize, smemEdge);
    cudaFuncSetAttribute(node2_mma_kernel,
                         cudaFuncAttributeMaxDynamicSharedMemorySize, smemNode);

    combine_kernel<<<dim3(H_DIM + 1, 4), H_DIM>>>(
        w2u, wp1u, b2u, bp1u, w2d, wp1d, b2d, bp1d, wu1,
        CpFrag, nodeFrag, bpc, bcu);

    fragw_kernel<<<dim3(H_DIM, 6), H_DIM>>>(w1u, w1d, wu1, wu2,
                                            preFrag, nodeFrag);

    pre_mma_kernel<<<dim3((nRows + 63) / 64, 4), 256, smemPre>>>(
        feat, preFrag, pre_au, pre_bu, pre_ad, pre_bd, nRows);

    EdgeParams EP;
    EP.d[0] = { pre_au, pre_bu, ei_up, deg_up, w1u, b1u,
                CpFrag,           bpc,          wp2u, bp2u, hacc_u, einv_u };
    EP.d[1] = { pre_ad, pre_bd, ei_dn, deg_dn, w1d, b1d,
                CpFrag + 16384,   bpc + H_DIM,  wp2d, bp2d, hacc_d, einv_d };

    dim3 egrid((E + TEC - 1) / TEC, B, 2);
    edge_mma_kernel<<<egrid, 256, smemEdge>>>(EP, pos, pos_upd, E, N);

    node2_mma_kernel<<<(nRows + 63) / 64, 256, smemNode>>>(
        feat, hacc_u, hacc_d, nodeFrag, einv_u, einv_d,
        bcu, bcu + H_DIM, bu1, bu2, (float*)d_out, N, nRows);

    size_t featN = (size_t)nRows * H_DIM;
    int pn = nRows * 3;
    pos_kernel<<<(pn + 255) / 256, 256>>>(
        pos, pos_upd, (float*)d_out + featN, pn);
}

// round 8
// speedup vs baseline: 6.2191x; 1.0189x over previous
#include <cuda_runtime.h>
#include <math.h>
#include <cstdint>

#define H_DIM 128
#define TEC 128        // edges per block (edge kernel)
#define BS1 132        // padded row stride
#define HS 132

#define MAX_B 2
#define MAX_N 20000
#define MAX_BN (MAX_B * MAX_N)

// ---------------------------------------------------------------------------
// Scratch (allocation-free rule: __device__ globals)
// ---------------------------------------------------------------------------
__device__ __align__(128) float g_pre[4][(size_t)MAX_BN * H_DIM];
__device__ __align__(128) float g_hacc[2][(size_t)MAX_BN * H_DIM];
__device__ __align__(128) float g_einv[2][MAX_N];
__device__ __align__(128) float g_pos_upd[(size_t)MAX_BN * 3];
__device__ __align__(128) float g_CpFrag[2][H_DIM * H_DIM];      // paired-hi layout
__device__ __align__(128) float g_bpc[2][H_DIM];
__device__ __align__(128) float g_bcu[2][H_DIM];
__device__ __align__(128) float g_preFrag[4][2][H_DIM * H_DIM];  // hi/lo uint4 layout
__device__ __align__(128) float g_nodeFrag[4][2][H_DIM * H_DIM]; // wu1top,Cu0,Cu1,wu2

__device__ __forceinline__ float silu_f(float v) {
    return __fdividef(v, 1.0f + __expf(-v));
}

// ---- tf32 mma.sync helpers --------------------------------------------------
__device__ __forceinline__ uint32_t cvt_tf32(float x) {
    uint32_t r;
    asm("cvt.rna.tf32.f32 %0, %1;" : "=r"(r) : "f"(x));
    return r;
}
__device__ __forceinline__ void mma_tf32(float c[4], const uint32_t a[4],
                                         uint32_t b0, uint32_t b1) {
    asm volatile(
        "mma.sync.aligned.m16n8k8.row.col.f32.tf32.tf32.f32 "
        "{%0,%1,%2,%3}, {%4,%5,%6,%7}, {%8,%9}, {%0,%1,%2,%3};"
        : "+f"(c[0]), "+f"(c[1]), "+f"(c[2]), "+f"(c[3])
        : "r"(a[0]), "r"(a[1]), "r"(a[2]), "r"(a[3]), "r"(b0), "r"(b1));
}

// hi/lo uint4 layout index (per 128x128 matrix, 32768 floats):
//   [( (ntile*16+ks)*32 + lane )*4 + reg]     = hi
//   [( (ntile*16+ks)*32 + lane )*4 + 2 + reg] = lo
__device__ __forceinline__ size_t frag_base(int i, int j) {
    int kstep = i >> 3, kk = i & 7;
    int ntile = j >> 3, nn = j & 7;
    int lane = nn * 4 + (kk & 3);
    return ((size_t)(ntile * 16 + kstep) * 32 + lane) * 4 + (kk >> 2);
}

// ---------------------------------------------------------------------------
// combine_kernel: y=0/1 Cp (paired-hi layout) + bpc ; y=2/3 Cu hi/lo + bcu
// ---------------------------------------------------------------------------
__global__ void combine_kernel(
    const float* __restrict__ w2u, const float* __restrict__ wp1u,
    const float* __restrict__ b2u, const float* __restrict__ bp1u,
    const float* __restrict__ w2d, const float* __restrict__ wp1d,
    const float* __restrict__ b2d, const float* __restrict__ bp1d,
    const float* __restrict__ wu1,
    float* __restrict__ CpFrag, float* __restrict__ nodeFrag,
    float* __restrict__ bpc, float* __restrict__ bcu)
{
    const float* wu1b = wu1 + 128 * H_DIM;
    const float* A; const float* Bm; const float* bvec; const float* badd;
    float* C; float* bout; bool split;
    switch (blockIdx.y) {
        case 0:  A = w2u; Bm = wp1u; bvec = b2u; badd = bp1u;
                 C = CpFrag;               bout = bpc;         split = false; break;
        case 1:  A = w2d; Bm = wp1d; bvec = b2d; badd = bp1d;
                 C = CpFrag + 16384;       bout = bpc + H_DIM; split = false; break;
        case 2:  A = w2u; Bm = wu1b; bvec = b2u; badd = 0;
                 C = nodeFrag + 1 * 32768; bout = bcu;         split = true;  break;
        default: A = w2d; Bm = wu1b; bvec = b2d; badd = 0;
                 C = nodeFrag + 2 * 32768; bout = bcu + H_DIM; split = true;  break;
    }
    int i = blockIdx.x;   // k
    int j = threadIdx.x;  // n
    const float* arow = (i < H_DIM) ? (A + (size_t)i * H_DIM) : bvec;
    float s = 0.f;
    #pragma unroll 8
    for (int k = 0; k < H_DIM; ++k) s += arow[k] * Bm[k * H_DIM + j];
    if (i < H_DIM) {
        uint32_t hi = cvt_tf32(s);
        if (split) {
            size_t b0 = frag_base(i, j);
            C[b0]     = __uint_as_float(hi);
            C[b0 + 2] = __uint_as_float(cvt_tf32(s - __uint_as_float(hi)));
        } else {
            // paired-hi layout: per pass-half, two ntiles share a uint4
            int kstep = i >> 3, kk = i & 7;
            int lane = (j & 7) * 4 + (kk & 3);
            int reg  = kk >> 2;
            int ntile = j >> 3, pass = ntile >> 3, ntl = ntile & 7;
            size_t idx = (size_t)pass * 8192
                       + ((size_t)((kstep * 4 + (ntl >> 1)) * 32 + lane)) * 4
                       + (ntl & 1) * 2 + reg;
            C[idx] = __uint_as_float(hi);
        }
    } else {
        bout[j] = s + (badd ? badd[j] : 0.f);
    }
}

// ---------------------------------------------------------------------------
// fragw_kernel: hi/lo uint4 images of raw weights
// ---------------------------------------------------------------------------
__global__ void fragw_kernel(const float* __restrict__ w1u,
                             const float* __restrict__ w1d,
                             const float* __restrict__ wu1,
                             const float* __restrict__ wu2,
                             float* __restrict__ preFrag,
                             float* __restrict__ nodeFrag)
{
    int y = blockIdx.y;
    const float* W; float* out;
    switch (y) {
        case 0: W = w1u;                out = preFrag;             break;
        case 1: W = w1u + 128 * H_DIM;  out = preFrag + 32768;     break;
        case 2: W = w1d;                out = preFrag + 2 * 32768; break;
        case 3: W = w1d + 128 * H_DIM;  out = preFrag + 3 * 32768; break;
        case 4: W = wu1;                out = nodeFrag;            break;
        default: W = wu2;               out = nodeFrag + 3 * 32768; break;
    }
    int i = blockIdx.x;
    int j = threadIdx.x;
    float w = W[i * H_DIM + j];
    uint32_t hi = cvt_tf32(w);
    size_t b0 = frag_base(i, j);
    out[b0]     = __uint_as_float(hi);
    out[b0 + 2] = __uint_as_float(cvt_tf32(w - __uint_as_float(hi)));
}

// ---------------------------------------------------------------------------
// pre_mma_kernel: all 4 pre-GEMMs in one block; A staged+split once;
// B fragments direct from global (uint4, hi+lo in one load).
// ---------------------------------------------------------------------------
__global__ void __launch_bounds__(256)
pre_mma_kernel(const float* __restrict__ feat, const float* __restrict__ frag,
               float* __restrict__ p0, float* __restrict__ p1,
               float* __restrict__ p2, float* __restrict__ p3, int nRows)
{
    extern __shared__ float sm[];
    uint32_t* sAhi = (uint32_t*)sm;            // [64][132]
    uint32_t* sAlo = sAhi + 64 * BS1;          // [64][132]

    const int tid = threadIdx.x;
    const int wid = tid >> 5, lane = tid & 31;
    const int rg = wid & 3, cg = wid >> 2;
    const int ar = rg * 16 + (lane >> 2);
    const int ak = lane & 3;
    const int g0 = blockIdx.x * 64;

    // stage + split A once
    #pragma unroll
    for (int p = 0; p < 8; ++p) {
        int idx = p * 256 + tid;
        int r = idx >> 5, c4 = idx & 31;
        float4 v = make_float4(0.f, 0.f, 0.f, 0.f);
        if (g0 + r < nRows)
            v = __ldg((const float4*)feat + (size_t)(g0 + r) * 32 + c4);
        uint32_t h0 = cvt_tf32(v.x), h1 = cvt_tf32(v.y),
                 h2 = cvt_tf32(v.z), h3 = cvt_tf32(v.w);
        uint32_t l0 = cvt_tf32(v.x - __uint_as_float(h0));
        uint32_t l1 = cvt_tf32(v.y - __uint_as_float(h1));
        uint32_t l2 = cvt_tf32(v.z - __uint_as_float(h2));
        uint32_t l3 = cvt_tf32(v.w - __uint_as_float(h3));
        *(uint4*)(sAhi + r * BS1 + c4 * 4) = make_uint4(h0, h1, h2, h3);
        *(uint4*)(sAlo + r * BS1 + c4 * 4) = make_uint4(l0, l1, l2, l3);
    }
    __syncthreads();

    float* outs[4] = {p0, p1, p2, p3};
    #pragma unroll
    for (int m = 0; m < 4; ++m) {
        const uint4* Bm = (const uint4*)(frag + (size_t)m * 32768);
        float* out = outs[m];
        #pragma unroll
        for (int pass = 0; pass < 2; ++pass) {
            float c[4][4];
            #pragma unroll
            for (int nt = 0; nt < 4; ++nt)
                #pragma unroll
                for (int q = 0; q < 4; ++q) c[nt][q] = 0.f;

            #pragma unroll 4
            for (int ks = 0; ks < 16; ++ks) {
                int k0 = ks * 8 + ak;
                uint32_t ah[4], al[4];
                ah[0] = sAhi[ar * BS1 + k0];
                ah[1] = sAhi[(ar + 8) * BS1 + k0];
                ah[2] = sAhi[ar * BS1 + k0 + 4];
                ah[3] = sAhi[(ar + 8) * BS1 + k0 + 4];
                al[0] = sAlo[ar * BS1 + k0];
                al[1] = sAlo[(ar + 8) * BS1 + k0];
                al[2] = sAlo[ar * BS1 + k0 + 4];
                al[3] = sAlo[(ar + 8) * BS1 + k0 + 4];
                #pragma unroll
                for (int nt = 0; nt < 4; ++nt) {
                    int ntile = pass * 8 + cg * 4 + nt;
                    uint4 v = __ldg(Bm + (size_t)(ntile * 16 + ks) * 32 + lane);
                    mma_tf32(c[nt], ah, v.x, v.y);
                    mma_tf32(c[nt], al, v.x, v.y);
                    mma_tf32(c[nt], ah, v.z, v.w);
                }
            }
            int rowA = g0 + ar, rowB = g0 + ar + 8;
            #pragma unroll
            for (int nt = 0; nt < 4; ++nt) {
                int col = (pass * 8 + cg * 4 + nt) * 8 + 2 * ak;
                if (rowA < nRows)
                    *(float2*)&out[(size_t)rowA * H_DIM + col] =
                        make_float2(c[nt][0], c[nt][1]);
                if (rowB < nRows)
                    *(float2*)&out[(size_t)rowB * H_DIM + col] =
                        make_float2(c[nt][2], c[nt][3]);
            }
        }
    }
}

// ---------------------------------------------------------------------------
// edge_mma_kernel: merged dirs; batched gather (MLP 8); tf32-prestored hidden;
// paired-uint4 B LDS.
// ---------------------------------------------------------------------------
struct EdgeDir {
    const float* pre_a; const float* pre_b;
    const int* ei; const float* deg;
    const float* w1; const float* b1;
    const float* CpFrag; const float* bpc;
    const float* wp2; const float* bp2;
    float* hacc; float* einv;
};
struct EdgeParams { EdgeDir d[2]; };

__global__ void __launch_bounds__(256)
edge_mma_kernel(EdgeParams P, const float* __restrict__ pos,
                float* __restrict__ pos_upd, int nE, int N)
{
    extern __shared__ float sm[];
    uint32_t* sHid = (uint32_t*)sm;         // [128][132] tf32 bits
    float* sBf   = sm + 128 * HS;           // [8192] half of Cp frags
    float* s_w1c = sBf + 8192;
    float* s_b1  = s_w1c + 128;
    float* s_bpc = s_b1 + 128;
    float* s_wp2 = s_bpc + 128;
    float* s_rel = s_wp2 + 128;             // [128*3]
    float* s_dist= s_rel + 384;
    float* s_inv = s_dist + 128;
    float* s_p   = s_inv + 128;             // [128]
    int*   s_src = (int*)(s_p + 128);
    int*   s_dst = s_src + 128;

    const EdgeDir& D = P.d[blockIdx.z];
    const int tid  = threadIdx.x;
    const int wid  = tid >> 5;
    const int lane = tid & 31;
    const int b    = blockIdx.y;
    const int e0   = blockIdx.x * TEC;
    const size_t bN = (size_t)b * N;

    if (tid < TEC) {
        int e = e0 + tid;
        int s = 0, d = 0;
        float x0 = 0.f, x1 = 0.f, x2 = 0.f, dist = 0.f, inv = 0.f;
        if (e < nE) {
            s = D.ei[e];
            d = D.ei[nE + e];
            const float* ps = pos + (bN + s) * 3;
            const float* pd = pos + (bN + d) * 3;
            x0 = ps[0] - pd[0];
            x1 = ps[1] - pd[1];
            x2 = ps[2] - pd[2];
            dist = sqrtf(x0 * x0 + x1 * x1 + x2 * x2);
            inv  = 1.0f / fmaxf(D.deg[d], 1.0f);
        }
        s_src[tid] = s; s_dst[tid] = d;
        s_rel[tid * 3 + 0] = x0; s_rel[tid * 3 + 1] = x1; s_rel[tid * 3 + 2] = x2;
        s_dist[tid] = dist; s_inv[tid] = inv;
        s_w1c[tid] = D.w1[256 * H_DIM + tid];
        s_b1[tid]  = D.b1[tid];
        s_bpc[tid] = D.bpc[tid];
        s_wp2[tid] = D.wp2[tid];
    }
    __syncthreads();

    // gather -> hidden; 4-step load batching for MLP
    #pragma unroll
    for (int p = 0; p < 16; p += 4) {
        float4 va[4], vb[4];
        #pragma unroll
        for (int q = 0; q < 4; ++q) {
            int r = (p + q) * 8 + wid;
            va[q] = __ldg((const float4*)D.pre_a + (bN + s_src[r]) * 32 + lane);
            vb[q] = __ldg((const float4*)D.pre_b + (bN + s_dst[r]) * 32 + lane);
        }
        #pragma unroll
        for (int q = 0; q < 4; ++q) {
            int r = (p + q) * 8 + wid;
            float dd = s_dist[r], inv = s_inv[r];
            float4 wc = *(const float4*)(s_w1c + lane * 4);
            float4 bb = *(const float4*)(s_b1 + lane * 4);
            float h0 = silu_f(va[q].x + vb[q].x + dd * wc.x + bb.x);
            float h1 = silu_f(va[q].y + vb[q].y + dd * wc.y + bb.y);
            float h2 = silu_f(va[q].z + vb[q].z + dd * wc.z + bb.z);
            float h3 = silu_f(va[q].w + vb[q].w + dd * wc.w + bb.w);
            *(uint4*)(sHid + r * HS + lane * 4) =
                make_uint4(cvt_tf32(h0), cvt_tf32(h1), cvt_tf32(h2), cvt_tf32(h3));
            float* gp = D.hacc + (bN + s_dst[r]) * H_DIM + lane * 4;
            asm volatile("red.global.add.v4.f32 [%0], {%1, %2, %3, %4};"
                         :: "l"(gp), "f"(h0 * inv), "f"(h1 * inv),
                            "f"(h2 * inv), "f"(h3 * inv) : "memory");
        }
    }
    if (tid < TEC && b == 0 && (e0 + tid) < nE)
        atomicAdd(&D.einv[s_dst[tid]], s_inv[tid]);

    const int ar = wid * 16 + (lane >> 2);
    const int ak = lane & 3;
    float sum0 = 0.f, sum1 = 0.f;

    #pragma unroll
    for (int pass = 0; pass < 2; ++pass) {
        __syncthreads();
        {
            const float4* src4 = (const float4*)(D.CpFrag + pass * 8192);
            float4* dst4 = (float4*)sBf;
            #pragma unroll
            for (int p = 0; p < 8; ++p) dst4[p * 256 + tid] = src4[p * 256 + tid];
        }
        __syncthreads();

        float c[8][4];
        #pragma unroll
        for (int nt = 0; nt < 8; ++nt)
            #pragma unroll
            for (int q = 0; q < 4; ++q) c[nt][q] = 0.f;

        #pragma unroll 4
        for (int ks = 0; ks < 16; ++ks) {
            uint32_t a[4];
            int k0 = ks * 8 + ak;
            a[0] = sHid[ar * HS + k0];
            a[1] = sHid[(ar + 8) * HS + k0];
            a[2] = sHid[ar * HS + k0 + 4];
            a[3] = sHid[(ar + 8) * HS + k0 + 4];
            #pragma unroll
            for (int ntp = 0; ntp < 4; ++ntp) {
                uint4 bv = *(const uint4*)
                    (sBf + ((size_t)((ks * 4 + ntp) * 32 + lane)) * 4);
                mma_tf32(c[2 * ntp],     a, bv.x, bv.y);
                mma_tf32(c[2 * ntp + 1], a, bv.z, bv.w);
            }
        }
        #pragma unroll
        for (int nt = 0; nt < 8; ++nt) {
            int cb = pass * 64 + nt * 8 + 2 * ak;
            float w0 = s_wp2[cb], w1v = s_wp2[cb + 1];
            float q0 = s_bpc[cb], q1 = s_bpc[cb + 1];
            sum0 += silu_f(c[nt][0] + q0) * w0 + silu_f(c[nt][1] + q1) * w1v;
            sum1 += silu_f(c[nt][2] + q0) * w0 + silu_f(c[nt][3] + q1) * w1v;
        }
    }

    sum0 += __shfl_xor_sync(0xFFFFFFFFu, sum0, 1);
    sum0 += __shfl_xor_sync(0xFFFFFFFFu, sum0, 2);
    sum1 += __shfl_xor_sync(0xFFFFFFFFu, sum1, 1);
    sum1 += __shfl_xor_sync(0xFFFFFFFFu, sum1, 2);
    if ((lane & 3) == 0) {
        s_p[ar]     = sum0;
        s_p[ar + 8] = sum1;
    }
    __syncthreads();

    if (tid < TEC && (e0 + tid) < nE) {
        float w = tanhf(s_p[tid] + D.bp2[0]);
        int d = s_dst[tid];
        float* pp = pos_upd + (bN + d) * 3;
        atomicAdd(&pp[0], w * s_rel[tid * 3 + 0]);
        atomicAdd(&pp[1], w * s_rel[tid * 3 + 1]);
        atomicAdd(&pp[2], w * s_rel[tid * 3 + 2]);
    }
}

// ---------------------------------------------------------------------------
// node2_mma_kernel: split-tf32 node update; A staged+split per matrix;
// B uint4 direct from global.
// ---------------------------------------------------------------------------
__global__ void __launch_bounds__(256)
node2_mma_kernel(const float* __restrict__ feat,
                 const float* __restrict__ hacc0, const float* __restrict__ hacc1,
                 const float* __restrict__ nodeFrag,
                 const float* __restrict__ einv0, const float* __restrict__ einv1,
                 const float* __restrict__ bcu0, const float* __restrict__ bcu1,
                 const float* __restrict__ bu1,  const float* __restrict__ bu2,
                 float* __restrict__ outf, int N, int nRows)
{
    extern __shared__ float sm[];
    uint32_t* sAhi = (uint32_t*)sm;           // [64][132]
    uint32_t* sAlo = sAhi + 64 * BS1;         // [64][132]
    float* s_eU   = sm + 2 * 64 * BS1;        // [64]
    float* s_eD   = s_eU + 64;
    float* s_bias = s_eD + 64;                // 4*128

    const int tid = threadIdx.x;
    const int wid = tid >> 5, lane = tid & 31;
    const int rg = wid & 3, cg = wid >> 2;
    const int ar = rg * 16 + (lane >> 2);
    const int ak = lane & 3;
    const int g0 = blockIdx.x * 64;

    if (tid < 64) {
        int g = g0 + tid;
        float eu = 0.f, ed = 0.f;
        if (g < nRows) {
            int node = g % N;
            eu = einv0[node];
            ed = einv1[node];
        }
        s_eU[tid] = eu; s_eD[tid] = ed;
    }
    if (tid < 128) {
        s_bias[tid]       = bu1[tid];
        s_bias[128 + tid] = bcu0[tid];
        s_bias[256 + tid] = bcu1[tid];
        s_bias[384 + tid] = bu2[tid];
    }

    // ---- layer 1 ----
    float c[2][4][4];
    #pragma unroll
    for (int p = 0; p < 2; ++p)
        #pragma unroll
        for (int nt = 0; nt < 4; ++nt)
            #pragma unroll
            for (int q = 0; q < 4; ++q) c[p][nt][q] = 0.f;

    for (int m = 0; m < 3; ++m) {
        const float* src = (m == 0) ? feat : (m == 1) ? hacc0 : hacc1;
        __syncthreads();
        #pragma unroll
        for (int p = 0; p < 8; ++p) {
            int idx = p * 256 + tid;
            int r = idx >> 5, c4 = idx & 31;
            float4 v = make_float4(0.f, 0.f, 0.f, 0.f);
            if (g0 + r < nRows)
                v = __ldg((const float4*)src + (size_t)(g0 + r) * 32 + c4);
            uint32_t h0 = cvt_tf32(v.x), h1 = cvt_tf32(v.y),
                     h2 = cvt_tf32(v.z), h3 = cvt_tf32(v.w);
            uint32_t l0 = cvt_tf32(v.x - __uint_as_float(h0));
            uint32_t l1 = cvt_tf32(v.y - __uint_as_float(h1));
            uint32_t l2 = cvt_tf32(v.z - __uint_as_float(h2));
            uint32_t l3 = cvt_tf32(v.w - __uint_as_float(h3));
            *(uint4*)(sAhi + r * BS1 + c4 * 4) = make_uint4(h0, h1, h2, h3);
            *(uint4*)(sAlo + r * BS1 + c4 * 4) = make_uint4(l0, l1, l2, l3);
        }
        __syncthreads();

        const uint4* Bm = (const uint4*)(nodeFrag + (size_t)m * 32768);
        #pragma unroll 2
        for (int ks = 0; ks < 16; ++ks) {
            int k0 = ks * 8 + ak;
            uint32_t ah[4], al[4];
            ah[0] = sAhi[ar * BS1 + k0];
            ah[1] = sAhi[(ar + 8) * BS1 + k0];
            ah[2] = sAhi[ar * BS1 + k0 + 4];
            ah[3] = sAhi[(ar + 8) * BS1 + k0 + 4];
            al[0] = sAlo[ar * BS1 + k0];
            al[1] = sAlo[(ar + 8) * BS1 + k0];
            al[2] = sAlo[ar * BS1 + k0 + 4];
            al[3] = sAlo[(ar + 8) * BS1 + k0 + 4];
            #pragma unroll
            for (int pass = 0; pass < 2; ++pass) {
                #pragma unroll
                for (int nt = 0; nt < 4; ++nt) {
                    int ntile = pass * 8 + cg * 4 + nt;
                    uint4 v = __ldg(Bm + (size_t)(ntile * 16 + ks) * 32 + lane);
                    mma_tf32(c[pass][nt], ah, v.x, v.y);
                    mma_tf32(c[pass][nt], al, v.x, v.y);
                    mma_tf32(c[pass][nt], ah, v.z, v.w);
                }
            }
        }
    }
    // bias + silu -> store hi/lo of h1 back into sAhi/sAlo
    __syncthreads();
    {
        float eu0 = s_eU[ar],     ed0 = s_eD[ar];
        float eu1 = s_eU[ar + 8], ed1 = s_eD[ar + 8];
        #pragma unroll
        for (int pass = 0; pass < 2; ++pass) {
            #pragma unroll
            for (int nt = 0; nt < 4; ++nt) {
                int col = (pass * 8 + cg * 4 + nt) * 8 + 2 * ak;
                float bA = s_bias[col],        bB = s_bias[col + 1];
                float cA0 = s_bias[128 + col], cA1 = s_bias[128 + col + 1];
                float cB0 = s_bias[256 + col], cB1 = s_bias[256 + col + 1];
                float v00 = silu_f(c[pass][nt][0] + bA + eu0 * cA0 + ed0 * cB0);
                float v01 = silu_f(c[pass][nt][1] + bB + eu0 * cA1 + ed0 * cB1);
                float v10 = silu_f(c[pass][nt][2] + bA + eu1 * cA0 + ed1 * cB0);
                float v11 = silu_f(c[pass][nt][3] + bB + eu1 * cA1 + ed1 * cB1);
                uint32_t h;
                h = cvt_tf32(v00); sAhi[ar * BS1 + col] = h;
                sAlo[ar * BS1 + col] = cvt_tf32(v00 - __uint_as_float(h));
                h = cvt_tf32(v01); sAhi[ar * BS1 + col + 1] = h;
                sAlo[ar * BS1 + col + 1] = cvt_tf32(v01 - __uint_as_float(h));
                h = cvt_tf32(v10); sAhi[(ar + 8) * BS1 + col] = h;
                sAlo[(ar + 8) * BS1 + col] = cvt_tf32(v10 - __uint_as_float(h));
                h = cvt_tf32(v11); sAhi[(ar + 8) * BS1 + col + 1] = h;
                sAlo[(ar + 8) * BS1 + col + 1] = cvt_tf32(v11 - __uint_as_float(h));
            }
        }
    }
    __syncthreads();

    // ---- layer 2 ----
    #pragma unroll
    for (int p = 0; p < 2; ++p)
        #pragma unroll
        for (int nt = 0; nt < 4; ++nt)
            #pragma unroll
            for (int q = 0; q < 4; ++q) c[p][nt][q] = 0.f;

    {
        const uint4* Bm = (const uint4*)(nodeFrag + (size_t)3 * 32768);
        #pragma unroll 2
        for (int ks = 0; ks < 16; ++ks) {
            int k0 = ks * 8 + ak;
            uint32_t ah[4], al[4];
            ah[0] = sAhi[ar * BS1 + k0];
            ah[1] = sAhi[(ar + 8) * BS1 + k0];
            ah[2] = sAhi[ar * BS1 + k0 + 4];
            ah[3] = sAhi[(ar + 8) * BS1 + k0 + 4];
            al[0] = sAlo[ar * BS1 + k0];
            al[1] = sAlo[(ar + 8) * BS1 + k0];
            al[2] = sAlo[ar * BS1 + k0 + 4];
            al[3] = sAlo[(ar + 8) * BS1 + k0 + 4];
            #pragma unroll
            for (int pass = 0; pass < 2; ++pass) {
                #pragma unroll
                for (int nt = 0; nt < 4; ++nt) {
                    int ntile = pass * 8 + cg * 4 + nt;
                    uint4 v = __ldg(Bm + (size_t)(ntile * 16 + ks) * 32 + lane);
                    mma_tf32(c[pass][nt], ah, v.x, v.y);
                    mma_tf32(c[pass][nt], al, v.x, v.y);
                    mma_tf32(c[pass][nt], ah, v.z, v.w);
                }
            }
        }
    }
    {
        int gA = g0 + ar, gB = g0 + ar + 8;
        #pragma unroll
        for (int pass = 0; pass < 2; ++pass) {
            #pragma unroll
            for (int nt = 0; nt < 4; ++nt) {
                int col = (pass * 8 + cg * 4 + nt) * 8 + 2 * ak;
                float bA = s_bias[384 + col], bB = s_bias[384 + col + 1];
                if (gA < nRows) {
                    size_t o = (size_t)gA * H_DIM + col;
                    float2 f = *(const float2*)&feat[o];
                    *(float2*)&outf[o] = make_float2(
                        f.x + c[pass][nt][0] + bA, f.y + c[pass][nt][1] + bB);
                }
                if (gB < nRows) {
                    size_t o = (size_t)gB * H_DIM + col;
                    float2 f = *(const float2*)&feat[o];
                    *(float2*)&outf[o] = make_float2(
                        f.x + c[pass][nt][2] + bA, f.y + c[pass][nt][3] + bB);
                }
            }
        }
    }
}

__global__ void pos_kernel(const float* __restrict__ pos,
                           const float* __restrict__ pos_upd,
                           float* __restrict__ out, int n)
{
    int i = blockIdx.x * blockDim.x + threadIdx.x;
    if (i < n) out[i] = pos[i] + 0.5f * pos_upd[i];
}

extern "C" void kernel_launch(void* const* d_in, const int* in_sizes, int n_in,
                              void* d_out, int out_size)
{
    const float* feat   = (const float*)d_in[0];
    const float* pos    = (const float*)d_in[1];
    const int*   ei_up  = (const int*)d_in[2];
    const int*   ei_dn  = (const int*)d_in[3];
    const float* deg_up = (const float*)d_in[4];
    const float* deg_dn = (const float*)d_in[5];

    const float* w1u  = (const float*)d_in[6];
    const float* b1u  = (const float*)d_in[7];
    const float* w2u  = (const float*)d_in[8];
    const float* b2u  = (const float*)d_in[9];
    const float* wp1u = (const float*)d_in[10];
    const float* bp1u = (const float*)d_in[11];
    const float* wp2u = (const float*)d_in[12];
    const float* bp2u = (const float*)d_in[13];

    const float* w1d  = (const float*)d_in[14];
    const float* b1d  = (const float*)d_in[15];
    const float* w2d  = (const float*)d_in[16];
    const float* b2d  = (const float*)d_in[17];
    const float* wp1d = (const float*)d_in[18];
    const float* bp1d = (const float*)d_in[19];
    const float* wp2d = (const float*)d_in[20];
    const float* bp2d = (const float*)d_in[21];

    const float* wu1 = (const float*)d_in[22];
    const float* bu1 = (const float*)d_in[23];
    const float* wu2 = (const float*)d_in[24];
    const float* bu2 = (const float*)d_in[25];

    int E = in_sizes[2] / 2;
    int N = in_sizes[4];
    int B = in_sizes[0] / (N * H_DIM);
    int nRows = B * N;

    float *pre, *hacc, *einv, *pos_upd, *CpFrag, *bpc, *bcu, *preFrag, *nodeFrag;
    cudaGetSymbolAddress((void**)&pre,      g_pre);
    cudaGetSymbolAddress((void**)&hacc,     g_hacc);
    cudaGetSymbolAddress((void**)&einv,     g_einv);
    cudaGetSymbolAddress((void**)&pos_upd,  g_pos_upd);
    cudaGetSymbolAddress((void**)&CpFrag,   g_CpFrag);
    cudaGetSymbolAddress((void**)&bpc,      g_bpc);
    cudaGetSymbolAddress((void**)&bcu,      g_bcu);
    cudaGetSymbolAddress((void**)&preFrag,  g_preFrag);
    cudaGetSymbolAddress((void**)&nodeFrag, g_nodeFrag);

    const size_t PS = (size_t)MAX_BN * H_DIM;
    float* pre_au = pre;
    float* pre_bu = pre + PS;
    float* pre_ad = pre + 2 * PS;
    float* pre_bd = pre + 3 * PS;
    float* hacc_u = hacc;
    float* hacc_d = hacc + PS;
    float* einv_u = einv;
    float* einv_d = einv + MAX_N;

    cudaMemsetAsync(hacc, 0, 2 * PS * sizeof(float));
    cudaMemsetAsync(einv, 0, 2 * MAX_N * sizeof(float));
    cudaMemsetAsync(pos_upd, 0, (size_t)nRows * 3 * sizeof(float));

    int smemPre  = (2 * 64 * BS1) * 4;                         //  67584 B
    int smemEdge = (128 * HS + 8192 + 4 * 128 + 384 + 128 + 128 + 128
                    + 2 * 128) * 4;                            // 106496 B
    int smemNode = (2 * 64 * BS1 + 128 + 512) * 4;             //  70144 B
    cudaFuncSetAttribute(pre_mma_kernel,
                         cudaFuncAttributeMaxDynamicSharedMemorySize, smemPre);
    cudaFuncSetAttribute(edge_mma_kernel,
                         cudaFuncAttributeMaxDynamicSharedMemorySize, smemEdge);
    cudaFuncSetAttribute(node2_mma_kernel,
                         cudaFuncAttributeMaxDynamicSharedMemorySize, smemNode);

    combine_kernel<<<dim3(H_DIM + 1, 4), H_DIM>>>(
        w2u, wp1u, b2u, bp1u, w2d, wp1d, b2d, bp1d, wu1,
        CpFrag, nodeFrag, bpc, bcu);

    fragw_kernel<<<dim3(H_DIM, 6), H_DIM>>>(w1u, w1d, wu1, wu2,
                                            preFrag, nodeFrag);

    pre_mma_kernel<<<(nRows + 63) / 64, 256, smemPre>>>(
        feat, preFrag, pre_au, pre_bu, pre_ad, pre_bd, nRows);

    EdgeParams EP;
    EP.d[0] = { pre_au, pre_bu, ei_up, deg_up, w1u, b1u,
                CpFrag,         bpc,         wp2u, bp2u, hacc_u, einv_u };
    EP.d[1] = { pre_ad, pre_bd, ei_dn, deg_dn, w1d, b1d,
                CpFrag + 16384, bpc + H_DIM, wp2d, bp2d, hacc_d, einv_d };

    dim3 egrid((E + TEC - 1) / TEC, B, 2);
    edge_mma_kernel<<<egrid, 256, smemEdge>>>(EP, pos, pos_upd, E, N);

    node2_mma_kernel<<<(nRows + 63) / 64, 256, smemNode>>>(
        feat, hacc_u, hacc_d, nodeFrag, einv_u, einv_d,
        bcu, bcu + H_DIM, bu1, bu2, (float*)d_out, N, nRows);

    size_t featN = (size_t)nRows * H_DIM;
    int pn = nRows * 3;
    pos_kernel<<<(pn + 255) / 256, 256>>>(
        pos, pos_upd, (float*)d_out + featN, pn);
}

// round 9
// speedup vs baseline: 6.6623x; 1.0713x over previous
#include <cuda_runtime.h>
#include <math.h>
#include <cstdint>

#define H_DIM 128
#define TEC 128        // edges per block (edge kernel)
#define BS1 132        // padded row stride
#define HS 132

#define MAX_B 2
#define MAX_N 20000
#define MAX_BN (MAX_B * MAX_N)

// ---------------------------------------------------------------------------
// Scratch (allocation-free rule: __device__ globals)
// ---------------------------------------------------------------------------
__device__ __align__(128) float g_pre[4][(size_t)MAX_BN * H_DIM];
__device__ __align__(128) float g_hacc[2][(size_t)MAX_BN * H_DIM];
__device__ __align__(128) float g_einv[2][MAX_N];
__device__ __align__(128) float g_pos_upd[(size_t)MAX_BN * 3];
__device__ __align__(128) float g_CpFrag[2][H_DIM * H_DIM];      // paired-hi layout
__device__ __align__(128) float g_bpc[2][H_DIM];
__device__ __align__(128) float g_bcu[2][H_DIM];
__device__ __align__(128) float g_preFrag[4][2][H_DIM * H_DIM];  // hi/lo uint4 layout
__device__ __align__(128) float g_nodeFrag[4][2][H_DIM * H_DIM]; // wu1top,Cu0,Cu1,wu2

__device__ __forceinline__ float silu_f(float v) {
    return __fdividef(v, 1.0f + __expf(-v));
}

// ---- tf32 mma.sync helpers --------------------------------------------------
__device__ __forceinline__ uint32_t cvt_tf32(float x) {
    uint32_t r;
    asm("cvt.rna.tf32.f32 %0, %1;" : "=r"(r) : "f"(x));
    return r;
}
__device__ __forceinline__ void mma_tf32(float c[4], const uint32_t a[4],
                                         uint32_t b0, uint32_t b1) {
    asm volatile(
        "mma.sync.aligned.m16n8k8.row.col.f32.tf32.tf32.f32 "
        "{%0,%1,%2,%3}, {%4,%5,%6,%7}, {%8,%9}, {%0,%1,%2,%3};"
        : "+f"(c[0]), "+f"(c[1]), "+f"(c[2]), "+f"(c[3])
        : "r"(a[0]), "r"(a[1]), "r"(a[2]), "r"(a[3]), "r"(b0), "r"(b1));
}

// hi/lo uint4 layout index (per 128x128 matrix, 32768 floats)
__device__ __forceinline__ size_t frag_base(int i, int j) {
    int kstep = i >> 3, kk = i & 7;
    int ntile = j >> 3, nn = j & 7;
    int lane = nn * 4 + (kk & 3);
    return ((size_t)(ntile * 16 + kstep) * 32 + lane) * 4 + (kk >> 2);
}

// ---------------------------------------------------------------------------
// combine_kernel: y=0/1 Cp (paired-hi layout) + bpc ; y=2/3 Cu hi/lo + bcu
// ---------------------------------------------------------------------------
__global__ void combine_kernel(
    const float* __restrict__ w2u, const float* __restrict__ wp1u,
    const float* __restrict__ b2u, const float* __restrict__ bp1u,
    const float* __restrict__ w2d, const float* __restrict__ wp1d,
    const float* __restrict__ b2d, const float* __restrict__ bp1d,
    const float* __restrict__ wu1,
    float* __restrict__ CpFrag, float* __restrict__ nodeFrag,
    float* __restrict__ bpc, float* __restrict__ bcu)
{
    const float* wu1b = wu1 + 128 * H_DIM;
    const float* A; const float* Bm; const float* bvec; const float* badd;
    float* C; float* bout; bool split;
    switch (blockIdx.y) {
        case 0:  A = w2u; Bm = wp1u; bvec = b2u; badd = bp1u;
                 C = CpFrag;               bout = bpc;         split = false; break;
        case 1:  A = w2d; Bm = wp1d; bvec = b2d; badd = bp1d;
                 C = CpFrag + 16384;       bout = bpc + H_DIM; split = false; break;
        case 2:  A = w2u; Bm = wu1b; bvec = b2u; badd = 0;
                 C = nodeFrag + 1 * 32768; bout = bcu;         split = true;  break;
        default: A = w2d; Bm = wu1b; bvec = b2d; badd = 0;
                 C = nodeFrag + 2 * 32768; bout = bcu + H_DIM; split = true;  break;
    }
    int i = blockIdx.x;   // k
    int j = threadIdx.x;  // n
    const float* arow = (i < H_DIM) ? (A + (size_t)i * H_DIM) : bvec;
    float s = 0.f;
    #pragma unroll 8
    for (int k = 0; k < H_DIM; ++k) s += arow[k] * Bm[k * H_DIM + j];
    if (i < H_DIM) {
        uint32_t hi = cvt_tf32(s);
        if (split) {
            size_t b0 = frag_base(i, j);
            C[b0]     = __uint_as_float(hi);
            C[b0 + 2] = __uint_as_float(cvt_tf32(s - __uint_as_float(hi)));
        } else {
            int kstep = i >> 3, kk = i & 7;
            int lane = (j & 7) * 4 + (kk & 3);
            int reg  = kk >> 2;
            int ntile = j >> 3, pass = ntile >> 3, ntl = ntile & 7;
            size_t idx = (size_t)pass * 8192
                       + ((size_t)((kstep * 4 + (ntl >> 1)) * 32 + lane)) * 4
                       + (ntl & 1) * 2 + reg;
            C[idx] = __uint_as_float(hi);
        }
    } else {
        bout[j] = s + (badd ? badd[j] : 0.f);
    }
}

// ---------------------------------------------------------------------------
// fragw_kernel: hi/lo uint4 images of raw weights
// ---------------------------------------------------------------------------
__global__ void fragw_kernel(const float* __restrict__ w1u,
                             const float* __restrict__ w1d,
                             const float* __restrict__ wu1,
                             const float* __restrict__ wu2,
                             float* __restrict__ preFrag,
                             float* __restrict__ nodeFrag)
{
    int y = blockIdx.y;
    const float* W; float* out;
    switch (y) {
        case 0: W = w1u;                out = preFrag;             break;
        case 1: W = w1u + 128 * H_DIM;  out = preFrag + 32768;     break;
        case 2: W = w1d;                out = preFrag + 2 * 32768; break;
        case 3: W = w1d + 128 * H_DIM;  out = preFrag + 3 * 32768; break;
        case 4: W = wu1;                out = nodeFrag;            break;
        default: W = wu2;               out = nodeFrag + 3 * 32768; break;
    }
    int i = blockIdx.x;
    int j = threadIdx.x;
    float w = W[i * H_DIM + j];
    uint32_t hi = cvt_tf32(w);
    size_t b0 = frag_base(i, j);
    out[b0]     = __uint_as_float(hi);
    out[b0 + 2] = __uint_as_float(cvt_tf32(w - __uint_as_float(hi)));
}

// ---------------------------------------------------------------------------
// pre_mma_kernel: all 4 pre-GEMMs; A staged+split once; A-frags loaded once
// per ks and reused across all 4 matrices; B uint4 direct from global.
// ---------------------------------------------------------------------------
__global__ void __launch_bounds__(256)
pre_mma_kernel(const float* __restrict__ feat, const float* __restrict__ frag,
               float* __restrict__ p0, float* __restrict__ p1,
               float* __restrict__ p2, float* __restrict__ p3, int nRows)
{
    extern __shared__ float sm[];
    uint32_t* sAhi = (uint32_t*)sm;            // [64][132]
    uint32_t* sAlo = sAhi + 64 * BS1;          // [64][132]

    const int tid = threadIdx.x;
    const int wid = tid >> 5, lane = tid & 31;
    const int rg = wid & 3, cg = wid >> 2;
    const int ar = rg * 16 + (lane >> 2);
    const int ak = lane & 3;
    const int g0 = blockIdx.x * 64;

    // stage + split A once
    #pragma unroll
    for (int p = 0; p < 8; ++p) {
        int idx = p * 256 + tid;
        int r = idx >> 5, c4 = idx & 31;
        float4 v = make_float4(0.f, 0.f, 0.f, 0.f);
        if (g0 + r < nRows)
            v = __ldg((const float4*)feat + (size_t)(g0 + r) * 32 + c4);
        uint32_t h0 = cvt_tf32(v.x), h1 = cvt_tf32(v.y),
                 h2 = cvt_tf32(v.z), h3 = cvt_tf32(v.w);
        uint32_t l0 = cvt_tf32(v.x - __uint_as_float(h0));
        uint32_t l1 = cvt_tf32(v.y - __uint_as_float(h1));
        uint32_t l2 = cvt_tf32(v.z - __uint_as_float(h2));
        uint32_t l3 = cvt_tf32(v.w - __uint_as_float(h3));
        *(uint4*)(sAhi + r * BS1 + c4 * 4) = make_uint4(h0, h1, h2, h3);
        *(uint4*)(sAlo + r * BS1 + c4 * 4) = make_uint4(l0, l1, l2, l3);
    }
    __syncthreads();

    float* outs[4] = {p0, p1, p2, p3};
    const uint4* frag4 = (const uint4*)frag;

    #pragma unroll
    for (int pass = 0; pass < 2; ++pass) {
        float c[4][4][4];   // [matrix][ntile][acc]
        #pragma unroll
        for (int m = 0; m < 4; ++m)
            #pragma unroll
            for (int nt = 0; nt < 4; ++nt)
                #pragma unroll
                for (int q = 0; q < 4; ++q) c[m][nt][q] = 0.f;

        #pragma unroll 2
        for (int ks = 0; ks < 16; ++ks) {
            int k0 = ks * 8 + ak;
            uint32_t ah[4], al[4];
            ah[0] = sAhi[ar * BS1 + k0];
            ah[1] = sAhi[(ar + 8) * BS1 + k0];
            ah[2] = sAhi[ar * BS1 + k0 + 4];
            ah[3] = sAhi[(ar + 8) * BS1 + k0 + 4];
            al[0] = sAlo[ar * BS1 + k0];
            al[1] = sAlo[(ar + 8) * BS1 + k0];
            al[2] = sAlo[ar * BS1 + k0 + 4];
            al[3] = sAlo[(ar + 8) * BS1 + k0 + 4];
            #pragma unroll
            for (int m = 0; m < 4; ++m) {
                const uint4* Bm = frag4 + (size_t)m * 8192;
                #pragma unroll
                for (int nt = 0; nt < 4; ++nt) {
                    int ntile = pass * 8 + cg * 4 + nt;
                    uint4 v = __ldg(Bm + (size_t)(ntile * 16 + ks) * 32 + lane);
                    mma_tf32(c[m][nt], ah, v.x, v.y);
                    mma_tf32(c[m][nt], al, v.x, v.y);
                    mma_tf32(c[m][nt], ah, v.z, v.w);
                }
            }
        }
        int rowA = g0 + ar, rowB = g0 + ar + 8;
        #pragma unroll
        for (int m = 0; m < 4; ++m) {
            float* out = outs[m];
            #pragma unroll
            for (int nt = 0; nt < 4; ++nt) {
                int col = (pass * 8 + cg * 4 + nt) * 8 + 2 * ak;
                if (rowA < nRows)
                    *(float2*)&out[(size_t)rowA * H_DIM + col] =
                        make_float2(c[m][nt][0], c[m][nt][1]);
                if (rowB < nRows)
                    *(float2*)&out[(size_t)rowB * H_DIM + col] =
                        make_float2(c[m][nt][2], c[m][nt][3]);
            }
        }
    }
}

// ---------------------------------------------------------------------------
// edge_mma_kernel: merged dirs; batched gather; B fragments direct from
// global (no sBf staging) -> smem 73.7KB -> 3 CTAs/SM.
// ---------------------------------------------------------------------------
struct EdgeDir {
    const float* pre_a; const float* pre_b;
    const int* ei; const float* deg;
    const float* w1; const float* b1;
    const float* CpFrag; const float* bpc;
    const float* wp2; const float* bp2;
    float* hacc; float* einv;
};
struct EdgeParams { EdgeDir d[2]; };

__global__ void __launch_bounds__(256, 3)
edge_mma_kernel(EdgeParams P, const float* __restrict__ pos,
                float* __restrict__ pos_upd, int nE, int N)
{
    extern __shared__ float sm[];
    uint32_t* sHid = (uint32_t*)sm;         // [128][132] tf32 bits
    float* s_w1c = sm + 128 * HS;
    float* s_b1  = s_w1c + 128;
    float* s_bpc = s_b1 + 128;
    float* s_wp2 = s_bpc + 128;
    float* s_rel = s_wp2 + 128;             // [128*3]
    float* s_dist= s_rel + 384;
    float* s_inv = s_dist + 128;
    float* s_p   = s_inv + 128;             // [128]
    int*   s_src = (int*)(s_p + 128);
    int*   s_dst = s_src + 128;

    const EdgeDir& D = P.d[blockIdx.z];
    const int tid  = threadIdx.x;
    const int wid  = tid >> 5;
    const int lane = tid & 31;
    const int b    = blockIdx.y;
    const int e0   = blockIdx.x * TEC;
    const size_t bN = (size_t)b * N;

    if (tid < TEC) {
        int e = e0 + tid;
        int s = 0, d = 0;
        float x0 = 0.f, x1 = 0.f, x2 = 0.f, dist = 0.f, inv = 0.f;
        if (e < nE) {
            s = D.ei[e];
            d = D.ei[nE + e];
            const float* ps = pos + (bN + s) * 3;
            const float* pd = pos + (bN + d) * 3;
            x0 = ps[0] - pd[0];
            x1 = ps[1] - pd[1];
            x2 = ps[2] - pd[2];
            dist = sqrtf(x0 * x0 + x1 * x1 + x2 * x2);
            inv  = 1.0f / fmaxf(D.deg[d], 1.0f);
        }
        s_src[tid] = s; s_dst[tid] = d;
        s_rel[tid * 3 + 0] = x0; s_rel[tid * 3 + 1] = x1; s_rel[tid * 3 + 2] = x2;
        s_dist[tid] = dist; s_inv[tid] = inv;
        s_w1c[tid] = D.w1[256 * H_DIM + tid];
        s_b1[tid]  = D.b1[tid];
        s_bpc[tid] = D.bpc[tid];
        s_wp2[tid] = D.wp2[tid];
    }
    __syncthreads();

    // gather -> hidden; 4-step load batching for MLP
    #pragma unroll
    for (int p = 0; p < 16; p += 4) {
        float4 va[4], vb[4];
        #pragma unroll
        for (int q = 0; q < 4; ++q) {
            int r = (p + q) * 8 + wid;
            va[q] = __ldg((const float4*)D.pre_a + (bN + s_src[r]) * 32 + lane);
            vb[q] = __ldg((const float4*)D.pre_b + (bN + s_dst[r]) * 32 + lane);
        }
        #pragma unroll
        for (int q = 0; q < 4; ++q) {
            int r = (p + q) * 8 + wid;
            float dd = s_dist[r], inv = s_inv[r];
            float4 wc = *(const float4*)(s_w1c + lane * 4);
            float4 bb = *(const float4*)(s_b1 + lane * 4);
            float h0 = silu_f(va[q].x + vb[q].x + dd * wc.x + bb.x);
            float h1 = silu_f(va[q].y + vb[q].y + dd * wc.y + bb.y);
            float h2 = silu_f(va[q].z + vb[q].z + dd * wc.z + bb.z);
            float h3 = silu_f(va[q].w + vb[q].w + dd * wc.w + bb.w);
            *(uint4*)(sHid + r * HS + lane * 4) =
                make_uint4(cvt_tf32(h0), cvt_tf32(h1), cvt_tf32(h2), cvt_tf32(h3));
            float* gp = D.hacc + (bN + s_dst[r]) * H_DIM + lane * 4;
            asm volatile("red.global.add.v4.f32 [%0], {%1, %2, %3, %4};"
                         :: "l"(gp), "f"(h0 * inv), "f"(h1 * inv),
                            "f"(h2 * inv), "f"(h3 * inv) : "memory");
        }
    }
    if (tid < TEC && b == 0 && (e0 + tid) < nE)
        atomicAdd(&D.einv[s_dst[tid]], s_inv[tid]);
    __syncthreads();

    const int ar = wid * 16 + (lane >> 2);
    const int ak = lane & 3;
    float sum0 = 0.f, sum1 = 0.f;
    const uint4* Cp4 = (const uint4*)D.CpFrag;

    #pragma unroll
    for (int pass = 0; pass < 2; ++pass) {
        float c[8][4];
        #pragma unroll
        for (int nt = 0; nt < 8; ++nt)
            #pragma unroll
            for (int q = 0; q < 4; ++q) c[nt][q] = 0.f;

        #pragma unroll 4
        for (int ks = 0; ks < 16; ++ks) {
            uint32_t a[4];
            int k0 = ks * 8 + ak;
            a[0] = sHid[ar * HS + k0];
            a[1] = sHid[(ar + 8) * HS + k0];
            a[2] = sHid[ar * HS + k0 + 4];
            a[3] = sHid[(ar + 8) * HS + k0 + 4];
            #pragma unroll
            for (int ntp = 0; ntp < 4; ++ntp) {
                uint4 bv = __ldg(Cp4 + (size_t)pass * 2048
                                 + (size_t)(ks * 4 + ntp) * 32 + lane);
                mma_tf32(c[2 * ntp],     a, bv.x, bv.y);
                mma_tf32(c[2 * ntp + 1], a, bv.z, bv.w);
            }
        }
        #pragma unroll
        for (int nt = 0; nt < 8; ++nt) {
            int cb = pass * 64 + nt * 8 + 2 * ak;
            float w0 = s_wp2[cb], w1v = s_wp2[cb + 1];
            float q0 = s_bpc[cb], q1 = s_bpc[cb + 1];
            sum0 += silu_f(c[nt][0] + q0) * w0 + silu_f(c[nt][1] + q1) * w1v;
            sum1 += silu_f(c[nt][2] + q0) * w0 + silu_f(c[nt][3] + q1) * w1v;
        }
    }

    sum0 += __shfl_xor_sync(0xFFFFFFFFu, sum0, 1);
    sum0 += __shfl_xor_sync(0xFFFFFFFFu, sum0, 2);
    sum1 += __shfl_xor_sync(0xFFFFFFFFu, sum1, 1);
    sum1 += __shfl_xor_sync(0xFFFFFFFFu, sum1, 2);
    if ((lane & 3) == 0) {
        s_p[ar]     = sum0;
        s_p[ar + 8] = sum1;
    }
    __syncthreads();

    if (tid < TEC && (e0 + tid) < nE) {
        float w = tanhf(s_p[tid] + D.bp2[0]);
        int d = s_dst[tid];
        float* pp = pos_upd + (bN + d) * 3;
        atomicAdd(&pp[0], w * s_rel[tid * 3 + 0]);
        atomicAdd(&pp[1], w * s_rel[tid * 3 + 1]);
        atomicAdd(&pp[2], w * s_rel[tid * 3 + 2]);
    }
}

// ---------------------------------------------------------------------------
// node2_mma_kernel: split-tf32 node update (unchanged from R8)
// ---------------------------------------------------------------------------
__global__ void __launch_bounds__(256)
node2_mma_kernel(const float* __restrict__ feat,
                 const float* __restrict__ hacc0, const float* __restrict__ hacc1,
                 const float* __restrict__ nodeFrag,
                 const float* __restrict__ einv0, const float* __restrict__ einv1,
                 const float* __restrict__ bcu0, const float* __restrict__ bcu1,
                 const float* __restrict__ bu1,  const float* __restrict__ bu2,
                 float* __restrict__ outf, int N, int nRows)
{
    extern __shared__ float sm[];
    uint32_t* sAhi = (uint32_t*)sm;           // [64][132]
    uint32_t* sAlo = sAhi + 64 * BS1;         // [64][132]
    float* s_eU   = sm + 2 * 64 * BS1;        // [64]
    float* s_eD   = s_eU + 64;
    float* s_bias = s_eD + 64;                // 4*128

    const int tid = threadIdx.x;
    const int wid = tid >> 5, lane = tid & 31;
    const int rg = wid & 3, cg = wid >> 2;
    const int ar = rg * 16 + (lane >> 2);
    const int ak = lane & 3;
    const int g0 = blockIdx.x * 64;

    if (tid < 64) {
        int g = g0 + tid;
        float eu = 0.f, ed = 0.f;
        if (g < nRows) {
            int node = g % N;
            eu = einv0[node];
            ed = einv1[node];
        }
        s_eU[tid] = eu; s_eD[tid] = ed;
    }
    if (tid < 128) {
        s_bias[tid]       = bu1[tid];
        s_bias[128 + tid] = bcu0[tid];
        s_bias[256 + tid] = bcu1[tid];
        s_bias[384 + tid] = bu2[tid];
    }

    float c[2][4][4];
    #pragma unroll
    for (int p = 0; p < 2; ++p)
        #pragma unroll
        for (int nt = 0; nt < 4; ++nt)
            #pragma unroll
            for (int q = 0; q < 4; ++q) c[p][nt][q] = 0.f;

    for (int m = 0; m < 3; ++m) {
        const float* src = (m == 0) ? feat : (m == 1) ? hacc0 : hacc1;
        __syncthreads();
        #pragma unroll
        for (int p = 0; p < 8; ++p) {
            int idx = p * 256 + tid;
            int r = idx >> 5, c4 = idx & 31;
            float4 v = make_float4(0.f, 0.f, 0.f, 0.f);
            if (g0 + r < nRows)
                v = __ldg((const float4*)src + (size_t)(g0 + r) * 32 + c4);
            uint32_t h0 = cvt_tf32(v.x), h1 = cvt_tf32(v.y),
                     h2 = cvt_tf32(v.z), h3 = cvt_tf32(v.w);
            uint32_t l0 = cvt_tf32(v.x - __uint_as_float(h0));
            uint32_t l1 = cvt_tf32(v.y - __uint_as_float(h1));
            uint32_t l2 = cvt_tf32(v.z - __uint_as_float(h2));
            uint32_t l3 = cvt_tf32(v.w - __uint_as_float(h3));
            *(uint4*)(sAhi + r * BS1 + c4 * 4) = make_uint4(h0, h1, h2, h3);
            *(uint4*)(sAlo + r * BS1 + c4 * 4) = make_uint4(l0, l1, l2, l3);
        }
        __syncthreads();

        const uint4* Bm = (const uint4*)(nodeFrag + (size_t)m * 32768);
        #pragma unroll 2
        for (int ks = 0; ks < 16; ++ks) {
            int k0 = ks * 8 + ak;
            uint32_t ah[4], al[4];
            ah[0] = sAhi[ar * BS1 + k0];
            ah[1] = sAhi[(ar + 8) * BS1 + k0];
            ah[2] = sAhi[ar * BS1 + k0 + 4];
            ah[3] = sAhi[(ar + 8) * BS1 + k0 + 4];
            al[0] = sAlo[ar * BS1 + k0];
            al[1] = sAlo[(ar + 8) * BS1 + k0];
            al[2] = sAlo[ar * BS1 + k0 + 4];
            al[3] = sAlo[(ar + 8) * BS1 + k0 + 4];
            #pragma unroll
            for (int pass = 0; pass < 2; ++pass) {
                #pragma unroll
                for (int nt = 0; nt < 4; ++nt) {
                    int ntile = pass * 8 + cg * 4 + nt;
                    uint4 v = __ldg(Bm + (size_t)(ntile * 16 + ks) * 32 + lane);
                    mma_tf32(c[pass][nt], ah, v.x, v.y);
                    mma_tf32(c[pass][nt], al, v.x, v.y);
                    mma_tf32(c[pass][nt], ah, v.z, v.w);
                }
            }
        }
    }
    __syncthreads();
    {
        float eu0 = s_eU[ar],     ed0 = s_eD[ar];
        float eu1 = s_eU[ar + 8], ed1 = s_eD[ar + 8];
        #pragma unroll
        for (int pass = 0; pass < 2; ++pass) {
            #pragma unroll
            for (int nt = 0; nt < 4; ++nt) {
                int col = (pass * 8 + cg * 4 + nt) * 8 + 2 * ak;
                float bA = s_bias[col],        bB = s_bias[col + 1];
                float cA0 = s_bias[128 + col], cA1 = s_bias[128 + col + 1];
                float cB0 = s_bias[256 + col], cB1 = s_bias[256 + col + 1];
                float v00 = silu_f(c[pass][nt][0] + bA + eu0 * cA0 + ed0 * cB0);
                float v01 = silu_f(c[pass][nt][1] + bB + eu0 * cA1 + ed0 * cB1);
                float v10 = silu_f(c[pass][nt][2] + bA + eu1 * cA0 + ed1 * cB0);
                float v11 = silu_f(c[pass][nt][3] + bB + eu1 * cA1 + ed1 * cB1);
                uint32_t h;
                h = cvt_tf32(v00); sAhi[ar * BS1 + col] = h;
                sAlo[ar * BS1 + col] = cvt_tf32(v00 - __uint_as_float(h));
                h = cvt_tf32(v01); sAhi[ar * BS1 + col + 1] = h;
                sAlo[ar * BS1 + col + 1] = cvt_tf32(v01 - __uint_as_float(h));
                h = cvt_tf32(v10); sAhi[(ar + 8) * BS1 + col] = h;
                sAlo[(ar + 8) * BS1 + col] = cvt_tf32(v10 - __uint_as_float(h));
                h = cvt_tf32(v11); sAhi[(ar + 8) * BS1 + col + 1] = h;
                sAlo[(ar + 8) * BS1 + col + 1] = cvt_tf32(v11 - __uint_as_float(h));
            }
        }
    }
    __syncthreads();

    #pragma unroll
    for (int p = 0; p < 2; ++p)
        #pragma unroll
        for (int nt = 0; nt < 4; ++nt)
            #pragma unroll
            for (int q = 0; q < 4; ++q) c[p][nt][q] = 0.f;

    {
        const uint4* Bm = (const uint4*)(nodeFrag + (size_t)3 * 32768);
        #pragma unroll 2
        for (int ks = 0; ks < 16; ++ks) {
            int k0 = ks * 8 + ak;
            uint32_t ah[4], al[4];
            ah[0] = sAhi[ar * BS1 + k0];
            ah[1] = sAhi[(ar + 8) * BS1 + k0];
            ah[2] = sAhi[ar * BS1 + k0 + 4];
            ah[3] = sAhi[(ar + 8) * BS1 + k0 + 4];
            al[0] = sAlo[ar * BS1 + k0];
            al[1] = sAlo[(ar + 8) * BS1 + k0];
            al[2] = sAlo[ar * BS1 + k0 + 4];
            al[3] = sAlo[(ar + 8) * BS1 + k0 + 4];
            #pragma unroll
            for (int pass = 0; pass < 2; ++pass) {
                #pragma unroll
                for (int nt = 0; nt < 4; ++nt) {
                    int ntile = pass * 8 + cg * 4 + nt;
                    uint4 v = __ldg(Bm + (size_t)(ntile * 16 + ks) * 32 + lane);
                    mma_tf32(c[pass][nt], ah, v.x, v.y);
                    mma_tf32(c[pass][nt], al, v.x, v.y);
                    mma_tf32(c[pass][nt], ah, v.z, v.w);
                }
            }
        }
    }
    {
        int gA = g0 + ar, gB = g0 + ar + 8;
        #pragma unroll
        for (int pass = 0; pass < 2; ++pass) {
            #pragma unroll
            for (int nt = 0; nt < 4; ++nt) {
                int col = (pass * 8 + cg * 4 + nt) * 8 + 2 * ak;
                float bA = s_bias[384 + col], bB = s_bias[384 + col + 1];
                if (gA < nRows) {
                    size_t o = (size_t)gA * H_DIM + col;
                    float2 f = *(const float2*)&feat[o];
                    *(float2*)&outf[o] = make_float2(
                        f.x + c[pass][nt][0] + bA, f.y + c[pass][nt][1] + bB);
                }
                if (gB < nRows) {
                    size_t o = (size_t)gB * H_DIM + col;
                    float2 f = *(const float2*)&feat[o];
                    *(float2*)&outf[o] = make_float2(
                        f.x + c[pass][nt][2] + bA, f.y + c[pass][nt][3] + bB);
                }
            }
        }
    }
}

__global__ void pos_kernel(const float* __restrict__ pos,
                           const float* __restrict__ pos_upd,
                           float* __restrict__ out, int n)
{
    int i = blockIdx.x * blockDim.x + threadIdx.x;
    if (i < n) out[i] = pos[i] + 0.5f * pos_upd[i];
}

extern "C" void kernel_launch(void* const* d_in, const int* in_sizes, int n_in,
                              void* d_out, int out_size)
{
    const float* feat   = (const float*)d_in[0];
    const float* pos    = (const float*)d_in[1];
    const int*   ei_up  = (const int*)d_in[2];
    const int*   ei_dn  = (const int*)d_in[3];
    const float* deg_up = (const float*)d_in[4];
    const float* deg_dn = (const float*)d_in[5];

    const float* w1u  = (const float*)d_in[6];
    const float* b1u  = (const float*)d_in[7];
    const float* w2u  = (const float*)d_in[8];
    const float* b2u  = (const float*)d_in[9];
    const float* wp1u = (const float*)d_in[10];
    const float* bp1u = (const float*)d_in[11];
    const float* wp2u = (const float*)d_in[12];
    const float* bp2u = (const float*)d_in[13];

    const float* w1d  = (const float*)d_in[14];
    const float* b1d  = (const float*)d_in[15];
    const float* w2d  = (const float*)d_in[16];
    const float* b2d  = (const float*)d_in[17];
    const float* wp1d = (const float*)d_in[18];
    const float* bp1d = (const float*)d_in[19];
    const float* wp2d = (const float*)d_in[20];
    const float* bp2d = (const float*)d_in[21];

    const float* wu1 = (const float*)d_in[22];
    const float* bu1 = (const float*)d_in[23];
    const float* wu2 = (const float*)d_in[24];
    const float* bu2 = (const float*)d_in[25];

    int E = in_sizes[2] / 2;
    int N = in_sizes[4];
    int B = in_sizes[0] / (N * H_DIM);
    int nRows = B * N;

    float *pre, *hacc, *einv, *pos_upd, *CpFrag, *bpc, *bcu, *preFrag, *nodeFrag;
    cudaGetSymbolAddress((void**)&pre,      g_pre);
    cudaGetSymbolAddress((void**)&hacc,     g_hacc);
    cudaGetSymbolAddress((void**)&einv,     g_einv);
    cudaGetSymbolAddress((void**)&pos_upd,  g_pos_upd);
    cudaGetSymbolAddress((void**)&CpFrag,   g_CpFrag);
    cudaGetSymbolAddress((void**)&bpc,      g_bpc);
    cudaGetSymbolAddress((void**)&bcu,      g_bcu);
    cudaGetSymbolAddress((void**)&preFrag,  g_preFrag);
    cudaGetSymbolAddress((void**)&nodeFrag, g_nodeFrag);

    const size_t PS = (size_t)MAX_BN * H_DIM;
    float* pre_au = pre;
    float* pre_bu = pre + PS;
    float* pre_ad = pre + 2 * PS;
    float* pre_bd = pre + 3 * PS;
    float* hacc_u = hacc;
    float* hacc_d = hacc + PS;
    float* einv_u = einv;
    float* einv_d = einv + MAX_N;

    cudaMemsetAsync(hacc, 0, 2 * PS * sizeof(float));
    cudaMemsetAsync(einv, 0, 2 * MAX_N * sizeof(float));
    cudaMemsetAsync(pos_upd, 0, (size_t)nRows * 3 * sizeof(float));

    int smemPre  = (2 * 64 * BS1) * 4;                         //  67584 B
    int smemEdge = (128 * HS + 512 + 384 + 128 + 128 + 128 + 256) * 4; // 73728 B
    int smemNode = (2 * 64 * BS1 + 128 + 512) * 4;             //  70144 B
    cudaFuncSetAttribute(pre_mma_kernel,
                         cudaFuncAttributeMaxDynamicSharedMemorySize, smemPre);
    cudaFuncSetAttribute(edge_mma_kernel,
                         cudaFuncAttributeMaxDynamicSharedMemorySize, smemEdge);
    cudaFuncSetAttribute(node2_mma_kernel,
                         cudaFuncAttributeMaxDynamicSharedMemorySize, smemNode);

    combine_kernel<<<dim3(H_DIM + 1, 4), H_DIM>>>(
        w2u, wp1u, b2u, bp1u, w2d, wp1d, b2d, bp1d, wu1,
        CpFrag, nodeFrag, bpc, bcu);

    fragw_kernel<<<dim3(H_DIM, 6), H_DIM>>>(w1u, w1d, wu1, wu2,
                                            preFrag, nodeFrag);

    pre_mma_kernel<<<(nRows + 63) / 64, 256, smemPre>>>(
        feat, preFrag, pre_au, pre_bu, pre_ad, pre_bd, nRows);

    EdgeParams EP;
    EP.d[0] = { pre_au, pre_bu, ei_up, deg_up, w1u, b1u,
                CpFrag,         bpc,         wp2u, bp2u, hacc_u, einv_u };
    EP.d[1] = { pre_ad, pre_bd, ei_dn, deg_dn, w1d, b1d,
                CpFrag + 16384, bpc + H_DIM, wp2d, bp2d, hacc_d, einv_d };

    dim3 egrid((E + TEC - 1) / TEC, B, 2);
    edge_mma_kernel<<<egrid, 256, smemEdge>>>(EP, pos, pos_upd, E, N);

    node2_mma_kernel<<<(nRows + 63) / 64, 256, smemNode>>>(
        feat, hacc_u, hacc_d, nodeFrag, einv_u, einv_d,
        bcu, bcu + H_DIM, bu1, bu2, (float*)d_out, N, nRows);

    size_t featN = (size_t)nRows * H_DIM;
    int pn = nRows * 3;
    pos_kernel<<<(pn + 255) / 256, 256>>>(
        pos, pos_upd, (float*)d_out + featN, pn);
}

// round 10
// speedup vs baseline: 7.4482x; 1.1180x over previous
#include <cuda_runtime.h>
#include <cuda_fp16.h>
#include <math.h>
#include <cstdint>

#define H_DIM 128
#define TEC 128        // edges per block (edge kernel)
#define PS1 68         // pair-row stride (uint32 units) for fp16x2 tiles

#define MAX_B 2
#define MAX_N 20000
#define MAX_BN (MAX_B * MAX_N)

// ---------------------------------------------------------------------------
// Scratch (allocation-free rule: __device__ globals)
// ---------------------------------------------------------------------------
__device__ __align__(128) float g_pre[4][(size_t)MAX_BN * H_DIM];
__device__ __align__(128) float g_hacc[2][(size_t)MAX_BN * H_DIM];
__device__ __align__(128) float g_einv[2][MAX_N];
__device__ __align__(128) float g_pos_upd[(size_t)MAX_BN * 3];
__device__ __align__(128) uint32_t g_CpFrag[2][8192];     // fp16 hi, paired-ntile uint4 layout
__device__ __align__(128) float g_bpc[2][H_DIM];
__device__ __align__(128) float g_bcu[2][H_DIM];
__device__ __align__(128) uint32_t g_preFrag[4][16384];   // fp16 hi/lo uint4 layout
__device__ __align__(128) uint32_t g_nodeFrag[4][16384];  // wu1top,Cu0,Cu1,wu2

__device__ __forceinline__ float silu_f(float v) {
    return __fdividef(v, 1.0f + __expf(-v));
}

// ---- fp16 mma.sync helpers --------------------------------------------------
__device__ __forceinline__ void mma_f16(float c[4], const uint32_t a[4],
                                        uint32_t b0, uint32_t b1) {
    asm volatile(
        "mma.sync.aligned.m16n8k16.row.col.f32.f16.f16.f32 "
        "{%0,%1,%2,%3}, {%4,%5,%6,%7}, {%8,%9}, {%0,%1,%2,%3};"
        : "+f"(c[0]), "+f"(c[1]), "+f"(c[2]), "+f"(c[3])
        : "r"(a[0]), "r"(a[1]), "r"(a[2]), "r"(a[3]), "r"(b0), "r"(b1));
}
__device__ __forceinline__ uint32_t pack_hh(__half lo, __half hi) {
    __half2 h = __halves2half2(lo, hi);
    return *reinterpret_cast<uint32_t*>(&h);
}
// pack two floats (even element -> low half)
__device__ __forceinline__ uint32_t pack_ff(float e, float o) {
    __half2 h = __floats2half2_rn(e, o);
    return *reinterpret_cast<uint32_t*>(&h);
}

// ---------------------------------------------------------------------------
// combine_kernel: grid (65, 4), 128 thr.
//  y=0/1: Cp (fp16 hi, paired-ntile layout) + bpc ; y=2/3: Cu hi/lo + bcu
//  blockIdx.x < 64: k-pair (2*bx, 2*bx+1); ==64: bias row.
// ---------------------------------------------------------------------------
__global__ void combine_kernel(
    const float* __restrict__ w2u, const float* __restrict__ wp1u,
    const float* __restrict__ b2u, const float* __restrict__ bp1u,
    const float* __restrict__ w2d, const float* __restrict__ wp1d,
    const float* __restrict__ b2d, const float* __restrict__ bp1d,
    const float* __restrict__ wu1,
    uint32_t* __restrict__ CpFrag, uint32_t* __restrict__ nodeFrag,
    float* __restrict__ bpc, float* __restrict__ bcu)
{
    const float* wu1b = wu1 + 128 * H_DIM;
    const float* A; const float* Bm; const float* bvec; const float* badd;
    uint32_t* C; float* bout; bool split;
    switch (blockIdx.y) {
        case 0:  A = w2u; Bm = wp1u; bvec = b2u; badd = bp1u;
                 C = CpFrag;               bout = bpc;         split = false; break;
        case 1:  A = w2d; Bm = wp1d; bvec = b2d; badd = bp1d;
                 C = CpFrag + 8192;        bout = bpc + H_DIM; split = false; break;
        case 2:  A = w2u; Bm = wu1b; bvec = b2u; badd = 0;
                 C = nodeFrag + 1 * 16384; bout = bcu;         split = true;  break;
        default: A = w2d; Bm = wu1b; bvec = b2d; badd = 0;
                 C = nodeFrag + 2 * 16384; bout = bcu + H_DIM; split = true;  break;
    }
    int i2 = blockIdx.x;
    int j  = threadIdx.x;
    if (i2 == 64) {   // bias row
        float s = 0.f;
        #pragma unroll 8
        for (int k = 0; k < H_DIM; ++k) s += bvec[k] * Bm[k * H_DIM + j];
        bout[j] = s + (badd ? badd[j] : 0.f);
        return;
    }
    float s0 = 0.f, s1 = 0.f;
    const float* a0r = A + (size_t)(2 * i2) * H_DIM;
    const float* a1r = a0r + H_DIM;
    #pragma unroll 8
    for (int k = 0; k < H_DIM; ++k) {
        float b = Bm[k * H_DIM + j];
        s0 += a0r[k] * b;
        s1 += a1r[k] * b;
    }
    int ks = i2 >> 3, m = i2 & 7;
    int lanep = m & 3, reg = m >> 2;
    int nn = j & 7;
    if (split) {
        __half h0 = __float2half_rn(s0), h1 = __float2half_rn(s1);
        __half l0 = __float2half_rn(s0 - __half2float(h0));
        __half l1 = __float2half_rn(s1 - __half2float(h1));
        int ntile = j >> 3;
        size_t base = ((size_t)(ntile * 8 + ks) * 32 + nn * 4 + lanep) * 4;
        C[base + reg]     = pack_hh(h0, h1);
        C[base + 2 + reg] = pack_hh(l0, l1);
    } else {
        int ntile = j >> 3, pass = ntile >> 3, ntl = ntile & 7;
        size_t idx = (size_t)pass * 4096
                   + ((size_t)(ks * 4 + (ntl >> 1)) * 32 + nn * 4 + lanep) * 4
                   + (ntl & 1) * 2 + reg;
        C[idx] = pack_ff(s0, s1);
    }
}

// ---------------------------------------------------------------------------
// fragw_kernel: grid (64, 6), 128 thr. hi/lo fp16 frag images of raw weights.
// ---------------------------------------------------------------------------
__global__ void fragw_kernel(const float* __restrict__ w1u,
                             const float* __restrict__ w1d,
                             const float* __restrict__ wu1,
                             const float* __restrict__ wu2,
                             uint32_t* __restrict__ preFrag,
                             uint32_t* __restrict__ nodeFrag)
{
    int y = blockIdx.y;
    const float* W; uint32_t* out;
    switch (y) {
        case 0: W = w1u;                out = preFrag;              break;
        case 1: W = w1u + 128 * H_DIM;  out = preFrag + 16384;      break;
        case 2: W = w1d;                out = preFrag + 2 * 16384;  break;
        case 3: W = w1d + 128 * H_DIM;  out = preFrag + 3 * 16384;  break;
        case 4: W = wu1;                out = nodeFrag;             break;
        default: W = wu2;               out = nodeFrag + 3 * 16384; break;
    }
    int i2 = blockIdx.x;  // k pair
    int j  = threadIdx.x; // n
    float x0 = W[(size_t)(2 * i2) * H_DIM + j];
    float x1 = W[(size_t)(2 * i2 + 1) * H_DIM + j];
    __half h0 = __float2half_rn(x0), h1 = __float2half_rn(x1);
    __half l0 = __float2half_rn(x0 - __half2float(h0));
    __half l1 = __float2half_rn(x1 - __half2float(h1));
    int ks = i2 >> 3, m = i2 & 7;
    int lanep = m & 3, reg = m >> 2;
    int ntile = j >> 3, nn = j & 7;
    size_t base = ((size_t)(ntile * 8 + ks) * 32 + nn * 4 + lanep) * 4;
    out[base + reg]     = pack_hh(h0, h1);
    out[base + 2 + reg] = pack_hh(l0, l1);
}

// ---------------------------------------------------------------------------
// pre_mma_kernel: all 4 pre-GEMMs; A staged as fp16x2 hi/lo once;
// split-fp16 (3 mma) per B uint4 (hi+lo together).
// ---------------------------------------------------------------------------
__global__ void __launch_bounds__(256)
pre_mma_kernel(const float* __restrict__ feat, const uint32_t* __restrict__ frag,
               float* __restrict__ p0, float* __restrict__ p1,
               float* __restrict__ p2, float* __restrict__ p3, int nRows)
{
    extern __shared__ uint32_t smu[];
    uint32_t* sAhi = smu;                 // [64][68] pairs
    uint32_t* sAlo = sAhi + 64 * PS1;

    const int tid = threadIdx.x;
    const int wid = tid >> 5, lane = tid & 31;
    const int rg = wid & 3, cg = wid >> 2;
    const int ar = rg * 16 + (lane >> 2);
    const int ak = lane & 3;
    const int g0 = blockIdx.x * 64;

    #pragma unroll
    for (int p = 0; p < 8; ++p) {
        int idx = p * 256 + tid;
        int r = idx >> 5, c4 = idx & 31;
        float4 v = make_float4(0.f, 0.f, 0.f, 0.f);
        if (g0 + r < nRows)
            v = __ldg((const float4*)feat + (size_t)(g0 + r) * 32 + c4);
        __half hx = __float2half_rn(v.x), hy = __float2half_rn(v.y);
        __half hz = __float2half_rn(v.z), hw = __float2half_rn(v.w);
        uint2 hi = make_uint2(pack_hh(hx, hy), pack_hh(hz, hw));
        uint2 lo = make_uint2(
            pack_ff(v.x - __half2float(hx), v.y - __half2float(hy)),
            pack_ff(v.z - __half2float(hz), v.w - __half2float(hw)));
        *(uint2*)(sAhi + r * PS1 + 2 * c4) = hi;
        *(uint2*)(sAlo + r * PS1 + 2 * c4) = lo;
    }
    __syncthreads();

    float* outs[4] = {p0, p1, p2, p3};
    const uint4* frag4 = (const uint4*)frag;

    #pragma unroll
    for (int pass = 0; pass < 2; ++pass) {
        float c[4][4][4];
        #pragma unroll
        for (int m = 0; m < 4; ++m)
            #pragma unroll
            for (int nt = 0; nt < 4; ++nt)
                #pragma unroll
                for (int q = 0; q < 4; ++q) c[m][nt][q] = 0.f;

        #pragma unroll 2
        for (int ks = 0; ks < 8; ++ks) {
            int kp = ks * 8 + ak;
            uint32_t ah[4], al[4];
            ah[0] = sAhi[ar * PS1 + kp];
            ah[1] = sAhi[(ar + 8) * PS1 + kp];
            ah[2] = sAhi[ar * PS1 + kp + 4];
            ah[3] = sAhi[(ar + 8) * PS1 + kp + 4];
            al[0] = sAlo[ar * PS1 + kp];
            al[1] = sAlo[(ar + 8) * PS1 + kp];
            al[2] = sAlo[ar * PS1 + kp + 4];
            al[3] = sAlo[(ar + 8) * PS1 + kp + 4];
            #pragma unroll
            for (int m = 0; m < 4; ++m) {
                const uint4* Bm = frag4 + (size_t)m * 4096;
                #pragma unroll
                for (int nt = 0; nt < 4; ++nt) {
                    int ntile = pass * 8 + cg * 4 + nt;
                    uint4 v = __ldg(Bm + (size_t)(ntile * 8 + ks) * 32 + lane);
                    mma_f16(c[m][nt], ah, v.x, v.y);   // hi*hi
                    mma_f16(c[m][nt], al, v.x, v.y);   // lo*hi
                    mma_f16(c[m][nt], ah, v.z, v.w);   // hi*lo
                }
            }
        }
        int rowA = g0 + ar, rowB = g0 + ar + 8;
        #pragma unroll
        for (int m = 0; m < 4; ++m) {
            float* out = outs[m];
            #pragma unroll
            for (int nt = 0; nt < 4; ++nt) {
                int col = (pass * 8 + cg * 4 + nt) * 8 + 2 * ak;
                if (rowA < nRows)
                    *(float2*)&out[(size_t)rowA * H_DIM + col] =
                        make_float2(c[m][nt][0], c[m][nt][1]);
                if (rowB < nRows)
                    *(float2*)&out[(size_t)rowB * H_DIM + col] =
                        make_float2(c[m][nt][2], c[m][nt][3]);
            }
        }
    }
}

// ---------------------------------------------------------------------------
// edge_mma_kernel: merged dirs; fp16 hi-only pos GEMM; smem ~39KB.
// ---------------------------------------------------------------------------
struct EdgeDir {
    const float* pre_a; const float* pre_b;
    const int* ei; const float* deg;
    const float* w1; const float* b1;
    const uint32_t* CpFrag; const float* bpc;
    const float* wp2; const float* bp2;
    float* hacc; float* einv;
};
struct EdgeParams { EdgeDir d[2]; };

__global__ void __launch_bounds__(256, 4)
edge_mma_kernel(EdgeParams P, const float* __restrict__ pos,
                float* __restrict__ pos_upd, int nE, int N)
{
    extern __shared__ uint32_t smu[];
    uint32_t* sHid = smu;                       // [128][68] fp16x2 pairs
    float* s_w1c = (float*)(smu + 128 * PS1);
    float* s_b1  = s_w1c + 128;
    float* s_bpc = s_b1 + 128;
    float* s_wp2 = s_bpc + 128;
    float* s_rel = s_wp2 + 128;                 // [128*3]
    float* s_dist= s_rel + 384;
    float* s_inv = s_dist + 128;
    float* s_p   = s_inv + 128;                 // [128]
    int*   s_src = (int*)(s_p + 128);
    int*   s_dst = s_src + 128;

    const EdgeDir& D = P.d[blockIdx.z];
    const int tid  = threadIdx.x;
    const int wid  = tid >> 5;
    const int lane = tid & 31;
    const int b    = blockIdx.y;
    const int e0   = blockIdx.x * TEC;
    const size_t bN = (size_t)b * N;

    if (tid < TEC) {
        int e = e0 + tid;
        int s = 0, d = 0;
        float x0 = 0.f, x1 = 0.f, x2 = 0.f, dist = 0.f, inv = 0.f;
        if (e < nE) {
            s = D.ei[e];
            d = D.ei[nE + e];
            const float* ps = pos + (bN + s) * 3;
            const float* pd = pos + (bN + d) * 3;
            x0 = ps[0] - pd[0];
            x1 = ps[1] - pd[1];
            x2 = ps[2] - pd[2];
            dist = sqrtf(x0 * x0 + x1 * x1 + x2 * x2);
            inv  = 1.0f / fmaxf(D.deg[d], 1.0f);
        }
        s_src[tid] = s; s_dst[tid] = d;
        s_rel[tid * 3 + 0] = x0; s_rel[tid * 3 + 1] = x1; s_rel[tid * 3 + 2] = x2;
        s_dist[tid] = dist; s_inv[tid] = inv;
        s_w1c[tid] = D.w1[256 * H_DIM + tid];
        s_b1[tid]  = D.b1[tid];
        s_bpc[tid] = D.bpc[tid];
        s_wp2[tid] = D.wp2[tid];
    }
    __syncthreads();

    // gather -> hidden (fp32, exact for hacc) -> fp16 pairs in sHid
    #pragma unroll
    for (int p = 0; p < 16; p += 4) {
        float4 va[4], vb[4];
        #pragma unroll
        for (int q = 0; q < 4; ++q) {
            int r = (p + q) * 8 + wid;
            va[q] = __ldg((const float4*)D.pre_a + (bN + s_src[r]) * 32 + lane);
            vb[q] = __ldg((const float4*)D.pre_b + (bN + s_dst[r]) * 32 + lane);
        }
        #pragma unroll
        for (int q = 0; q < 4; ++q) {
            int r = (p + q) * 8 + wid;
            float dd = s_dist[r], inv = s_inv[r];
            float4 wc = *(const float4*)(s_w1c + lane * 4);
            float4 bb = *(const float4*)(s_b1 + lane * 4);
            float h0 = silu_f(va[q].x + vb[q].x + dd * wc.x + bb.x);
            float h1 = silu_f(va[q].y + vb[q].y + dd * wc.y + bb.y);
            float h2 = silu_f(va[q].z + vb[q].z + dd * wc.z + bb.z);
            float h3 = silu_f(va[q].w + vb[q].w + dd * wc.w + bb.w);
            *(uint2*)(sHid + r * PS1 + 2 * lane) =
                make_uint2(pack_ff(h0, h1), pack_ff(h2, h3));
            float* gp = D.hacc + (bN + s_dst[r]) * H_DIM + lane * 4;
            asm volatile("red.global.add.v4.f32 [%0], {%1, %2, %3, %4};"
                         :: "l"(gp), "f"(h0 * inv), "f"(h1 * inv),
                            "f"(h2 * inv), "f"(h3 * inv) : "memory");
        }
    }
    if (tid < TEC && b == 0 && (e0 + tid) < nE)
        atomicAdd(&D.einv[s_dst[tid]], s_inv[tid]);
    __syncthreads();

    const int ar = wid * 16 + (lane >> 2);
    const int ak = lane & 3;
    float sum0 = 0.f, sum1 = 0.f;
    const uint4* Cp4 = (const uint4*)D.CpFrag;

    #pragma unroll
    for (int pass = 0; pass < 2; ++pass) {
        float c[8][4];
        #pragma unroll
        for (int nt = 0; nt < 8; ++nt)
            #pragma unroll
            for (int q = 0; q < 4; ++q) c[nt][q] = 0.f;

        #pragma unroll 4
        for (int ks = 0; ks < 8; ++ks) {
            uint32_t a[4];
            int kp = ks * 8 + ak;
            a[0] = sHid[ar * PS1 + kp];
            a[1] = sHid[(ar + 8) * PS1 + kp];
            a[2] = sHid[ar * PS1 + kp + 4];
            a[3] = sHid[(ar + 8) * PS1 + kp + 4];
            #pragma unroll
            for (int ntp = 0; ntp < 4; ++ntp) {
                uint4 bv = __ldg(Cp4 + (size_t)pass * 1024
                                 + (size_t)(ks * 4 + ntp) * 32 + lane);
                mma_f16(c[2 * ntp],     a, bv.x, bv.y);
                mma_f16(c[2 * ntp + 1], a, bv.z, bv.w);
            }
        }
        #pragma unroll
        for (int nt = 0; nt < 8; ++nt) {
            int cb = pass * 64 + nt * 8 + 2 * ak;
            float w0 = s_wp2[cb], w1v = s_wp2[cb + 1];
            float q0 = s_bpc[cb], q1 = s_bpc[cb + 1];
            sum0 += silu_f(c[nt][0] + q0) * w0 + silu_f(c[nt][1] + q1) * w1v;
            sum1 += silu_f(c[nt][2] + q0) * w0 + silu_f(c[nt][3] + q1) * w1v;
        }
    }

    sum0 += __shfl_xor_sync(0xFFFFFFFFu, sum0, 1);
    sum0 += __shfl_xor_sync(0xFFFFFFFFu, sum0, 2);
    sum1 += __shfl_xor_sync(0xFFFFFFFFu, sum1, 1);
    sum1 += __shfl_xor_sync(0xFFFFFFFFu, sum1, 2);
    if ((lane & 3) == 0) {
        s_p[ar]     = sum0;
        s_p[ar + 8] = sum1;
    }
    __syncthreads();

    if (tid < TEC && (e0 + tid) < nE) {
        float w = tanhf(s_p[tid] + D.bp2[0]);
        int d = s_dst[tid];
        float* pp = pos_upd + (bN + d) * 3;
        atomicAdd(&pp[0], w * s_rel[tid * 3 + 0]);
        atomicAdd(&pp[1], w * s_rel[tid * 3 + 1]);
        atomicAdd(&pp[2], w * s_rel[tid * 3 + 2]);
    }
}

// ---------------------------------------------------------------------------
// node2_mma_kernel: split-fp16 node update
// ---------------------------------------------------------------------------
__global__ void __launch_bounds__(256)
node2_mma_kernel(const float* __restrict__ feat,
                 const float* __restrict__ hacc0, const float* __restrict__ hacc1,
                 const uint32_t* __restrict__ nodeFrag,
                 const float* __restrict__ einv0, const float* __restrict__ einv1,
                 const float* __restrict__ bcu0, const float* __restrict__ bcu1,
                 const float* __restrict__ bu1,  const float* __restrict__ bu2,
                 float* __restrict__ outf, int N, int nRows)
{
    extern __shared__ uint32_t smu[];
    uint32_t* sAhi = smu;                   // [64][68]
    uint32_t* sAlo = sAhi + 64 * PS1;
    float* s_eU   = (float*)(smu + 2 * 64 * PS1);   // [64]
    float* s_eD   = s_eU + 64;
    float* s_bias = s_eD + 64;              // 4*128

    const int tid = threadIdx.x;
    const int wid = tid >> 5, lane = tid & 31;
    const int rg = wid & 3, cg = wid >> 2;
    const int ar = rg * 16 + (lane >> 2);
    const int ak = lane & 3;
    const int g0 = blockIdx.x * 64;

    if (tid < 64) {
        int g = g0 + tid;
        float eu = 0.f, ed = 0.f;
        if (g < nRows) {
            int node = g % N;
            eu = einv0[node];
            ed = einv1[node];
        }
        s_eU[tid] = eu; s_eD[tid] = ed;
    }
    if (tid < 128) {
        s_bias[tid]       = bu1[tid];
        s_bias[128 + tid] = bcu0[tid];
        s_bias[256 + tid] = bcu1[tid];
        s_bias[384 + tid] = bu2[tid];
    }

    float c[2][4][4];
    #pragma unroll
    for (int p = 0; p < 2; ++p)
        #pragma unroll
        for (int nt = 0; nt < 4; ++nt)
            #pragma unroll
            for (int q = 0; q < 4; ++q) c[p][nt][q] = 0.f;

    for (int m = 0; m < 3; ++m) {
        const float* src = (m == 0) ? feat : (m == 1) ? hacc0 : hacc1;
        __syncthreads();
        #pragma unroll
        for (int p = 0; p < 8; ++p) {
            int idx = p * 256 + tid;
            int r = idx >> 5, c4 = idx & 31;
            float4 v = make_float4(0.f, 0.f, 0.f, 0.f);
            if (g0 + r < nRows)
                v = __ldg((const float4*)src + (size_t)(g0 + r) * 32 + c4);
            __half hx = __float2half_rn(v.x), hy = __float2half_rn(v.y);
            __half hz = __float2half_rn(v.z), hw = __float2half_rn(v.w);
            *(uint2*)(sAhi + r * PS1 + 2 * c4) =
                make_uint2(pack_hh(hx, hy), pack_hh(hz, hw));
            *(uint2*)(sAlo + r * PS1 + 2 * c4) = make_uint2(
                pack_ff(v.x - __half2float(hx), v.y - __half2float(hy)),
                pack_ff(v.z - __half2float(hz), v.w - __half2float(hw)));
        }
        __syncthreads();

        const uint4* Bm = (const uint4*)(nodeFrag + (size_t)m * 16384);
        #pragma unroll 2
        for (int ks = 0; ks < 8; ++ks) {
            int kp = ks * 8 + ak;
            uint32_t ah[4], al[4];
            ah[0] = sAhi[ar * PS1 + kp];
            ah[1] = sAhi[(ar + 8) * PS1 + kp];
            ah[2] = sAhi[ar * PS1 + kp + 4];
            ah[3] = sAhi[(ar + 8) * PS1 + kp + 4];
            al[0] = sAlo[ar * PS1 + kp];
            al[1] = sAlo[(ar + 8) * PS1 + kp];
            al[2] = sAlo[ar * PS1 + kp + 4];
            al[3] = sAlo[(ar + 8) * PS1 + kp + 4];
            #pragma unroll
            for (int pass = 0; pass < 2; ++pass) {
                #pragma unroll
                for (int nt = 0; nt < 4; ++nt) {
                    int ntile = pass * 8 + cg * 4 + nt;
                    uint4 v = __ldg(Bm + (size_t)(ntile * 8 + ks) * 32 + lane);
                    mma_f16(c[pass][nt], ah, v.x, v.y);
                    mma_f16(c[pass][nt], al, v.x, v.y);
                    mma_f16(c[pass][nt], ah, v.z, v.w);
                }
            }
        }
    }
    __syncthreads();
    // bias + silu -> hi/lo of h1 back into sAhi/sAlo (paired columns)
    {
        float eu0 = s_eU[ar],     ed0 = s_eD[ar];
        float eu1 = s_eU[ar + 8], ed1 = s_eD[ar + 8];
        #pragma unroll
        for (int pass = 0; pass < 2; ++pass) {
            #pragma unroll
            for (int nt = 0; nt < 4; ++nt) {
                int col = (pass * 8 + cg * 4 + nt) * 8 + 2 * ak;
                int kp  = col >> 1;
                float bA = s_bias[col],        bB = s_bias[col + 1];
                float cA0 = s_bias[128 + col], cA1 = s_bias[128 + col + 1];
                float cB0 = s_bias[256 + col], cB1 = s_bias[256 + col + 1];
                float v00 = silu_f(c[pass][nt][0] + bA + eu0 * cA0 + ed0 * cB0);
                float v01 = silu_f(c[pass][nt][1] + bB + eu0 * cA1 + ed0 * cB1);
                float v10 = silu_f(c[pass][nt][2] + bA + eu1 * cA0 + ed1 * cB0);
                float v11 = silu_f(c[pass][nt][3] + bB + eu1 * cA1 + ed1 * cB1);
                __half h00 = __float2half_rn(v00), h01 = __float2half_rn(v01);
                __half h10 = __float2half_rn(v10), h11 = __float2half_rn(v11);
                sAhi[ar * PS1 + kp]       = pack_hh(h00, h01);
                sAhi[(ar + 8) * PS1 + kp] = pack_hh(h10, h11);
                sAlo[ar * PS1 + kp] = pack_ff(
                    v00 - __half2float(h00), v01 - __half2float(h01));
                sAlo[(ar + 8) * PS1 + kp] = pack_ff(
                    v10 - __half2float(h10), v11 - __half2float(h11));
            }
        }
    }
    __syncthreads();

    #pragma unroll
    for (int p = 0; p < 2; ++p)
        #pragma unroll
        for (int nt = 0; nt < 4; ++nt)
            #pragma unroll
            for (int q = 0; q < 4; ++q) c[p][nt][q] = 0.f;

    {
        const uint4* Bm = (const uint4*)(nodeFrag + (size_t)3 * 16384);
        #pragma unroll 2
        for (int ks = 0; ks < 8; ++ks) {
            int kp = ks * 8 + ak;
            uint32_t ah[4], al[4];
            ah[0] = sAhi[ar * PS1 + kp];
            ah[1] = sAhi[(ar + 8) * PS1 + kp];
            ah[2] = sAhi[ar * PS1 + kp + 4];
            ah[3] = sAhi[(ar + 8) * PS1 + kp + 4];
            al[0] = sAlo[ar * PS1 + kp];
            al[1] = sAlo[(ar + 8) * PS1 + kp];
            al[2] = sAlo[ar * PS1 + kp + 4];
            al[3] = sAlo[(ar + 8) * PS1 + kp + 4];
            #pragma unroll
            for (int pass = 0; pass < 2; ++pass) {
                #pragma unroll
                for (int nt = 0; nt < 4; ++nt) {
                    int ntile = pass * 8 + cg * 4 + nt;
                    uint4 v = __ldg(Bm + (size_t)(ntile * 8 + ks) * 32 + lane);
                    mma_f16(c[pass][nt], ah, v.x, v.y);
                    mma_f16(c[pass][nt], al, v.x, v.y);
                    mma_f16(c[pass][nt], ah, v.z, v.w);
                }
            }
        }
    }
    {
        int gA = g0 + ar, gB = g0 + ar + 8;
        #pragma unroll
        for (int pass = 0; pass < 2; ++pass) {
            #pragma unroll
            for (int nt = 0; nt < 4; ++nt) {
                int col = (pass * 8 + cg * 4 + nt) * 8 + 2 * ak;
                float bA = s_bias[384 + col], bB = s_bias[384 + col + 1];
                if (gA < nRows) {
                    size_t o = (size_t)gA * H_DIM + col;
                    float2 f = *(const float2*)&feat[o];
                    *(float2*)&outf[o] = make_float2(
                        f.x + c[pass][nt][0] + bA, f.y + c[pass][nt][1] + bB);
                }
                if (gB < nRows) {
                    size_t o = (size_t)gB * H_DIM + col;
                    float2 f = *(const float2*)&feat[o];
                    *(float2*)&outf[o] = make_float2(
                        f.x + c[pass][nt][2] + bA, f.y + c[pass][nt][3] + bB);
                }
            }
        }
    }
}

__global__ void pos_kernel(const float* __restrict__ pos,
                           const float* __restrict__ pos_upd,
                           float* __restrict__ out, int n)
{
    int i = blockIdx.x * blockDim.x + threadIdx.x;
    if (i < n) out[i] = pos[i] + 0.5f * pos_upd[i];
}

extern "C" void kernel_launch(void* const* d_in, const int* in_sizes, int n_in,
                              void* d_out, int out_size)
{
    const float* feat   = (const float*)d_in[0];
    const float* pos    = (const float*)d_in[1];
    const int*   ei_up  = (const int*)d_in[2];
    const int*   ei_dn  = (const int*)d_in[3];
    const float* deg_up = (const float*)d_in[4];
    const float* deg_dn = (const float*)d_in[5];

    const float* w1u  = (const float*)d_in[6];
    const float* b1u  = (const float*)d_in[7];
    const float* w2u  = (const float*)d_in[8];
    const float* b2u  = (const float*)d_in[9];
    const float* wp1u = (const float*)d_in[10];
    const float* bp1u = (const float*)d_in[11];
    const float* wp2u = (const float*)d_in[12];
    const float* bp2u = (const float*)d_in[13];

    const float* w1d  = (const float*)d_in[14];
    const float* b1d  = (const float*)d_in[15];
    const float* w2d  = (const float*)d_in[16];
    const float* b2d  = (const float*)d_in[17];
    const float* wp1d = (const float*)d_in[18];
    const float* bp1d = (const float*)d_in[19];
    const float* wp2d = (const float*)d_in[20];
    const float* bp2d = (const float*)d_in[21];

    const float* wu1 = (const float*)d_in[22];
    const float* bu1 = (const float*)d_in[23];
    const float* wu2 = (const float*)d_in[24];
    const float* bu2 = (const float*)d_in[25];

    int E = in_sizes[2] / 2;
    int N = in_sizes[4];
    int B = in_sizes[0] / (N * H_DIM);
    int nRows = B * N;

    float *pre, *hacc, *einv, *pos_upd, *bpc, *bcu;
    uint32_t *CpFrag, *preFrag, *nodeFrag;
    cudaGetSymbolAddress((void**)&pre,      g_pre);
    cudaGetSymbolAddress((void**)&hacc,     g_hacc);
    cudaGetSymbolAddress((void**)&einv,     g_einv);
    cudaGetSymbolAddress((void**)&pos_upd,  g_pos_upd);
    cudaGetSymbolAddress((void**)&CpFrag,   g_CpFrag);
    cudaGetSymbolAddress((void**)&bpc,      g_bpc);
    cudaGetSymbolAddress((void**)&bcu,      g_bcu);
    cudaGetSymbolAddress((void**)&preFrag,  g_preFrag);
    cudaGetSymbolAddress((void**)&nodeFrag, g_nodeFrag);

    const size_t PS = (size_t)MAX_BN * H_DIM;
    float* pre_au = pre;
    float* pre_bu = pre + PS;
    float* pre_ad = pre + 2 * PS;
    float* pre_bd = pre + 3 * PS;
    float* hacc_u = hacc;
    float* hacc_d = hacc + PS;
    float* einv_u = einv;
    float* einv_d = einv + MAX_N;

    cudaMemsetAsync(hacc, 0, 2 * PS * sizeof(float));
    cudaMemsetAsync(einv, 0, 2 * MAX_N * sizeof(float));
    cudaMemsetAsync(pos_upd, 0, (size_t)nRows * 3 * sizeof(float));

    int smemPre  = 2 * 64 * PS1 * 4;                           // 34816 B
    int smemEdge = 128 * PS1 * 4
                 + (512 + 384 + 128 + 128 + 128) * 4 + 256 * 4; // 41216 B
    int smemNode = (2 * 64 * PS1 + 128 + 512) * 4;             // 37376 B
    cudaFuncSetAttribute(pre_mma_kernel,
                         cudaFuncAttributeMaxDynamicSharedMemorySize, smemPre);
    cudaFuncSetAttribute(edge_mma_kernel,
                         cudaFuncAttributeMaxDynamicSharedMemorySize, smemEdge);
    cudaFuncSetAttribute(node2_mma_kernel,
                         cudaFuncAttributeMaxDynamicSharedMemorySize, smemNode);

    combine_kernel<<<dim3(65, 4), H_DIM>>>(
        w2u, wp1u, b2u, bp1u, w2d, wp1d, b2d, bp1d, wu1,
        CpFrag, nodeFrag, bpc, bcu);

    fragw_kernel<<<dim3(64, 6), H_DIM>>>(w1u, w1d, wu1, wu2,
                                         preFrag, nodeFrag);

    pre_mma_kernel<<<(nRows + 63) / 64, 256, smemPre>>>(
        feat, preFrag, pre_au, pre_bu, pre_ad, pre_bd, nRows);

    EdgeParams EP;
    EP.d[0] = { pre_au, pre_bu, ei_up, deg_up, w1u, b1u,
                CpFrag,        bpc,         wp2u, bp2u, hacc_u, einv_u };
    EP.d[1] = { pre_ad, pre_bd, ei_dn, deg_dn, w1d, b1d,
                CpFrag + 8192, bpc + H_DIM, wp2d, bp2d, hacc_d, einv_d };

    dim3 egrid((E + TEC - 1) / TEC, B, 2);
    edge_mma_kernel<<<egrid, 256, smemEdge>>>(EP, pos, pos_upd, E, N);

    node2_mma_kernel<<<(nRows + 63) / 64, 256, smemNode>>>(
        feat, hacc_u, hacc_d, nodeFrag, einv_u, einv_d,
        bcu, bcu + H_DIM, bu1, bu2, (float*)d_out, N, nRows);

    size_t featN = (size_t)nRows * H_DIM;
    int pn = nRows * 3;
    pos_kernel<<<(pn + 255) / 256, 256>>>(
        pos, pos_upd, (float*)d_out + featN, pn);
}

// round 11
// speedup vs baseline: 10.1348x; 1.3607x over previous
#include <cuda_runtime.h>
#include <cuda_fp16.h>
#include <math.h>
#include <cstdint>

#define H_DIM 128
#define TEC 128        // edges per block (edge kernel)
#define PS1 68         // pair-row stride (uint32 units) for fp16x2 tiles

#define MAX_B 2
#define MAX_N 20000
#define MAX_BN (MAX_B * MAX_N)

// ---------------------------------------------------------------------------
// Scratch (allocation-free rule: __device__ globals)
// ---------------------------------------------------------------------------
__device__ __align__(128) float g_pre[4][(size_t)MAX_BN * H_DIM];
__device__ __align__(128) float g_hacc[2][(size_t)MAX_BN * H_DIM];
__device__ __align__(128) float g_einv[2][MAX_N];
__device__ __align__(128) float g_pos_upd[(size_t)MAX_BN * 3];
__device__ __align__(128) uint32_t g_CpFrag[2][8192];     // fp16 hi, paired-ntile uint4 layout
__device__ __align__(128) float g_bpc[2][H_DIM];
__device__ __align__(128) float g_bcu[2][H_DIM];
__device__ __align__(128) uint32_t g_preFrag[4][16384];   // fp16 hi/lo uint4 layout
__device__ __align__(128) uint32_t g_nodeFrag[4][16384];  // wu1top,Cu0,Cu1,wu2

__device__ __forceinline__ float silu_f(float v) {
    return __fdividef(v, 1.0f + __expf(-v));
}

// ---- fp16 mma.sync helpers --------------------------------------------------
__device__ __forceinline__ void mma_f16(float c[4], const uint32_t a[4],
                                        uint32_t b0, uint32_t b1) {
    asm volatile(
        "mma.sync.aligned.m16n8k16.row.col.f32.f16.f16.f32 "
        "{%0,%1,%2,%3}, {%4,%5,%6,%7}, {%8,%9}, {%0,%1,%2,%3};"
        : "+f"(c[0]), "+f"(c[1]), "+f"(c[2]), "+f"(c[3])
        : "r"(a[0]), "r"(a[1]), "r"(a[2]), "r"(a[3]), "r"(b0), "r"(b1));
}
__device__ __forceinline__ uint32_t pack_hh(__half lo, __half hi) {
    __half2 h = __halves2half2(lo, hi);
    return *reinterpret_cast<uint32_t*>(&h);
}
__device__ __forceinline__ uint32_t pack_ff(float e, float o) {
    __half2 h = __floats2half2_rn(e, o);
    return *reinterpret_cast<uint32_t*>(&h);
}

// ---------------------------------------------------------------------------
// combine_kernel: grid (65, 4), 128 thr.
// ---------------------------------------------------------------------------
__global__ void combine_kernel(
    const float* __restrict__ w2u, const float* __restrict__ wp1u,
    const float* __restrict__ b2u, const float* __restrict__ bp1u,
    const float* __restrict__ w2d, const float* __restrict__ wp1d,
    const float* __restrict__ b2d, const float* __restrict__ bp1d,
    const float* __restrict__ wu1,
    uint32_t* __restrict__ CpFrag, uint32_t* __restrict__ nodeFrag,
    float* __restrict__ bpc, float* __restrict__ bcu)
{
    const float* wu1b = wu1 + 128 * H_DIM;
    const float* A; const float* Bm; const float* bvec; const float* badd;
    uint32_t* C; float* bout; bool split;
    switch (blockIdx.y) {
        case 0:  A = w2u; Bm = wp1u; bvec = b2u; badd = bp1u;
                 C = CpFrag;               bout = bpc;         split = false; break;
        case 1:  A = w2d; Bm = wp1d; bvec = b2d; badd = bp1d;
                 C = CpFrag + 8192;        bout = bpc + H_DIM; split = false; break;
        case 2:  A = w2u; Bm = wu1b; bvec = b2u; badd = 0;
                 C = nodeFrag + 1 * 16384; bout = bcu;         split = true;  break;
        default: A = w2d; Bm = wu1b; bvec = b2d; badd = 0;
                 C = nodeFrag + 2 * 16384; bout = bcu + H_DIM; split = true;  break;
    }
    int i2 = blockIdx.x;
    int j  = threadIdx.x;
    if (i2 == 64) {
        float s = 0.f;
        #pragma unroll 8
        for (int k = 0; k < H_DIM; ++k) s += bvec[k] * Bm[k * H_DIM + j];
        bout[j] = s + (badd ? badd[j] : 0.f);
        return;
    }
    float s0 = 0.f, s1 = 0.f;
    const float* a0r = A + (size_t)(2 * i2) * H_DIM;
    const float* a1r = a0r + H_DIM;
    #pragma unroll 8
    for (int k = 0; k < H_DIM; ++k) {
        float b = Bm[k * H_DIM + j];
        s0 += a0r[k] * b;
        s1 += a1r[k] * b;
    }
    int ks = i2 >> 3, m = i2 & 7;
    int lanep = m & 3, reg = m >> 2;
    int nn = j & 7;
    if (split) {
        __half h0 = __float2half_rn(s0), h1 = __float2half_rn(s1);
        __half l0 = __float2half_rn(s0 - __half2float(h0));
        __half l1 = __float2half_rn(s1 - __half2float(h1));
        int ntile = j >> 3;
        size_t base = ((size_t)(ntile * 8 + ks) * 32 + nn * 4 + lanep) * 4;
        C[base + reg]     = pack_hh(h0, h1);
        C[base + 2 + reg] = pack_hh(l0, l1);
    } else {
        int ntile = j >> 3, pass = ntile >> 3, ntl = ntile & 7;
        size_t idx = (size_t)pass * 4096
                   + ((size_t)(ks * 4 + (ntl >> 1)) * 32 + nn * 4 + lanep) * 4
                   + (ntl & 1) * 2 + reg;
        C[idx] = pack_ff(s0, s1);
    }
}

// ---------------------------------------------------------------------------
// fragw_kernel: grid (64, 6), 128 thr.
// ---------------------------------------------------------------------------
__global__ void fragw_kernel(const float* __restrict__ w1u,
                             const float* __restrict__ w1d,
                             const float* __restrict__ wu1,
                             const float* __restrict__ wu2,
                             uint32_t* __restrict__ preFrag,
                             uint32_t* __restrict__ nodeFrag)
{
    int y = blockIdx.y;
    const float* W; uint32_t* out;
    switch (y) {
        case 0: W = w1u;                out = preFrag;              break;
        case 1: W = w1u + 128 * H_DIM;  out = preFrag + 16384;      break;
        case 2: W = w1d;                out = preFrag + 2 * 16384;  break;
        case 3: W = w1d + 128 * H_DIM;  out = preFrag + 3 * 16384;  break;
        case 4: W = wu1;                out = nodeFrag;             break;
        default: W = wu2;               out = nodeFrag + 3 * 16384; break;
    }
    int i2 = blockIdx.x;
    int j  = threadIdx.x;
    float x0 = W[(size_t)(2 * i2) * H_DIM + j];
    float x1 = W[(size_t)(2 * i2 + 1) * H_DIM + j];
    __half h0 = __float2half_rn(x0), h1 = __float2half_rn(x1);
    __half l0 = __float2half_rn(x0 - __half2float(h0));
    __half l1 = __float2half_rn(x1 - __half2float(h1));
    int ks = i2 >> 3, m = i2 & 7;
    int lanep = m & 3, reg = m >> 2;
    int ntile = j >> 3, nn = j & 7;
    size_t base = ((size_t)(ntile * 8 + ks) * 32 + nn * 4 + lanep) * 4;
    out[base + reg]     = pack_hh(h0, h1);
    out[base + 2 + reg] = pack_hh(l0, l1);
}

// ---------------------------------------------------------------------------
// pre_mma_kernel: 128-row blocks. Warps 0-3 -> matrices {0,1}, warps 4-7 ->
// matrices {2,3}. Each warp owns 32 rows (two 16-row tiles) and all 16
// ntiles: every B fragment load feeds 2 mmas and 2x fewer redundant copies.
// ---------------------------------------------------------------------------
__global__ void __launch_bounds__(256)
pre_mma_kernel(const float* __restrict__ feat, const uint32_t* __restrict__ frag,
               float* __restrict__ p0, float* __restrict__ p1,
               float* __restrict__ p2, float* __restrict__ p3, int nRows)
{
    extern __shared__ uint32_t smu[];
    uint32_t* sAhi = smu;                  // [128][68] pairs
    uint32_t* sAlo = sAhi + 128 * PS1;

    const int tid = threadIdx.x;
    const int wid = tid >> 5, lane = tid & 31;
    const int wg = wid >> 2;               // matrix half
    const int rw = wid & 3;                // 32-row group
    const int ar = rw * 32 + (lane >> 2);
    const int ak = lane & 3;
    const int g0 = blockIdx.x * 128;

    // stage + split A once (128 rows)
    #pragma unroll
    for (int p = 0; p < 16; ++p) {
        int idx = p * 256 + tid;
        int r = idx >> 5, c4 = idx & 31;
        float4 v = make_float4(0.f, 0.f, 0.f, 0.f);
        if (g0 + r < nRows)
            v = __ldg((const float4*)feat + (size_t)(g0 + r) * 32 + c4);
        __half hx = __float2half_rn(v.x), hy = __float2half_rn(v.y);
        __half hz = __float2half_rn(v.z), hw = __float2half_rn(v.w);
        *(uint2*)(sAhi + r * PS1 + 2 * c4) =
            make_uint2(pack_hh(hx, hy), pack_hh(hz, hw));
        *(uint2*)(sAlo + r * PS1 + 2 * c4) = make_uint2(
            pack_ff(v.x - __half2float(hx), v.y - __half2float(hy)),
            pack_ff(v.z - __half2float(hz), v.w - __half2float(hw)));
    }
    __syncthreads();

    float* outs[4] = {p0, p1, p2, p3};

    #pragma unroll
    for (int m2 = 0; m2 < 2; ++m2) {
        int m = wg * 2 + m2;
        const uint4* Bm = (const uint4*)frag + (size_t)m * 4096;
        float* out = outs[m];
        #pragma unroll
        for (int pass = 0; pass < 2; ++pass) {
            float c[2][8][4];
            #pragma unroll
            for (int t = 0; t < 2; ++t)
                #pragma unroll
                for (int nt = 0; nt < 8; ++nt)
                    #pragma unroll
                    for (int q = 0; q < 4; ++q) c[t][nt][q] = 0.f;

            #pragma unroll 2
            for (int ks = 0; ks < 8; ++ks) {
                int kp = ks * 8 + ak;
                uint32_t ah0[4], al0[4], ah1[4], al1[4];
                ah0[0] = sAhi[ar * PS1 + kp];
                ah0[1] = sAhi[(ar + 8) * PS1 + kp];
                ah0[2] = sAhi[ar * PS1 + kp + 4];
                ah0[3] = sAhi[(ar + 8) * PS1 + kp + 4];
                al0[0] = sAlo[ar * PS1 + kp];
                al0[1] = sAlo[(ar + 8) * PS1 + kp];
                al0[2] = sAlo[ar * PS1 + kp + 4];
                al0[3] = sAlo[(ar + 8) * PS1 + kp + 4];
                ah1[0] = sAhi[(ar + 16) * PS1 + kp];
                ah1[1] = sAhi[(ar + 24) * PS1 + kp];
                ah1[2] = sAhi[(ar + 16) * PS1 + kp + 4];
                ah1[3] = sAhi[(ar + 24) * PS1 + kp + 4];
                al1[0] = sAlo[(ar + 16) * PS1 + kp];
                al1[1] = sAlo[(ar + 24) * PS1 + kp];
                al1[2] = sAlo[(ar + 16) * PS1 + kp + 4];
                al1[3] = sAlo[(ar + 24) * PS1 + kp + 4];
                #pragma unroll
                for (int nt = 0; nt < 8; ++nt) {
                    int ntile = pass * 8 + nt;
                    uint4 v = __ldg(Bm + (size_t)(ntile * 8 + ks) * 32 + lane);
                    mma_f16(c[0][nt], ah0, v.x, v.y);
                    mma_f16(c[0][nt], al0, v.x, v.y);
                    mma_f16(c[0][nt], ah0, v.z, v.w);
                    mma_f16(c[1][nt], ah1, v.x, v.y);
                    mma_f16(c[1][nt], al1, v.x, v.y);
                    mma_f16(c[1][nt], ah1, v.z, v.w);
                }
            }
            #pragma unroll
            for (int t = 0; t < 2; ++t) {
                int rowA = g0 + ar + t * 16, rowB = rowA + 8;
                #pragma unroll
                for (int nt = 0; nt < 8; ++nt) {
                    int col = (pass * 8 + nt) * 8 + 2 * ak;
                    if (rowA < nRows)
                        *(float2*)&out[(size_t)rowA * H_DIM + col] =
                            make_float2(c[t][nt][0], c[t][nt][1]);
                    if (rowB < nRows)
                        *(float2*)&out[(size_t)rowB * H_DIM + col] =
                            make_float2(c[t][nt][2], c[t][nt][3]);
                }
            }
        }
    }
}

// ---------------------------------------------------------------------------
// edge_mma_kernel: merged dirs; fp16 hi-only pos GEMM; 3 CTAs/SM (85 regs).
// ---------------------------------------------------------------------------
struct EdgeDir {
    const float* pre_a; const float* pre_b;
    const int* ei; const float* deg;
    const float* w1; const float* b1;
    const uint32_t* CpFrag; const float* bpc;
    const float* wp2; const float* bp2;
    float* hacc; float* einv;
};
struct EdgeParams { EdgeDir d[2]; };

__global__ void __launch_bounds__(256, 3)
edge_mma_kernel(EdgeParams P, const float* __restrict__ pos,
                float* __restrict__ pos_upd, int nE, int N)
{
    extern __shared__ uint32_t smu[];
    uint32_t* sHid = smu;                       // [128][68] fp16x2 pairs
    float* s_w1c = (float*)(smu + 128 * PS1);
    float* s_b1  = s_w1c + 128;
    float* s_bpc = s_b1 + 128;
    float* s_wp2 = s_bpc + 128;
    float* s_rel = s_wp2 + 128;                 // [128*3]
    float* s_dist= s_rel + 384;
    float* s_inv = s_dist + 128;
    float* s_p   = s_inv + 128;                 // [128]
    int*   s_src = (int*)(s_p + 128);
    int*   s_dst = s_src + 128;

    const EdgeDir& D = P.d[blockIdx.z];
    const int tid  = threadIdx.x;
    const int wid  = tid >> 5;
    const int lane = tid & 31;
    const int b    = blockIdx.y;
    const int e0   = blockIdx.x * TEC;
    const size_t bN = (size_t)b * N;

    if (tid < TEC) {
        int e = e0 + tid;
        int s = 0, d = 0;
        float x0 = 0.f, x1 = 0.f, x2 = 0.f, dist = 0.f, inv = 0.f;
        if (e < nE) {
            s = D.ei[e];
            d = D.ei[nE + e];
            const float* ps = pos + (bN + s) * 3;
            const float* pd = pos + (bN + d) * 3;
            x0 = ps[0] - pd[0];
            x1 = ps[1] - pd[1];
            x2 = ps[2] - pd[2];
            dist = sqrtf(x0 * x0 + x1 * x1 + x2 * x2);
            inv  = 1.0f / fmaxf(D.deg[d], 1.0f);
        }
        s_src[tid] = s; s_dst[tid] = d;
        s_rel[tid * 3 + 0] = x0; s_rel[tid * 3 + 1] = x1; s_rel[tid * 3 + 2] = x2;
        s_dist[tid] = dist; s_inv[tid] = inv;
        s_w1c[tid] = D.w1[256 * H_DIM + tid];
        s_b1[tid]  = D.b1[tid];
        s_bpc[tid] = D.bpc[tid];
        s_wp2[tid] = D.wp2[tid];
    }
    __syncthreads();

    // gather -> hidden (fp32, exact for hacc) -> fp16 pairs in sHid
    #pragma unroll
    for (int p = 0; p < 16; p += 4) {
        float4 va[4], vb[4];
        #pragma unroll
        for (int q = 0; q < 4; ++q) {
            int r = (p + q) * 8 + wid;
            va[q] = __ldg((const float4*)D.pre_a + (bN + s_src[r]) * 32 + lane);
            vb[q] = __ldg((const float4*)D.pre_b + (bN + s_dst[r]) * 32 + lane);
        }
        #pragma unroll
        for (int q = 0; q < 4; ++q) {
            int r = (p + q) * 8 + wid;
            float dd = s_dist[r], inv = s_inv[r];
            float4 wc = *(const float4*)(s_w1c + lane * 4);
            float4 bb = *(const float4*)(s_b1 + lane * 4);
            float h0 = silu_f(va[q].x + vb[q].x + dd * wc.x + bb.x);
            float h1 = silu_f(va[q].y + vb[q].y + dd * wc.y + bb.y);
            float h2 = silu_f(va[q].z + vb[q].z + dd * wc.z + bb.z);
            float h3 = silu_f(va[q].w + vb[q].w + dd * wc.w + bb.w);
            *(uint2*)(sHid + r * PS1 + 2 * lane) =
                make_uint2(pack_ff(h0, h1), pack_ff(h2, h3));
            float* gp = D.hacc + (bN + s_dst[r]) * H_DIM + lane * 4;
            asm volatile("red.global.add.v4.f32 [%0], {%1, %2, %3, %4};"
                         :: "l"(gp), "f"(h0 * inv), "f"(h1 * inv),
                            "f"(h2 * inv), "f"(h3 * inv) : "memory");
        }
    }
    if (tid < TEC && b == 0 && (e0 + tid) < nE)
        atomicAdd(&D.einv[s_dst[tid]], s_inv[tid]);
    __syncthreads();

    const int ar = wid * 16 + (lane >> 2);
    const int ak = lane & 3;
    float sum0 = 0.f, sum1 = 0.f;
    const uint4* Cp4 = (const uint4*)D.CpFrag;

    #pragma unroll
    for (int pass = 0; pass < 2; ++pass) {
        float c[8][4];
        #pragma unroll
        for (int nt = 0; nt < 8; ++nt)
            #pragma unroll
            for (int q = 0; q < 4; ++q) c[nt][q] = 0.f;

        #pragma unroll 4
        for (int ks = 0; ks < 8; ++ks) {
            uint32_t a[4];
            int kp = ks * 8 + ak;
            a[0] = sHid[ar * PS1 + kp];
            a[1] = sHid[(ar + 8) * PS1 + kp];
            a[2] = sHid[ar * PS1 + kp + 4];
            a[3] = sHid[(ar + 8) * PS1 + kp + 4];
            #pragma unroll
            for (int ntp = 0; ntp < 4; ++ntp) {
                uint4 bv = __ldg(Cp4 + (size_t)pass * 1024
                                 + (size_t)(ks * 4 + ntp) * 32 + lane);
                mma_f16(c[2 * ntp],     a, bv.x, bv.y);
                mma_f16(c[2 * ntp + 1], a, bv.z, bv.w);
            }
        }
        #pragma unroll
        for (int nt = 0; nt < 8; ++nt) {
            int cb = pass * 64 + nt * 8 + 2 * ak;
            float w0 = s_wp2[cb], w1v = s_wp2[cb + 1];
            float q0 = s_bpc[cb], q1 = s_bpc[cb + 1];
            sum0 += silu_f(c[nt][0] + q0) * w0 + silu_f(c[nt][1] + q1) * w1v;
            sum1 += silu_f(c[nt][2] + q0) * w0 + silu_f(c[nt][3] + q1) * w1v;
        }
    }

    sum0 += __shfl_xor_sync(0xFFFFFFFFu, sum0, 1);
    sum0 += __shfl_xor_sync(0xFFFFFFFFu, sum0, 2);
    sum1 += __shfl_xor_sync(0xFFFFFFFFu, sum1, 1);
    sum1 += __shfl_xor_sync(0xFFFFFFFFu, sum1, 2);
    if ((lane & 3) == 0) {
        s_p[ar]     = sum0;
        s_p[ar + 8] = sum1;
    }
    __syncthreads();

    if (tid < TEC && (e0 + tid) < nE) {
        float w = tanhf(s_p[tid] + D.bp2[0]);
        int d = s_dst[tid];
        float* pp = pos_upd + (bN + d) * 3;
        atomicAdd(&pp[0], w * s_rel[tid * 3 + 0]);
        atomicAdd(&pp[1], w * s_rel[tid * 3 + 1]);
        atomicAdd(&pp[2], w * s_rel[tid * 3 + 2]);
    }
}

// ---------------------------------------------------------------------------
// node2_mma_kernel: split-fp16 node update (unchanged from R10)
// ---------------------------------------------------------------------------
__global__ void __launch_bounds__(256)
node2_mma_kernel(const float* __restrict__ feat,
                 const float* __restrict__ hacc0, const float* __restrict__ hacc1,
                 const uint32_t* __restrict__ nodeFrag,
                 const float* __restrict__ einv0, const float* __restrict__ einv1,
                 const float* __restrict__ bcu0, const float* __restrict__ bcu1,
                 const float* __restrict__ bu1,  const float* __restrict__ bu2,
                 float* __restrict__ outf, int N, int nRows)
{
    extern __shared__ uint32_t smu[];
    uint32_t* sAhi = smu;                   // [64][68]
    uint32_t* sAlo = sAhi + 64 * PS1;
    float* s_eU   = (float*)(smu + 2 * 64 * PS1);   // [64]
    float* s_eD   = s_eU + 64;
    float* s_bias = s_eD + 64;              // 4*128

    const int tid = threadIdx.x;
    const int wid = tid >> 5, lane = tid & 31;
    const int rg = wid & 3, cg = wid >> 2;
    const int ar = rg * 16 + (lane >> 2);
    const int ak = lane & 3;
    const int g0 = blockIdx.x * 64;

    if (tid < 64) {
        int g = g0 + tid;
        float eu = 0.f, ed = 0.f;
        if (g < nRows) {
            int node = g % N;
            eu = einv0[node];
            ed = einv1[node];
        }
        s_eU[tid] = eu; s_eD[tid] = ed;
    }
    if (tid < 128) {
        s_bias[tid]       = bu1[tid];
        s_bias[128 + tid] = bcu0[tid];
        s_bias[256 + tid] = bcu1[tid];
        s_bias[384 + tid] = bu2[tid];
    }

    float c[2][4][4];
    #pragma unroll
    for (int p = 0; p < 2; ++p)
        #pragma unroll
        for (int nt = 0; nt < 4; ++nt)
            #pragma unroll
            for (int q = 0; q < 4; ++q) c[p][nt][q] = 0.f;

    for (int m = 0; m < 3; ++m) {
        const float* src = (m == 0) ? feat : (m == 1) ? hacc0 : hacc1;
        __syncthreads();
        #pragma unroll
        for (int p = 0; p < 8; ++p) {
            int idx = p * 256 + tid;
            int r = idx >> 5, c4 = idx & 31;
            float4 v = make_float4(0.f, 0.f, 0.f, 0.f);
            if (g0 + r < nRows)
                v = __ldg((const float4*)src + (size_t)(g0 + r) * 32 + c4);
            __half hx = __float2half_rn(v.x), hy = __float2half_rn(v.y);
            __half hz = __float2half_rn(v.z), hw = __float2half_rn(v.w);
            *(uint2*)(sAhi + r * PS1 + 2 * c4) =
                make_uint2(pack_hh(hx, hy), pack_hh(hz, hw));
            *(uint2*)(sAlo + r * PS1 + 2 * c4) = make_uint2(
                pack_ff(v.x - __half2float(hx), v.y - __half2float(hy)),
                pack_ff(v.z - __half2float(hz), v.w - __half2float(hw)));
        }
        __syncthreads();

        const uint4* Bm = (const uint4*)(nodeFrag + (size_t)m * 16384);
        #pragma unroll 2
        for (int ks = 0; ks < 8; ++ks) {
            int kp = ks * 8 + ak;
            uint32_t ah[4], al[4];
            ah[0] = sAhi[ar * PS1 + kp];
            ah[1] = sAhi[(ar + 8) * PS1 + kp];
            ah[2] = sAhi[ar * PS1 + kp + 4];
            ah[3] = sAhi[(ar + 8) * PS1 + kp + 4];
            al[0] = sAlo[ar * PS1 + kp];
            al[1] = sAlo[(ar + 8) * PS1 + kp];
            al[2] = sAlo[ar * PS1 + kp + 4];
            al[3] = sAlo[(ar + 8) * PS1 + kp + 4];
            #pragma unroll
            for (int pass = 0; pass < 2; ++pass) {
                #pragma unroll
                for (int nt = 0; nt < 4; ++nt) {
                    int ntile = pass * 8 + cg * 4 + nt;
                    uint4 v = __ldg(Bm + (size_t)(ntile * 8 + ks) * 32 + lane);
                    mma_f16(c[pass][nt], ah, v.x, v.y);
                    mma_f16(c[pass][nt], al, v.x, v.y);
                    mma_f16(c[pass][nt], ah, v.z, v.w);
                }
            }
        }
    }
    __syncthreads();
    {
        float eu0 = s_eU[ar],     ed0 = s_eD[ar];
        float eu1 = s_eU[ar + 8], ed1 = s_eD[ar + 8];
        #pragma unroll
        for (int pass = 0; pass < 2; ++pass) {
            #pragma unroll
            for (int nt = 0; nt < 4; ++nt) {
                int col = (pass * 8 + cg * 4 + nt) * 8 + 2 * ak;
                int kp  = col >> 1;
                float bA = s_bias[col],        bB = s_bias[col + 1];
                float cA0 = s_bias[128 + col], cA1 = s_bias[128 + col + 1];
                float cB0 = s_bias[256 + col], cB1 = s_bias[256 + col + 1];
                float v00 = silu_f(c[pass][nt][0] + bA + eu0 * cA0 + ed0 * cB0);
                float v01 = silu_f(c[pass][nt][1] + bB + eu0 * cA1 + ed0 * cB1);
                float v10 = silu_f(c[pass][nt][2] + bA + eu1 * cA0 + ed1 * cB0);
                float v11 = silu_f(c[pass][nt][3] + bB + eu1 * cA1 + ed1 * cB1);
                __half h00 = __float2half_rn(v00), h01 = __float2half_rn(v01);
                __half h10 = __float2half_rn(v10), h11 = __float2half_rn(v11);
                sAhi[ar * PS1 + kp]       = pack_hh(h00, h01);
                sAhi[(ar + 8) * PS1 + kp] = pack_hh(h10, h11);
                sAlo[ar * PS1 + kp] = pack_ff(
                    v00 - __half2float(h00), v01 - __half2float(h01));
                sAlo[(ar + 8) * PS1 + kp] = pack_ff(
                    v10 - __half2float(h10), v11 - __half2float(h11));
            }
        }
    }
    __syncthreads();

    #pragma unroll
    for (int p = 0; p < 2; ++p)
        #pragma unroll
        for (int nt = 0; nt < 4; ++nt)
            #pragma unroll
            for (int q = 0; q < 4; ++q) c[p][nt][q] = 0.f;

    {
        const uint4* Bm = (const uint4*)(nodeFrag + (size_t)3 * 16384);
        #pragma unroll 2
        for (int ks = 0; ks < 8; ++ks) {
            int kp = ks * 8 + ak;
            uint32_t ah[4], al[4];
            ah[0] = sAhi[ar * PS1 + kp];
            ah[1] = sAhi[(ar + 8) * PS1 + kp];
            ah[2] = sAhi[ar * PS1 + kp + 4];
            ah[3] = sAhi[(ar + 8) * PS1 + kp + 4];
            al[0] = sAlo[ar * PS1 + kp];
            al[1] = sAlo[(ar + 8) * PS1 + kp];
            al[2] = sAlo[ar * PS1 + kp + 4];
            al[3] = sAlo[(ar + 8) * PS1 + kp + 4];
            #pragma unroll
            for (int pass = 0; pass < 2; ++pass) {
                #pragma unroll
                for (int nt = 0; nt < 4; ++nt) {
                    int ntile = pass * 8 + cg * 4 + nt;
                    uint4 v = __ldg(Bm + (size_t)(ntile * 8 + ks) * 32 + lane);
                    mma_f16(c[pass][nt], ah, v.x, v.y);
                    mma_f16(c[pass][nt], al, v.x, v.y);
                    mma_f16(c[pass][nt], ah, v.z, v.w);
                }
            }
        }
    }
    {
        int gA = g0 + ar, gB = g0 + ar + 8;
        #pragma unroll
        for (int pass = 0; pass < 2; ++pass) {
            #pragma unroll
            for (int nt = 0; nt < 4; ++nt) {
                int col = (pass * 8 + cg * 4 + nt) * 8 + 2 * ak;
                float bA = s_bias[384 + col], bB = s_bias[384 + col + 1];
                if (gA < nRows) {
                    size_t o = (size_t)gA * H_DIM + col;
                    float2 f = *(const float2*)&feat[o];
                    *(float2*)&outf[o] = make_float2(
                        f.x + c[pass][nt][0] + bA, f.y + c[pass][nt][1] + bB);
                }
                if (gB < nRows) {
                    size_t o = (size_t)gB * H_DIM + col;
                    float2 f = *(const float2*)&feat[o];
                    *(float2*)&outf[o] = make_float2(
                        f.x + c[pass][nt][2] + bA, f.y + c[pass][nt][3] + bB);
                }
            }
        }
    }
}

__global__ void pos_kernel(const float* __restrict__ pos,
                           const float* __restrict__ pos_upd,
                           float* __restrict__ out, int n)
{
    int i = blockIdx.x * blockDim.x + threadIdx.x;
    if (i < n) out[i] = pos[i] + 0.5f * pos_upd[i];
}

extern "C" void kernel_launch(void* const* d_in, const int* in_sizes, int n_in,
                              void* d_out, int out_size)
{
    const float* feat   = (const float*)d_in[0];
    const float* pos    = (const float*)d_in[1];
    const int*   ei_up  = (const int*)d_in[2];
    const int*   ei_dn  = (const int*)d_in[3];
    const float* deg_up = (const float*)d_in[4];
    const float* deg_dn = (const float*)d_in[5];

    const float* w1u  = (const float*)d_in[6];
    const float* b1u  = (const float*)d_in[7];
    const float* w2u  = (const float*)d_in[8];
    const float* b2u  = (const float*)d_in[9];
    const float* wp1u = (const float*)d_in[10];
    const float* bp1u = (const float*)d_in[11];
    const float* wp2u = (const float*)d_in[12];
    const float* bp2u = (const float*)d_in[13];

    const float* w1d  = (const float*)d_in[14];
    const float* b1d  = (const float*)d_in[15];
    const float* w2d  = (const float*)d_in[16];
    const float* b2d  = (const float*)d_in[17];
    const float* wp1d = (const float*)d_in[18];
    const float* bp1d = (const float*)d_in[19];
    const float* wp2d = (const float*)d_in[20];
    const float* bp2d = (const float*)d_in[21];

    const float* wu1 = (const float*)d_in[22];
    const float* bu1 = (const float*)d_in[23];
    const float* wu2 = (const float*)d_in[24];
    const float* bu2 = (const float*)d_in[25];

    int E = in_sizes[2] / 2;
    int N = in_sizes[4];
    int B = in_sizes[0] / (N * H_DIM);
    int nRows = B * N;

    float *pre, *hacc, *einv, *pos_upd, *bpc, *bcu;
    uint32_t *CpFrag, *preFrag, *nodeFrag;
    cudaGetSymbolAddress((void**)&pre,      g_pre);
    cudaGetSymbolAddress((void**)&hacc,     g_hacc);
    cudaGetSymbolAddress((void**)&einv,     g_einv);
    cudaGetSymbolAddress((void**)&pos_upd,  g_pos_upd);
    cudaGetSymbolAddress((void**)&CpFrag,   g_CpFrag);
    cudaGetSymbolAddress((void**)&bpc,      g_bpc);
    cudaGetSymbolAddress((void**)&bcu,      g_bcu);
    cudaGetSymbolAddress((void**)&preFrag,  g_preFrag);
    cudaGetSymbolAddress((void**)&nodeFrag, g_nodeFrag);

    const size_t PS = (size_t)MAX_BN * H_DIM;
    float* pre_au = pre;
    float* pre_bu = pre + PS;
    float* pre_ad = pre + 2 * PS;
    float* pre_bd = pre + 3 * PS;
    float* hacc_u = hacc;
    float* hacc_d = hacc + PS;
    float* einv_u = einv;
    float* einv_d = einv + MAX_N;

    cudaMemsetAsync(hacc, 0, 2 * PS * sizeof(float));
    cudaMemsetAsync(einv, 0, 2 * MAX_N * sizeof(float));
    cudaMemsetAsync(pos_upd, 0, (size_t)nRows * 3 * sizeof(float));

    int smemPre  = 2 * 128 * PS1 * 4;                           // 69632 B
    int smemEdge = 128 * PS1 * 4
                 + (512 + 384 + 128 + 128 + 128) * 4 + 256 * 4; // 41216 B
    int smemNode = (2 * 64 * PS1 + 128 + 512) * 4;              // 37376 B
    cudaFuncSetAttribute(pre_mma_kernel,
                         cudaFuncAttributeMaxDynamicSharedMemorySize, smemPre);
    cudaFuncSetAttribute(edge_mma_kernel,
                         cudaFuncAttributeMaxDynamicSharedMemorySize, smemEdge);
    cudaFuncSetAttribute(node2_mma_kernel,
                         cudaFuncAttributeMaxDynamicSharedMemorySize, smemNode);

    combine_kernel<<<dim3(65, 4), H_DIM>>>(
        w2u, wp1u, b2u, bp1u, w2d, wp1d, b2d, bp1d, wu1,
        CpFrag, nodeFrag, bpc, bcu);

    fragw_kernel<<<dim3(64, 6), H_DIM>>>(w1u, w1d, wu1, wu2,
                                         preFrag, nodeFrag);

    pre_mma_kernel<<<(nRows + 127) / 128, 256, smemPre>>>(
        feat, preFrag, pre_au, pre_bu, pre_ad, pre_bd, nRows);

    EdgeParams EP;
    EP.d[0] = { pre_au, pre_bu, ei_up, deg_up, w1u, b1u,
                CpFrag,        bpc,         wp2u, bp2u, hacc_u, einv_u };
    EP.d[1] = { pre_ad, pre_bd, ei_dn, deg_dn, w1d, b1d,
                CpFrag + 8192, bpc + H_DIM, wp2d, bp2d, hacc_d, einv_d };

    dim3 egrid((E + TEC - 1) / TEC, B, 2);
    edge_mma_kernel<<<egrid, 256, smemEdge>>>(EP, pos, pos_upd, E, N);

    node2_mma_kernel<<<(nRows + 63) / 64, 256, smemNode>>>(
        feat, hacc_u, hacc_d, nodeFrag, einv_u, einv_d,
        bcu, bcu + H_DIM, bu1, bu2, (float*)d_out, N, nRows);

    size_t featN = (size_t)nRows * H_DIM;
    int pn = nRows * 3;
    pos_kernel<<<(pn + 255) / 256, 256>>>(
        pos, pos_upd, (float*)d_out + featN, pn);
}

// round 12
// speedup vs baseline: 10.4971x; 1.0357x over previous
#include <cuda_runtime.h>
#include <cuda_fp16.h>
#include <math.h>
#include <cstdint>

#define H_DIM 128
#define TEC 128        // edges per block (edge kernel)
#define PS1 68         // pair-row stride (uint32 units) for fp16x2 tiles

#define MAX_B 2
#define MAX_N 20000
#define MAX_BN (MAX_B * MAX_N)

// ---------------------------------------------------------------------------
// Scratch (allocation-free rule: __device__ globals)
// ---------------------------------------------------------------------------
__device__ __align__(128) uint32_t g_pre[4][(size_t)MAX_BN * 64]; // fp16x2 pairs
__device__ __align__(128) float g_hacc[2][(size_t)MAX_BN * H_DIM];
__device__ __align__(128) float g_einv[2][MAX_N];
__device__ __align__(128) float g_pos_upd[(size_t)MAX_BN * 3];
__device__ __align__(128) uint32_t g_CpFrag[2][8192];     // fp16 hi, paired-ntile uint4 layout
__device__ __align__(128) float g_bpc[2][H_DIM];
__device__ __align__(128) float g_bcu[2][H_DIM];
__device__ __align__(128) uint32_t g_preFrag[4][16384];   // fp16 hi/lo uint4 layout
__device__ __align__(128) uint32_t g_nodeFrag[4][16384];  // wu1top,Cu0,Cu1,wu2

__device__ __forceinline__ float silu_f(float v) {
    return __fdividef(v, 1.0f + __expf(-v));
}

// ---- fp16 mma.sync helpers --------------------------------------------------
__device__ __forceinline__ void mma_f16(float c[4], const uint32_t a[4],
                                        uint32_t b0, uint32_t b1) {
    asm volatile(
        "mma.sync.aligned.m16n8k16.row.col.f32.f16.f16.f32 "
        "{%0,%1,%2,%3}, {%4,%5,%6,%7}, {%8,%9}, {%0,%1,%2,%3};"
        : "+f"(c[0]), "+f"(c[1]), "+f"(c[2]), "+f"(c[3])
        : "r"(a[0]), "r"(a[1]), "r"(a[2]), "r"(a[3]), "r"(b0), "r"(b1));
}
__device__ __forceinline__ uint32_t pack_hh(__half lo, __half hi) {
    __half2 h = __halves2half2(lo, hi);
    return *reinterpret_cast<uint32_t*>(&h);
}
__device__ __forceinline__ uint32_t pack_ff(float e, float o) {
    __half2 h = __floats2half2_rn(e, o);
    return *reinterpret_cast<uint32_t*>(&h);
}
__device__ __forceinline__ float2 up2(uint32_t v) {
    return __half22float2(*reinterpret_cast<__half2*>(&v));
}

// ---------------------------------------------------------------------------
// combine_kernel: grid (65, 4), 128 thr.
// ---------------------------------------------------------------------------
__global__ void combine_kernel(
    const float* __restrict__ w2u, const float* __restrict__ wp1u,
    const float* __restrict__ b2u, const float* __restrict__ bp1u,
    const float* __restrict__ w2d, const float* __restrict__ wp1d,
    const float* __restrict__ b2d, const float* __restrict__ bp1d,
    const float* __restrict__ wu1,
    uint32_t* __restrict__ CpFrag, uint32_t* __restrict__ nodeFrag,
    float* __restrict__ bpc, float* __restrict__ bcu)
{
    const float* wu1b = wu1 + 128 * H_DIM;
    const float* A; const float* Bm; const float* bvec; const float* badd;
    uint32_t* C; float* bout; bool split;
    switch (blockIdx.y) {
        case 0:  A = w2u; Bm = wp1u; bvec = b2u; badd = bp1u;
                 C = CpFrag;               bout = bpc;         split = false; break;
        case 1:  A = w2d; Bm = wp1d; bvec = b2d; badd = bp1d;
                 C = CpFrag + 8192;        bout = bpc + H_DIM; split = false; break;
        case 2:  A = w2u; Bm = wu1b; bvec = b2u; badd = 0;
                 C = nodeFrag + 1 * 16384; bout = bcu;         split = true;  break;
        default: A = w2d; Bm = wu1b; bvec = b2d; badd = 0;
                 C = nodeFrag + 2 * 16384; bout = bcu + H_DIM; split = true;  break;
    }
    int i2 = blockIdx.x;
    int j  = threadIdx.x;
    if (i2 == 64) {
        float s = 0.f;
        #pragma unroll 8
        for (int k = 0; k < H_DIM; ++k) s += bvec[k] * Bm[k * H_DIM + j];
        bout[j] = s + (badd ? badd[j] : 0.f);
        return;
    }
    float s0 = 0.f, s1 = 0.f;
    const float* a0r = A + (size_t)(2 * i2) * H_DIM;
    const float* a1r = a0r + H_DIM;
    #pragma unroll 8
    for (int k = 0; k < H_DIM; ++k) {
        float b = Bm[k * H_DIM + j];
        s0 += a0r[k] * b;
        s1 += a1r[k] * b;
    }
    int ks = i2 >> 3, m = i2 & 7;
    int lanep = m & 3, reg = m >> 2;
    int nn = j & 7;
    if (split) {
        __half h0 = __float2half_rn(s0), h1 = __float2half_rn(s1);
        __half l0 = __float2half_rn(s0 - __half2float(h0));
        __half l1 = __float2half_rn(s1 - __half2float(h1));
        int ntile = j >> 3;
        size_t base = ((size_t)(ntile * 8 + ks) * 32 + nn * 4 + lanep) * 4;
        C[base + reg]     = pack_hh(h0, h1);
        C[base + 2 + reg] = pack_hh(l0, l1);
    } else {
        int ntile = j >> 3, pass = ntile >> 3, ntl = ntile & 7;
        size_t idx = (size_t)pass * 4096
                   + ((size_t)(ks * 4 + (ntl >> 1)) * 32 + nn * 4 + lanep) * 4
                   + (ntl & 1) * 2 + reg;
        C[idx] = pack_ff(s0, s1);
    }
}

// ---------------------------------------------------------------------------
// fragw_kernel: grid (64, 6), 128 thr.
// ---------------------------------------------------------------------------
__global__ void fragw_kernel(const float* __restrict__ w1u,
                             const float* __restrict__ w1d,
                             const float* __restrict__ wu1,
                             const float* __restrict__ wu2,
                             uint32_t* __restrict__ preFrag,
                             uint32_t* __restrict__ nodeFrag)
{
    int y = blockIdx.y;
    const float* W; uint32_t* out;
    switch (y) {
        case 0: W = w1u;                out = preFrag;              break;
        case 1: W = w1u + 128 * H_DIM;  out = preFrag + 16384;      break;
        case 2: W = w1d;                out = preFrag + 2 * 16384;  break;
        case 3: W = w1d + 128 * H_DIM;  out = preFrag + 3 * 16384;  break;
        case 4: W = wu1;                out = nodeFrag;             break;
        default: W = wu2;               out = nodeFrag + 3 * 16384; break;
    }
    int i2 = blockIdx.x;
    int j  = threadIdx.x;
    float x0 = W[(size_t)(2 * i2) * H_DIM + j];
    float x1 = W[(size_t)(2 * i2 + 1) * H_DIM + j];
    __half h0 = __float2half_rn(x0), h1 = __float2half_rn(x1);
    __half l0 = __float2half_rn(x0 - __half2float(h0));
    __half l1 = __float2half_rn(x1 - __half2float(h1));
    int ks = i2 >> 3, m = i2 & 7;
    int lanep = m & 3, reg = m >> 2;
    int ntile = j >> 3, nn = j & 7;
    size_t base = ((size_t)(ntile * 8 + ks) * 32 + nn * 4 + lanep) * 4;
    out[base + reg]     = pack_hh(h0, h1);
    out[base + 2 + reg] = pack_hh(l0, l1);
}

// ---------------------------------------------------------------------------
// pre_mma_kernel: 128-row blocks; outputs fp16x2 (uint32 per col-pair).
// ---------------------------------------------------------------------------
__global__ void __launch_bounds__(256)
pre_mma_kernel(const float* __restrict__ feat, const uint32_t* __restrict__ frag,
               uint32_t* __restrict__ p0, uint32_t* __restrict__ p1,
               uint32_t* __restrict__ p2, uint32_t* __restrict__ p3, int nRows)
{
    extern __shared__ uint32_t smu[];
    uint32_t* sAhi = smu;                  // [128][68] pairs
    uint32_t* sAlo = sAhi + 128 * PS1;

    const int tid = threadIdx.x;
    const int wid = tid >> 5, lane = tid & 31;
    const int wg = wid >> 2;               // matrix half
    const int rw = wid & 3;                // 32-row group
    const int ar = rw * 32 + (lane >> 2);
    const int ak = lane & 3;
    const int g0 = blockIdx.x * 128;

    #pragma unroll
    for (int p = 0; p < 16; ++p) {
        int idx = p * 256 + tid;
        int r = idx >> 5, c4 = idx & 31;
        float4 v = make_float4(0.f, 0.f, 0.f, 0.f);
        if (g0 + r < nRows)
            v = __ldg((const float4*)feat + (size_t)(g0 + r) * 32 + c4);
        __half hx = __float2half_rn(v.x), hy = __float2half_rn(v.y);
        __half hz = __float2half_rn(v.z), hw = __float2half_rn(v.w);
        *(uint2*)(sAhi + r * PS1 + 2 * c4) =
            make_uint2(pack_hh(hx, hy), pack_hh(hz, hw));
        *(uint2*)(sAlo + r * PS1 + 2 * c4) = make_uint2(
            pack_ff(v.x - __half2float(hx), v.y - __half2float(hy)),
            pack_ff(v.z - __half2float(hz), v.w - __half2float(hw)));
    }
    __syncthreads();

    uint32_t* outs[4] = {p0, p1, p2, p3};

    #pragma unroll
    for (int m2 = 0; m2 < 2; ++m2) {
        int m = wg * 2 + m2;
        const uint4* Bm = (const uint4*)frag + (size_t)m * 4096;
        uint32_t* out = outs[m];
        #pragma unroll
        for (int pass = 0; pass < 2; ++pass) {
            float c[2][8][4];
            #pragma unroll
            for (int t = 0; t < 2; ++t)
                #pragma unroll
                for (int nt = 0; nt < 8; ++nt)
                    #pragma unroll
                    for (int q = 0; q < 4; ++q) c[t][nt][q] = 0.f;

            #pragma unroll 2
            for (int ks = 0; ks < 8; ++ks) {
                int kp = ks * 8 + ak;
                uint32_t ah0[4], al0[4], ah1[4], al1[4];
                ah0[0] = sAhi[ar * PS1 + kp];
                ah0[1] = sAhi[(ar + 8) * PS1 + kp];
                ah0[2] = sAhi[ar * PS1 + kp + 4];
                ah0[3] = sAhi[(ar + 8) * PS1 + kp + 4];
                al0[0] = sAlo[ar * PS1 + kp];
                al0[1] = sAlo[(ar + 8) * PS1 + kp];
                al0[2] = sAlo[ar * PS1 + kp + 4];
                al0[3] = sAlo[(ar + 8) * PS1 + kp + 4];
                ah1[0] = sAhi[(ar + 16) * PS1 + kp];
                ah1[1] = sAhi[(ar + 24) * PS1 + kp];
                ah1[2] = sAhi[(ar + 16) * PS1 + kp + 4];
                ah1[3] = sAhi[(ar + 24) * PS1 + kp + 4];
                al1[0] = sAlo[(ar + 16) * PS1 + kp];
                al1[1] = sAlo[(ar + 24) * PS1 + kp];
                al1[2] = sAlo[(ar + 16) * PS1 + kp + 4];
                al1[3] = sAlo[(ar + 24) * PS1 + kp + 4];
                #pragma unroll
                for (int nt = 0; nt < 8; ++nt) {
                    int ntile = pass * 8 + nt;
                    uint4 v = __ldg(Bm + (size_t)(ntile * 8 + ks) * 32 + lane);
                    mma_f16(c[0][nt], ah0, v.x, v.y);
                    mma_f16(c[0][nt], al0, v.x, v.y);
                    mma_f16(c[0][nt], ah0, v.z, v.w);
                    mma_f16(c[1][nt], ah1, v.x, v.y);
                    mma_f16(c[1][nt], al1, v.x, v.y);
                    mma_f16(c[1][nt], ah1, v.z, v.w);
                }
            }
            #pragma unroll
            for (int t = 0; t < 2; ++t) {
                int rowA = g0 + ar + t * 16, rowB = rowA + 8;
                #pragma unroll
                for (int nt = 0; nt < 8; ++nt) {
                    int cp = ((pass * 8 + nt) * 8 + 2 * ak) >> 1;  // uint32 index
                    if (rowA < nRows)
                        out[(size_t)rowA * 64 + cp] = pack_ff(c[t][nt][0], c[t][nt][1]);
                    if (rowB < nRows)
                        out[(size_t)rowB * 64 + cp] = pack_ff(c[t][nt][2], c[t][nt][3]);
                }
            }
        }
    }
}

// ---------------------------------------------------------------------------
// edge_mma_kernel: merged dirs; fp16 gather (uint2/lane); 3 CTAs/SM.
// ---------------------------------------------------------------------------
struct EdgeDir {
    const uint32_t* pre_a; const uint32_t* pre_b;   // fp16x2 rows (64 u32/row)
    const int* ei; const float* deg;
    const float* w1; const float* b1;
    const uint32_t* CpFrag; const float* bpc;
    const float* wp2; const float* bp2;
    float* hacc; float* einv;
};
struct EdgeParams { EdgeDir d[2]; };

__global__ void __launch_bounds__(256, 3)
edge_mma_kernel(EdgeParams P, const float* __restrict__ pos,
                float* __restrict__ pos_upd, int nE, int N)
{
    extern __shared__ uint32_t smu[];
    uint32_t* sHid = smu;                       // [128][68] fp16x2 pairs
    float* s_w1c = (float*)(smu + 128 * PS1);
    float* s_b1  = s_w1c + 128;
    float* s_bpc = s_b1 + 128;
    float* s_wp2 = s_bpc + 128;
    float* s_rel = s_wp2 + 128;                 // [128*3]
    float* s_dist= s_rel + 384;
    float* s_inv = s_dist + 128;
    float* s_p   = s_inv + 128;                 // [128]
    int*   s_src = (int*)(s_p + 128);
    int*   s_dst = s_src + 128;

    const EdgeDir& D = P.d[blockIdx.z];
    const int tid  = threadIdx.x;
    const int wid  = tid >> 5;
    const int lane = tid & 31;
    const int b    = blockIdx.y;
    const int e0   = blockIdx.x * TEC;
    const size_t bN = (size_t)b * N;

    if (tid < TEC) {
        int e = e0 + tid;
        int s = 0, d = 0;
        float x0 = 0.f, x1 = 0.f, x2 = 0.f, dist = 0.f, inv = 0.f;
        if (e < nE) {
            s = D.ei[e];
            d = D.ei[nE + e];
            const float* ps = pos + (bN + s) * 3;
            const float* pd = pos + (bN + d) * 3;
            x0 = ps[0] - pd[0];
            x1 = ps[1] - pd[1];
            x2 = ps[2] - pd[2];
            dist = sqrtf(x0 * x0 + x1 * x1 + x2 * x2);
            inv  = 1.0f / fmaxf(D.deg[d], 1.0f);
        }
        s_src[tid] = s; s_dst[tid] = d;
        s_rel[tid * 3 + 0] = x0; s_rel[tid * 3 + 1] = x1; s_rel[tid * 3 + 2] = x2;
        s_dist[tid] = dist; s_inv[tid] = inv;
        s_w1c[tid] = D.w1[256 * H_DIM + tid];
        s_b1[tid]  = D.b1[tid];
        s_bpc[tid] = D.bpc[tid];
        s_wp2[tid] = D.wp2[tid];
    }
    __syncthreads();

    // gather (fp16 rows, uint2/lane = 4 cols) -> hidden fp32 -> sHid + RED
    #pragma unroll
    for (int p = 0; p < 16; p += 4) {
        uint2 va[4], vb[4];
        #pragma unroll
        for (int q = 0; q < 4; ++q) {
            int r = (p + q) * 8 + wid;
            va[q] = __ldg((const uint2*)D.pre_a + (size_t)(bN + s_src[r]) * 32 + lane);
            vb[q] = __ldg((const uint2*)D.pre_b + (size_t)(bN + s_dst[r]) * 32 + lane);
        }
        #pragma unroll
        for (int q = 0; q < 4; ++q) {
            int r = (p + q) * 8 + wid;
            float dd = s_dist[r], inv = s_inv[r];
            float4 wc = *(const float4*)(s_w1c + lane * 4);
            float4 bb = *(const float4*)(s_b1 + lane * 4);
            float2 a01 = up2(va[q].x), a23 = up2(va[q].y);
            float2 b01 = up2(vb[q].x), b23 = up2(vb[q].y);
            float h0 = silu_f(a01.x + b01.x + dd * wc.x + bb.x);
            float h1 = silu_f(a01.y + b01.y + dd * wc.y + bb.y);
            float h2 = silu_f(a23.x + b23.x + dd * wc.z + bb.z);
            float h3 = silu_f(a23.y + b23.y + dd * wc.w + bb.w);
            *(uint2*)(sHid + r * PS1 + 2 * lane) =
                make_uint2(pack_ff(h0, h1), pack_ff(h2, h3));
            float* gp = D.hacc + (bN + s_dst[r]) * H_DIM + lane * 4;
            asm volatile("red.global.add.v4.f32 [%0], {%1, %2, %3, %4};"
                         :: "l"(gp), "f"(h0 * inv), "f"(h1 * inv),
                            "f"(h2 * inv), "f"(h3 * inv) : "memory");
        }
    }
    if (tid < TEC && b == 0 && (e0 + tid) < nE)
        atomicAdd(&D.einv[s_dst[tid]], s_inv[tid]);
    __syncthreads();

    const int ar = wid * 16 + (lane >> 2);
    const int ak = lane & 3;
    float sum0 = 0.f, sum1 = 0.f;
    const uint4* Cp4 = (const uint4*)D.CpFrag;

    #pragma unroll
    for (int pass = 0; pass < 2; ++pass) {
        float c[8][4];
        #pragma unroll
        for (int nt = 0; nt < 8; ++nt)
            #pragma unroll
            for (int q = 0; q < 4; ++q) c[nt][q] = 0.f;

        #pragma unroll 4
        for (int ks = 0; ks < 8; ++ks) {
            uint32_t a[4];
            int kp = ks * 8 + ak;
            a[0] = sHid[ar * PS1 + kp];
            a[1] = sHid[(ar + 8) * PS1 + kp];
            a[2] = sHid[ar * PS1 + kp + 4];
            a[3] = sHid[(ar + 8) * PS1 + kp + 4];
            #pragma unroll
            for (int ntp = 0; ntp < 4; ++ntp) {
                uint4 bv = __ldg(Cp4 + (size_t)pass * 1024
                                 + (size_t)(ks * 4 + ntp) * 32 + lane);
                mma_f16(c[2 * ntp],     a, bv.x, bv.y);
                mma_f16(c[2 * ntp + 1], a, bv.z, bv.w);
            }
        }
        #pragma unroll
        for (int nt = 0; nt < 8; ++nt) {
            int cb = pass * 64 + nt * 8 + 2 * ak;
            float w0 = s_wp2[cb], w1v = s_wp2[cb + 1];
            float q0 = s_bpc[cb], q1 = s_bpc[cb + 1];
            sum0 += silu_f(c[nt][0] + q0) * w0 + silu_f(c[nt][1] + q1) * w1v;
            sum1 += silu_f(c[nt][2] + q0) * w0 + silu_f(c[nt][3] + q1) * w1v;
        }
    }

    sum0 += __shfl_xor_sync(0xFFFFFFFFu, sum0, 1);
    sum0 += __shfl_xor_sync(0xFFFFFFFFu, sum0, 2);
    sum1 += __shfl_xor_sync(0xFFFFFFFFu, sum1, 1);
    sum1 += __shfl_xor_sync(0xFFFFFFFFu, sum1, 2);
    if ((lane & 3) == 0) {
        s_p[ar]     = sum0;
        s_p[ar + 8] = sum1;
    }
    __syncthreads();

    if (tid < TEC && (e0 + tid) < nE) {
        float w = tanhf(s_p[tid] + D.bp2[0]);
        int d = s_dst[tid];
        float* pp = pos_upd + (bN + d) * 3;
        atomicAdd(&pp[0], w * s_rel[tid * 3 + 0]);
        atomicAdd(&pp[1], w * s_rel[tid * 3 + 1]);
        atomicAdd(&pp[2], w * s_rel[tid * 3 + 2]);
    }
}

// ---------------------------------------------------------------------------
// node2_mma_kernel: split-fp16 node update (unchanged from R11)
// ---------------------------------------------------------------------------
__global__ void __launch_bounds__(256)
node2_mma_kernel(const float* __restrict__ feat,
                 const float* __restrict__ hacc0, const float* __restrict__ hacc1,
                 const uint32_t* __restrict__ nodeFrag,
                 const float* __restrict__ einv0, const float* __restrict__ einv1,
                 const float* __restrict__ bcu0, const float* __restrict__ bcu1,
                 const float* __restrict__ bu1,  const float* __restrict__ bu2,
                 float* __restrict__ outf, int N, int nRows)
{
    extern __shared__ uint32_t smu[];
    uint32_t* sAhi = smu;                   // [64][68]
    uint32_t* sAlo = sAhi + 64 * PS1;
    float* s_eU   = (float*)(smu + 2 * 64 * PS1);   // [64]
    float* s_eD   = s_eU + 64;
    float* s_bias = s_eD + 64;              // 4*128

    const int tid = threadIdx.x;
    const int wid = tid >> 5, lane = tid & 31;
    const int rg = wid & 3, cg = wid >> 2;
    const int ar = rg * 16 + (lane >> 2);
    const int ak = lane & 3;
    const int g0 = blockIdx.x * 64;

    if (tid < 64) {
        int g = g0 + tid;
        float eu = 0.f, ed = 0.f;
        if (g < nRows) {
            int node = g % N;
            eu = einv0[node];
            ed = einv1[node];
        }
        s_eU[tid] = eu; s_eD[tid] = ed;
    }
    if (tid < 128) {
        s_bias[tid]       = bu1[tid];
        s_bias[128 + tid] = bcu0[tid];
        s_bias[256 + tid] = bcu1[tid];
        s_bias[384 + tid] = bu2[tid];
    }

    float c[2][4][4];
    #pragma unroll
    for (int p = 0; p < 2; ++p)
        #pragma unroll
        for (int nt = 0; nt < 4; ++nt)
            #pragma unroll
            for (int q = 0; q < 4; ++q) c[p][nt][q] = 0.f;

    for (int m = 0; m < 3; ++m) {
        const float* src = (m == 0) ? feat : (m == 1) ? hacc0 : hacc1;
        __syncthreads();
        #pragma unroll
        for (int p = 0; p < 8; ++p) {
            int idx = p * 256 + tid;
            int r = idx >> 5, c4 = idx & 31;
            float4 v = make_float4(0.f, 0.f, 0.f, 0.f);
            if (g0 + r < nRows)
                v = __ldg((const float4*)src + (size_t)(g0 + r) * 32 + c4);
            __half hx = __float2half_rn(v.x), hy = __float2half_rn(v.y);
            __half hz = __float2half_rn(v.z), hw = __float2half_rn(v.w);
            *(uint2*)(sAhi + r * PS1 + 2 * c4) =
                make_uint2(pack_hh(hx, hy), pack_hh(hz, hw));
            *(uint2*)(sAlo + r * PS1 + 2 * c4) = make_uint2(
                pack_ff(v.x - __half2float(hx), v.y - __half2float(hy)),
                pack_ff(v.z - __half2float(hz), v.w - __half2float(hw)));
        }
        __syncthreads();

        const uint4* Bm = (const uint4*)(nodeFrag + (size_t)m * 16384);
        #pragma unroll 2
        for (int ks = 0; ks < 8; ++ks) {
            int kp = ks * 8 + ak;
            uint32_t ah[4], al[4];
            ah[0] = sAhi[ar * PS1 + kp];
            ah[1] = sAhi[(ar + 8) * PS1 + kp];
            ah[2] = sAhi[ar * PS1 + kp + 4];
            ah[3] = sAhi[(ar + 8) * PS1 + kp + 4];
            al[0] = sAlo[ar * PS1 + kp];
            al[1] = sAlo[(ar + 8) * PS1 + kp];
            al[2] = sAlo[ar * PS1 + kp + 4];
            al[3] = sAlo[(ar + 8) * PS1 + kp + 4];
            #pragma unroll
            for (int pass = 0; pass < 2; ++pass) {
                #pragma unroll
                for (int nt = 0; nt < 4; ++nt) {
                    int ntile = pass * 8 + cg * 4 + nt;
                    uint4 v = __ldg(Bm + (size_t)(ntile * 8 + ks) * 32 + lane);
                    mma_f16(c[pass][nt], ah, v.x, v.y);
                    mma_f16(c[pass][nt], al, v.x, v.y);
                    mma_f16(c[pass][nt], ah, v.z, v.w);
                }
            }
        }
    }
    __syncthreads();
    {
        float eu0 = s_eU[ar],     ed0 = s_eD[ar];
        float eu1 = s_eU[ar + 8], ed1 = s_eD[ar + 8];
        #pragma unroll
        for (int pass = 0; pass < 2; ++pass) {
            #pragma unroll
            for (int nt = 0; nt < 4; ++nt) {
                int col = (pass * 8 + cg * 4 + nt) * 8 + 2 * ak;
                int kp  = col >> 1;
                float bA = s_bias[col],        bB = s_bias[col + 1];
                float cA0 = s_bias[128 + col], cA1 = s_bias[128 + col + 1];
                float cB0 = s_bias[256 + col], cB1 = s_bias[256 + col + 1];
                float v00 = silu_f(c[pass][nt][0] + bA + eu0 * cA0 + ed0 * cB0);
                float v01 = silu_f(c[pass][nt][1] + bB + eu0 * cA1 + ed0 * cB1);
                float v10 = silu_f(c[pass][nt][2] + bA + eu1 * cA0 + ed1 * cB0);
                float v11 = silu_f(c[pass][nt][3] + bB + eu1 * cA1 + ed1 * cB1);
                __half h00 = __float2half_rn(v00), h01 = __float2half_rn(v01);
                __half h10 = __float2half_rn(v10), h11 = __float2half_rn(v11);
                sAhi[ar * PS1 + kp]       = pack_hh(h00, h01);
                sAhi[(ar + 8) * PS1 + kp] = pack_hh(h10, h11);
                sAlo[ar * PS1 + kp] = pack_ff(
                    v00 - __half2float(h00), v01 - __half2float(h01));
                sAlo[(ar + 8) * PS1 + kp] = pack_ff(
                    v10 - __half2float(h10), v11 - __half2float(h11));
            }
        }
    }
    __syncthreads();

    #pragma unroll
    for (int p = 0; p < 2; ++p)
        #pragma unroll
        for (int nt = 0; nt < 4; ++nt)
            #pragma unroll
            for (int q = 0; q < 4; ++q) c[p][nt][q] = 0.f;

    {
        const uint4* Bm = (const uint4*)(nodeFrag + (size_t)3 * 16384);
        #pragma unroll 2
        for (int ks = 0; ks < 8; ++ks) {
            int kp = ks * 8 + ak;
            uint32_t ah[4], al[4];
            ah[0] = sAhi[ar * PS1 + kp];
            ah[1] = sAhi[(ar + 8) * PS1 + kp];
            ah[2] = sAhi[ar * PS1 + kp + 4];
            ah[3] = sAhi[(ar + 8) * PS1 + kp + 4];
            al[0] = sAlo[ar * PS1 + kp];
            al[1] = sAlo[(ar + 8) * PS1 + kp];
            al[2] = sAlo[ar * PS1 + kp + 4];
            al[3] = sAlo[(ar + 8) * PS1 + kp + 4];
            #pragma unroll
            for (int pass = 0; pass < 2; ++pass) {
                #pragma unroll
                for (int nt = 0; nt < 4; ++nt) {
                    int ntile = pass * 8 + cg * 4 + nt;
                    uint4 v = __ldg(Bm + (size_t)(ntile * 8 + ks) * 32 + lane);
                    mma_f16(c[pass][nt], ah, v.x, v.y);
                    mma_f16(c[pass][nt], al, v.x, v.y);
                    mma_f16(c[pass][nt], ah, v.z, v.w);
                }
            }
        }
    }
    {
        int gA = g0 + ar, gB = g0 + ar + 8;
        #pragma unroll
        for (int pass = 0; pass < 2; ++pass) {
            #pragma unroll
            for (int nt = 0; nt < 4; ++nt) {
                int col = (pass * 8 + cg * 4 + nt) * 8 + 2 * ak;
                float bA = s_bias[384 + col], bB = s_bias[384 + col + 1];
                if (gA < nRows) {
                    size_t o = (size_t)gA * H_DIM + col;
                    float2 f = *(const float2*)&feat[o];
                    *(float2*)&outf[o] = make_float2(
                        f.x + c[pass][nt][0] + bA, f.y + c[pass][nt][1] + bB);
                }
                if (gB < nRows) {
                    size_t o = (size_t)gB * H_DIM + col;
                    float2 f = *(const float2*)&feat[o];
                    *(float2*)&outf[o] = make_float2(
                        f.x + c[pass][nt][2] + bA, f.y + c[pass][nt][3] + bB);
                }
            }
        }
    }
}

__global__ void pos_kernel(const float* __restrict__ pos,
                           const float* __restrict__ pos_upd,
                           float* __restrict__ out, int n)
{
    int i = blockIdx.x * blockDim.x + threadIdx.x;
    if (i < n) out[i] = pos[i] + 0.5f * pos_upd[i];
}

extern "C" void kernel_launch(void* const* d_in, const int* in_sizes, int n_in,
                              void* d_out, int out_size)
{
    const float* feat   = (const float*)d_in[0];
    const float* pos    = (const float*)d_in[1];
    const int*   ei_up  = (const int*)d_in[2];
    const int*   ei_dn  = (const int*)d_in[3];
    const float* deg_up = (const float*)d_in[4];
    const float* deg_dn = (const float*)d_in[5];

    const float* w1u  = (const float*)d_in[6];
    const float* b1u  = (const float*)d_in[7];
    const float* w2u  = (const float*)d_in[8];
    const float* b2u  = (const float*)d_in[9];
    const float* wp1u = (const float*)d_in[10];
    const float* bp1u = (const float*)d_in[11];
    const float* wp2u = (const float*)d_in[12];
    const float* bp2u = (const float*)d_in[13];

    const float* w1d  = (const float*)d_in[14];
    const float* b1d  = (const float*)d_in[15];
    const float* w2d  = (const float*)d_in[16];
    const float* b2d  = (const float*)d_in[17];
    const float* wp1d = (const float*)d_in[18];
    const float* bp1d = (const float*)d_in[19];
    const float* wp2d = (const float*)d_in[20];
    const float* bp2d = (const float*)d_in[21];

    const float* wu1 = (const float*)d_in[22];
    const float* bu1 = (const float*)d_in[23];
    const float* wu2 = (const float*)d_in[24];
    const float* bu2 = (const float*)d_in[25];

    int E = in_sizes[2] / 2;
    int N = in_sizes[4];
    int B = in_sizes[0] / (N * H_DIM);
    int nRows = B * N;

    float *hacc, *einv, *pos_upd, *bpc, *bcu;
    uint32_t *pre, *CpFrag, *preFrag, *nodeFrag;
    cudaGetSymbolAddress((void**)&pre,      g_pre);
    cudaGetSymbolAddress((void**)&hacc,     g_hacc);
    cudaGetSymbolAddress((void**)&einv,     g_einv);
    cudaGetSymbolAddress((void**)&pos_upd,  g_pos_upd);
    cudaGetSymbolAddress((void**)&CpFrag,   g_CpFrag);
    cudaGetSymbolAddress((void**)&bpc,      g_bpc);
    cudaGetSymbolAddress((void**)&bcu,      g_bcu);
    cudaGetSymbolAddress((void**)&preFrag,  g_preFrag);
    cudaGetSymbolAddress((void**)&nodeFrag, g_nodeFrag);

    const size_t PS = (size_t)MAX_BN * 64;   // per-array stride in uint32
    uint32_t* pre_au = pre;
    uint32_t* pre_bu = pre + PS;
    uint32_t* pre_ad = pre + 2 * PS;
    uint32_t* pre_bd = pre + 3 * PS;
    const size_t HPS = (size_t)MAX_BN * H_DIM;
    float* hacc_u = hacc;
    float* hacc_d = hacc + HPS;
    float* einv_u = einv;
    float* einv_d = einv + MAX_N;

    cudaMemsetAsync(hacc, 0, 2 * HPS * sizeof(float));
    cudaMemsetAsync(einv, 0, 2 * MAX_N * sizeof(float));
    cudaMemsetAsync(pos_upd, 0, (size_t)nRows * 3 * sizeof(float));

    int smemPre  = 2 * 128 * PS1 * 4;                           // 69632 B
    int smemEdge = 128 * PS1 * 4
                 + (512 + 384 + 128 + 128 + 128) * 4 + 256 * 4; // 41216 B
    int smemNode = (2 * 64 * PS1 + 128 + 512) * 4;              // 37376 B
    cudaFuncSetAttribute(pre_mma_kernel,
                         cudaFuncAttributeMaxDynamicSharedMemorySize, smemPre);
    cudaFuncSetAttribute(edge_mma_kernel,
                         cudaFuncAttributeMaxDynamicSharedMemorySize, smemEdge);
    cudaFuncSetAttribute(node2_mma_kernel,
                         cudaFuncAttributeMaxDynamicSharedMemorySize, smemNode);

    combine_kernel<<<dim3(65, 4), H_DIM>>>(
        w2u, wp1u, b2u, bp1u, w2d, wp1d, b2d, bp1d, wu1,
        CpFrag, nodeFrag, bpc, bcu);

    fragw_kernel<<<dim3(64, 6), H_DIM>>>(w1u, w1d, wu1, wu2,
                                         preFrag, nodeFrag);

    pre_mma_kernel<<<(nRows + 127) / 128, 256, smemPre>>>(
        feat, preFrag, pre_au, pre_bu, pre_ad, pre_bd, nRows);

    EdgeParams EP;
    EP.d[0] = { pre_au, pre_bu, ei_up, deg_up, w1u, b1u,
                CpFrag,        bpc,         wp2u, bp2u, hacc_u, einv_u };
    EP.d[1] = { pre_ad, pre_bd, ei_dn, deg_dn, w1d, b1d,
                CpFrag + 8192, bpc + H_DIM, wp2d, bp2d, hacc_d, einv_d };

    dim3 egrid((E + TEC - 1) / TEC, B, 2);
    edge_mma_kernel<<<egrid, 256, smemEdge>>>(EP, pos, pos_upd, E, N);

    node2_mma_kernel<<<(nRows + 63) / 64, 256, smemNode>>>(
        feat, hacc_u, hacc_d, nodeFrag, einv_u, einv_d,
        bcu, bcu + H_DIM, bu1, bu2, (float*)d_out, N, nRows);

    size_t featN = (size_t)nRows * H_DIM;
    int pn = nRows * 3;
    pos_kernel<<<(pn + 255) / 256, 256>>>(
        pos, pos_upd, (float*)d_out + featN, pn);
}

// round 13
// speedup vs baseline: 10.9282x; 1.0411x over previous
#include <cuda_runtime.h>
#include <cuda_fp16.h>
#include <math.h>
#include <cstdint>

#define H_DIM 128
#define TEC 128        // edges per block (edge kernel)
#define PS1 68         // pair-row stride (uint32 units) for fp16x2 tiles

#define MAX_B 2
#define MAX_N 20000
#define MAX_BN (MAX_B * MAX_N)

// ---------------------------------------------------------------------------
// Scratch (allocation-free rule: __device__ globals)
// ---------------------------------------------------------------------------
__device__ __align__(128) uint32_t g_pre[4][(size_t)MAX_BN * 64]; // fp16x2 pairs
__device__ __align__(128) float g_hacc[2][(size_t)MAX_BN * H_DIM];
__device__ __align__(128) float g_einv[2][MAX_N];
__device__ __align__(128) float g_pos_upd[(size_t)MAX_BN * 3];
__device__ __align__(128) uint32_t g_CpFrag[2][8192];     // fp16 hi, paired-ntile uint4 layout
__device__ __align__(128) float g_bpc[2][H_DIM];
__device__ __align__(128) float g_bcu[2][H_DIM];
__device__ __align__(128) uint32_t g_preFrag[4][16384];   // fp16 hi/lo uint4 layout
__device__ __align__(128) uint32_t g_nodeFrag[4][16384];  // wu1top,Cu0,Cu1,wu2

// silu via single-MUFU tanh.approx: silu(x) = 0.5x + 0.5x*tanh(x/2)
__device__ __forceinline__ float silu_f(float v) {
    float t;
    asm("tanh.approx.f32 %0, %1;" : "=f"(t) : "f"(0.5f * v));
    float hv = 0.5f * v;
    return fmaf(hv, t, hv);
}
__device__ __forceinline__ float tanh_f(float v) {
    float t;
    asm("tanh.approx.f32 %0, %1;" : "=f"(t) : "f"(v));
    return t;
}

// ---- fp16 mma.sync helpers --------------------------------------------------
__device__ __forceinline__ void mma_f16(float c[4], const uint32_t a[4],
                                        uint32_t b0, uint32_t b1) {
    asm volatile(
        "mma.sync.aligned.m16n8k16.row.col.f32.f16.f16.f32 "
        "{%0,%1,%2,%3}, {%4,%5,%6,%7}, {%8,%9}, {%0,%1,%2,%3};"
        : "+f"(c[0]), "+f"(c[1]), "+f"(c[2]), "+f"(c[3])
        : "r"(a[0]), "r"(a[1]), "r"(a[2]), "r"(a[3]), "r"(b0), "r"(b1));
}
__device__ __forceinline__ uint32_t pack_hh(__half lo, __half hi) {
    __half2 h = __halves2half2(lo, hi);
    return *reinterpret_cast<uint32_t*>(&h);
}
__device__ __forceinline__ uint32_t pack_ff(float e, float o) {
    __half2 h = __floats2half2_rn(e, o);
    return *reinterpret_cast<uint32_t*>(&h);
}
__device__ __forceinline__ float2 up2(uint32_t v) {
    return __half22float2(*reinterpret_cast<__half2*>(&v));
}

// ---------------------------------------------------------------------------
// combine_kernel: grid (65, 4), 128 thr.
// ---------------------------------------------------------------------------
__global__ void combine_kernel(
    const float* __restrict__ w2u, const float* __restrict__ wp1u,
    const float* __restrict__ b2u, const float* __restrict__ bp1u,
    const float* __restrict__ w2d, const float* __restrict__ wp1d,
    const float* __restrict__ b2d, const float* __restrict__ bp1d,
    const float* __restrict__ wu1,
    uint32_t* __restrict__ CpFrag, uint32_t* __restrict__ nodeFrag,
    float* __restrict__ bpc, float* __restrict__ bcu)
{
    const float* wu1b = wu1 + 128 * H_DIM;
    const float* A; const float* Bm; const float* bvec; const float* badd;
    uint32_t* C; float* bout; bool split;
    switch (blockIdx.y) {
        case 0:  A = w2u; Bm = wp1u; bvec = b2u; badd = bp1u;
                 C = CpFrag;               bout = bpc;         split = false; break;
        case 1:  A = w2d; Bm = wp1d; bvec = b2d; badd = bp1d;
                 C = CpFrag + 8192;        bout = bpc + H_DIM; split = false; break;
        case 2:  A = w2u; Bm = wu1b; bvec = b2u; badd = 0;
                 C = nodeFrag + 1 * 16384; bout = bcu;         split = true;  break;
        default: A = w2d; Bm = wu1b; bvec = b2d; badd = 0;
                 C = nodeFrag + 2 * 16384; bout = bcu + H_DIM; split = true;  break;
    }
    int i2 = blockIdx.x;
    int j  = threadIdx.x;
    if (i2 == 64) {
        float s = 0.f;
        #pragma unroll 8
        for (int k = 0; k < H_DIM; ++k) s += bvec[k] * Bm[k * H_DIM + j];
        bout[j] = s + (badd ? badd[j] : 0.f);
        return;
    }
    float s0 = 0.f, s1 = 0.f;
    const float* a0r = A + (size_t)(2 * i2) * H_DIM;
    const float* a1r = a0r + H_DIM;
    #pragma unroll 8
    for (int k = 0; k < H_DIM; ++k) {
        float b = Bm[k * H_DIM + j];
        s0 += a0r[k] * b;
        s1 += a1r[k] * b;
    }
    int ks = i2 >> 3, m = i2 & 7;
    int lanep = m & 3, reg = m >> 2;
    int nn = j & 7;
    if (split) {
        __half h0 = __float2half_rn(s0), h1 = __float2half_rn(s1);
        __half l0 = __float2half_rn(s0 - __half2float(h0));
        __half l1 = __float2half_rn(s1 - __half2float(h1));
        int ntile = j >> 3;
        size_t base = ((size_t)(ntile * 8 + ks) * 32 + nn * 4 + lanep) * 4;
        C[base + reg]     = pack_hh(h0, h1);
        C[base + 2 + reg] = pack_hh(l0, l1);
    } else {
        int ntile = j >> 3, pass = ntile >> 3, ntl = ntile & 7;
        size_t idx = (size_t)pass * 4096
                   + ((size_t)(ks * 4 + (ntl >> 1)) * 32 + nn * 4 + lanep) * 4
                   + (ntl & 1) * 2 + reg;
        C[idx] = pack_ff(s0, s1);
    }
}

// ---------------------------------------------------------------------------
// fragw_kernel: grid (64, 6), 128 thr.
// ---------------------------------------------------------------------------
__global__ void fragw_kernel(const float* __restrict__ w1u,
                             const float* __restrict__ w1d,
                             const float* __restrict__ wu1,
                             const float* __restrict__ wu2,
                             uint32_t* __restrict__ preFrag,
                             uint32_t* __restrict__ nodeFrag)
{
    int y = blockIdx.y;
    const float* W; uint32_t* out;
    switch (y) {
        case 0: W = w1u;                out = preFrag;              break;
        case 1: W = w1u + 128 * H_DIM;  out = preFrag + 16384;      break;
        case 2: W = w1d;                out = preFrag + 2 * 16384;  break;
        case 3: W = w1d + 128 * H_DIM;  out = preFrag + 3 * 16384;  break;
        case 4: W = wu1;                out = nodeFrag;             break;
        default: W = wu2;               out = nodeFrag + 3 * 16384; break;
    }
    int i2 = blockIdx.x;
    int j  = threadIdx.x;
    float x0 = W[(size_t)(2 * i2) * H_DIM + j];
    float x1 = W[(size_t)(2 * i2 + 1) * H_DIM + j];
    __half h0 = __float2half_rn(x0), h1 = __float2half_rn(x1);
    __half l0 = __float2half_rn(x0 - __half2float(h0));
    __half l1 = __float2half_rn(x1 - __half2float(h1));
    int ks = i2 >> 3, m = i2 & 7;
    int lanep = m & 3, reg = m >> 2;
    int ntile = j >> 3, nn = j & 7;
    size_t base = ((size_t)(ntile * 8 + ks) * 32 + nn * 4 + lanep) * 4;
    out[base + reg]     = pack_hh(h0, h1);
    out[base + 2 + reg] = pack_hh(l0, l1);
}

// ---------------------------------------------------------------------------
// pre_mma_kernel: 128-row blocks; outputs fp16x2 (uint32 per col-pair).
// ---------------------------------------------------------------------------
__global__ void __launch_bounds__(256)
pre_mma_kernel(const float* __restrict__ feat, const uint32_t* __restrict__ frag,
               uint32_t* __restrict__ p0, uint32_t* __restrict__ p1,
               uint32_t* __restrict__ p2, uint32_t* __restrict__ p3, int nRows)
{
    extern __shared__ uint32_t smu[];
    uint32_t* sAhi = smu;                  // [128][68] pairs
    uint32_t* sAlo = sAhi + 128 * PS1;

    const int tid = threadIdx.x;
    const int wid = tid >> 5, lane = tid & 31;
    const int wg = wid >> 2;               // matrix half
    const int rw = wid & 3;                // 32-row group
    const int ar = rw * 32 + (lane >> 2);
    const int ak = lane & 3;
    const int g0 = blockIdx.x * 128;

    #pragma unroll
    for (int p = 0; p < 16; ++p) {
        int idx = p * 256 + tid;
        int r = idx >> 5, c4 = idx & 31;
        float4 v = make_float4(0.f, 0.f, 0.f, 0.f);
        if (g0 + r < nRows)
            v = __ldg((const float4*)feat + (size_t)(g0 + r) * 32 + c4);
        __half hx = __float2half_rn(v.x), hy = __float2half_rn(v.y);
        __half hz = __float2half_rn(v.z), hw = __float2half_rn(v.w);
        *(uint2*)(sAhi + r * PS1 + 2 * c4) =
            make_uint2(pack_hh(hx, hy), pack_hh(hz, hw));
        *(uint2*)(sAlo + r * PS1 + 2 * c4) = make_uint2(
            pack_ff(v.x - __half2float(hx), v.y - __half2float(hy)),
            pack_ff(v.z - __half2float(hz), v.w - __half2float(hw)));
    }
    __syncthreads();

    uint32_t* outs[4] = {p0, p1, p2, p3};

    #pragma unroll
    for (int m2 = 0; m2 < 2; ++m2) {
        int m = wg * 2 + m2;
        const uint4* Bm = (const uint4*)frag + (size_t)m * 4096;
        uint32_t* out = outs[m];
        #pragma unroll
        for (int pass = 0; pass < 2; ++pass) {
            float c[2][8][4];
            #pragma unroll
            for (int t = 0; t < 2; ++t)
                #pragma unroll
                for (int nt = 0; nt < 8; ++nt)
                    #pragma unroll
                    for (int q = 0; q < 4; ++q) c[t][nt][q] = 0.f;

            #pragma unroll 2
            for (int ks = 0; ks < 8; ++ks) {
                int kp = ks * 8 + ak;
                uint32_t ah0[4], al0[4], ah1[4], al1[4];
                ah0[0] = sAhi[ar * PS1 + kp];
                ah0[1] = sAhi[(ar + 8) * PS1 + kp];
                ah0[2] = sAhi[ar * PS1 + kp + 4];
                ah0[3] = sAhi[(ar + 8) * PS1 + kp + 4];
                al0[0] = sAlo[ar * PS1 + kp];
                al0[1] = sAlo[(ar + 8) * PS1 + kp];
                al0[2] = sAlo[ar * PS1 + kp + 4];
                al0[3] = sAlo[(ar + 8) * PS1 + kp + 4];
                ah1[0] = sAhi[(ar + 16) * PS1 + kp];
                ah1[1] = sAhi[(ar + 24) * PS1 + kp];
                ah1[2] = sAhi[(ar + 16) * PS1 + kp + 4];
                ah1[3] = sAhi[(ar + 24) * PS1 + kp + 4];
                al1[0] = sAlo[(ar + 16) * PS1 + kp];
                al1[1] = sAlo[(ar + 24) * PS1 + kp];
                al1[2] = sAlo[(ar + 16) * PS1 + kp + 4];
                al1[3] = sAlo[(ar + 24) * PS1 + kp + 4];
                #pragma unroll
                for (int nt = 0; nt < 8; ++nt) {
                    int ntile = pass * 8 + nt;
                    uint4 v = __ldg(Bm + (size_t)(ntile * 8 + ks) * 32 + lane);
                    mma_f16(c[0][nt], ah0, v.x, v.y);
                    mma_f16(c[0][nt], al0, v.x, v.y);
                    mma_f16(c[0][nt], ah0, v.z, v.w);
                    mma_f16(c[1][nt], ah1, v.x, v.y);
                    mma_f16(c[1][nt], al1, v.x, v.y);
                    mma_f16(c[1][nt], ah1, v.z, v.w);
                }
            }
            #pragma unroll
            for (int t = 0; t < 2; ++t) {
                int rowA = g0 + ar + t * 16, rowB = rowA + 8;
                #pragma unroll
                for (int nt = 0; nt < 8; ++nt) {
                    int cp = ((pass * 8 + nt) * 8 + 2 * ak) >> 1;  // uint32 index
                    if (rowA < nRows)
                        out[(size_t)rowA * 64 + cp] = pack_ff(c[t][nt][0], c[t][nt][1]);
                    if (rowB < nRows)
                        out[(size_t)rowB * 64 + cp] = pack_ff(c[t][nt][2], c[t][nt][3]);
                }
            }
        }
    }
}

// ---------------------------------------------------------------------------
// edge_mma_kernel: merged dirs; fp16 gather (uint2/lane); 3 CTAs/SM.
// ---------------------------------------------------------------------------
struct EdgeDir {
    const uint32_t* pre_a; const uint32_t* pre_b;   // fp16x2 rows (64 u32/row)
    const int* ei; const float* deg;
    const float* w1; const float* b1;
    const uint32_t* CpFrag; const float* bpc;
    const float* wp2; const float* bp2;
    float* hacc; float* einv;
};
struct EdgeParams { EdgeDir d[2]; };

__global__ void __launch_bounds__(256, 3)
edge_mma_kernel(EdgeParams P, const float* __restrict__ pos,
                float* __restrict__ pos_upd, int nE, int N)
{
    extern __shared__ uint32_t smu[];
    uint32_t* sHid = smu;                       // [128][68] fp16x2 pairs
    float* s_w1c = (float*)(smu + 128 * PS1);
    float* s_b1  = s_w1c + 128;
    float* s_bpc = s_b1 + 128;
    float* s_wp2 = s_bpc + 128;
    float* s_rel = s_wp2 + 128;                 // [128*3]
    float* s_dist= s_rel + 384;
    float* s_inv = s_dist + 128;
    float* s_p   = s_inv + 128;                 // [128]
    int*   s_src = (int*)(s_p + 128);
    int*   s_dst = s_src + 128;

    const EdgeDir& D = P.d[blockIdx.z];
    const int tid  = threadIdx.x;
    const int wid  = tid >> 5;
    const int lane = tid & 31;
    const int b    = blockIdx.y;
    const int e0   = blockIdx.x * TEC;
    const size_t bN = (size_t)b * N;

    if (tid < TEC) {
        int e = e0 + tid;
        int s = 0, d = 0;
        float x0 = 0.f, x1 = 0.f, x2 = 0.f, dist = 0.f, inv = 0.f;
        if (e < nE) {
            s = D.ei[e];
            d = D.ei[nE + e];
            const float* ps = pos + (bN + s) * 3;
            const float* pd = pos + (bN + d) * 3;
            x0 = ps[0] - pd[0];
            x1 = ps[1] - pd[1];
            x2 = ps[2] - pd[2];
            dist = sqrtf(x0 * x0 + x1 * x1 + x2 * x2);
            inv  = 1.0f / fmaxf(D.deg[d], 1.0f);
        }
        s_src[tid] = s; s_dst[tid] = d;
        s_rel[tid * 3 + 0] = x0; s_rel[tid * 3 + 1] = x1; s_rel[tid * 3 + 2] = x2;
        s_dist[tid] = dist; s_inv[tid] = inv;
        s_w1c[tid] = D.w1[256 * H_DIM + tid];
        s_b1[tid]  = D.b1[tid];
        s_bpc[tid] = D.bpc[tid];
        s_wp2[tid] = D.wp2[tid];
    }
    __syncthreads();

    // gather (fp16 rows, uint2/lane = 4 cols) -> hidden fp32 -> sHid + RED
    #pragma unroll
    for (int p = 0; p < 16; p += 4) {
        uint2 va[4], vb[4];
        #pragma unroll
        for (int q = 0; q < 4; ++q) {
            int r = (p + q) * 8 + wid;
            va[q] = __ldg((const uint2*)D.pre_a + (size_t)(bN + s_src[r]) * 32 + lane);
            vb[q] = __ldg((const uint2*)D.pre_b + (size_t)(bN + s_dst[r]) * 32 + lane);
        }
        #pragma unroll
        for (int q = 0; q < 4; ++q) {
            int r = (p + q) * 8 + wid;
            float dd = s_dist[r], inv = s_inv[r];
            float4 wc = *(const float4*)(s_w1c + lane * 4);
            float4 bb = *(const float4*)(s_b1 + lane * 4);
            float2 a01 = up2(va[q].x), a23 = up2(va[q].y);
            float2 b01 = up2(vb[q].x), b23 = up2(vb[q].y);
            float h0 = silu_f(a01.x + b01.x + dd * wc.x + bb.x);
            float h1 = silu_f(a01.y + b01.y + dd * wc.y + bb.y);
            float h2 = silu_f(a23.x + b23.x + dd * wc.z + bb.z);
            float h3 = silu_f(a23.y + b23.y + dd * wc.w + bb.w);
            *(uint2*)(sHid + r * PS1 + 2 * lane) =
                make_uint2(pack_ff(h0, h1), pack_ff(h2, h3));
            float* gp = D.hacc + (bN + s_dst[r]) * H_DIM + lane * 4;
            asm volatile("red.global.add.v4.f32 [%0], {%1, %2, %3, %4};"
                         :: "l"(gp), "f"(h0 * inv), "f"(h1 * inv),
                            "f"(h2 * inv), "f"(h3 * inv) : "memory");
        }
    }
    if (tid < TEC && b == 0 && (e0 + tid) < nE)
        atomicAdd(&D.einv[s_dst[tid]], s_inv[tid]);
    __syncthreads();

    const int ar = wid * 16 + (lane >> 2);
    const int ak = lane & 3;
    float sum0 = 0.f, sum1 = 0.f;
    const uint4* Cp4 = (const uint4*)D.CpFrag;

    #pragma unroll
    for (int pass = 0; pass < 2; ++pass) {
        float c[8][4];
        #pragma unroll
        for (int nt = 0; nt < 8; ++nt)
            #pragma unroll
            for (int q = 0; q < 4; ++q) c[nt][q] = 0.f;

        #pragma unroll 4
        for (int ks = 0; ks < 8; ++ks) {
            uint32_t a[4];
            int kp = ks * 8 + ak;
            a[0] = sHid[ar * PS1 + kp];
            a[1] = sHid[(ar + 8) * PS1 + kp];
            a[2] = sHid[ar * PS1 + kp + 4];
            a[3] = sHid[(ar + 8) * PS1 + kp + 4];
            #pragma unroll
            for (int ntp = 0; ntp < 4; ++ntp) {
                uint4 bv = __ldg(Cp4 + (size_t)pass * 1024
                                 + (size_t)(ks * 4 + ntp) * 32 + lane);
                mma_f16(c[2 * ntp],     a, bv.x, bv.y);
                mma_f16(c[2 * ntp + 1], a, bv.z, bv.w);
            }
        }
        #pragma unroll
        for (int nt = 0; nt < 8; ++nt) {
            int cb = pass * 64 + nt * 8 + 2 * ak;
            float w0 = s_wp2[cb], w1v = s_wp2[cb + 1];
            float q0 = s_bpc[cb], q1 = s_bpc[cb + 1];
            sum0 += silu_f(c[nt][0] + q0) * w0 + silu_f(c[nt][1] + q1) * w1v;
            sum1 += silu_f(c[nt][2] + q0) * w0 + silu_f(c[nt][3] + q1) * w1v;
        }
    }

    sum0 += __shfl_xor_sync(0xFFFFFFFFu, sum0, 1);
    sum0 += __shfl_xor_sync(0xFFFFFFFFu, sum0, 2);
    sum1 += __shfl_xor_sync(0xFFFFFFFFu, sum1, 1);
    sum1 += __shfl_xor_sync(0xFFFFFFFFu, sum1, 2);
    if ((lane & 3) == 0) {
        s_p[ar]     = sum0;
        s_p[ar + 8] = sum1;
    }
    __syncthreads();

    if (tid < TEC && (e0 + tid) < nE) {
        float w = tanh_f(s_p[tid] + D.bp2[0]);
        int d = s_dst[tid];
        float* pp = pos_upd + (bN + d) * 3;
        atomicAdd(&pp[0], w * s_rel[tid * 3 + 0]);
        atomicAdd(&pp[1], w * s_rel[tid * 3 + 1]);
        atomicAdd(&pp[2], w * s_rel[tid * 3 + 2]);
    }
}

// ---------------------------------------------------------------------------
// node2_mma_kernel: split-fp16 node update
// ---------------------------------------------------------------------------
__global__ void __launch_bounds__(256)
node2_mma_kernel(const float* __restrict__ feat,
                 const float* __restrict__ hacc0, const float* __restrict__ hacc1,
                 const uint32_t* __restrict__ nodeFrag,
                 const float* __restrict__ einv0, const float* __restrict__ einv1,
                 const float* __restrict__ bcu0, const float* __restrict__ bcu1,
                 const float* __restrict__ bu1,  const float* __restrict__ bu2,
                 float* __restrict__ outf, int N, int nRows)
{
    extern __shared__ uint32_t smu[];
    uint32_t* sAhi = smu;                   // [64][68]
    uint32_t* sAlo = sAhi + 64 * PS1;
    float* s_eU   = (float*)(smu + 2 * 64 * PS1);   // [64]
    float* s_eD   = s_eU + 64;
    float* s_bias = s_eD + 64;              // 4*128

    const int tid = threadIdx.x;
    const int wid = tid >> 5, lane = tid & 31;
    const int rg = wid & 3, cg = wid >> 2;
    const int ar = rg * 16 + (lane >> 2);
    const int ak = lane & 3;
    const int g0 = blockIdx.x * 64;

    if (tid < 64) {
        int g = g0 + tid;
        float eu = 0.f, ed = 0.f;
        if (g < nRows) {
            int node = g % N;
            eu = einv0[node];
            ed = einv1[node];
        }
        s_eU[tid] = eu; s_eD[tid] = ed;
    }
    if (tid < 128) {
        s_bias[tid]       = bu1[tid];
        s_bias[128 + tid] = bcu0[tid];
        s_bias[256 + tid] = bcu1[tid];
        s_bias[384 + tid] = bu2[tid];
    }

    float c[2][4][4];
    #pragma unroll
    for (int p = 0; p < 2; ++p)
        #pragma unroll
        for (int nt = 0; nt < 4; ++nt)
            #pragma unroll
            for (int q = 0; q < 4; ++q) c[p][nt][q] = 0.f;

    for (int m = 0; m < 3; ++m) {
        const float* src = (m == 0) ? feat : (m == 1) ? hacc0 : hacc1;
        __syncthreads();
        #pragma unroll
        for (int p = 0; p < 8; ++p) {
            int idx = p * 256 + tid;
            int r = idx >> 5, c4 = idx & 31;
            float4 v = make_float4(0.f, 0.f, 0.f, 0.f);
            if (g0 + r < nRows)
                v = __ldg((const float4*)src + (size_t)(g0 + r) * 32 + c4);
            __half hx = __float2half_rn(v.x), hy = __float2half_rn(v.y);
            __half hz = __float2half_rn(v.z), hw = __float2half_rn(v.w);
            *(uint2*)(sAhi + r * PS1 + 2 * c4) =
                make_uint2(pack_hh(hx, hy), pack_hh(hz, hw));
            *(uint2*)(sAlo + r * PS1 + 2 * c4) = make_uint2(
                pack_ff(v.x - __half2float(hx), v.y - __half2float(hy)),
                pack_ff(v.z - __half2float(hz), v.w - __half2float(hw)));
        }
        __syncthreads();

        const uint4* Bm = (const uint4*)(nodeFrag + (size_t)m * 16384);
        #pragma unroll 2
        for (int ks = 0; ks < 8; ++ks) {
            int kp = ks * 8 + ak;
            uint32_t ah[4], al[4];
            ah[0] = sAhi[ar * PS1 + kp];
            ah[1] = sAhi[(ar + 8) * PS1 + kp];
            ah[2] = sAhi[ar * PS1 + kp + 4];
            ah[3] = sAhi[(ar + 8) * PS1 + kp + 4];
            al[0] = sAlo[ar * PS1 + kp];
            al[1] = sAlo[(ar + 8) * PS1 + kp];
            al[2] = sAlo[ar * PS1 + kp + 4];
            al[3] = sAlo[(ar + 8) * PS1 + kp + 4];
            #pragma unroll
            for (int pass = 0; pass < 2; ++pass) {
                #pragma unroll
                for (int nt = 0; nt < 4; ++nt) {
                    int ntile = pass * 8 + cg * 4 + nt;
                    uint4 v = __ldg(Bm + (size_t)(ntile * 8 + ks) * 32 + lane);
                    mma_f16(c[pass][nt], ah, v.x, v.y);
                    mma_f16(c[pass][nt], al, v.x, v.y);
                    mma_f16(c[pass][nt], ah, v.z, v.w);
                }
            }
        }
    }
    __syncthreads();
    {
        float eu0 = s_eU[ar],     ed0 = s_eD[ar];
        float eu1 = s_eU[ar + 8], ed1 = s_eD[ar + 8];
        #pragma unroll
        for (int pass = 0; pass < 2; ++pass) {
            #pragma unroll
            for (int nt = 0; nt < 4; ++nt) {
                int col = (pass * 8 + cg * 4 + nt) * 8 + 2 * ak;
                int kp  = col >> 1;
                float bA = s_bias[col],        bB = s_bias[col + 1];
                float cA0 = s_bias[128 + col], cA1 = s_bias[128 + col + 1];
                float cB0 = s_bias[256 + col], cB1 = s_bias[256 + col + 1];
                float v00 = silu_f(c[pass][nt][0] + bA + eu0 * cA0 + ed0 * cB0);
                float v01 = silu_f(c[pass][nt][1] + bB + eu0 * cA1 + ed0 * cB1);
                float v10 = silu_f(c[pass][nt][2] + bA + eu1 * cA0 + ed1 * cB0);
                float v11 = silu_f(c[pass][nt][3] + bB + eu1 * cA1 + ed1 * cB1);
                __half h00 = __float2half_rn(v00), h01 = __float2half_rn(v01);
                __half h10 = __float2half_rn(v10), h11 = __float2half_rn(v11);
                sAhi[ar * PS1 + kp]       = pack_hh(h00, h01);
                sAhi[(ar + 8) * PS1 + kp] = pack_hh(h10, h11);
                sAlo[ar * PS1 + kp] = pack_ff(
                    v00 - __half2float(h00), v01 - __half2float(h01));
                sAlo[(ar + 8) * PS1 + kp] = pack_ff(
                    v10 - __half2float(h10), v11 - __half2float(h11));
            }
        }
    }
    __syncthreads();

    #pragma unroll
    for (int p = 0; p < 2; ++p)
        #pragma unroll
        for (int nt = 0; nt < 4; ++nt)
            #pragma unroll
            for (int q = 0; q < 4; ++q) c[p][nt][q] = 0.f;

    {
        const uint4* Bm = (const uint4*)(nodeFrag + (size_t)3 * 16384);
        #pragma unroll 2
        for (int ks = 0; ks < 8; ++ks) {
            int kp = ks * 8 + ak;
            uint32_t ah[4], al[4];
            ah[0] = sAhi[ar * PS1 + kp];
            ah[1] = sAhi[(ar + 8) * PS1 + kp];
            ah[2] = sAhi[ar * PS1 + kp + 4];
            ah[3] = sAhi[(ar + 8) * PS1 + kp + 4];
            al[0] = sAlo[ar * PS1 + kp];
            al[1] = sAlo[(ar + 8) * PS1 + kp];
            al[2] = sAlo[ar * PS1 + kp + 4];
            al[3] = sAlo[(ar + 8) * PS1 + kp + 4];
            #pragma unroll
            for (int pass = 0; pass < 2; ++pass) {
                #pragma unroll
                for (int nt = 0; nt < 4; ++nt) {
                    int ntile = pass * 8 + cg * 4 + nt;
                    uint4 v = __ldg(Bm + (size_t)(ntile * 8 + ks) * 32 + lane);
                    mma_f16(c[pass][nt], ah, v.x, v.y);
                    mma_f16(c[pass][nt], al, v.x, v.y);
                    mma_f16(c[pass][nt], ah, v.z, v.w);
                }
            }
        }
    }
    {
        int gA = g0 + ar, gB = g0 + ar + 8;
        #pragma unroll
        for (int pass = 0; pass < 2; ++pass) {
            #pragma unroll
            for (int nt = 0; nt < 4; ++nt) {
                int col = (pass * 8 + cg * 4 + nt) * 8 + 2 * ak;
                float bA = s_bias[384 + col], bB = s_bias[384 + col + 1];
                if (gA < nRows) {
                    size_t o = (size_t)gA * H_DIM + col;
                    float2 f = *(const float2*)&feat[o];
                    *(float2*)&outf[o] = make_float2(
                        f.x + c[pass][nt][0] + bA, f.y + c[pass][nt][1] + bB);
                }
                if (gB < nRows) {
                    size_t o = (size_t)gB * H_DIM + col;
                    float2 f = *(const float2*)&feat[o];
                    *(float2*)&outf[o] = make_float2(
                        f.x + c[pass][nt][2] + bA, f.y + c[pass][nt][3] + bB);
                }
            }
        }
    }
}

__global__ void pos_kernel(const float* __restrict__ pos,
                           const float* __restrict__ pos_upd,
                           float* __restrict__ out, int n)
{
    int i = blockIdx.x * blockDim.x + threadIdx.x;
    if (i < n) out[i] = pos[i] + 0.5f * pos_upd[i];
}

extern "C" void kernel_launch(void* const* d_in, const int* in_sizes, int n_in,
                              void* d_out, int out_size)
{
    const float* feat   = (const float*)d_in[0];
    const float* pos    = (const float*)d_in[1];
    const int*   ei_up  = (const int*)d_in[2];
    const int*   ei_dn  = (const int*)d_in[3];
    const float* deg_up = (const float*)d_in[4];
    const float* deg_dn = (const float*)d_in[5];

    const float* w1u  = (const float*)d_in[6];
    const float* b1u  = (const float*)d_in[7];
    const float* w2u  = (const float*)d_in[8];
    const float* b2u  = (const float*)d_in[9];
    const float* wp1u = (const float*)d_in[10];
    const float* bp1u = (const float*)d_in[11];
    const float* wp2u = (const float*)d_in[12];
    const float* bp2u = (const float*)d_in[13];

    const float* w1d  = (const float*)d_in[14];
    const float* b1d  = (const float*)d_in[15];
    const float* w2d  = (const float*)d_in[16];
    const float* b2d  = (const float*)d_in[17];
    const float* wp1d = (const float*)d_in[18];
    const float* bp1d = (const float*)d_in[19];
    const float* wp2d = (const float*)d_in[20];
    const float* bp2d = (const float*)d_in[21];

    const float* wu1 = (const float*)d_in[22];
    const float* bu1 = (const float*)d_in[23];
    const float* wu2 = (const float*)d_in[24];
    const float* bu2 = (const float*)d_in[25];

    int E = in_sizes[2] / 2;
    int N = in_sizes[4];
    int B = in_sizes[0] / (N * H_DIM);
    int nRows = B * N;

    float *hacc, *einv, *pos_upd, *bpc, *bcu;
    uint32_t *pre, *CpFrag, *preFrag, *nodeFrag;
    cudaGetSymbolAddress((void**)&pre,      g_pre);
    cudaGetSymbolAddress((void**)&hacc,     g_hacc);
    cudaGetSymbolAddress((void**)&einv,     g_einv);
    cudaGetSymbolAddress((void**)&pos_upd,  g_pos_upd);
    cudaGetSymbolAddress((void**)&CpFrag,   g_CpFrag);
    cudaGetSymbolAddress((void**)&bpc,      g_bpc);
    cudaGetSymbolAddress((void**)&bcu,      g_bcu);
    cudaGetSymbolAddress((void**)&preFrag,  g_preFrag);
    cudaGetSymbolAddress((void**)&nodeFrag, g_nodeFrag);

    const size_t PS = (size_t)MAX_BN * 64;
    uint32_t* pre_au = pre;
    uint32_t* pre_bu = pre + PS;
    uint32_t* pre_ad = pre + 2 * PS;
    uint32_t* pre_bd = pre + 3 * PS;
    const size_t HPS = (size_t)MAX_BN * H_DIM;
    float* hacc_u = hacc;
    float* hacc_d = hacc + HPS;
    float* einv_u = einv;
    float* einv_d = einv + MAX_N;

    cudaMemsetAsync(hacc, 0, 2 * HPS * sizeof(float));
    cudaMemsetAsync(einv, 0, 2 * MAX_N * sizeof(float));
    cudaMemsetAsync(pos_upd, 0, (size_t)nRows * 3 * sizeof(float));

    int smemPre  = 2 * 128 * PS1 * 4;                           // 69632 B
    int smemEdge = 128 * PS1 * 4
                 + (512 + 384 + 128 + 128 + 128) * 4 + 256 * 4; // 41216 B
    int smemNode = (2 * 64 * PS1 + 128 + 512) * 4;              // 37376 B
    cudaFuncSetAttribute(pre_mma_kernel,
                         cudaFuncAttributeMaxDynamicSharedMemorySize, smemPre);
    cudaFuncSetAttribute(edge_mma_kernel,
                         cudaFuncAttributeMaxDynamicSharedMemorySize, smemEdge);
    cudaFuncSetAttribute(node2_mma_kernel,
                         cudaFuncAttributeMaxDynamicSharedMemorySize, smemNode);

    combine_kernel<<<dim3(65, 4), H_DIM>>>(
        w2u, wp1u, b2u, bp1u, w2d, wp1d, b2d, bp1d, wu1,
        CpFrag, nodeFrag, bpc, bcu);

    fragw_kernel<<<dim3(64, 6), H_DIM>>>(w1u, w1d, wu1, wu2,
                                         preFrag, nodeFrag);

    pre_mma_kernel<<<(nRows + 127) / 128, 256, smemPre>>>(
        feat, preFrag, pre_au, pre_bu, pre_ad, pre_bd, nRows);

    EdgeParams EP;
    EP.d[0] = { pre_au, pre_bu, ei_up, deg_up, w1u, b1u,
                CpFrag,        bpc,         wp2u, bp2u, hacc_u, einv_u };
    EP.d[1] = { pre_ad, pre_bd, ei_dn, deg_dn, w1d, b1d,
                CpFrag + 8192, bpc + H_DIM, wp2d, bp2d, hacc_d, einv_d };

    dim3 egrid((E + TEC - 1) / TEC, B, 2);
    edge_mma_kernel<<<egrid, 256, smemEdge>>>(EP, pos, pos_upd, E, N);

    node2_mma_kernel<<<(nRows + 63) / 64, 256, smemNode>>>(
        feat, hacc_u, hacc_d, nodeFrag, einv_u, einv_d,
        bcu, bcu + H_DIM, bu1, bu2, (float*)d_out, N, nRows);

    size_t featN = (size_t)nRows * H_DIM;
    int pn = nRows * 3;
    pos_kernel<<<(pn + 255) / 256, 256>>>(
        pos, pos_upd, (float*)d_out + featN, pn);
}

// round 14
// speedup vs baseline: 11.0876x; 1.0146x over previous
#include <cuda_runtime.h>
#include <cuda_fp16.h>
#include <math.h>
#include <cstdint>

#define H_DIM 128
#define TEC 256        // edges per block (edge kernel)
#define PS1 68         // pair-row stride (uint32 units) for fp16x2 tiles

#define MAX_B 2
#define MAX_N 20000
#define MAX_BN (MAX_B * MAX_N)

// ---------------------------------------------------------------------------
// Scratch (allocation-free rule: __device__ globals)
// ---------------------------------------------------------------------------
__device__ __align__(128) uint32_t g_pre[4][(size_t)MAX_BN * 64]; // fp16x2 pairs
__device__ __align__(128) float g_hacc[2][(size_t)MAX_BN * H_DIM];
__device__ __align__(128) float g_einv[2][MAX_N];
__device__ __align__(128) float g_pos_upd[(size_t)MAX_BN * 3];
__device__ __align__(128) uint32_t g_CpFrag[2][8192];     // fp16 hi, paired-ntile uint4 layout
__device__ __align__(128) float g_bpc[2][H_DIM];
__device__ __align__(128) float g_bcu[2][H_DIM];
__device__ __align__(128) uint32_t g_preFrag[4][16384];   // fp16 hi/lo uint4 layout
__device__ __align__(128) uint32_t g_nodeFrag[4][16384];  // wu1top,Cu0,Cu1,wu2

// silu via single-MUFU tanh.approx: silu(x) = 0.5x + 0.5x*tanh(x/2)
__device__ __forceinline__ float silu_f(float v) {
    float t;
    asm("tanh.approx.f32 %0, %1;" : "=f"(t) : "f"(0.5f * v));
    float hv = 0.5f * v;
    return fmaf(hv, t, hv);
}
__device__ __forceinline__ float tanh_f(float v) {
    float t;
    asm("tanh.approx.f32 %0, %1;" : "=f"(t) : "f"(v));
    return t;
}

// ---- fp16 mma.sync helpers --------------------------------------------------
__device__ __forceinline__ void mma_f16(float c[4], const uint32_t a[4],
                                        uint32_t b0, uint32_t b1) {
    asm volatile(
        "mma.sync.aligned.m16n8k16.row.col.f32.f16.f16.f32 "
        "{%0,%1,%2,%3}, {%4,%5,%6,%7}, {%8,%9}, {%0,%1,%2,%3};"
        : "+f"(c[0]), "+f"(c[1]), "+f"(c[2]), "+f"(c[3])
        : "r"(a[0]), "r"(a[1]), "r"(a[2]), "r"(a[3]), "r"(b0), "r"(b1));
}
__device__ __forceinline__ uint32_t pack_hh(__half lo, __half hi) {
    __half2 h = __halves2half2(lo, hi);
    return *reinterpret_cast<uint32_t*>(&h);
}
__device__ __forceinline__ uint32_t pack_ff(float e, float o) {
    __half2 h = __floats2half2_rn(e, o);
    return *reinterpret_cast<uint32_t*>(&h);
}
__device__ __forceinline__ float2 up2(uint32_t v) {
    return __half22float2(*reinterpret_cast<__half2*>(&v));
}

// ---------------------------------------------------------------------------
// combine_kernel: grid (65, 4), 128 thr.
// ---------------------------------------------------------------------------
__global__ void combine_kernel(
    const float* __restrict__ w2u, const float* __restrict__ wp1u,
    const float* __restrict__ b2u, const float* __restrict__ bp1u,
    const float* __restrict__ w2d, const float* __restrict__ wp1d,
    const float* __restrict__ b2d, const float* __restrict__ bp1d,
    const float* __restrict__ wu1,
    uint32_t* __restrict__ CpFrag, uint32_t* __restrict__ nodeFrag,
    float* __restrict__ bpc, float* __restrict__ bcu)
{
    const float* wu1b = wu1 + 128 * H_DIM;
    const float* A; const float* Bm; const float* bvec; const float* badd;
    uint32_t* C; float* bout; bool split;
    switch (blockIdx.y) {
        case 0:  A = w2u; Bm = wp1u; bvec = b2u; badd = bp1u;
                 C = CpFrag;               bout = bpc;         split = false; break;
        case 1:  A = w2d; Bm = wp1d; bvec = b2d; badd = bp1d;
                 C = CpFrag + 8192;        bout = bpc + H_DIM; split = false; break;
        case 2:  A = w2u; Bm = wu1b; bvec = b2u; badd = 0;
                 C = nodeFrag + 1 * 16384; bout = bcu;         split = true;  break;
        default: A = w2d; Bm = wu1b; bvec = b2d; badd = 0;
                 C = nodeFrag + 2 * 16384; bout = bcu + H_DIM; split = true;  break;
    }
    int i2 = blockIdx.x;
    int j  = threadIdx.x;
    if (i2 == 64) {
        float s = 0.f;
        #pragma unroll 8
        for (int k = 0; k < H_DIM; ++k) s += bvec[k] * Bm[k * H_DIM + j];
        bout[j] = s + (badd ? badd[j] : 0.f);
        return;
    }
    float s0 = 0.f, s1 = 0.f;
    const float* a0r = A + (size_t)(2 * i2) * H_DIM;
    const float* a1r = a0r + H_DIM;
    #pragma unroll 8
    for (int k = 0; k < H_DIM; ++k) {
        float b = Bm[k * H_DIM + j];
        s0 += a0r[k] * b;
        s1 += a1r[k] * b;
    }
    int ks = i2 >> 3, m = i2 & 7;
    int lanep = m & 3, reg = m >> 2;
    int nn = j & 7;
    if (split) {
        __half h0 = __float2half_rn(s0), h1 = __float2half_rn(s1);
        __half l0 = __float2half_rn(s0 - __half2float(h0));
        __half l1 = __float2half_rn(s1 - __half2float(h1));
        int ntile = j >> 3;
        size_t base = ((size_t)(ntile * 8 + ks) * 32 + nn * 4 + lanep) * 4;
        C[base + reg]     = pack_hh(h0, h1);
        C[base + 2 + reg] = pack_hh(l0, l1);
    } else {
        int ntile = j >> 3, pass = ntile >> 3, ntl = ntile & 7;
        size_t idx = (size_t)pass * 4096
                   + ((size_t)(ks * 4 + (ntl >> 1)) * 32 + nn * 4 + lanep) * 4
                   + (ntl & 1) * 2 + reg;
        C[idx] = pack_ff(s0, s1);
    }
}

// ---------------------------------------------------------------------------
// fragw_kernel: grid (64, 6), 128 thr.
// ---------------------------------------------------------------------------
__global__ void fragw_kernel(const float* __restrict__ w1u,
                             const float* __restrict__ w1d,
                             const float* __restrict__ wu1,
                             const float* __restrict__ wu2,
                             uint32_t* __restrict__ preFrag,
                             uint32_t* __restrict__ nodeFrag)
{
    int y = blockIdx.y;
    const float* W; uint32_t* out;
    switch (y) {
        case 0: W = w1u;                out = preFrag;              break;
        case 1: W = w1u + 128 * H_DIM;  out = preFrag + 16384;      break;
        case 2: W = w1d;                out = preFrag + 2 * 16384;  break;
        case 3: W = w1d + 128 * H_DIM;  out = preFrag + 3 * 16384;  break;
        case 4: W = wu1;                out = nodeFrag;             break;
        default: W = wu2;               out = nodeFrag + 3 * 16384; break;
    }
    int i2 = blockIdx.x;
    int j  = threadIdx.x;
    float x0 = W[(size_t)(2 * i2) * H_DIM + j];
    float x1 = W[(size_t)(2 * i2 + 1) * H_DIM + j];
    __half h0 = __float2half_rn(x0), h1 = __float2half_rn(x1);
    __half l0 = __float2half_rn(x0 - __half2float(h0));
    __half l1 = __float2half_rn(x1 - __half2float(h1));
    int ks = i2 >> 3, m = i2 & 7;
    int lanep = m & 3, reg = m >> 2;
    int ntile = j >> 3, nn = j & 7;
    size_t base = ((size_t)(ntile * 8 + ks) * 32 + nn * 4 + lanep) * 4;
    out[base + reg]     = pack_hh(h0, h1);
    out[base + 2 + reg] = pack_hh(l0, l1);
}

// ---------------------------------------------------------------------------
// pre_mma_kernel: 128-row blocks; outputs fp16x2 (uint32 per col-pair).
// ---------------------------------------------------------------------------
__global__ void __launch_bounds__(256)
pre_mma_kernel(const float* __restrict__ feat, const uint32_t* __restrict__ frag,
               uint32_t* __restrict__ p0, uint32_t* __restrict__ p1,
               uint32_t* __restrict__ p2, uint32_t* __restrict__ p3, int nRows)
{
    extern __shared__ uint32_t smu[];
    uint32_t* sAhi = smu;                  // [128][68] pairs
    uint32_t* sAlo = sAhi + 128 * PS1;

    const int tid = threadIdx.x;
    const int wid = tid >> 5, lane = tid & 31;
    const int wg = wid >> 2;               // matrix half
    const int rw = wid & 3;                // 32-row group
    const int ar = rw * 32 + (lane >> 2);
    const int ak = lane & 3;
    const int g0 = blockIdx.x * 128;

    #pragma unroll
    for (int p = 0; p < 16; ++p) {
        int idx = p * 256 + tid;
        int r = idx >> 5, c4 = idx & 31;
        float4 v = make_float4(0.f, 0.f, 0.f, 0.f);
        if (g0 + r < nRows)
            v = __ldg((const float4*)feat + (size_t)(g0 + r) * 32 + c4);
        __half hx = __float2half_rn(v.x), hy = __float2half_rn(v.y);
        __half hz = __float2half_rn(v.z), hw = __float2half_rn(v.w);
        *(uint2*)(sAhi + r * PS1 + 2 * c4) =
            make_uint2(pack_hh(hx, hy), pack_hh(hz, hw));
        *(uint2*)(sAlo + r * PS1 + 2 * c4) = make_uint2(
            pack_ff(v.x - __half2float(hx), v.y - __half2float(hy)),
            pack_ff(v.z - __half2float(hz), v.w - __half2float(hw)));
    }
    __syncthreads();

    uint32_t* outs[4] = {p0, p1, p2, p3};

    #pragma unroll
    for (int m2 = 0; m2 < 2; ++m2) {
        int m = wg * 2 + m2;
        const uint4* Bm = (const uint4*)frag + (size_t)m * 4096;
        uint32_t* out = outs[m];
        #pragma unroll
        for (int pass = 0; pass < 2; ++pass) {
            float c[2][8][4];
            #pragma unroll
            for (int t = 0; t < 2; ++t)
                #pragma unroll
                for (int nt = 0; nt < 8; ++nt)
                    #pragma unroll
                    for (int q = 0; q < 4; ++q) c[t][nt][q] = 0.f;

            #pragma unroll 2
            for (int ks = 0; ks < 8; ++ks) {
                int kp = ks * 8 + ak;
                uint32_t ah0[4], al0[4], ah1[4], al1[4];
                ah0[0] = sAhi[ar * PS1 + kp];
                ah0[1] = sAhi[(ar + 8) * PS1 + kp];
                ah0[2] = sAhi[ar * PS1 + kp + 4];
                ah0[3] = sAhi[(ar + 8) * PS1 + kp + 4];
                al0[0] = sAlo[ar * PS1 + kp];
                al0[1] = sAlo[(ar + 8) * PS1 + kp];
                al0[2] = sAlo[ar * PS1 + kp + 4];
                al0[3] = sAlo[(ar + 8) * PS1 + kp + 4];
                ah1[0] = sAhi[(ar + 16) * PS1 + kp];
                ah1[1] = sAhi[(ar + 24) * PS1 + kp];
                ah1[2] = sAhi[(ar + 16) * PS1 + kp + 4];
                ah1[3] = sAhi[(ar + 24) * PS1 + kp + 4];
                al1[0] = sAlo[(ar + 16) * PS1 + kp];
                al1[1] = sAlo[(ar + 24) * PS1 + kp];
                al1[2] = sAlo[(ar + 16) * PS1 + kp + 4];
                al1[3] = sAlo[(ar + 24) * PS1 + kp + 4];
                #pragma unroll
                for (int nt = 0; nt < 8; ++nt) {
                    int ntile = pass * 8 + nt;
                    uint4 v = __ldg(Bm + (size_t)(ntile * 8 + ks) * 32 + lane);
                    mma_f16(c[0][nt], ah0, v.x, v.y);
                    mma_f16(c[0][nt], al0, v.x, v.y);
                    mma_f16(c[0][nt], ah0, v.z, v.w);
                    mma_f16(c[1][nt], ah1, v.x, v.y);
                    mma_f16(c[1][nt], al1, v.x, v.y);
                    mma_f16(c[1][nt], ah1, v.z, v.w);
                }
            }
            #pragma unroll
            for (int t = 0; t < 2; ++t) {
                int rowA = g0 + ar + t * 16, rowB = rowA + 8;
                #pragma unroll
                for (int nt = 0; nt < 8; ++nt) {
                    int cp = ((pass * 8 + nt) * 8 + 2 * ak) >> 1;  // uint32 index
                    if (rowA < nRows)
                        out[(size_t)rowA * 64 + cp] = pack_ff(c[t][nt][0], c[t][nt][1]);
                    if (rowB < nRows)
                        out[(size_t)rowB * 64 + cp] = pack_ff(c[t][nt][2], c[t][nt][3]);
                }
            }
        }
    }
}

// ---------------------------------------------------------------------------
// edge_mma_kernel: merged dirs; 256 edges/block; each warp owns 32 rows so
// every B fragment load feeds both 16-row tiles (B bytes/edge halved).
// ---------------------------------------------------------------------------
struct EdgeDir {
    const uint32_t* pre_a; const uint32_t* pre_b;   // fp16x2 rows (64 u32/row)
    const int* ei; const float* deg;
    const float* w1; const float* b1;
    const uint32_t* CpFrag; const float* bpc;
    const float* wp2; const float* bp2;
    float* hacc; float* einv;
};
struct EdgeParams { EdgeDir d[2]; };

__global__ void __launch_bounds__(256, 2)
edge_mma_kernel(EdgeParams P, const float* __restrict__ pos,
                float* __restrict__ pos_upd, int nE, int N)
{
    extern __shared__ uint32_t smu[];
    uint32_t* sHid = smu;                       // [256][68] fp16x2 pairs
    float* s_w1c = (float*)(smu + 256 * PS1);
    float* s_b1  = s_w1c + 128;
    float* s_bpc = s_b1 + 128;
    float* s_wp2 = s_bpc + 128;
    float* s_rel = s_wp2 + 128;                 // [256*3]
    float* s_dist= s_rel + 768;
    float* s_inv = s_dist + 256;
    float* s_p   = s_inv + 256;                 // [256]
    int*   s_src = (int*)(s_p + 256);
    int*   s_dst = s_src + 256;

    const EdgeDir& D = P.d[blockIdx.z];
    const int tid  = threadIdx.x;
    const int wid  = tid >> 5;
    const int lane = tid & 31;
    const int b    = blockIdx.y;
    const int e0   = blockIdx.x * TEC;
    const size_t bN = (size_t)b * N;

    {
        int e = e0 + tid;
        int s = 0, d = 0;
        float x0 = 0.f, x1 = 0.f, x2 = 0.f, dist = 0.f, inv = 0.f;
        if (e < nE) {
            s = D.ei[e];
            d = D.ei[nE + e];
            const float* ps = pos + (bN + s) * 3;
            const float* pd = pos + (bN + d) * 3;
            x0 = ps[0] - pd[0];
            x1 = ps[1] - pd[1];
            x2 = ps[2] - pd[2];
            dist = sqrtf(x0 * x0 + x1 * x1 + x2 * x2);
            inv  = 1.0f / fmaxf(D.deg[d], 1.0f);
        }
        s_src[tid] = s; s_dst[tid] = d;
        s_rel[tid * 3 + 0] = x0; s_rel[tid * 3 + 1] = x1; s_rel[tid * 3 + 2] = x2;
        s_dist[tid] = dist; s_inv[tid] = inv;
        if (tid < 128) {
            s_w1c[tid] = D.w1[256 * H_DIM + tid];
            s_b1[tid]  = D.b1[tid];
            s_bpc[tid] = D.bpc[tid];
            s_wp2[tid] = D.wp2[tid];
        }
    }
    __syncthreads();

    // gather (fp16 rows, uint2/lane = 4 cols) -> hidden fp32 -> sHid + RED
    #pragma unroll
    for (int p = 0; p < 32; p += 4) {
        uint2 va[4], vb[4];
        #pragma unroll
        for (int q = 0; q < 4; ++q) {
            int r = (p + q) * 8 + wid;
            va[q] = __ldg((const uint2*)D.pre_a + (size_t)(bN + s_src[r]) * 32 + lane);
            vb[q] = __ldg((const uint2*)D.pre_b + (size_t)(bN + s_dst[r]) * 32 + lane);
        }
        #pragma unroll
        for (int q = 0; q < 4; ++q) {
            int r = (p + q) * 8 + wid;
            float dd = s_dist[r], inv = s_inv[r];
            float4 wc = *(const float4*)(s_w1c + lane * 4);
            float4 bb = *(const float4*)(s_b1 + lane * 4);
            float2 a01 = up2(va[q].x), a23 = up2(va[q].y);
            float2 b01 = up2(vb[q].x), b23 = up2(vb[q].y);
            float h0 = silu_f(a01.x + b01.x + dd * wc.x + bb.x);
            float h1 = silu_f(a01.y + b01.y + dd * wc.y + bb.y);
            float h2 = silu_f(a23.x + b23.x + dd * wc.z + bb.z);
            float h3 = silu_f(a23.y + b23.y + dd * wc.w + bb.w);
            *(uint2*)(sHid + r * PS1 + 2 * lane) =
                make_uint2(pack_ff(h0, h1), pack_ff(h2, h3));
            float* gp = D.hacc + (bN + s_dst[r]) * H_DIM + lane * 4;
            asm volatile("red.global.add.v4.f32 [%0], {%1, %2, %3, %4};"
                         :: "l"(gp), "f"(h0 * inv), "f"(h1 * inv),
                            "f"(h2 * inv), "f"(h3 * inv) : "memory");
        }
    }
    if (b == 0 && (e0 + tid) < nE)
        atomicAdd(&D.einv[s_dst[tid]], s_inv[tid]);
    __syncthreads();

    // mma: warp owns rows [32*wid, 32*wid+32) = two 16-row tiles
    const int arb = wid * 32 + (lane >> 2);
    const int ak  = lane & 3;
    float sum[4] = {0.f, 0.f, 0.f, 0.f};
    const uint4* Cp4 = (const uint4*)D.CpFrag;

    #pragma unroll
    for (int pass = 0; pass < 2; ++pass) {
        float c[2][8][4];
        #pragma unroll
        for (int t = 0; t < 2; ++t)
            #pragma unroll
            for (int nt = 0; nt < 8; ++nt)
                #pragma unroll
                for (int q = 0; q < 4; ++q) c[t][nt][q] = 0.f;

        #pragma unroll 2
        for (int ks = 0; ks < 8; ++ks) {
            int kp = ks * 8 + ak;
            uint4 bv[4];
            #pragma unroll
            for (int ntp = 0; ntp < 4; ++ntp)
                bv[ntp] = __ldg(Cp4 + (size_t)pass * 1024
                                + (size_t)(ks * 4 + ntp) * 32 + lane);
            #pragma unroll
            for (int t = 0; t < 2; ++t) {
                int ar = arb + t * 16;
                uint32_t a[4];
                a[0] = sHid[ar * PS1 + kp];
                a[1] = sHid[(ar + 8) * PS1 + kp];
                a[2] = sHid[ar * PS1 + kp + 4];
                a[3] = sHid[(ar + 8) * PS1 + kp + 4];
                #pragma unroll
                for (int ntp = 0; ntp < 4; ++ntp) {
                    mma_f16(c[t][2 * ntp],     a, bv[ntp].x, bv[ntp].y);
                    mma_f16(c[t][2 * ntp + 1], a, bv[ntp].z, bv[ntp].w);
                }
            }
        }
        #pragma unroll
        for (int t = 0; t < 2; ++t) {
            #pragma unroll
            for (int nt = 0; nt < 8; ++nt) {
                int cb = pass * 64 + nt * 8 + 2 * ak;
                float w0 = s_wp2[cb], w1v = s_wp2[cb + 1];
                float q0 = s_bpc[cb], q1 = s_bpc[cb + 1];
                sum[2 * t]     += silu_f(c[t][nt][0] + q0) * w0
                                + silu_f(c[t][nt][1] + q1) * w1v;
                sum[2 * t + 1] += silu_f(c[t][nt][2] + q0) * w0
                                + silu_f(c[t][nt][3] + q1) * w1v;
            }
        }
    }

    #pragma unroll
    for (int i = 0; i < 4; ++i) {
        sum[i] += __shfl_xor_sync(0xFFFFFFFFu, sum[i], 1);
        sum[i] += __shfl_xor_sync(0xFFFFFFFFu, sum[i], 2);
    }
    if (ak == 0) {
        s_p[arb]      = sum[0];
        s_p[arb + 8]  = sum[1];
        s_p[arb + 16] = sum[2];
        s_p[arb + 24] = sum[3];
    }
    __syncthreads();

    if ((e0 + tid) < nE) {
        float w = tanh_f(s_p[tid] + D.bp2[0]);
        int d = s_dst[tid];
        float* pp = pos_upd + (bN + d) * 3;
        atomicAdd(&pp[0], w * s_rel[tid * 3 + 0]);
        atomicAdd(&pp[1], w * s_rel[tid * 3 + 1]);
        atomicAdd(&pp[2], w * s_rel[tid * 3 + 2]);
    }
}

// ---------------------------------------------------------------------------
// node2_mma_kernel: split-fp16 node update (unchanged from R13)
// ---------------------------------------------------------------------------
__global__ void __launch_bounds__(256)
node2_mma_kernel(const float* __restrict__ feat,
                 const float* __restrict__ hacc0, const float* __restrict__ hacc1,
                 const uint32_t* __restrict__ nodeFrag,
                 const float* __restrict__ einv0, const float* __restrict__ einv1,
                 const float* __restrict__ bcu0, const float* __restrict__ bcu1,
                 const float* __restrict__ bu1,  const float* __restrict__ bu2,
                 float* __restrict__ outf, int N, int nRows)
{
    extern __shared__ uint32_t smu[];
    uint32_t* sAhi = smu;                   // [64][68]
    uint32_t* sAlo = sAhi + 64 * PS1;
    float* s_eU   = (float*)(smu + 2 * 64 * PS1);   // [64]
    float* s_eD   = s_eU + 64;
    float* s_bias = s_eD + 64;              // 4*128

    const int tid = threadIdx.x;
    const int wid = tid >> 5, lane = tid & 31;
    const int rg = wid & 3, cg = wid >> 2;
    const int ar = rg * 16 + (lane >> 2);
    const int ak = lane & 3;
    const int g0 = blockIdx.x * 64;

    if (tid < 64) {
        int g = g0 + tid;
        float eu = 0.f, ed = 0.f;
        if (g < nRows) {
            int node = g % N;
            eu = einv0[node];
            ed = einv1[node];
        }
        s_eU[tid] = eu; s_eD[tid] = ed;
    }
    if (tid < 128) {
        s_bias[tid]       = bu1[tid];
        s_bias[128 + tid] = bcu0[tid];
        s_bias[256 + tid] = bcu1[tid];
        s_bias[384 + tid] = bu2[tid];
    }

    float c[2][4][4];
    #pragma unroll
    for (int p = 0; p < 2; ++p)
        #pragma unroll
        for (int nt = 0; nt < 4; ++nt)
            #pragma unroll
            for (int q = 0; q < 4; ++q) c[p][nt][q] = 0.f;

    for (int m = 0; m < 3; ++m) {
        const float* src = (m == 0) ? feat : (m == 1) ? hacc0 : hacc1;
        __syncthreads();
        #pragma unroll
        for (int p = 0; p < 8; ++p) {
            int idx = p * 256 + tid;
            int r = idx >> 5, c4 = idx & 31;
            float4 v = make_float4(0.f, 0.f, 0.f, 0.f);
            if (g0 + r < nRows)
                v = __ldg((const float4*)src + (size_t)(g0 + r) * 32 + c4);
            __half hx = __float2half_rn(v.x), hy = __float2half_rn(v.y);
            __half hz = __float2half_rn(v.z), hw = __float2half_rn(v.w);
            *(uint2*)(sAhi + r * PS1 + 2 * c4) =
                make_uint2(pack_hh(hx, hy), pack_hh(hz, hw));
            *(uint2*)(sAlo + r * PS1 + 2 * c4) = make_uint2(
                pack_ff(v.x - __half2float(hx), v.y - __half2float(hy)),
                pack_ff(v.z - __half2float(hz), v.w - __half2float(hw)));
        }
        __syncthreads();

        const uint4* Bm = (const uint4*)(nodeFrag + (size_t)m * 16384);
        #pragma unroll 2
        for (int ks = 0; ks < 8; ++ks) {
            int kp = ks * 8 + ak;
            uint32_t ah[4], al[4];
            ah[0] = sAhi[ar * PS1 + kp];
            ah[1] = sAhi[(ar + 8) * PS1 + kp];
            ah[2] = sAhi[ar * PS1 + kp + 4];
            ah[3] = sAhi[(ar + 8) * PS1 + kp + 4];
            al[0] = sAlo[ar * PS1 + kp];
            al[1] = sAlo[(ar + 8) * PS1 + kp];
            al[2] = sAlo[ar * PS1 + kp + 4];
            al[3] = sAlo[(ar + 8) * PS1 + kp + 4];
            #pragma unroll
            for (int pass = 0; pass < 2; ++pass) {
                #pragma unroll
                for (int nt = 0; nt < 4; ++nt) {
                    int ntile = pass * 8 + cg * 4 + nt;
                    uint4 v = __ldg(Bm + (size_t)(ntile * 8 + ks) * 32 + lane);
                    mma_f16(c[pass][nt], ah, v.x, v.y);
                    mma_f16(c[pass][nt], al, v.x, v.y);
                    mma_f16(c[pass][nt], ah, v.z, v.w);
                }
            }
        }
    }
    __syncthreads();
    {
        float eu0 = s_eU[ar],     ed0 = s_eD[ar];
        float eu1 = s_eU[ar + 8], ed1 = s_eD[ar + 8];
        #pragma unroll
        for (int pass = 0; pass < 2; ++pass) {
            #pragma unroll
            for (int nt = 0; nt < 4; ++nt) {
                int col = (pass * 8 + cg * 4 + nt) * 8 + 2 * ak;
                int kp  = col >> 1;
                float bA = s_bias[col],        bB = s_bias[col + 1];
                float cA0 = s_bias[128 + col], cA1 = s_bias[128 + col + 1];
                float cB0 = s_bias[256 + col], cB1 = s_bias[256 + col + 1];
                float v00 = silu_f(c[pass][nt][0] + bA + eu0 * cA0 + ed0 * cB0);
                float v01 = silu_f(c[pass][nt][1] + bB + eu0 * cA1 + ed0 * cB1);
                float v10 = silu_f(c[pass][nt][2] + bA + eu1 * cA0 + ed1 * cB0);
                float v11 = silu_f(c[pass][nt][3] + bB + eu1 * cA1 + ed1 * cB1);
                __half h00 = __float2half_rn(v00), h01 = __float2half_rn(v01);
                __half h10 = __float2half_rn(v10), h11 = __float2half_rn(v11);
                sAhi[ar * PS1 + kp]       = pack_hh(h00, h01);
                sAhi[(ar + 8) * PS1 + kp] = pack_hh(h10, h11);
                sAlo[ar * PS1 + kp] = pack_ff(
                    v00 - __half2float(h00), v01 - __half2float(h01));
                sAlo[(ar + 8) * PS1 + kp] = pack_ff(
                    v10 - __half2float(h10), v11 - __half2float(h11));
            }
        }
    }
    __syncthreads();

    #pragma unroll
    for (int p = 0; p < 2; ++p)
        #pragma unroll
        for (int nt = 0; nt < 4; ++nt)
            #pragma unroll
            for (int q = 0; q < 4; ++q) c[p][nt][q] = 0.f;

    {
        const uint4* Bm = (const uint4*)(nodeFrag + (size_t)3 * 16384);
        #pragma unroll 2
        for (int ks = 0; ks < 8; ++ks) {
            int kp = ks * 8 + ak;
            uint32_t ah[4], al[4];
            ah[0] = sAhi[ar * PS1 + kp];
            ah[1] = sAhi[(ar + 8) * PS1 + kp];
            ah[2] = sAhi[ar * PS1 + kp + 4];
            ah[3] = sAhi[(ar + 8) * PS1 + kp + 4];
            al[0] = sAlo[ar * PS1 + kp];
            al[1] = sAlo[(ar + 8) * PS1 + kp];
            al[2] = sAlo[ar * PS1 + kp + 4];
            al[3] = sAlo[(ar + 8) * PS1 + kp + 4];
            #pragma unroll
            for (int pass = 0; pass < 2; ++pass) {
                #pragma unroll
                for (int nt = 0; nt < 4; ++nt) {
                    int ntile = pass * 8 + cg * 4 + nt;
                    uint4 v = __ldg(Bm + (size_t)(ntile * 8 + ks) * 32 + lane);
                    mma_f16(c[pass][nt], ah, v.x, v.y);
                    mma_f16(c[pass][nt], al, v.x, v.y);
                    mma_f16(c[pass][nt], ah, v.z, v.w);
                }
            }
        }
    }
    {
        int gA = g0 + ar, gB = g0 + ar + 8;
        #pragma unroll
        for (int pass = 0; pass < 2; ++pass) {
            #pragma unroll
            for (int nt = 0; nt < 4; ++nt) {
                int col = (pass * 8 + cg * 4 + nt) * 8 + 2 * ak;
                float bA = s_bias[384 + col], bB = s_bias[384 + col + 1];
                if (gA < nRows) {
                    size_t o = (size_t)gA * H_DIM + col;
                    float2 f = *(const float2*)&feat[o];
                    *(float2*)&outf[o] = make_float2(
                        f.x + c[pass][nt][0] + bA, f.y + c[pass][nt][1] + bB);
                }
                if (gB < nRows) {
                    size_t o = (size_t)gB * H_DIM + col;
                    float2 f = *(const float2*)&feat[o];
                    *(float2*)&outf[o] = make_float2(
                        f.x + c[pass][nt][2] + bA, f.y + c[pass][nt][3] + bB);
                }
            }
        }
    }
}

__global__ void pos_kernel(const float* __restrict__ pos,
                           const float* __restrict__ pos_upd,
                           float* __restrict__ out, int n)
{
    int i = blockIdx.x * blockDim.x + threadIdx.x;
    if (i < n) out[i] = pos[i] + 0.5f * pos_upd[i];
}

extern "C" void kernel_launch(void* const* d_in, const int* in_sizes, int n_in,
                              void* d_out, int out_size)
{
    const float* feat   = (const float*)d_in[0];
    const float* pos    = (const float*)d_in[1];
    const int*   ei_up  = (const int*)d_in[2];
    const int*   ei_dn  = (const int*)d_in[3];
    const float* deg_up = (const float*)d_in[4];
    const float* deg_dn = (const float*)d_in[5];

    const float* w1u  = (const float*)d_in[6];
    const float* b1u  = (const float*)d_in[7];
    const float* w2u  = (const float*)d_in[8];
    const float* b2u  = (const float*)d_in[9];
    const float* wp1u = (const float*)d_in[10];
    const float* bp1u = (const float*)d_in[11];
    const float* wp2u = (const float*)d_in[12];
    const float* bp2u = (const float*)d_in[13];

    const float* w1d  = (const float*)d_in[14];
    const float* b1d  = (const float*)d_in[15];
    const float* w2d  = (const float*)d_in[16];
    const float* b2d  = (const float*)d_in[17];
    const float* wp1d = (const float*)d_in[18];
    const float* bp1d = (const float*)d_in[19];
    const float* wp2d = (const float*)d_in[20];
    const float* bp2d = (const float*)d_in[21];

    const float* wu1 = (const float*)d_in[22];
    const float* bu1 = (const float*)d_in[23];
    const float* wu2 = (const float*)d_in[24];
    const float* bu2 = (const float*)d_in[25];

    int E = in_sizes[2] / 2;
    int N = in_sizes[4];
    int B = in_sizes[0] / (N * H_DIM);
    int nRows = B * N;

    float *hacc, *einv, *pos_upd, *bpc, *bcu;
    uint32_t *pre, *CpFrag, *preFrag, *nodeFrag;
    cudaGetSymbolAddress((void**)&pre,      g_pre);
    cudaGetSymbolAddress((void**)&hacc,     g_hacc);
    cudaGetSymbolAddress((void**)&einv,     g_einv);
    cudaGetSymbolAddress((void**)&pos_upd,  g_pos_upd);
    cudaGetSymbolAddress((void**)&CpFrag,   g_CpFrag);
    cudaGetSymbolAddress((void**)&bpc,      g_bpc);
    cudaGetSymbolAddress((void**)&bcu,      g_bcu);
    cudaGetSymbolAddress((void**)&preFrag,  g_preFrag);
    cudaGetSymbolAddress((void**)&nodeFrag, g_nodeFrag);

    const size_t PS = (size_t)MAX_BN * 64;
    uint32_t* pre_au = pre;
    uint32_t* pre_bu = pre + PS;
    uint32_t* pre_ad = pre + 2 * PS;
    uint32_t* pre_bd = pre + 3 * PS;
    const size_t HPS = (size_t)MAX_BN * H_DIM;
    float* hacc_u = hacc;
    float* hacc_d = hacc + HPS;
    float* einv_u = einv;
    float* einv_d = einv + MAX_N;

    cudaMemsetAsync(hacc, 0, 2 * HPS * sizeof(float));
    cudaMemsetAsync(einv, 0, 2 * MAX_N * sizeof(float));
    cudaMemsetAsync(pos_upd, 0, (size_t)nRows * 3 * sizeof(float));

    int smemPre  = 2 * 128 * PS1 * 4;                           // 69632 B
    int smemEdge = 256 * PS1 * 4
                 + (512 + 768 + 256 + 256 + 256) * 4 + 512 * 4; // 79872 B
    int smemNode = (2 * 64 * PS1 + 128 + 512) * 4;              // 37376 B
    cudaFuncSetAttribute(pre_mma_kernel,
                         cudaFuncAttributeMaxDynamicSharedMemorySize, smemPre);
    cudaFuncSetAttribute(edge_mma_kernel,
                         cudaFuncAttributeMaxDynamicSharedMemorySize, smemEdge);
    cudaFuncSetAttribute(node2_mma_kernel,
                         cudaFuncAttributeMaxDynamicSharedMemorySize, smemNode);

    combine_kernel<<<dim3(65, 4), H_DIM>>>(
        w2u, wp1u, b2u, bp1u, w2d, wp1d, b2d, bp1d, wu1,
        CpFrag, nodeFrag, bpc, bcu);

    fragw_kernel<<<dim3(64, 6), H_DIM>>>(w1u, w1d, wu1, wu2,
                                         preFrag, nodeFrag);

    pre_mma_kernel<<<(nRows + 127) / 128, 256, smemPre>>>(
        feat, preFrag, pre_au, pre_bu, pre_ad, pre_bd, nRows);

    EdgeParams EP;
    EP.d[0] = { pre_au, pre_bu, ei_up, deg_up, w1u, b1u,
                CpFrag,        bpc,         wp2u, bp2u, hacc_u, einv_u };
    EP.d[1] = { pre_ad, pre_bd, ei_dn, deg_dn, w1d, b1d,
                CpFrag + 8192, bpc + H_DIM, wp2d, bp2d, hacc_d, einv_d };

    dim3 egrid((E + TEC - 1) / TEC, B, 2);
    edge_mma_kernel<<<egrid, 256, smemEdge>>>(EP, pos, pos_upd, E, N);

    node2_mma_kernel<<<(nRows + 63) / 64, 256, smemNode>>>(
        feat, hacc_u, hacc_d, nodeFrag, einv_u, einv_d,
        bcu, bcu + H_DIM, bu1, bu2, (float*)d_out, N, nRows);

    size_t featN = (size_t)nRows * H_DIM;
    int pn = nRows * 3;
    pos_kernel<<<(pn + 255) / 256, 256>>>(
        pos, pos_upd, (float*)d_out + featN, pn);
}